// round 1
// baseline (speedup 1.0000x reference)
#include <cuda_runtime.h>
#include <cuda_bf16.h>
#include <math_constants.h>

#define TT 4
#define NN 20000
#define EE 160000
#define IN_DIM 64
#define DD 128
#define G3 384   // 3*D
#define QKVS 512 // q|k|v|skip packed

// ------------------- static device scratch (no runtime allocs) -------------------
__device__ float g_GI[(size_t)TT * NN * G3];   // gi for all timesteps  [T*N,384]
__device__ float g_GH[(size_t)NN * G3];        // gh for current step   [N,384]
__device__ float g_H [(size_t)NN * DD];        // GRU hidden
__device__ float g_HA[(size_t)NN * DD];        // conv layer-0 output
__device__ float g_HS[(size_t)NN * DD];        // sum over t of conv outputs
__device__ float g_QK[(size_t)NN * QKVS];      // q|k|v|skip per node
__device__ float g_WIHT[IN_DIM * G3];          // W_ih^T
__device__ float g_WHHT[DD * G3];              // W_hh^T
__device__ float g_WPK[2 * DD * QKVS];         // packed conv weights per layer
__device__ float g_BPK[2 * QKVS];              // packed conv biases
__device__ float g_OQ[NN], g_OKs[NN], g_OV[NN], g_OSK[NN];
__device__ int   g_RP [TT * (NN + 1)];
__device__ int   g_EID[TT * EE];
__device__ int   g_CNT[TT * NN];
__device__ int   g_CUR[TT * NN];

// ------------------------------- small utility kernels ---------------------------
__global__ void k_zero_f(float* p, int n) {
    int i = blockIdx.x * blockDim.x + threadIdx.x;
    if (i < n) p[i] = 0.f;
}
__global__ void k_zero_i(int* p, int n) {
    int i = blockIdx.x * blockDim.x + threadIdx.x;
    if (i < n) p[i] = 0;
}

__global__ void k_transpose_gru(const float* __restrict__ Wih, const float* __restrict__ Whh,
                                float* __restrict__ WihT, float* __restrict__ WhhT) {
    int i = blockIdx.x * blockDim.x + threadIdx.x;
    if (i < G3 * IN_DIM) {
        int j = i / IN_DIM, k = i % IN_DIM;
        WihT[k * G3 + j] = Wih[i];
    } else if (i < G3 * IN_DIM + G3 * DD) {
        int i2 = i - G3 * IN_DIM;
        int j = i2 / DD, k = i2 % DD;
        WhhT[k * G3 + j] = Whh[i2];
    }
}

__global__ void k_pack_conv(const float* __restrict__ Wq, const float* __restrict__ Wk,
                            const float* __restrict__ Wv, const float* __restrict__ Ws,
                            const float* __restrict__ bq, const float* __restrict__ bk,
                            const float* __restrict__ bv, const float* __restrict__ bs,
                            float* __restrict__ WP, float* __restrict__ BP) {
    int i = blockIdx.x * blockDim.x + threadIdx.x;
    if (i < 2 * DD * QKVS) {
        int l = i / (DD * QKVS);
        int rem = i % (DD * QKVS);
        int k = rem / QKVS, c = rem % QKVS;
        int base = l * DD * DD + k * DD;
        float v;
        if      (c < 128) v = Wq[base + c];
        else if (c < 256) v = Wk[base + c - 128];
        else if (c < 384) v = Wv[base + c - 256];
        else              v = Ws[base + c - 384];
        WP[i] = v;
    }
    if (i < 2 * QKVS) {
        int l = i / QKVS, c = i % QKVS;
        int b2 = l * DD;
        float v;
        if      (c < 128) v = bq[b2 + c];
        else if (c < 256) v = bk[b2 + c - 128];
        else if (c < 384) v = bv[b2 + c - 256];
        else              v = bs[b2 + c - 384];
        BP[i] = v;
    }
}

// ------------------------------- CSR build ---------------------------------------
__global__ void k_hist(const int* __restrict__ ei, int* __restrict__ cnt) {
    int i = blockIdx.x * blockDim.x + threadIdx.x;
    if (i >= TT * EE) return;
    int t = i / EE, e = i % EE;
    int dst = ei[(size_t)t * 2 * EE + EE + e];
    atomicAdd(&cnt[t * NN + dst], 1);
}

__global__ void k_scan(const int* __restrict__ cnt, int* __restrict__ rowptr, int* __restrict__ cur) {
    int t = blockIdx.x;
    __shared__ int sh[1024];
    const int* c = cnt + t * NN;
    int* rp = rowptr + t * (NN + 1);
    int* cu = cur + t * NN;
    int carry = 0;
    for (int base = 0; base < NN; base += 1024) {
        int idx = base + threadIdx.x;
        int v = (idx < NN) ? c[idx] : 0;
        sh[threadIdx.x] = v;
        __syncthreads();
        for (int off = 1; off < 1024; off <<= 1) {
            int tval = (threadIdx.x >= off) ? sh[threadIdx.x - off] : 0;
            __syncthreads();
            sh[threadIdx.x] += tval;
            __syncthreads();
        }
        int excl = sh[threadIdx.x] - v;
        if (idx < NN) { rp[idx] = carry + excl; cu[idx] = carry + excl; }
        carry += sh[1023];
        __syncthreads();
    }
    if (threadIdx.x == 0) rp[NN] = carry;
}

__global__ void k_scatter(const int* __restrict__ ei, int* __restrict__ cur, int* __restrict__ eids) {
    int i = blockIdx.x * blockDim.x + threadIdx.x;
    if (i >= TT * EE) return;
    int t = i / EE, e = i % EE;
    int dst = ei[(size_t)t * 2 * EE + EE + e];
    int p = atomicAdd(&cur[t * NN + dst], 1);
    eids[(size_t)t * EE + p] = e;
}

// ------------------------------- SGEMM: C = A[M,K] @ B[K,Nc] + bias --------------
// 128x128 block tile, 8x8 per-thread microtile, K chunked by 32 through smem.
template <int K>
__global__ void __launch_bounds__(256) k_sgemm(const float* __restrict__ A,
                                               const float* __restrict__ B,
                                               const float* __restrict__ bias,
                                               float* __restrict__ C,
                                               int M, int Nc) {
    constexpr int KB = 32;
    __shared__ float As[KB][128]; // [k][row]
    __shared__ float Bs[KB][128]; // [k][col]
    int tid = threadIdx.x;
    int rowBase = blockIdx.y * 128;
    int colBase = blockIdx.x * 128;
    float acc[8][8];
#pragma unroll
    for (int i = 0; i < 8; i++)
#pragma unroll
        for (int j = 0; j < 8; j++) acc[i][j] = 0.f;

    int ty = tid >> 4, tx = tid & 15;

    for (int k0 = 0; k0 < K; k0 += KB) {
        // load A tile (transposed into smem)
        {
            int kq = tid & 7;    // which float4 of 32 k
            int r0 = tid >> 3;   // 0..31
#pragma unroll
            for (int rr = 0; rr < 4; rr++) {
                int row = r0 + rr * 32;
                int grow = rowBase + row;
                float4 v = make_float4(0.f, 0.f, 0.f, 0.f);
                if (grow < M) v = *(const float4*)&A[(size_t)grow * K + k0 + kq * 4];
                As[kq * 4 + 0][row] = v.x;
                As[kq * 4 + 1][row] = v.y;
                As[kq * 4 + 2][row] = v.z;
                As[kq * 4 + 3][row] = v.w;
            }
        }
        // load B tile
        {
            int cq = tid & 31;
            int kk0 = tid >> 5; // 0..7
#pragma unroll
            for (int rr = 0; rr < 4; rr++) {
                int kk = kk0 + rr * 8;
                float4 v = *(const float4*)&B[(size_t)(k0 + kk) * Nc + colBase + cq * 4];
                *(float4*)&Bs[kk][cq * 4] = v;
            }
        }
        __syncthreads();
#pragma unroll
        for (int k = 0; k < KB; k++) {
            float a[8], b[8];
            *(float4*)&a[0] = *(const float4*)&As[k][ty * 8];
            *(float4*)&a[4] = *(const float4*)&As[k][ty * 8 + 4];
            *(float4*)&b[0] = *(const float4*)&Bs[k][tx * 8];
            *(float4*)&b[4] = *(const float4*)&Bs[k][tx * 8 + 4];
#pragma unroll
            for (int i = 0; i < 8; i++)
#pragma unroll
                for (int j = 0; j < 8; j++) acc[i][j] += a[i] * b[j];
        }
        __syncthreads();
    }

#pragma unroll
    for (int i = 0; i < 8; i++) {
        int grow = rowBase + ty * 8 + i;
        if (grow >= M) continue;
#pragma unroll
        for (int j = 0; j < 8; j += 4) {
            int col = colBase + tx * 8 + j;
            float4 v;
            v.x = acc[i][j + 0] + (bias ? bias[col + 0] : 0.f);
            v.y = acc[i][j + 1] + (bias ? bias[col + 1] : 0.f);
            v.z = acc[i][j + 2] + (bias ? bias[col + 2] : 0.f);
            v.w = acc[i][j + 3] + (bias ? bias[col + 3] : 0.f);
            *(float4*)&C[(size_t)grow * Nc + col] = v;
        }
    }
}

// ------------------------------- GRU gates ---------------------------------------
__global__ void k_gru_gate(const float* __restrict__ GI, const float* __restrict__ GH,
                           float* __restrict__ H) {
    int i = blockIdx.x * blockDim.x + threadIdx.x;
    if (i >= NN * DD) return;
    int n = i >> 7, j = i & 127;
    const float* gi = GI + (size_t)n * G3;
    const float* gh = GH + (size_t)n * G3;
    float ir = gi[j], iz = gi[j + 128], in = gi[j + 256];
    float hr = gh[j], hz = gh[j + 128], hn = gh[j + 256];
    float r = 1.f / (1.f + __expf(-(ir + hr)));
    float z = 1.f / (1.f + __expf(-(iz + hz)));
    float nv = tanhf(in + r * hn);
    float hp = H[i];
    H[i] = (1.f - z) * nv + z * hp;
}

// ---------------------- TransformerConv edge attention (D=128) -------------------
// warp per destination node, online softmax, 4 channels per lane
__global__ void k_conv_edge(const float* __restrict__ qkvs,
                            const int* __restrict__ rowptr, const int* __restrict__ eids,
                            const int* __restrict__ src_arr, const float* __restrict__ eattr,
                            const float* __restrict__ We, float* __restrict__ out,
                            int accum) {
    int w = (blockIdx.x * blockDim.x + threadIdx.x) >> 5;
    if (w >= NN) return;
    int lane = threadIdx.x & 31;
    int c0 = lane * 4;
    float4 q  = *(const float4*)&qkvs[(size_t)w * QKVS + c0];
    float4 sk = *(const float4*)&qkvs[(size_t)w * QKVS + 384 + c0];
    float4 we = *(const float4*)&We[c0];
    float m = -CUDART_INF_F, s = 0.f;
    float4 acc = make_float4(0.f, 0.f, 0.f, 0.f);
    int beg = rowptr[w], end = rowptr[w + 1];
    for (int i = beg; i < end; i++) {
        int e = eids[i];
        int sn = src_arr[e];
        float eaV = eattr[e];
        float4 k4 = *(const float4*)&qkvs[(size_t)sn * QKVS + 128 + c0];
        float4 v4 = *(const float4*)&qkvs[(size_t)sn * QKVS + 256 + c0];
        float ex = eaV * we.x, ey = eaV * we.y, ez = eaV * we.z, ew = eaV * we.w;
        float part = q.x * (k4.x + ex) + q.y * (k4.y + ey) + q.z * (k4.z + ez) + q.w * (k4.w + ew);
#pragma unroll
        for (int o = 16; o; o >>= 1) part += __shfl_xor_sync(0xffffffffu, part, o);
        float alpha = part * 0.08838834764831845f; // 1/sqrt(128)
        float mn = fmaxf(m, alpha);
        float corr = __expf(m - mn);
        float p = __expf(alpha - mn);
        s = s * corr + p;
        acc.x = acc.x * corr + p * (v4.x + ex);
        acc.y = acc.y * corr + p * (v4.y + ey);
        acc.z = acc.z * corr + p * (v4.z + ez);
        acc.w = acc.w * corr + p * (v4.w + ew);
        m = mn;
    }
    float inv = 1.f / (s + 1e-16f);
    float4 o;
    o.x = acc.x * inv + sk.x;
    o.y = acc.y * inv + sk.y;
    o.z = acc.z * inv + sk.z;
    o.w = acc.w * inv + sk.w;
    // leaky_relu(0.01)
    o.x = o.x > 0.f ? o.x : 0.01f * o.x;
    o.y = o.y > 0.f ? o.y : 0.01f * o.y;
    o.z = o.z > 0.f ? o.z : 0.01f * o.z;
    o.w = o.w > 0.f ? o.w : 0.01f * o.w;
    if (accum) {
        float4 prev = *(const float4*)&out[(size_t)w * DD + c0];
        o.x += prev.x; o.y += prev.y; o.z += prev.z; o.w += prev.w;
    }
    *(float4*)&out[(size_t)w * DD + c0] = o;
}

// ------------------------ output conv (D -> 1) -----------------------------------
__global__ void k_out_node(const float* __restrict__ hsum,
                           const float* __restrict__ Wq, const float* __restrict__ bq,
                           const float* __restrict__ Wk, const float* __restrict__ bk,
                           const float* __restrict__ Wv, const float* __restrict__ bv,
                           const float* __restrict__ Ws, const float* __restrict__ bs,
                           float* __restrict__ oq, float* __restrict__ ok,
                           float* __restrict__ ov, float* __restrict__ osk) {
    int w = (blockIdx.x * blockDim.x + threadIdx.x) >> 5;
    if (w >= NN) return;
    int lane = threadIdx.x & 31;
    int c0 = lane * 4;
    float4 h = *(const float4*)&hsum[(size_t)w * DD + c0];
    h.x *= 0.25f; h.y *= 0.25f; h.z *= 0.25f; h.w *= 0.25f;
    float4 wq = *(const float4*)&Wq[c0];
    float4 wk = *(const float4*)&Wk[c0];
    float4 wv = *(const float4*)&Wv[c0];
    float4 ws = *(const float4*)&Ws[c0];
    float dq = h.x * wq.x + h.y * wq.y + h.z * wq.z + h.w * wq.w;
    float dk = h.x * wk.x + h.y * wk.y + h.z * wk.z + h.w * wk.w;
    float dv = h.x * wv.x + h.y * wv.y + h.z * wv.z + h.w * wv.w;
    float ds = h.x * ws.x + h.y * ws.y + h.z * ws.z + h.w * ws.w;
#pragma unroll
    for (int o = 16; o; o >>= 1) {
        dq += __shfl_xor_sync(0xffffffffu, dq, o);
        dk += __shfl_xor_sync(0xffffffffu, dk, o);
        dv += __shfl_xor_sync(0xffffffffu, dv, o);
        ds += __shfl_xor_sync(0xffffffffu, ds, o);
    }
    if (lane == 0) {
        oq[w]  = dq + bq[0];
        ok[w]  = dk + bk[0];
        ov[w]  = dv + bv[0];
        osk[w] = ds + bs[0];
    }
}

__global__ void k_out_edge(const int* __restrict__ rowptr, const int* __restrict__ eids,
                           const int* __restrict__ src_arr, const float* __restrict__ eattr,
                           const float* __restrict__ We,
                           const float* __restrict__ oq, const float* __restrict__ ok,
                           const float* __restrict__ ov, const float* __restrict__ osk,
                           float* __restrict__ out) {
    int n = blockIdx.x * blockDim.x + threadIdx.x;
    if (n >= NN) return;
    float q = oq[n];
    float we = We[0];
    float m = -CUDART_INF_F, s = 0.f, acc = 0.f;
    int beg = rowptr[n], end = rowptr[n + 1];
    for (int i = beg; i < end; i++) {
        int e = eids[i];
        int sn = src_arr[e];
        float et = eattr[e] * we;
        float alpha = q * (ok[sn] + et); // 1/sqrt(1) = 1
        float mn = fmaxf(m, alpha);
        float corr = __expf(m - mn);
        float p = __expf(alpha - mn);
        s = s * corr + p;
        acc = acc * corr + p * (ov[sn] + et);
        m = mn;
    }
    out[n] = acc / (s + 1e-16f) + osk[n];
}

// =================================== host side ====================================
extern "C" void kernel_launch(void* const* d_in, const int* in_sizes, int n_in,
                              void* d_out, int out_size) {
    // ---- resolve inputs by element count (robust to dict vs signature ordering) ----
    const float* x_seq = nullptr;
    const int*   ei    = nullptr;
    const float* ea    = nullptr;
    const float* P[22];
    int r = 0;
    for (int i = 0; i < n_in; i++) {
        if      (in_sizes[i] == TT * NN * IN_DIM) x_seq = (const float*)d_in[i];
        else if (in_sizes[i] == TT * 2 * EE)      ei    = (const int*)d_in[i];
        else if (in_sizes[i] == TT * EE)          ea    = (const float*)d_in[i];
        else if (r < 22)                          P[r++] = (const float*)d_in[i];
    }
    const float* gW_ih   = P[0];
    const float* gW_hh   = P[1];
    const float* gb_ih   = P[2];
    const float* gb_hh   = P[3];
    const float* cWq     = P[4];
    const float* cbq     = P[5];
    const float* cWk     = P[6];
    const float* cbk     = P[7];
    const float* cWv     = P[8];
    const float* cbv     = P[9];
    const float* cWe     = P[10];
    const float* cWs     = P[11];
    const float* cbs     = P[12];
    const float* oWq     = P[13];
    const float* obq     = P[14];
    const float* oWk     = P[15];
    const float* obk     = P[16];
    const float* oWv     = P[17];
    const float* obv     = P[18];
    const float* oWe     = P[19];
    const float* oWs     = P[20];
    const float* obs     = P[21];

    float *GI, *GH, *H, *HA, *HS, *QK, *WIHT, *WHHT, *WPK, *BPK, *OQ, *OKp, *OV, *OSK;
    int *RP, *EID, *CNT, *CUR;
    cudaGetSymbolAddress((void**)&GI,   g_GI);
    cudaGetSymbolAddress((void**)&GH,   g_GH);
    cudaGetSymbolAddress((void**)&H,    g_H);
    cudaGetSymbolAddress((void**)&HA,   g_HA);
    cudaGetSymbolAddress((void**)&HS,   g_HS);
    cudaGetSymbolAddress((void**)&QK,   g_QK);
    cudaGetSymbolAddress((void**)&WIHT, g_WIHT);
    cudaGetSymbolAddress((void**)&WHHT, g_WHHT);
    cudaGetSymbolAddress((void**)&WPK,  g_WPK);
    cudaGetSymbolAddress((void**)&BPK,  g_BPK);
    cudaGetSymbolAddress((void**)&OQ,   g_OQ);
    cudaGetSymbolAddress((void**)&OKp,  g_OKs);
    cudaGetSymbolAddress((void**)&OV,   g_OV);
    cudaGetSymbolAddress((void**)&OSK,  g_OSK);
    cudaGetSymbolAddress((void**)&RP,   g_RP);
    cudaGetSymbolAddress((void**)&EID,  g_EID);
    cudaGetSymbolAddress((void**)&CNT,  g_CNT);
    cudaGetSymbolAddress((void**)&CUR,  g_CUR);

    const int TPB = 256;

    // init state
    k_zero_f<<<(NN * DD + TPB - 1) / TPB, TPB>>>(H, NN * DD);
    k_zero_f<<<(NN * DD + TPB - 1) / TPB, TPB>>>(HS, NN * DD);
    k_zero_i<<<(TT * NN + TPB - 1) / TPB, TPB>>>(CNT, TT * NN);

    // weight prep
    k_transpose_gru<<<(G3 * IN_DIM + G3 * DD + TPB - 1) / TPB, TPB>>>(gW_ih, gW_hh, WIHT, WHHT);
    k_pack_conv<<<(2 * DD * QKVS + TPB - 1) / TPB, TPB>>>(cWq, cWk, cWv, cWs, cbq, cbk, cbv, cbs, WPK, BPK);

    // CSR build for all 4 timesteps
    k_hist<<<(TT * EE + TPB - 1) / TPB, TPB>>>(ei, CNT);
    k_scan<<<TT, 1024>>>(CNT, RP, CUR);
    k_scatter<<<(TT * EE + TPB - 1) / TPB, TPB>>>(ei, CUR, EID);

    // GI = X @ W_ih^T + b_ih for all T at once: [80000,64] @ [64,384]
    k_sgemm<64><<<dim3(G3 / 128, (TT * NN + 127) / 128), 256>>>(x_seq, WIHT, gb_ih, GI, TT * NN, G3);

    for (int t = 0; t < TT; t++) {
        // GH = h @ W_hh^T + b_hh : [20000,128] @ [128,384]
        k_sgemm<128><<<dim3(G3 / 128, (NN + 127) / 128), 256>>>(H, WHHT, gb_hh, GH, NN, G3);
        k_gru_gate<<<(NN * DD + TPB - 1) / TPB, TPB>>>(GI + (size_t)t * NN * G3, GH, H);

        const int* rp_t  = RP + t * (NN + 1);
        const int* eid_t = EID + (size_t)t * EE;
        const int* src_t = ei + (size_t)t * 2 * EE;
        const float* ea_t = ea + (size_t)t * EE;

        // layer 0: qkvs from GRU output
        k_sgemm<128><<<dim3(QKVS / 128, (NN + 127) / 128), 256>>>(H, WPK, BPK, QK, NN, QKVS);
        k_conv_edge<<<NN / 8, 256>>>(QK, rp_t, eid_t, src_t, ea_t, cWe, HA, 0);

        // layer 1: qkvs from layer-0 output; accumulate into HS
        k_sgemm<128><<<dim3(QKVS / 128, (NN + 127) / 128), 256>>>(HA, WPK + DD * QKVS, BPK + QKVS, QK, NN, QKVS);
        k_conv_edge<<<NN / 8, 256>>>(QK, rp_t, eid_t, src_t, ea_t, cWe + DD, HS, 1);
    }

    // output conv (edges of last timestep)
    k_out_node<<<NN / 8, 256>>>(HS, oWq, obq, oWk, obk, oWv, obv, oWs, obs, OQ, OKp, OV, OSK);
    k_out_edge<<<(NN + TPB - 1) / TPB, TPB>>>(RP + (TT - 1) * (NN + 1), EID + (size_t)(TT - 1) * EE,
                                              ei + (size_t)(TT - 1) * 2 * EE, ea + (size_t)(TT - 1) * EE,
                                              oWe, OQ, OKp, OV, OSK, (float*)d_out);
}

// round 3
// speedup vs baseline: 1.3524x; 1.3524x over previous
#include <cuda_runtime.h>
#include <cuda_bf16.h>
#include <math_constants.h>
#include <cstdint>

#define TT 4
#define NN 20000
#define EE 160000
#define IN_DIM 64
#define DD 128
#define G3 384   // 3*D
#define QKVS 512 // q|k|v|skip packed

// ------------------- static device scratch (no runtime allocs) -------------------
__device__ float g_GI[(size_t)TT * NN * G3];
__device__ float g_GH[(size_t)NN * G3];
__device__ float g_H [(size_t)NN * DD];
__device__ float g_HA[(size_t)NN * DD];
__device__ float g_HS[(size_t)NN * DD];
__device__ float g_QK[(size_t)NN * QKVS];
// weights pre-split to bf16 hi/lo, [N][K] layout
__device__ __nv_bfloat16 g_WIHh[G3 * IN_DIM], g_WIHl[G3 * IN_DIM];
__device__ __nv_bfloat16 g_WHHh[G3 * DD],     g_WHHl[G3 * DD];
__device__ __nv_bfloat16 g_WPKh[2 * QKVS * DD], g_WPKl[2 * QKVS * DD];
__device__ float g_BPK[2 * QKVS];
__device__ float g_OQ[NN], g_OKs[NN], g_OV[NN], g_OSK[NN];
__device__ int   g_RP [TT * (NN + 1)];
__device__ int   g_EID[TT * EE];
__device__ int   g_CNT[TT * NN];
__device__ int   g_CUR[TT * NN];

// ------------------------------- small utility kernels ---------------------------
__global__ void k_zero_f(float* p, int n) {
    int i = blockIdx.x * blockDim.x + threadIdx.x;
    if (i < n) p[i] = 0.f;
}
__global__ void k_zero_i(int* p, int n) {
    int i = blockIdx.x * blockDim.x + threadIdx.x;
    if (i < n) p[i] = 0;
}

__device__ __forceinline__ void split_bf16(float v, __nv_bfloat16& h, __nv_bfloat16& l) {
    h = __float2bfloat16_rn(v);
    l = __float2bfloat16_rn(v - __bfloat162float(h));
}

// GRU weights: W_ih [384,64] and W_hh [384,128] are natively [N,K].
__global__ void k_prep_gru(const float* __restrict__ Wih, const float* __restrict__ Whh,
                           __nv_bfloat16* __restrict__ ah, __nv_bfloat16* __restrict__ al,
                           __nv_bfloat16* __restrict__ bh, __nv_bfloat16* __restrict__ bl) {
    int i = blockIdx.x * blockDim.x + threadIdx.x;
    if (i < G3 * IN_DIM) split_bf16(Wih[i], ah[i], al[i]);
    int j = i - G3 * IN_DIM;
    if (j >= 0 && j < G3 * DD) split_bf16(Whh[j], bh[j], bl[j]);
}

// Pack conv weights transposed into [layer][n(512)][k(128)] hi/lo + bias pack
__global__ void k_prep_conv(const float* __restrict__ Wq, const float* __restrict__ Wk,
                            const float* __restrict__ Wv, const float* __restrict__ Ws,
                            const float* __restrict__ bq, const float* __restrict__ bk,
                            const float* __restrict__ bv, const float* __restrict__ bs,
                            __nv_bfloat16* __restrict__ WPh, __nv_bfloat16* __restrict__ WPl,
                            float* __restrict__ BP) {
    int i = blockIdx.x * blockDim.x + threadIdx.x;
    if (i < 2 * QKVS * DD) {
        int l = i >> 16;
        int rem = i & 65535;
        int n = rem >> 7, k = rem & 127;
        int base = l * DD * DD + k * DD;
        float v;
        if      (n < 128) v = Wq[base + n];
        else if (n < 256) v = Wk[base + n - 128];
        else if (n < 384) v = Wv[base + n - 256];
        else              v = Ws[base + n - 384];
        split_bf16(v, WPh[i], WPl[i]);
    }
    if (i < 2 * QKVS) {
        int l = i >> 9, c = i & 511;
        int b2 = l * DD;
        float v;
        if      (c < 128) v = bq[b2 + c];
        else if (c < 256) v = bk[b2 + c - 128];
        else if (c < 384) v = bv[b2 + c - 256];
        else              v = bs[b2 + c - 384];
        BP[i] = v;
    }
}

// ------------------------------- CSR build ---------------------------------------
__global__ void k_hist(const int* __restrict__ ei, int* __restrict__ cnt) {
    int i = blockIdx.x * blockDim.x + threadIdx.x;
    if (i >= TT * EE) return;
    int t = i / EE, e = i % EE;
    int dst = ei[(size_t)t * 2 * EE + EE + e];
    atomicAdd(&cnt[t * NN + dst], 1);
}

__global__ void k_scan(const int* __restrict__ cnt, int* __restrict__ rowptr, int* __restrict__ cur) {
    int t = blockIdx.x;
    __shared__ int sh[1024];
    const int* c = cnt + t * NN;
    int* rp = rowptr + t * (NN + 1);
    int* cu = cur + t * NN;
    int carry = 0;
    for (int base = 0; base < NN; base += 1024) {
        int idx = base + threadIdx.x;
        int v = (idx < NN) ? c[idx] : 0;
        sh[threadIdx.x] = v;
        __syncthreads();
        for (int off = 1; off < 1024; off <<= 1) {
            int tval = (threadIdx.x >= off) ? sh[threadIdx.x - off] : 0;
            __syncthreads();
            sh[threadIdx.x] += tval;
            __syncthreads();
        }
        int excl = sh[threadIdx.x] - v;
        if (idx < NN) { rp[idx] = carry + excl; cu[idx] = carry + excl; }
        carry += sh[1023];
        __syncthreads();
    }
    if (threadIdx.x == 0) rp[NN] = carry;
}

__global__ void k_scatter(const int* __restrict__ ei, int* __restrict__ cur, int* __restrict__ eids) {
    int i = blockIdx.x * blockDim.x + threadIdx.x;
    if (i >= TT * EE) return;
    int t = i / EE, e = i % EE;
    int dst = ei[(size_t)t * 2 * EE + EE + e];
    int p = atomicAdd(&cur[t * NN + dst], 1);
    eids[(size_t)t * EE + p] = e;
}

// ===================== bf16 HMMA GEMM with 3-pass split ===========================
// C[M,Nc] = A[M,K] @ B^T + bias, B pre-split bf16 hi/lo stored [Nc][K].
// A split in-kernel. D = Ahi*Bhi + Ahi*Blo + Alo*Bhi (fp32 accumulate).
#define KC 32          // K chunk through smem
#define AST 40         // smem row stride (bf16 units), conflict-free pad

__device__ __forceinline__ void mma_bf16(float c[4], const uint32_t a[4],
                                         uint32_t b0, uint32_t b1) {
    asm volatile(
        "mma.sync.aligned.m16n8k16.row.col.f32.bf16.bf16.f32 "
        "{%0,%1,%2,%3}, {%4,%5,%6,%7}, {%8,%9}, {%0,%1,%2,%3};"
        : "+f"(c[0]), "+f"(c[1]), "+f"(c[2]), "+f"(c[3])
        : "r"(a[0]), "r"(a[1]), "r"(a[2]), "r"(a[3]), "r"(b0), "r"(b1));
}

__device__ __forceinline__ uint32_t pack_bf16x2(float v_lo, float v_hi) {
    uint32_t d;
    asm("cvt.rn.bf16x2.f32 %0, %1, %2;" : "=r"(d) : "f"(v_hi), "f"(v_lo));
    return d;
}

__global__ void __launch_bounds__(256) k_mmagemm(
    const float* __restrict__ A,
    const __nv_bfloat16* __restrict__ Bhi, const __nv_bfloat16* __restrict__ Blo,
    const float* __restrict__ bias, float* __restrict__ C, int M, int Nc, int K) {
    __shared__ __nv_bfloat16 sAhi[128 * AST];
    __shared__ __nv_bfloat16 sAlo[128 * AST];
    __shared__ __nv_bfloat16 sBhi[128 * AST];
    __shared__ __nv_bfloat16 sBlo[128 * AST];

    int tid = threadIdx.x, wid = tid >> 5, lane = tid & 31;
    int gid = lane >> 2, t4 = lane & 3;
    int rowBase = blockIdx.y * 128;
    int colBase = blockIdx.x * 128;
    int warpRow = (wid & 3) * 32;
    int warpCol = (wid >> 2) * 64;

    float acc[2][8][4];
#pragma unroll
    for (int mt = 0; mt < 2; mt++)
#pragma unroll
        for (int nt = 0; nt < 8; nt++)
#pragma unroll
            for (int q = 0; q < 4; q++) acc[mt][nt][q] = 0.f;

    const uint32_t* B32h = (const uint32_t*)Bhi;
    const uint32_t* B32l = (const uint32_t*)Blo;
    int K2 = K >> 1;

    int nchunk = K / KC;
    for (int ch = 0; ch < nchunk; ch++) {
        int k0 = ch * KC;
        // ---- fill A chunk [128 x 32] f32 -> split bf16 hi/lo ----
#pragma unroll
        for (int it = 0; it < 4; it++) {
            int idx = tid + it * 256;           // 1024 float4
            int r = idx >> 3;
            int c4 = (idx & 7) << 2;
            int grow = rowBase + r;
            float4 v = make_float4(0.f, 0.f, 0.f, 0.f);
            if (grow < M) v = *(const float4*)&A[(size_t)grow * K + k0 + c4];
            float hx = __bfloat162float(__float2bfloat16_rn(v.x));
            float hy = __bfloat162float(__float2bfloat16_rn(v.y));
            float hz = __bfloat162float(__float2bfloat16_rn(v.z));
            float hw = __bfloat162float(__float2bfloat16_rn(v.w));
            uint2 hp, lp;
            hp.x = pack_bf16x2(hx, hy);
            hp.y = pack_bf16x2(hz, hw);
            lp.x = pack_bf16x2(v.x - hx, v.y - hy);
            lp.y = pack_bf16x2(v.z - hz, v.w - hw);
            *(uint2*)&sAhi[r * AST + c4] = hp;
            *(uint2*)&sAlo[r * AST + c4] = lp;
        }
        // ---- fill B chunk [128 x 32] bf16 (pre-split) ----
#pragma unroll
        for (int it = 0; it < 8; it++) {
            int u = tid + it * 256;             // 2048 u32
            int r = u >> 4;
            int cw = u & 15;
            size_t gaddr = (size_t)(colBase + r) * K2 + (k0 >> 1) + cw;
            ((uint32_t*)&sBhi[r * AST])[cw] = B32h[gaddr];
            ((uint32_t*)&sBlo[r * AST])[cw] = B32l[gaddr];
        }
        __syncthreads();

        // ---- 2 k-steps of 16 ----
#pragma unroll
        for (int ks = 0; ks < KC; ks += 16) {
            uint32_t ah[2][4], al[2][4];
#pragma unroll
            for (int mt = 0; mt < 2; mt++) {
                int rbase = (warpRow + mt * 16 + gid) * AST + ks + t4 * 2;
                ah[mt][0] = *(const uint32_t*)&sAhi[rbase];
                ah[mt][1] = *(const uint32_t*)&sAhi[rbase + 8 * AST];
                ah[mt][2] = *(const uint32_t*)&sAhi[rbase + 8];
                ah[mt][3] = *(const uint32_t*)&sAhi[rbase + 8 * AST + 8];
                al[mt][0] = *(const uint32_t*)&sAlo[rbase];
                al[mt][1] = *(const uint32_t*)&sAlo[rbase + 8 * AST];
                al[mt][2] = *(const uint32_t*)&sAlo[rbase + 8];
                al[mt][3] = *(const uint32_t*)&sAlo[rbase + 8 * AST + 8];
            }
            uint32_t bh[8][2], bl[8][2];
#pragma unroll
            for (int nt = 0; nt < 8; nt++) {
                int bbase = (warpCol + nt * 8 + gid) * AST + ks + t4 * 2;
                bh[nt][0] = *(const uint32_t*)&sBhi[bbase];
                bh[nt][1] = *(const uint32_t*)&sBhi[bbase + 8];
                bl[nt][0] = *(const uint32_t*)&sBlo[bbase];
                bl[nt][1] = *(const uint32_t*)&sBlo[bbase + 8];
            }
            // pass 1: hi*hi  (independent accumulators back-to-back)
#pragma unroll
            for (int mt = 0; mt < 2; mt++)
#pragma unroll
                for (int nt = 0; nt < 8; nt++)
                    mma_bf16(acc[mt][nt], ah[mt], bh[nt][0], bh[nt][1]);
            // pass 2: hi*lo
#pragma unroll
            for (int mt = 0; mt < 2; mt++)
#pragma unroll
                for (int nt = 0; nt < 8; nt++)
                    mma_bf16(acc[mt][nt], ah[mt], bl[nt][0], bl[nt][1]);
            // pass 3: lo*hi
#pragma unroll
            for (int mt = 0; mt < 2; mt++)
#pragma unroll
                for (int nt = 0; nt < 8; nt++)
                    mma_bf16(acc[mt][nt], al[mt], bh[nt][0], bh[nt][1]);
        }
        __syncthreads();
    }

    // ---- epilogue: add bias, store ----
#pragma unroll
    for (int mt = 0; mt < 2; mt++) {
        int r0 = rowBase + warpRow + mt * 16 + gid;
        int r1 = r0 + 8;
#pragma unroll
        for (int nt = 0; nt < 8; nt++) {
            int col = colBase + warpCol + nt * 8 + t4 * 2;
            float b0 = bias[col], b1 = bias[col + 1];
            if (r0 < M) {
                float2 o = make_float2(acc[mt][nt][0] + b0, acc[mt][nt][1] + b1);
                *(float2*)&C[(size_t)r0 * Nc + col] = o;
            }
            if (r1 < M) {
                float2 o = make_float2(acc[mt][nt][2] + b0, acc[mt][nt][3] + b1);
                *(float2*)&C[(size_t)r1 * Nc + col] = o;
            }
        }
    }
}

// ------------------------------- GRU gates ---------------------------------------
__global__ void k_gru_gate(const float* __restrict__ GI, const float* __restrict__ GH,
                           float* __restrict__ H) {
    int i = blockIdx.x * blockDim.x + threadIdx.x;
    if (i >= NN * DD) return;
    int n = i >> 7, j = i & 127;
    const float* gi = GI + (size_t)n * G3;
    const float* gh = GH + (size_t)n * G3;
    float ir = gi[j], iz = gi[j + 128], in = gi[j + 256];
    float hr = gh[j], hz = gh[j + 128], hn = gh[j + 256];
    float r = 1.f / (1.f + __expf(-(ir + hr)));
    float z = 1.f / (1.f + __expf(-(iz + hz)));
    float nv = tanhf(in + r * hn);
    float hp = H[i];
    H[i] = (1.f - z) * nv + z * hp;
}

// ---------------------- TransformerConv edge attention (D=128) -------------------
__global__ void k_conv_edge(const float* __restrict__ qkvs,
                            const int* __restrict__ rowptr, const int* __restrict__ eids,
                            const int* __restrict__ src_arr, const float* __restrict__ eattr,
                            const float* __restrict__ We, float* __restrict__ out,
                            int accum) {
    int w = (blockIdx.x * blockDim.x + threadIdx.x) >> 5;
    if (w >= NN) return;
    int lane = threadIdx.x & 31;
    int c0 = lane * 4;
    float4 q  = *(const float4*)&qkvs[(size_t)w * QKVS + c0];
    float4 sk = *(const float4*)&qkvs[(size_t)w * QKVS + 384 + c0];
    float4 we = *(const float4*)&We[c0];
    float m = -CUDART_INF_F, s = 0.f;
    float4 acc = make_float4(0.f, 0.f, 0.f, 0.f);
    int beg = rowptr[w], end = rowptr[w + 1];
    for (int i = beg; i < end; i++) {
        int e = eids[i];
        int sn = src_arr[e];
        float eaV = eattr[e];
        float4 k4 = *(const float4*)&qkvs[(size_t)sn * QKVS + 128 + c0];
        float4 v4 = *(const float4*)&qkvs[(size_t)sn * QKVS + 256 + c0];
        float ex = eaV * we.x, ey = eaV * we.y, ez = eaV * we.z, ew = eaV * we.w;
        float part = q.x * (k4.x + ex) + q.y * (k4.y + ey) + q.z * (k4.z + ez) + q.w * (k4.w + ew);
#pragma unroll
        for (int o = 16; o; o >>= 1) part += __shfl_xor_sync(0xffffffffu, part, o);
        float alpha = part * 0.08838834764831845f; // 1/sqrt(128)
        float mn = fmaxf(m, alpha);
        float corr = __expf(m - mn);
        float p = __expf(alpha - mn);
        s = s * corr + p;
        acc.x = acc.x * corr + p * (v4.x + ex);
        acc.y = acc.y * corr + p * (v4.y + ey);
        acc.z = acc.z * corr + p * (v4.z + ez);
        acc.w = acc.w * corr + p * (v4.w + ew);
        m = mn;
    }
    float inv = 1.f / (s + 1e-16f);
    float4 o;
    o.x = acc.x * inv + sk.x;
    o.y = acc.y * inv + sk.y;
    o.z = acc.z * inv + sk.z;
    o.w = acc.w * inv + sk.w;
    o.x = o.x > 0.f ? o.x : 0.01f * o.x;
    o.y = o.y > 0.f ? o.y : 0.01f * o.y;
    o.z = o.z > 0.f ? o.z : 0.01f * o.z;
    o.w = o.w > 0.f ? o.w : 0.01f * o.w;
    if (accum) {
        float4 prev = *(const float4*)&out[(size_t)w * DD + c0];
        o.x += prev.x; o.y += prev.y; o.z += prev.z; o.w += prev.w;
    }
    *(float4*)&out[(size_t)w * DD + c0] = o;
}

// ------------------------ output conv (D -> 1) -----------------------------------
__global__ void k_out_node(const float* __restrict__ hsum,
                           const float* __restrict__ Wq, const float* __restrict__ bq,
                           const float* __restrict__ Wk, const float* __restrict__ bk,
                           const float* __restrict__ Wv, const float* __restrict__ bv,
                           const float* __restrict__ Ws, const float* __restrict__ bs,
                           float* __restrict__ oq, float* __restrict__ ok,
                           float* __restrict__ ov, float* __restrict__ osk) {
    int w = (blockIdx.x * blockDim.x + threadIdx.x) >> 5;
    if (w >= NN) return;
    int lane = threadIdx.x & 31;
    int c0 = lane * 4;
    float4 h = *(const float4*)&hsum[(size_t)w * DD + c0];
    h.x *= 0.25f; h.y *= 0.25f; h.z *= 0.25f; h.w *= 0.25f;
    float4 wq = *(const float4*)&Wq[c0];
    float4 wk = *(const float4*)&Wk[c0];
    float4 wv = *(const float4*)&Wv[c0];
    float4 ws = *(const float4*)&Ws[c0];
    float dq = h.x * wq.x + h.y * wq.y + h.z * wq.z + h.w * wq.w;
    float dk = h.x * wk.x + h.y * wk.y + h.z * wk.z + h.w * wk.w;
    float dv = h.x * wv.x + h.y * wv.y + h.z * wv.z + h.w * wv.w;
    float ds = h.x * ws.x + h.y * ws.y + h.z * ws.z + h.w * ws.w;
#pragma unroll
    for (int o = 16; o; o >>= 1) {
        dq += __shfl_xor_sync(0xffffffffu, dq, o);
        dk += __shfl_xor_sync(0xffffffffu, dk, o);
        dv += __shfl_xor_sync(0xffffffffu, dv, o);
        ds += __shfl_xor_sync(0xffffffffu, ds, o);
    }
    if (lane == 0) {
        oq[w]  = dq + bq[0];
        ok[w]  = dk + bk[0];
        ov[w]  = dv + bv[0];
        osk[w] = ds + bs[0];
    }
}

__global__ void k_out_edge(const int* __restrict__ rowptr, const int* __restrict__ eids,
                           const int* __restrict__ src_arr, const float* __restrict__ eattr,
                           const float* __restrict__ We,
                           const float* __restrict__ oq, const float* __restrict__ ok,
                           const float* __restrict__ ov, const float* __restrict__ osk,
                           float* __restrict__ out) {
    int n = blockIdx.x * blockDim.x + threadIdx.x;
    if (n >= NN) return;
    float q = oq[n];
    float we = We[0];
    float m = -CUDART_INF_F, s = 0.f, acc = 0.f;
    int beg = rowptr[n], end = rowptr[n + 1];
    for (int i = beg; i < end; i++) {
        int e = eids[i];
        int sn = src_arr[e];
        float et = eattr[e] * we;
        float alpha = q * (ok[sn] + et);
        float mn = fmaxf(m, alpha);
        float corr = __expf(m - mn);
        float p = __expf(alpha - mn);
        s = s * corr + p;
        acc = acc * corr + p * (ov[sn] + et);
        m = mn;
    }
    out[n] = acc / (s + 1e-16f) + osk[n];
}

// =================================== host side ====================================
extern "C" void kernel_launch(void* const* d_in, const int* in_sizes, int n_in,
                              void* d_out, int out_size) {
    const float* x_seq = nullptr;
    const int*   ei    = nullptr;
    const float* ea    = nullptr;
    const float* P[22];
    int r = 0;
    for (int i = 0; i < n_in; i++) {
        if      (in_sizes[i] == TT * NN * IN_DIM) x_seq = (const float*)d_in[i];
        else if (in_sizes[i] == TT * 2 * EE)      ei    = (const int*)d_in[i];
        else if (in_sizes[i] == TT * EE)          ea    = (const float*)d_in[i];
        else if (r < 22)                          P[r++] = (const float*)d_in[i];
    }
    const float* gW_ih = P[0];
    const float* gW_hh = P[1];
    const float* gb_ih = P[2];
    const float* gb_hh = P[3];
    const float* cWq   = P[4];
    const float* cbq   = P[5];
    const float* cWk   = P[6];
    const float* cbk   = P[7];
    const float* cWv   = P[8];
    const float* cbv   = P[9];
    const float* cWe   = P[10];
    const float* cWs   = P[11];
    const float* cbs   = P[12];
    const float* oWq   = P[13];
    const float* obq   = P[14];
    const float* oWk   = P[15];
    const float* obk   = P[16];
    const float* oWv   = P[17];
    const float* obv   = P[18];
    const float* oWe   = P[19];
    const float* oWs   = P[20];
    const float* obs   = P[21];

    float *GI, *GH, *H, *HA, *HS, *QK, *BPK;
    __nv_bfloat16 *WIHh, *WIHl, *WHHh, *WHHl, *WPh, *WPl;
    float *OQ, *OKp, *OV, *OSK;
    int *RP, *EID, *CNT, *CUR;
    cudaGetSymbolAddress((void**)&GI,   g_GI);
    cudaGetSymbolAddress((void**)&GH,   g_GH);
    cudaGetSymbolAddress((void**)&H,    g_H);
    cudaGetSymbolAddress((void**)&HA,   g_HA);
    cudaGetSymbolAddress((void**)&HS,   g_HS);
    cudaGetSymbolAddress((void**)&QK,   g_QK);
    cudaGetSymbolAddress((void**)&WIHh, g_WIHh);
    cudaGetSymbolAddress((void**)&WIHl, g_WIHl);
    cudaGetSymbolAddress((void**)&WHHh, g_WHHh);
    cudaGetSymbolAddress((void**)&WHHl, g_WHHl);
    cudaGetSymbolAddress((void**)&WPh,  g_WPKh);
    cudaGetSymbolAddress((void**)&WPl,  g_WPKl);
    cudaGetSymbolAddress((void**)&BPK,  g_BPK);
    cudaGetSymbolAddress((void**)&OQ,   g_OQ);
    cudaGetSymbolAddress((void**)&OKp,  g_OKs);
    cudaGetSymbolAddress((void**)&OV,   g_OV);
    cudaGetSymbolAddress((void**)&OSK,  g_OSK);
    cudaGetSymbolAddress((void**)&RP,   g_RP);
    cudaGetSymbolAddress((void**)&EID,  g_EID);
    cudaGetSymbolAddress((void**)&CNT,  g_CNT);
    cudaGetSymbolAddress((void**)&CUR,  g_CUR);

    const int TPB = 256;

    // init state
    k_zero_f<<<(NN * DD + TPB - 1) / TPB, TPB>>>(H, NN * DD);
    k_zero_f<<<(NN * DD + TPB - 1) / TPB, TPB>>>(HS, NN * DD);
    k_zero_i<<<(TT * NN + TPB - 1) / TPB, TPB>>>(CNT, TT * NN);

    // weight prep (bf16 hi/lo split)
    k_prep_gru<<<(G3 * IN_DIM + G3 * DD + TPB - 1) / TPB, TPB>>>(gW_ih, gW_hh, WIHh, WIHl, WHHh, WHHl);
    k_prep_conv<<<(2 * QKVS * DD + TPB - 1) / TPB, TPB>>>(cWq, cWk, cWv, cWs, cbq, cbk, cbv, cbs, WPh, WPl, BPK);

    // CSR build for all 4 timesteps
    k_hist<<<(TT * EE + TPB - 1) / TPB, TPB>>>(ei, CNT);
    k_scan<<<TT, 1024>>>(CNT, RP, CUR);
    k_scatter<<<(TT * EE + TPB - 1) / TPB, TPB>>>(ei, CUR, EID);

    // GI = X @ W_ih^T + b_ih for all T at once: [80000,64] @ [64,384]
    k_mmagemm<<<dim3(G3 / 128, (TT * NN + 127) / 128), 256>>>(
        x_seq, WIHh, WIHl, gb_ih, GI, TT * NN, G3, IN_DIM);

    for (int t = 0; t < TT; t++) {
        // GH = h @ W_hh^T + b_hh : [20000,128] @ [128,384]
        k_mmagemm<<<dim3(G3 / 128, (NN + 127) / 128), 256>>>(
            H, WHHh, WHHl, gb_hh, GH, NN, G3, DD);
        k_gru_gate<<<(NN * DD + TPB - 1) / TPB, TPB>>>(GI + (size_t)t * NN * G3, GH, H);

        const int* rp_t   = RP + t * (NN + 1);
        const int* eid_t  = EID + (size_t)t * EE;
        const int* src_t  = ei + (size_t)t * 2 * EE;
        const float* ea_t = ea + (size_t)t * EE;

        // layer 0: qkvs from GRU output
        k_mmagemm<<<dim3(QKVS / 128, (NN + 127) / 128), 256>>>(
            H, WPh, WPl, BPK, QK, NN, QKVS, DD);
        k_conv_edge<<<NN / 8, 256>>>(QK, rp_t, eid_t, src_t, ea_t, cWe, HA, 0);

        // layer 1: qkvs from layer-0 output; accumulate into HS
        k_mmagemm<<<dim3(QKVS / 128, (NN + 127) / 128), 256>>>(
            HA, WPh + QKVS * DD, WPl + QKVS * DD, BPK + QKVS, QK, NN, QKVS, DD);
        k_conv_edge<<<NN / 8, 256>>>(QK, rp_t, eid_t, src_t, ea_t, cWe + DD, HS, 1);
    }

    // output conv (edges of last timestep)
    k_out_node<<<NN / 8, 256>>>(HS, oWq, obq, oWk, obk, oWv, obv, oWs, obs, OQ, OKp, OV, OSK);
    k_out_edge<<<(NN + TPB - 1) / TPB, TPB>>>(RP + (TT - 1) * (NN + 1), EID + (size_t)(TT - 1) * EE,
                                              ei + (size_t)(TT - 1) * 2 * EE, ea + (size_t)(TT - 1) * EE,
                                              oWe, OQ, OKp, OV, OSK, (float*)d_out);
}

// round 4
// speedup vs baseline: 1.6544x; 1.2232x over previous
#include <cuda_runtime.h>
#include <cuda_bf16.h>
#include <math_constants.h>
#include <cstdint>

#define TT 4
#define NN 20000
#define EE 160000
#define IN_DIM 64
#define DD 128
#define G3 384   // 3*D
#define QKVS 512 // q|k|v|skip packed

// ------------------- static device scratch (no runtime allocs) -------------------
__device__ float g_GI[(size_t)TT * NN * G3];
__device__ float g_GH[(size_t)NN * G3];
__device__ float g_H [(size_t)NN * DD];
__device__ float g_HS[(size_t)NN * DD];
__device__ float g_QK[(size_t)NN * QKVS];
// activations pre-split to bf16 hi/lo
__device__ __nv_bfloat16 g_Xh[(size_t)TT * NN * IN_DIM], g_Xl[(size_t)TT * NN * IN_DIM];
__device__ __nv_bfloat16 g_Hh[(size_t)NN * DD], g_Hl[(size_t)NN * DD];
__device__ __nv_bfloat16 g_HAh[(size_t)NN * DD], g_HAl[(size_t)NN * DD];
// weights pre-split to bf16 hi/lo, [N][K] layout
__device__ __nv_bfloat16 g_WIHh[G3 * IN_DIM], g_WIHl[G3 * IN_DIM];
__device__ __nv_bfloat16 g_WHHh[G3 * DD],     g_WHHl[G3 * DD];
__device__ __nv_bfloat16 g_WPKh[2 * QKVS * DD], g_WPKl[2 * QKVS * DD];
__device__ float g_BPK[2 * QKVS];
__device__ float g_OQ[NN], g_OKs[NN], g_OV[NN], g_OSK[NN];
__device__ int   g_RP [TT * (NN + 1)];
__device__ int   g_EID[TT * EE];
__device__ int   g_CNT[TT * NN];
__device__ int   g_CUR[TT * NN];

// ------------------------------- small utility kernels ---------------------------
__global__ void k_zero_f(float* p, int n) {
    int i = blockIdx.x * blockDim.x + threadIdx.x;
    if (i < n) p[i] = 0.f;
}
__global__ void k_zero_i(int* p, int n) {
    int i = blockIdx.x * blockDim.x + threadIdx.x;
    if (i < n) p[i] = 0;
}

__device__ __forceinline__ void split_bf16(float v, __nv_bfloat16& h, __nv_bfloat16& l) {
    h = __float2bfloat16_rn(v);
    l = __float2bfloat16_rn(v - __bfloat162float(h));
}

__global__ void k_split_x(const float* __restrict__ x,
                          __nv_bfloat16* __restrict__ xh, __nv_bfloat16* __restrict__ xl) {
    int i = blockIdx.x * blockDim.x + threadIdx.x;
    if (i < TT * NN * IN_DIM) split_bf16(x[i], xh[i], xl[i]);
}

// GRU weights: W_ih [384,64] and W_hh [384,128] are natively [N,K].
__global__ void k_prep_gru(const float* __restrict__ Wih, const float* __restrict__ Whh,
                           __nv_bfloat16* __restrict__ ah, __nv_bfloat16* __restrict__ al,
                           __nv_bfloat16* __restrict__ bh, __nv_bfloat16* __restrict__ bl) {
    int i = blockIdx.x * blockDim.x + threadIdx.x;
    if (i < G3 * IN_DIM) split_bf16(Wih[i], ah[i], al[i]);
    int j = i - G3 * IN_DIM;
    if (j >= 0 && j < G3 * DD) split_bf16(Whh[j], bh[j], bl[j]);
}

// Pack conv weights transposed into [layer][n(512)][k(128)] hi/lo + bias pack
__global__ void k_prep_conv(const float* __restrict__ Wq, const float* __restrict__ Wk,
                            const float* __restrict__ Wv, const float* __restrict__ Ws,
                            const float* __restrict__ bq, const float* __restrict__ bk,
                            const float* __restrict__ bv, const float* __restrict__ bs,
                            __nv_bfloat16* __restrict__ WPh, __nv_bfloat16* __restrict__ WPl,
                            float* __restrict__ BP) {
    int i = blockIdx.x * blockDim.x + threadIdx.x;
    if (i < 2 * QKVS * DD) {
        int l = i >> 16;
        int rem = i & 65535;
        int n = rem >> 7, k = rem & 127;
        int base = l * DD * DD + k * DD;
        float v;
        if      (n < 128) v = Wq[base + n];
        else if (n < 256) v = Wk[base + n - 128];
        else if (n < 384) v = Wv[base + n - 256];
        else              v = Ws[base + n - 384];
        split_bf16(v, WPh[i], WPl[i]);
    }
    if (i < 2 * QKVS) {
        int l = i >> 9, c = i & 511;
        int b2 = l * DD;
        float v;
        if      (c < 128) v = bq[b2 + c];
        else if (c < 256) v = bk[b2 + c - 128];
        else if (c < 384) v = bv[b2 + c - 256];
        else              v = bs[b2 + c - 384];
        BP[i] = v;
    }
}

// ------------------------------- CSR build ---------------------------------------
__global__ void k_hist(const int* __restrict__ ei, int* __restrict__ cnt) {
    int i = blockIdx.x * blockDim.x + threadIdx.x;
    if (i >= TT * EE) return;
    int t = i / EE, e = i % EE;
    int dst = ei[(size_t)t * 2 * EE + EE + e];
    atomicAdd(&cnt[t * NN + dst], 1);
}

__global__ void k_scan(const int* __restrict__ cnt, int* __restrict__ rowptr, int* __restrict__ cur) {
    int t = blockIdx.x;
    __shared__ int sh[1024];
    const int* c = cnt + t * NN;
    int* rp = rowptr + t * (NN + 1);
    int* cu = cur + t * NN;
    int carry = 0;
    for (int base = 0; base < NN; base += 1024) {
        int idx = base + threadIdx.x;
        int v = (idx < NN) ? c[idx] : 0;
        sh[threadIdx.x] = v;
        __syncthreads();
        for (int off = 1; off < 1024; off <<= 1) {
            int tval = (threadIdx.x >= off) ? sh[threadIdx.x - off] : 0;
            __syncthreads();
            sh[threadIdx.x] += tval;
            __syncthreads();
        }
        int excl = sh[threadIdx.x] - v;
        if (idx < NN) { rp[idx] = carry + excl; cu[idx] = carry + excl; }
        carry += sh[1023];
        __syncthreads();
    }
    if (threadIdx.x == 0) rp[NN] = carry;
}

__global__ void k_scatter(const int* __restrict__ ei, int* __restrict__ cur, int* __restrict__ eids) {
    int i = blockIdx.x * blockDim.x + threadIdx.x;
    if (i >= TT * EE) return;
    int t = i / EE, e = i % EE;
    int dst = ei[(size_t)t * 2 * EE + EE + e];
    int p = atomicAdd(&cur[t * NN + dst], 1);
    eids[(size_t)t * EE + p] = e;
}

// ============== pipelined bf16 HMMA GEMM (cp.async double-buffered) ===============
// C[M,Nc] = A @ B^T + bias. A,B pre-split bf16 hi/lo, both stored [rows][K] row-major.
// 3-pass: D = Ahi*Bhi + Ahi*Blo + Alo*Bhi, fp32 accumulate.
#define KC 32
#define STG_WORDS (128 * 16)   // words per array per stage (128 rows x 32 bf16)

__device__ __forceinline__ void mma_bf16(float c[4], const uint32_t a[4],
                                         uint32_t b0, uint32_t b1) {
    asm volatile(
        "mma.sync.aligned.m16n8k16.row.col.f32.bf16.bf16.f32 "
        "{%0,%1,%2,%3}, {%4,%5,%6,%7}, {%8,%9}, {%0,%1,%2,%3};"
        : "+f"(c[0]), "+f"(c[1]), "+f"(c[2]), "+f"(c[3])
        : "r"(a[0]), "r"(a[1]), "r"(a[2]), "r"(a[3]), "r"(b0), "r"(b1));
}

// swizzled word index inside one [128 x 16-word] tile (16B-chunk XOR swizzle)
__device__ __forceinline__ int widx(int r, int w) {
    return (r << 4) + ((((w >> 2) ^ ((r >> 1) & 3)) << 2) | (w & 3));
}

__global__ void __launch_bounds__(256) k_pgemm(
    const __nv_bfloat16* __restrict__ Ah, const __nv_bfloat16* __restrict__ Al,
    const __nv_bfloat16* __restrict__ Bh, const __nv_bfloat16* __restrict__ Bl,
    const float* __restrict__ bias, float* __restrict__ C, int M, int Nc, int K) {
    extern __shared__ uint32_t smw[];   // 2 stages x 4 arrays x STG_WORDS = 64KB

    int tid = threadIdx.x, wid = tid >> 5, lane = tid & 31;
    int gid = lane >> 2, t4 = lane & 3;
    int rowBase = blockIdx.y * 128;
    int colBase = blockIdx.x * 128;
    int warpRow = (wid & 3) * 32;
    int warpCol = (wid >> 2) * 64;

    float acc[2][8][4];
#pragma unroll
    for (int mt = 0; mt < 2; mt++)
#pragma unroll
        for (int nt = 0; nt < 8; nt++)
#pragma unroll
            for (int q = 0; q < 4; q++) acc[mt][nt][q] = 0.f;

    uint32_t sm0;
    asm("{ .reg .u64 t; cvta.to.shared.u64 t, %1; cvt.u32.u64 %0, t; }"
        : "=r"(sm0) : "l"(smw));

    const __nv_bfloat16* srcs[4] = {Ah, Al, Bh, Bl};

    // ---------------- fill one stage via cp.async ----------------
    auto fill = [&](int stage, int k0) {
        uint32_t sb = sm0 + (uint32_t)stage * 4 * STG_WORDS * 4;
#pragma unroll
        for (int it = 0; it < 8; it++) {
            int idx = tid + it * 256;
            int arr = idx >> 9;
            int rem = idx & 511;
            int r = rem >> 2, c = rem & 3;
            int grow = (arr < 2) ? (rowBase + r) : (colBase + r);
            int valid = (arr >= 2) || (grow < M);
            const __nv_bfloat16* src = srcs[arr] + (valid ? ((size_t)grow * K + k0 + c * 8) : 0);
            int sz = valid ? 16 : 0;
            uint32_t dst = sb + (uint32_t)(arr * STG_WORDS + (r << 4) + ((c ^ ((r >> 1) & 3)) << 2)) * 4;
            asm volatile("cp.async.cg.shared.global [%0], [%1], 16, %2;"
                         :: "r"(dst), "l"(src), "r"(sz));
        }
        asm volatile("cp.async.commit_group;");
    };

    fill(0, 0);
    int nch = K / KC;

    for (int ch = 0; ch < nch; ch++) {
        if (ch + 1 < nch) {
            fill((ch + 1) & 1, (ch + 1) * KC);
            asm volatile("cp.async.wait_group 1;");
        } else {
            asm volatile("cp.async.wait_group 0;");
        }
        __syncthreads();

        const uint32_t* pah = smw + (ch & 1) * 4 * STG_WORDS;
        const uint32_t* pal = pah + STG_WORDS;
        const uint32_t* pbh = pal + STG_WORDS;
        const uint32_t* pbl = pbh + STG_WORDS;

#pragma unroll
        for (int ks = 0; ks < KC; ks += 16) {
            int w0 = (ks >> 1) + t4;
            uint32_t ah[2][4], al[2][4];
#pragma unroll
            for (int mt = 0; mt < 2; mt++) {
                int r0 = warpRow + mt * 16 + gid;
                ah[mt][0] = pah[widx(r0,     w0)];
                ah[mt][1] = pah[widx(r0 + 8, w0)];
                ah[mt][2] = pah[widx(r0,     w0 + 4)];
                ah[mt][3] = pah[widx(r0 + 8, w0 + 4)];
                al[mt][0] = pal[widx(r0,     w0)];
                al[mt][1] = pal[widx(r0 + 8, w0)];
                al[mt][2] = pal[widx(r0,     w0 + 4)];
                al[mt][3] = pal[widx(r0 + 8, w0 + 4)];
            }
            uint32_t bh[8][2], bl[8][2];
#pragma unroll
            for (int nt = 0; nt < 8; nt++) {
                int rb = warpCol + nt * 8 + gid;
                bh[nt][0] = pbh[widx(rb, w0)];
                bh[nt][1] = pbh[widx(rb, w0 + 4)];
                bl[nt][0] = pbl[widx(rb, w0)];
                bl[nt][1] = pbl[widx(rb, w0 + 4)];
            }
            // pass 1: hi*hi
#pragma unroll
            for (int mt = 0; mt < 2; mt++)
#pragma unroll
                for (int nt = 0; nt < 8; nt++)
                    mma_bf16(acc[mt][nt], ah[mt], bh[nt][0], bh[nt][1]);
            // pass 2: hi*lo
#pragma unroll
            for (int mt = 0; mt < 2; mt++)
#pragma unroll
                for (int nt = 0; nt < 8; nt++)
                    mma_bf16(acc[mt][nt], ah[mt], bl[nt][0], bl[nt][1]);
            // pass 3: lo*hi
#pragma unroll
            for (int mt = 0; mt < 2; mt++)
#pragma unroll
                for (int nt = 0; nt < 8; nt++)
                    mma_bf16(acc[mt][nt], al[mt], bh[nt][0], bh[nt][1]);
        }
        __syncthreads();
    }

    // ---- epilogue: add bias, store ----
#pragma unroll
    for (int mt = 0; mt < 2; mt++) {
        int r0 = rowBase + warpRow + mt * 16 + gid;
        int r1 = r0 + 8;
#pragma unroll
        for (int nt = 0; nt < 8; nt++) {
            int col = colBase + warpCol + nt * 8 + t4 * 2;
            float b0 = bias[col], b1 = bias[col + 1];
            if (r0 < M) {
                float2 o = make_float2(acc[mt][nt][0] + b0, acc[mt][nt][1] + b1);
                *(float2*)&C[(size_t)r0 * Nc + col] = o;
            }
            if (r1 < M) {
                float2 o = make_float2(acc[mt][nt][2] + b0, acc[mt][nt][3] + b1);
                *(float2*)&C[(size_t)r1 * Nc + col] = o;
            }
        }
    }
}

// ------------------------------- GRU gates ---------------------------------------
// first: h_prev = 0 and gh = b_hh (skips the t=0 GH GEMM entirely)
__global__ void k_gru_gate(const float* __restrict__ GI, const float* __restrict__ GH,
                           const float* __restrict__ bhh, float* __restrict__ H,
                           __nv_bfloat16* __restrict__ Hh, __nv_bfloat16* __restrict__ Hl,
                           int first) {
    int i = blockIdx.x * blockDim.x + threadIdx.x;
    if (i >= NN * DD) return;
    int n = i >> 7, j = i & 127;
    const float* gi = GI + (size_t)n * G3;
    float ir = gi[j], iz = gi[j + 128], in = gi[j + 256];
    float hr, hz, hn, hp;
    if (first) {
        hr = bhh[j]; hz = bhh[j + 128]; hn = bhh[j + 256];
        hp = 0.f;
    } else {
        const float* gh = GH + (size_t)n * G3;
        hr = gh[j]; hz = gh[j + 128]; hn = gh[j + 256];
        hp = H[i];
    }
    float r = 1.f / (1.f + __expf(-(ir + hr)));
    float z = 1.f / (1.f + __expf(-(iz + hz)));
    float nv = tanhf(in + r * hn);
    float h = (1.f - z) * nv + z * hp;
    H[i] = h;
    split_bf16(h, Hh[i], Hl[i]);
}

// ---------------------- TransformerConv edge attention (D=128) -------------------
// accum==0: write bf16 hi/lo split (feeds next GEMM). accum==1: accumulate f32 into out.
__global__ void k_conv_edge(const float* __restrict__ qkvs,
                            const int* __restrict__ rowptr, const int* __restrict__ eids,
                            const int* __restrict__ src_arr, const float* __restrict__ eattr,
                            const float* __restrict__ We, float* __restrict__ out,
                            __nv_bfloat16* __restrict__ oh, __nv_bfloat16* __restrict__ ol,
                            int accum) {
    int w = (blockIdx.x * blockDim.x + threadIdx.x) >> 5;
    if (w >= NN) return;
    int lane = threadIdx.x & 31;
    int c0 = lane * 4;
    float4 q  = *(const float4*)&qkvs[(size_t)w * QKVS + c0];
    float4 sk = *(const float4*)&qkvs[(size_t)w * QKVS + 384 + c0];
    float4 we = *(const float4*)&We[c0];
    float m = -CUDART_INF_F, s = 0.f;
    float4 acc = make_float4(0.f, 0.f, 0.f, 0.f);
    int beg = rowptr[w], end = rowptr[w + 1];
    for (int i = beg; i < end; i++) {
        int e = eids[i];
        int sn = src_arr[e];
        float eaV = eattr[e];
        float4 k4 = *(const float4*)&qkvs[(size_t)sn * QKVS + 128 + c0];
        float4 v4 = *(const float4*)&qkvs[(size_t)sn * QKVS + 256 + c0];
        float ex = eaV * we.x, ey = eaV * we.y, ez = eaV * we.z, ew = eaV * we.w;
        float part = q.x * (k4.x + ex) + q.y * (k4.y + ey) + q.z * (k4.z + ez) + q.w * (k4.w + ew);
#pragma unroll
        for (int o = 16; o; o >>= 1) part += __shfl_xor_sync(0xffffffffu, part, o);
        float alpha = part * 0.08838834764831845f; // 1/sqrt(128)
        float mn = fmaxf(m, alpha);
        float corr = __expf(m - mn);
        float p = __expf(alpha - mn);
        s = s * corr + p;
        acc.x = acc.x * corr + p * (v4.x + ex);
        acc.y = acc.y * corr + p * (v4.y + ey);
        acc.z = acc.z * corr + p * (v4.z + ez);
        acc.w = acc.w * corr + p * (v4.w + ew);
        m = mn;
    }
    float inv = 1.f / (s + 1e-16f);
    float4 o;
    o.x = acc.x * inv + sk.x;
    o.y = acc.y * inv + sk.y;
    o.z = acc.z * inv + sk.z;
    o.w = acc.w * inv + sk.w;
    o.x = o.x > 0.f ? o.x : 0.01f * o.x;
    o.y = o.y > 0.f ? o.y : 0.01f * o.y;
    o.z = o.z > 0.f ? o.z : 0.01f * o.z;
    o.w = o.w > 0.f ? o.w : 0.01f * o.w;
    if (accum) {
        float4 prev = *(const float4*)&out[(size_t)w * DD + c0];
        o.x += prev.x; o.y += prev.y; o.z += prev.z; o.w += prev.w;
        *(float4*)&out[(size_t)w * DD + c0] = o;
    } else {
        __nv_bfloat16 hx, lx, hy, ly, hz, lz, hw, lw;
        split_bf16(o.x, hx, lx);
        split_bf16(o.y, hy, ly);
        split_bf16(o.z, hz, lz);
        split_bf16(o.w, hw, lw);
        __nv_bfloat16 hv[4] = {hx, hy, hz, hw};
        __nv_bfloat16 lv[4] = {lx, ly, lz, lw};
        *(uint2*)&oh[(size_t)w * DD + c0] = *(uint2*)hv;
        *(uint2*)&ol[(size_t)w * DD + c0] = *(uint2*)lv;
    }
}

// ------------------------ output conv (D -> 1) -----------------------------------
__global__ void k_out_node(const float* __restrict__ hsum,
                           const float* __restrict__ Wq, const float* __restrict__ bq,
                           const float* __restrict__ Wk, const float* __restrict__ bk,
                           const float* __restrict__ Wv, const float* __restrict__ bv,
                           const float* __restrict__ Ws, const float* __restrict__ bs,
                           float* __restrict__ oq, float* __restrict__ ok,
                           float* __restrict__ ov, float* __restrict__ osk) {
    int w = (blockIdx.x * blockDim.x + threadIdx.x) >> 5;
    if (w >= NN) return;
    int lane = threadIdx.x & 31;
    int c0 = lane * 4;
    float4 h = *(const float4*)&hsum[(size_t)w * DD + c0];
    h.x *= 0.25f; h.y *= 0.25f; h.z *= 0.25f; h.w *= 0.25f;
    float4 wq = *(const float4*)&Wq[c0];
    float4 wk = *(const float4*)&Wk[c0];
    float4 wv = *(const float4*)&Wv[c0];
    float4 ws = *(const float4*)&Ws[c0];
    float dq = h.x * wq.x + h.y * wq.y + h.z * wq.z + h.w * wq.w;
    float dk = h.x * wk.x + h.y * wk.y + h.z * wk.z + h.w * wk.w;
    float dv = h.x * wv.x + h.y * wv.y + h.z * wv.z + h.w * wv.w;
    float ds = h.x * ws.x + h.y * ws.y + h.z * ws.z + h.w * ws.w;
#pragma unroll
    for (int o = 16; o; o >>= 1) {
        dq += __shfl_xor_sync(0xffffffffu, dq, o);
        dk += __shfl_xor_sync(0xffffffffu, dk, o);
        dv += __shfl_xor_sync(0xffffffffu, dv, o);
        ds += __shfl_xor_sync(0xffffffffu, ds, o);
    }
    if (lane == 0) {
        oq[w]  = dq + bq[0];
        ok[w]  = dk + bk[0];
        ov[w]  = dv + bv[0];
        osk[w] = ds + bs[0];
    }
}

__global__ void k_out_edge(const int* __restrict__ rowptr, const int* __restrict__ eids,
                           const int* __restrict__ src_arr, const float* __restrict__ eattr,
                           const float* __restrict__ We,
                           const float* __restrict__ oq, const float* __restrict__ ok,
                           const float* __restrict__ ov, const float* __restrict__ osk,
                           float* __restrict__ out) {
    int n = blockIdx.x * blockDim.x + threadIdx.x;
    if (n >= NN) return;
    float q = oq[n];
    float we = We[0];
    float m = -CUDART_INF_F, s = 0.f, acc = 0.f;
    int beg = rowptr[n], end = rowptr[n + 1];
    for (int i = beg; i < end; i++) {
        int e = eids[i];
        int sn = src_arr[e];
        float et = eattr[e] * we;
        float alpha = q * (ok[sn] + et);
        float mn = fmaxf(m, alpha);
        float corr = __expf(m - mn);
        float p = __expf(alpha - mn);
        s = s * corr + p;
        acc = acc * corr + p * (ov[sn] + et);
        m = mn;
    }
    out[n] = acc / (s + 1e-16f) + osk[n];
}

// =================================== host side ====================================
extern "C" void kernel_launch(void* const* d_in, const int* in_sizes, int n_in,
                              void* d_out, int out_size) {
    const float* x_seq = nullptr;
    const int*   ei    = nullptr;
    const float* ea    = nullptr;
    const float* P[22];
    int r = 0;
    for (int i = 0; i < n_in; i++) {
        if      (in_sizes[i] == TT * NN * IN_DIM) x_seq = (const float*)d_in[i];
        else if (in_sizes[i] == TT * 2 * EE)      ei    = (const int*)d_in[i];
        else if (in_sizes[i] == TT * EE)          ea    = (const float*)d_in[i];
        else if (r < 22)                          P[r++] = (const float*)d_in[i];
    }
    const float* gW_ih = P[0];
    const float* gW_hh = P[1];
    const float* gb_ih = P[2];
    const float* gb_hh = P[3];
    const float* cWq   = P[4];
    const float* cbq   = P[5];
    const float* cWk   = P[6];
    const float* cbk   = P[7];
    const float* cWv   = P[8];
    const float* cbv   = P[9];
    const float* cWe   = P[10];
    const float* cWs   = P[11];
    const float* cbs   = P[12];
    const float* oWq   = P[13];
    const float* obq   = P[14];
    const float* oWk   = P[15];
    const float* obk   = P[16];
    const float* oWv   = P[17];
    const float* obv   = P[18];
    const float* oWe   = P[19];
    const float* oWs   = P[20];
    const float* obs   = P[21];

    float *GI, *GH, *H, *HS, *QK, *BPK;
    __nv_bfloat16 *Xh, *Xl, *Hh, *Hl, *HAh, *HAl;
    __nv_bfloat16 *WIHh, *WIHl, *WHHh, *WHHl, *WPh, *WPl;
    float *OQ, *OKp, *OV, *OSK;
    int *RP, *EID, *CNT, *CUR;
    cudaGetSymbolAddress((void**)&GI,   g_GI);
    cudaGetSymbolAddress((void**)&GH,   g_GH);
    cudaGetSymbolAddress((void**)&H,    g_H);
    cudaGetSymbolAddress((void**)&HS,   g_HS);
    cudaGetSymbolAddress((void**)&QK,   g_QK);
    cudaGetSymbolAddress((void**)&Xh,   g_Xh);
    cudaGetSymbolAddress((void**)&Xl,   g_Xl);
    cudaGetSymbolAddress((void**)&Hh,   g_Hh);
    cudaGetSymbolAddress((void**)&Hl,   g_Hl);
    cudaGetSymbolAddress((void**)&HAh,  g_HAh);
    cudaGetSymbolAddress((void**)&HAl,  g_HAl);
    cudaGetSymbolAddress((void**)&WIHh, g_WIHh);
    cudaGetSymbolAddress((void**)&WIHl, g_WIHl);
    cudaGetSymbolAddress((void**)&WHHh, g_WHHh);
    cudaGetSymbolAddress((void**)&WHHl, g_WHHl);
    cudaGetSymbolAddress((void**)&WPh,  g_WPKh);
    cudaGetSymbolAddress((void**)&WPl,  g_WPKl);
    cudaGetSymbolAddress((void**)&BPK,  g_BPK);
    cudaGetSymbolAddress((void**)&OQ,   g_OQ);
    cudaGetSymbolAddress((void**)&OKp,  g_OKs);
    cudaGetSymbolAddress((void**)&OV,   g_OV);
    cudaGetSymbolAddress((void**)&OSK,  g_OSK);
    cudaGetSymbolAddress((void**)&RP,   g_RP);
    cudaGetSymbolAddress((void**)&EID,  g_EID);
    cudaGetSymbolAddress((void**)&CNT,  g_CNT);
    cudaGetSymbolAddress((void**)&CUR,  g_CUR);

    // host-side attribute set (runs on capture/correctness call only, not on replay)
    cudaFuncSetAttribute(k_pgemm, cudaFuncAttributeMaxDynamicSharedMemorySize, 65536);

    const int TPB = 256;
    const int SMEM = 2 * 4 * STG_WORDS * 4;  // 64KB

    // 1..3: prep (placed so the big GI GEMM is our 4th launch for ncu's capture window)
    k_zero_f<<<(NN * DD + TPB - 1) / TPB, TPB>>>(HS, NN * DD);
    k_split_x<<<(TT * NN * IN_DIM + TPB - 1) / TPB, TPB>>>(x_seq, Xh, Xl);
    k_prep_gru<<<(G3 * IN_DIM + G3 * DD + TPB - 1) / TPB, TPB>>>(gW_ih, gW_hh, WIHh, WIHl, WHHh, WHHl);

    // 4: GI = X @ W_ih^T + b_ih for all T at once: [80000,64] @ [64,384]
    k_pgemm<<<dim3(G3 / 128, (TT * NN + 127) / 128), 256, SMEM>>>(
        Xh, Xl, WIHh, WIHl, gb_ih, GI, TT * NN, G3, IN_DIM);

    k_prep_conv<<<(2 * QKVS * DD + TPB - 1) / TPB, TPB>>>(cWq, cWk, cWv, cWs, cbq, cbk, cbv, cbs, WPh, WPl, BPK);
    k_zero_i<<<(TT * NN + TPB - 1) / TPB, TPB>>>(CNT, TT * NN);
    k_hist<<<(TT * EE + TPB - 1) / TPB, TPB>>>(ei, CNT);
    k_scan<<<TT, 1024>>>(CNT, RP, CUR);
    k_scatter<<<(TT * EE + TPB - 1) / TPB, TPB>>>(ei, CUR, EID);

    for (int t = 0; t < TT; t++) {
        // GH = h @ W_hh^T + b_hh : skipped at t=0 (h == 0 -> gh = b_hh in gate kernel)
        if (t > 0) {
            k_pgemm<<<dim3(G3 / 128, (NN + 127) / 128), 256, SMEM>>>(
                Hh, Hl, WHHh, WHHl, gb_hh, GH, NN, G3, DD);
        }
        k_gru_gate<<<(NN * DD + TPB - 1) / TPB, TPB>>>(GI + (size_t)t * NN * G3, GH, gb_hh,
                                                       H, Hh, Hl, t == 0 ? 1 : 0);

        const int* rp_t   = RP + t * (NN + 1);
        const int* eid_t  = EID + (size_t)t * EE;
        const int* src_t  = ei + (size_t)t * 2 * EE;
        const float* ea_t = ea + (size_t)t * EE;

        // layer 0: qkvs from GRU output
        k_pgemm<<<dim3(QKVS / 128, (NN + 127) / 128), 256, SMEM>>>(
            Hh, Hl, WPh, WPl, BPK, QK, NN, QKVS, DD);
        k_conv_edge<<<NN / 8, 256>>>(QK, rp_t, eid_t, src_t, ea_t, cWe, HS, HAh, HAl, 0);

        // layer 1: qkvs from layer-0 output; accumulate into HS
        k_pgemm<<<dim3(QKVS / 128, (NN + 127) / 128), 256, SMEM>>>(
            HAh, HAl, WPh + QKVS * DD, WPl + QKVS * DD, BPK + QKVS, QK, NN, QKVS, DD);
        k_conv_edge<<<NN / 8, 256>>>(QK, rp_t, eid_t, src_t, ea_t, cWe + DD, HS, HAh, HAl, 1);
    }

    // output conv (edges of last timestep)
    k_out_node<<<NN / 8, 256>>>(HS, oWq, obq, oWk, obk, oWv, obv, oWs, obs, OQ, OKp, OV, OSK);
    k_out_edge<<<(NN + TPB - 1) / TPB, TPB>>>(RP + (TT - 1) * (NN + 1), EID + (size_t)(TT - 1) * EE,
                                              ei + (size_t)(TT - 1) * 2 * EE, ea + (size_t)(TT - 1) * EE,
                                              oWe, OQ, OKp, OV, OSK, (float*)d_out);
}

// round 5
// speedup vs baseline: 1.8782x; 1.1353x over previous
#include <cuda_runtime.h>
#include <cuda_bf16.h>
#include <math_constants.h>
#include <cstdint>

#define TT 4
#define NN 20000
#define EE 160000
#define IN_DIM 64
#define DD 128
#define G3 384   // 3*D
#define QKVS 512 // q|k|v|skip packed

// ------------------- static device scratch (no runtime allocs) -------------------
__device__ float g_GI[(size_t)TT * NN * G3];
__device__ float g_GH[(size_t)NN * G3];
__device__ float g_H [(size_t)NN * DD];
__device__ float g_HS[(size_t)NN * DD];
__device__ float g_QK[(size_t)NN * QKVS];
// activations pre-split to bf16 hi/lo
__device__ __nv_bfloat16 g_Xh[(size_t)TT * NN * IN_DIM], g_Xl[(size_t)TT * NN * IN_DIM];
__device__ __nv_bfloat16 g_Hh[(size_t)NN * DD], g_Hl[(size_t)NN * DD];
__device__ __nv_bfloat16 g_HAh[(size_t)NN * DD], g_HAl[(size_t)NN * DD];
// weights pre-split to bf16 hi/lo, [N][K] layout
__device__ __nv_bfloat16 g_WIHh[G3 * IN_DIM], g_WIHl[G3 * IN_DIM];
__device__ __nv_bfloat16 g_WHHh[G3 * DD],     g_WHHl[G3 * DD];
__device__ __nv_bfloat16 g_WPKh[2 * QKVS * DD], g_WPKl[2 * QKVS * DD];
__device__ float g_BPK[2 * QKVS];
__device__ float g_OQ[NN], g_OKs[NN], g_OV[NN], g_OSK[NN];
__device__ int   g_RP [TT * (NN + 1)];
__device__ int   g_EID[TT * EE];
__device__ int   g_CNT[TT * NN];
__device__ int   g_CUR[TT * NN];

// ------------------------------- small utility kernels ---------------------------
__global__ void k_zero_f(float* p, int n) {
    int i = blockIdx.x * blockDim.x + threadIdx.x;
    if (i < n) p[i] = 0.f;
}
__global__ void k_zero_i(int* p, int n) {
    int i = blockIdx.x * blockDim.x + threadIdx.x;
    if (i < n) p[i] = 0;
}

__device__ __forceinline__ void split_bf16(float v, __nv_bfloat16& h, __nv_bfloat16& l) {
    h = __float2bfloat16_rn(v);
    l = __float2bfloat16_rn(v - __bfloat162float(h));
}

__global__ void k_split_x(const float* __restrict__ x,
                          __nv_bfloat16* __restrict__ xh, __nv_bfloat16* __restrict__ xl) {
    int i = blockIdx.x * blockDim.x + threadIdx.x;
    if (i < TT * NN * IN_DIM) split_bf16(x[i], xh[i], xl[i]);
}

// GRU weights: W_ih [384,64] and W_hh [384,128] are natively [N,K].
__global__ void k_prep_gru(const float* __restrict__ Wih, const float* __restrict__ Whh,
                           __nv_bfloat16* __restrict__ ah, __nv_bfloat16* __restrict__ al,
                           __nv_bfloat16* __restrict__ bh, __nv_bfloat16* __restrict__ bl) {
    int i = blockIdx.x * blockDim.x + threadIdx.x;
    if (i < G3 * IN_DIM) split_bf16(Wih[i], ah[i], al[i]);
    int j = i - G3 * IN_DIM;
    if (j >= 0 && j < G3 * DD) split_bf16(Whh[j], bh[j], bl[j]);
}

// Pack conv weights transposed into [layer][n(512)][k(128)] hi/lo + bias pack
__global__ void k_prep_conv(const float* __restrict__ Wq, const float* __restrict__ Wk,
                            const float* __restrict__ Wv, const float* __restrict__ Ws,
                            const float* __restrict__ bq, const float* __restrict__ bk,
                            const float* __restrict__ bv, const float* __restrict__ bs,
                            __nv_bfloat16* __restrict__ WPh, __nv_bfloat16* __restrict__ WPl,
                            float* __restrict__ BP) {
    int i = blockIdx.x * blockDim.x + threadIdx.x;
    if (i < 2 * QKVS * DD) {
        int l = i >> 16;
        int rem = i & 65535;
        int n = rem >> 7, k = rem & 127;
        int base = l * DD * DD + k * DD;
        float v;
        if      (n < 128) v = Wq[base + n];
        else if (n < 256) v = Wk[base + n - 128];
        else if (n < 384) v = Wv[base + n - 256];
        else              v = Ws[base + n - 384];
        split_bf16(v, WPh[i], WPl[i]);
    }
    if (i < 2 * QKVS) {
        int l = i >> 9, c = i & 511;
        int b2 = l * DD;
        float v;
        if      (c < 128) v = bq[b2 + c];
        else if (c < 256) v = bk[b2 + c - 128];
        else if (c < 384) v = bv[b2 + c - 256];
        else              v = bs[b2 + c - 384];
        BP[i] = v;
    }
}

// ------------------------------- CSR build ---------------------------------------
__global__ void k_hist(const int* __restrict__ ei, int* __restrict__ cnt) {
    int i = blockIdx.x * blockDim.x + threadIdx.x;
    if (i >= TT * EE) return;
    int t = i / EE, e = i % EE;
    int dst = ei[(size_t)t * 2 * EE + EE + e];
    atomicAdd(&cnt[t * NN + dst], 1);
}

__global__ void k_scan(const int* __restrict__ cnt, int* __restrict__ rowptr, int* __restrict__ cur) {
    int t = blockIdx.x;
    __shared__ int sh[1024];
    const int* c = cnt + t * NN;
    int* rp = rowptr + t * (NN + 1);
    int* cu = cur + t * NN;
    int carry = 0;
    for (int base = 0; base < NN; base += 1024) {
        int idx = base + threadIdx.x;
        int v = (idx < NN) ? c[idx] : 0;
        sh[threadIdx.x] = v;
        __syncthreads();
        for (int off = 1; off < 1024; off <<= 1) {
            int tval = (threadIdx.x >= off) ? sh[threadIdx.x - off] : 0;
            __syncthreads();
            sh[threadIdx.x] += tval;
            __syncthreads();
        }
        int excl = sh[threadIdx.x] - v;
        if (idx < NN) { rp[idx] = carry + excl; cu[idx] = carry + excl; }
        carry += sh[1023];
        __syncthreads();
    }
    if (threadIdx.x == 0) rp[NN] = carry;
}

__global__ void k_scatter(const int* __restrict__ ei, int* __restrict__ cur, int* __restrict__ eids) {
    int i = blockIdx.x * blockDim.x + threadIdx.x;
    if (i >= TT * EE) return;
    int t = i / EE, e = i % EE;
    int dst = ei[(size_t)t * 2 * EE + EE + e];
    int p = atomicAdd(&cur[t * NN + dst], 1);
    eids[(size_t)t * EE + p] = e;
}

// ======== pipelined bf16 HMMA GEMM: cp.async + ldmatrix, 2 CTAs/SM ================
// C[M,Nc] = A @ B^T + bias. A,B pre-split bf16 hi/lo, both stored [rows][K] row-major.
// 3-pass: D = Ahi*Bhi + Ahi*Blo + Alo*Bhi, fp32 accumulate.
#define KC 32
#define STG_WORDS (128 * 16)   // words per array per stage (128 rows x 32 bf16)

__device__ __forceinline__ void mma_bf16(float c[4], const uint32_t a[4],
                                         uint32_t b0, uint32_t b1) {
    asm volatile(
        "mma.sync.aligned.m16n8k16.row.col.f32.bf16.bf16.f32 "
        "{%0,%1,%2,%3}, {%4,%5,%6,%7}, {%8,%9}, {%0,%1,%2,%3};"
        : "+f"(c[0]), "+f"(c[1]), "+f"(c[2]), "+f"(c[3])
        : "r"(a[0]), "r"(a[1]), "r"(a[2]), "r"(a[3]), "r"(b0), "r"(b1));
}

__device__ __forceinline__ void ldsm_x4(uint32_t addr, uint32_t& r0, uint32_t& r1,
                                        uint32_t& r2, uint32_t& r3) {
    asm volatile("ldmatrix.sync.aligned.m8n8.x4.shared.b16 {%0,%1,%2,%3}, [%4];"
                 : "=r"(r0), "=r"(r1), "=r"(r2), "=r"(r3) : "r"(addr));
}

__global__ void __launch_bounds__(256, 2) k_pgemm(
    const __nv_bfloat16* __restrict__ Ah, const __nv_bfloat16* __restrict__ Al,
    const __nv_bfloat16* __restrict__ Bh, const __nv_bfloat16* __restrict__ Bl,
    const float* __restrict__ bias, float* __restrict__ C, int M, int Nc, int K) {
    extern __shared__ uint32_t smw[];   // 2 stages x 4 arrays x STG_WORDS = 64KB

    int tid = threadIdx.x, wid = tid >> 5, lane = tid & 31;
    int gid = lane >> 2, t4 = lane & 3;
    int rowBase = blockIdx.y * 128;
    int colBase = blockIdx.x * 128;
    int warpRow = (wid & 3) * 32;
    int warpCol = (wid >> 2) * 64;

    float acc[2][8][4];
#pragma unroll
    for (int mt = 0; mt < 2; mt++)
#pragma unroll
        for (int nt = 0; nt < 8; nt++)
#pragma unroll
            for (int q = 0; q < 4; q++) acc[mt][nt][q] = 0.f;

    uint32_t sm0;
    asm("{ .reg .u64 t; cvta.to.shared.u64 t, %1; cvt.u32.u64 %0, t; }"
        : "=r"(sm0) : "l"(smw));

    const __nv_bfloat16* srcs[4] = {Ah, Al, Bh, Bl};

    // ldmatrix per-lane row/xor precompute
    int lm_m = lane >> 3;          // matrix id 0..3
    int lm_r = lane & 7;
    // A: matrix -> (row half = lm_m&1, k half = lm_m>>1)
    int a_row0 = warpRow + ((lm_m & 1) << 3) + lm_r;        // mt=0 row; mt=1 adds 16
    int a_kh   = lm_m >> 1;
    // B: matrix -> (nt parity = lm_m>>1, k half = lm_m&1)
    int b_row0 = warpCol + ((lm_m >> 1) << 3) + lm_r;       // pair p adds 16p
    int b_kh   = lm_m & 1;

    // ---------------- fill one stage via cp.async ----------------
    auto fill = [&](int stage, int k0) {
        uint32_t sb = sm0 + (uint32_t)stage * 4 * STG_WORDS * 4;
#pragma unroll
        for (int it = 0; it < 8; it++) {
            int idx = tid + it * 256;
            int arr = idx >> 9;
            int rem = idx & 511;
            int r = rem >> 2, c = rem & 3;
            int grow = (arr < 2) ? (rowBase + r) : (colBase + r);
            int valid = (arr >= 2) || (grow < M);
            const __nv_bfloat16* src = srcs[arr] + (valid ? ((size_t)grow * K + k0 + c * 8) : 0);
            int sz = valid ? 16 : 0;
            uint32_t dst = sb + (uint32_t)(arr * STG_WORDS + (r << 4) + ((c ^ ((r >> 1) & 3)) << 2)) * 4;
            asm volatile("cp.async.cg.shared.global [%0], [%1], 16, %2;"
                         :: "r"(dst), "l"(src), "r"(sz));
        }
        asm volatile("cp.async.commit_group;");
    };

    fill(0, 0);
    int nch = K / KC;

    for (int ch = 0; ch < nch; ch++) {
        if (ch + 1 < nch) {
            fill((ch + 1) & 1, (ch + 1) * KC);
            asm volatile("cp.async.wait_group 1;");
        } else {
            asm volatile("cp.async.wait_group 0;");
        }
        __syncthreads();

        uint32_t st = sm0 + (uint32_t)(ch & 1) * 4 * STG_WORDS * 4;
        uint32_t pAh = st;
        uint32_t pAl = st + STG_WORDS * 4;
        uint32_t pBh = st + 2 * STG_WORDS * 4;
        uint32_t pBl = st + 3 * STG_WORDS * 4;

#pragma unroll
        for (int ks = 0; ks < KC; ks += 16) {
            // ---- A fragments (hi/lo) via ldmatrix.x4 ----
            uint32_t ah[2][4], al[2][4];
            int ach = (ks >> 3) + a_kh;
#pragma unroll
            for (int mt = 0; mt < 2; mt++) {
                int ar = a_row0 + mt * 16;
                uint32_t aoff = (uint32_t)(ar << 6) + (uint32_t)((ach ^ ((ar >> 1) & 3)) << 4);
                ldsm_x4(pAh + aoff, ah[mt][0], ah[mt][1], ah[mt][2], ah[mt][3]);
                ldsm_x4(pAl + aoff, al[mt][0], al[mt][1], al[mt][2], al[mt][3]);
            }
            int bch = (ks >> 3) + b_kh;
            // ---- B pairs: each x4 covers nt=2p and 2p+1 ----
#pragma unroll
            for (int p = 0; p < 4; p++) {
                int br = b_row0 + p * 16;
                uint32_t boff = (uint32_t)(br << 6) + (uint32_t)((bch ^ ((br >> 1) & 3)) << 4);
                uint32_t bh0, bh1, bh2, bh3, bl0, bl1, bl2, bl3;
                ldsm_x4(pBh + boff, bh0, bh1, bh2, bh3);
                ldsm_x4(pBl + boff, bl0, bl1, bl2, bl3);
                int n0 = 2 * p, n1 = 2 * p + 1;
                // pass hh
                mma_bf16(acc[0][n0], ah[0], bh0, bh1);
                mma_bf16(acc[0][n1], ah[0], bh2, bh3);
                mma_bf16(acc[1][n0], ah[1], bh0, bh1);
                mma_bf16(acc[1][n1], ah[1], bh2, bh3);
                // pass hl
                mma_bf16(acc[0][n0], ah[0], bl0, bl1);
                mma_bf16(acc[0][n1], ah[0], bl2, bl3);
                mma_bf16(acc[1][n0], ah[1], bl0, bl1);
                mma_bf16(acc[1][n1], ah[1], bl2, bl3);
                // pass lh
                mma_bf16(acc[0][n0], al[0], bh0, bh1);
                mma_bf16(acc[0][n1], al[0], bh2, bh3);
                mma_bf16(acc[1][n0], al[1], bh0, bh1);
                mma_bf16(acc[1][n1], al[1], bh2, bh3);
            }
        }
        __syncthreads();
    }

    // ---- epilogue: add bias, store ----
#pragma unroll
    for (int mt = 0; mt < 2; mt++) {
        int r0 = rowBase + warpRow + mt * 16 + gid;
        int r1 = r0 + 8;
#pragma unroll
        for (int nt = 0; nt < 8; nt++) {
            int col = colBase + warpCol + nt * 8 + t4 * 2;
            float b0 = bias[col], b1 = bias[col + 1];
            if (r0 < M) {
                float2 o = make_float2(acc[mt][nt][0] + b0, acc[mt][nt][1] + b1);
                *(float2*)&C[(size_t)r0 * Nc + col] = o;
            }
            if (r1 < M) {
                float2 o = make_float2(acc[mt][nt][2] + b0, acc[mt][nt][3] + b1);
                *(float2*)&C[(size_t)r1 * Nc + col] = o;
            }
        }
    }
}

// ------------------------------- GRU gates ---------------------------------------
// first: h_prev = 0 and gh = b_hh (skips the t=0 GH GEMM entirely)
__global__ void k_gru_gate(const float* __restrict__ GI, const float* __restrict__ GH,
                           const float* __restrict__ bhh, float* __restrict__ H,
                           __nv_bfloat16* __restrict__ Hh, __nv_bfloat16* __restrict__ Hl,
                           int first) {
    int i = blockIdx.x * blockDim.x + threadIdx.x;
    if (i >= NN * DD) return;
    int n = i >> 7, j = i & 127;
    const float* gi = GI + (size_t)n * G3;
    float ir = gi[j], iz = gi[j + 128], in = gi[j + 256];
    float hr, hz, hn, hp;
    if (first) {
        hr = bhh[j]; hz = bhh[j + 128]; hn = bhh[j + 256];
        hp = 0.f;
    } else {
        const float* gh = GH + (size_t)n * G3;
        hr = gh[j]; hz = gh[j + 128]; hn = gh[j + 256];
        hp = H[i];
    }
    float r = 1.f / (1.f + __expf(-(ir + hr)));
    float z = 1.f / (1.f + __expf(-(iz + hz)));
    float nv = tanhf(in + r * hn);
    float h = (1.f - z) * nv + z * hp;
    H[i] = h;
    split_bf16(h, Hh[i], Hl[i]);
}

// ---------------------- TransformerConv edge attention (D=128) -------------------
// accum==0: write bf16 hi/lo split (feeds next GEMM). accum==1: accumulate f32 into out.
__global__ void k_conv_edge(const float* __restrict__ qkvs,
                            const int* __restrict__ rowptr, const int* __restrict__ eids,
                            const int* __restrict__ src_arr, const float* __restrict__ eattr,
                            const float* __restrict__ We, float* __restrict__ out,
                            __nv_bfloat16* __restrict__ oh, __nv_bfloat16* __restrict__ ol,
                            int accum) {
    int w = (blockIdx.x * blockDim.x + threadIdx.x) >> 5;
    if (w >= NN) return;
    int lane = threadIdx.x & 31;
    int c0 = lane * 4;
    float4 q  = *(const float4*)&qkvs[(size_t)w * QKVS + c0];
    float4 sk = *(const float4*)&qkvs[(size_t)w * QKVS + 384 + c0];
    float4 we = *(const float4*)&We[c0];
    float m = -CUDART_INF_F, s = 0.f;
    float4 acc = make_float4(0.f, 0.f, 0.f, 0.f);
    int beg = rowptr[w], end = rowptr[w + 1];
    for (int i = beg; i < end; i++) {
        int e = eids[i];
        int sn = src_arr[e];
        float eaV = eattr[e];
        float4 k4 = *(const float4*)&qkvs[(size_t)sn * QKVS + 128 + c0];
        float4 v4 = *(const float4*)&qkvs[(size_t)sn * QKVS + 256 + c0];
        float ex = eaV * we.x, ey = eaV * we.y, ez = eaV * we.z, ew = eaV * we.w;
        float part = q.x * (k4.x + ex) + q.y * (k4.y + ey) + q.z * (k4.z + ez) + q.w * (k4.w + ew);
#pragma unroll
        for (int o = 16; o; o >>= 1) part += __shfl_xor_sync(0xffffffffu, part, o);
        float alpha = part * 0.08838834764831845f; // 1/sqrt(128)
        float mn = fmaxf(m, alpha);
        float corr = __expf(m - mn);
        float p = __expf(alpha - mn);
        s = s * corr + p;
        acc.x = acc.x * corr + p * (v4.x + ex);
        acc.y = acc.y * corr + p * (v4.y + ey);
        acc.z = acc.z * corr + p * (v4.z + ez);
        acc.w = acc.w * corr + p * (v4.w + ew);
        m = mn;
    }
    float inv = 1.f / (s + 1e-16f);
    float4 o;
    o.x = acc.x * inv + sk.x;
    o.y = acc.y * inv + sk.y;
    o.z = acc.z * inv + sk.z;
    o.w = acc.w * inv + sk.w;
    o.x = o.x > 0.f ? o.x : 0.01f * o.x;
    o.y = o.y > 0.f ? o.y : 0.01f * o.y;
    o.z = o.z > 0.f ? o.z : 0.01f * o.z;
    o.w = o.w > 0.f ? o.w : 0.01f * o.w;
    if (accum) {
        float4 prev = *(const float4*)&out[(size_t)w * DD + c0];
        o.x += prev.x; o.y += prev.y; o.z += prev.z; o.w += prev.w;
        *(float4*)&out[(size_t)w * DD + c0] = o;
    } else {
        __nv_bfloat16 hx, lx, hy, ly, hz, lz, hw, lw;
        split_bf16(o.x, hx, lx);
        split_bf16(o.y, hy, ly);
        split_bf16(o.z, hz, lz);
        split_bf16(o.w, hw, lw);
        __nv_bfloat16 hv[4] = {hx, hy, hz, hw};
        __nv_bfloat16 lv[4] = {lx, ly, lz, lw};
        *(uint2*)&oh[(size_t)w * DD + c0] = *(uint2*)hv;
        *(uint2*)&ol[(size_t)w * DD + c0] = *(uint2*)lv;
    }
}

// ------------------------ output conv (D -> 1) -----------------------------------
__global__ void k_out_node(const float* __restrict__ hsum,
                           const float* __restrict__ Wq, const float* __restrict__ bq,
                           const float* __restrict__ Wk, const float* __restrict__ bk,
                           const float* __restrict__ Wv, const float* __restrict__ bv,
                           const float* __restrict__ Ws, const float* __restrict__ bs,
                           float* __restrict__ oq, float* __restrict__ ok,
                           float* __restrict__ ov, float* __restrict__ osk) {
    int w = (blockIdx.x * blockDim.x + threadIdx.x) >> 5;
    if (w >= NN) return;
    int lane = threadIdx.x & 31;
    int c0 = lane * 4;
    float4 h = *(const float4*)&hsum[(size_t)w * DD + c0];
    h.x *= 0.25f; h.y *= 0.25f; h.z *= 0.25f; h.w *= 0.25f;
    float4 wq = *(const float4*)&Wq[c0];
    float4 wk = *(const float4*)&Wk[c0];
    float4 wv = *(const float4*)&Wv[c0];
    float4 ws = *(const float4*)&Ws[c0];
    float dq = h.x * wq.x + h.y * wq.y + h.z * wq.z + h.w * wq.w;
    float dk = h.x * wk.x + h.y * wk.y + h.z * wk.z + h.w * wk.w;
    float dv = h.x * wv.x + h.y * wv.y + h.z * wv.z + h.w * wv.w;
    float ds = h.x * ws.x + h.y * ws.y + h.z * ws.z + h.w * ws.w;
#pragma unroll
    for (int o = 16; o; o >>= 1) {
        dq += __shfl_xor_sync(0xffffffffu, dq, o);
        dk += __shfl_xor_sync(0xffffffffu, dk, o);
        dv += __shfl_xor_sync(0xffffffffu, dv, o);
        ds += __shfl_xor_sync(0xffffffffu, ds, o);
    }
    if (lane == 0) {
        oq[w]  = dq + bq[0];
        ok[w]  = dk + bk[0];
        ov[w]  = dv + bv[0];
        osk[w] = ds + bs[0];
    }
}

__global__ void k_out_edge(const int* __restrict__ rowptr, const int* __restrict__ eids,
                           const int* __restrict__ src_arr, const float* __restrict__ eattr,
                           const float* __restrict__ We,
                           const float* __restrict__ oq, const float* __restrict__ ok,
                           const float* __restrict__ ov, const float* __restrict__ osk,
                           float* __restrict__ out) {
    int n = blockIdx.x * blockDim.x + threadIdx.x;
    if (n >= NN) return;
    float q = oq[n];
    float we = We[0];
    float m = -CUDART_INF_F, s = 0.f, acc = 0.f;
    int beg = rowptr[n], end = rowptr[n + 1];
    for (int i = beg; i < end; i++) {
        int e = eids[i];
        int sn = src_arr[e];
        float et = eattr[e] * we;
        float alpha = q * (ok[sn] + et);
        float mn = fmaxf(m, alpha);
        float corr = __expf(m - mn);
        float p = __expf(alpha - mn);
        s = s * corr + p;
        acc = acc * corr + p * (ov[sn] + et);
        m = mn;
    }
    out[n] = acc / (s + 1e-16f) + osk[n];
}

// =================================== host side ====================================
extern "C" void kernel_launch(void* const* d_in, const int* in_sizes, int n_in,
                              void* d_out, int out_size) {
    const float* x_seq = nullptr;
    const int*   ei    = nullptr;
    const float* ea    = nullptr;
    const float* P[22];
    int r = 0;
    for (int i = 0; i < n_in; i++) {
        if      (in_sizes[i] == TT * NN * IN_DIM) x_seq = (const float*)d_in[i];
        else if (in_sizes[i] == TT * 2 * EE)      ei    = (const int*)d_in[i];
        else if (in_sizes[i] == TT * EE)          ea    = (const float*)d_in[i];
        else if (r < 22)                          P[r++] = (const float*)d_in[i];
    }
    const float* gW_ih = P[0];
    const float* gW_hh = P[1];
    const float* gb_ih = P[2];
    const float* gb_hh = P[3];
    const float* cWq   = P[4];
    const float* cbq   = P[5];
    const float* cWk   = P[6];
    const float* cbk   = P[7];
    const float* cWv   = P[8];
    const float* cbv   = P[9];
    const float* cWe   = P[10];
    const float* cWs   = P[11];
    const float* cbs   = P[12];
    const float* oWq   = P[13];
    const float* obq   = P[14];
    const float* oWk   = P[15];
    const float* obk   = P[16];
    const float* oWv   = P[17];
    const float* obv   = P[18];
    const float* oWe   = P[19];
    const float* oWs   = P[20];
    const float* obs   = P[21];

    float *GI, *GH, *H, *HS, *QK, *BPK;
    __nv_bfloat16 *Xh, *Xl, *Hh, *Hl, *HAh, *HAl;
    __nv_bfloat16 *WIHh, *WIHl, *WHHh, *WHHl, *WPh, *WPl;
    float *OQ, *OKp, *OV, *OSK;
    int *RP, *EID, *CNT, *CUR;
    cudaGetSymbolAddress((void**)&GI,   g_GI);
    cudaGetSymbolAddress((void**)&GH,   g_GH);
    cudaGetSymbolAddress((void**)&H,    g_H);
    cudaGetSymbolAddress((void**)&HS,   g_HS);
    cudaGetSymbolAddress((void**)&QK,   g_QK);
    cudaGetSymbolAddress((void**)&Xh,   g_Xh);
    cudaGetSymbolAddress((void**)&Xl,   g_Xl);
    cudaGetSymbolAddress((void**)&Hh,   g_Hh);
    cudaGetSymbolAddress((void**)&Hl,   g_Hl);
    cudaGetSymbolAddress((void**)&HAh,  g_HAh);
    cudaGetSymbolAddress((void**)&HAl,  g_HAl);
    cudaGetSymbolAddress((void**)&WIHh, g_WIHh);
    cudaGetSymbolAddress((void**)&WIHl, g_WIHl);
    cudaGetSymbolAddress((void**)&WHHh, g_WHHh);
    cudaGetSymbolAddress((void**)&WHHl, g_WHHl);
    cudaGetSymbolAddress((void**)&WPh,  g_WPKh);
    cudaGetSymbolAddress((void**)&WPl,  g_WPKl);
    cudaGetSymbolAddress((void**)&BPK,  g_BPK);
    cudaGetSymbolAddress((void**)&OQ,   g_OQ);
    cudaGetSymbolAddress((void**)&OKp,  g_OKs);
    cudaGetSymbolAddress((void**)&OV,   g_OV);
    cudaGetSymbolAddress((void**)&OSK,  g_OSK);
    cudaGetSymbolAddress((void**)&RP,   g_RP);
    cudaGetSymbolAddress((void**)&EID,  g_EID);
    cudaGetSymbolAddress((void**)&CNT,  g_CNT);
    cudaGetSymbolAddress((void**)&CUR,  g_CUR);

    cudaFuncSetAttribute(k_pgemm, cudaFuncAttributeMaxDynamicSharedMemorySize, 65536);

    const int TPB = 256;
    const int SMEM = 2 * 4 * STG_WORDS * 4;  // 64KB

    // 1..3: prep (GI GEMM stays the 4th launch for ncu's capture window)
    k_zero_f<<<(NN * DD + TPB - 1) / TPB, TPB>>>(HS, NN * DD);
    k_split_x<<<(TT * NN * IN_DIM + TPB - 1) / TPB, TPB>>>(x_seq, Xh, Xl);
    k_prep_gru<<<(G3 * IN_DIM + G3 * DD + TPB - 1) / TPB, TPB>>>(gW_ih, gW_hh, WIHh, WIHl, WHHh, WHHl);

    // 4: GI = X @ W_ih^T + b_ih for all T at once: [80000,64] @ [64,384]
    k_pgemm<<<dim3(G3 / 128, (TT * NN + 127) / 128), 256, SMEM>>>(
        Xh, Xl, WIHh, WIHl, gb_ih, GI, TT * NN, G3, IN_DIM);

    k_prep_conv<<<(2 * QKVS * DD + TPB - 1) / TPB, TPB>>>(cWq, cWk, cWv, cWs, cbq, cbk, cbv, cbs, WPh, WPl, BPK);
    k_zero_i<<<(TT * NN + TPB - 1) / TPB, TPB>>>(CNT, TT * NN);
    k_hist<<<(TT * EE + TPB - 1) / TPB, TPB>>>(ei, CNT);
    k_scan<<<TT, 1024>>>(CNT, RP, CUR);
    k_scatter<<<(TT * EE + TPB - 1) / TPB, TPB>>>(ei, CUR, EID);

    for (int t = 0; t < TT; t++) {
        // GH = h @ W_hh^T + b_hh : skipped at t=0 (h == 0 -> gh = b_hh in gate kernel)
        if (t > 0) {
            k_pgemm<<<dim3(G3 / 128, (NN + 127) / 128), 256, SMEM>>>(
                Hh, Hl, WHHh, WHHl, gb_hh, GH, NN, G3, DD);
        }
        k_gru_gate<<<(NN * DD + TPB - 1) / TPB, TPB>>>(GI + (size_t)t * NN * G3, GH, gb_hh,
                                                       H, Hh, Hl, t == 0 ? 1 : 0);

        const int* rp_t   = RP + t * (NN + 1);
        const int* eid_t  = EID + (size_t)t * EE;
        const int* src_t  = ei + (size_t)t * 2 * EE;
        const float* ea_t = ea + (size_t)t * EE;

        // layer 0: qkvs from GRU output
        k_pgemm<<<dim3(QKVS / 128, (NN + 127) / 128), 256, SMEM>>>(
            Hh, Hl, WPh, WPl, BPK, QK, NN, QKVS, DD);
        k_conv_edge<<<NN / 8, 256>>>(QK, rp_t, eid_t, src_t, ea_t, cWe, HS, HAh, HAl, 0);

        // layer 1: qkvs from layer-0 output; accumulate into HS
        k_pgemm<<<dim3(QKVS / 128, (NN + 127) / 128), 256, SMEM>>>(
            HAh, HAl, WPh + QKVS * DD, WPl + QKVS * DD, BPK + QKVS, QK, NN, QKVS, DD);
        k_conv_edge<<<NN / 8, 256>>>(QK, rp_t, eid_t, src_t, ea_t, cWe + DD, HS, HAh, HAl, 1);
    }

    // output conv (edges of last timestep)
    k_out_node<<<NN / 8, 256>>>(HS, oWq, obq, oWk, obk, oWv, obv, oWs, obs, OQ, OKp, OV, OSK);
    k_out_edge<<<(NN + TPB - 1) / TPB, TPB>>>(RP + (TT - 1) * (NN + 1), EID + (size_t)(TT - 1) * EE,
                                              ei + (size_t)(TT - 1) * 2 * EE, ea + (size_t)(TT - 1) * EE,
                                              oWe, OQ, OKp, OV, OSK, (float*)d_out);
}

// round 6
// speedup vs baseline: 1.9765x; 1.0524x over previous
#include <cuda_runtime.h>
#include <cuda_bf16.h>
#include <math_constants.h>
#include <cstdint>

#define TT 4
#define NN 20000
#define EE 160000
#define IN_DIM 64
#define DD 128
#define G3 384   // 3*D
#define QKVS 512 // q|k|v|skip packed

// ------------------- static device scratch (no runtime allocs) -------------------
__device__ float g_GI[(size_t)TT * NN * G3];
__device__ float g_GH[(size_t)NN * G3];
__device__ float g_H [(size_t)NN * DD];
__device__ float g_HA2[(size_t)TT * NN * DD];          // layer-1 conv outputs (f32, per t)
__device__ float g_QK[(size_t)TT * NN * QKVS];         // batched qkvs for all t
// activations pre-split to bf16 hi/lo (batched over t)
__device__ __nv_bfloat16 g_Xh[(size_t)TT * NN * IN_DIM], g_Xl[(size_t)TT * NN * IN_DIM];
__device__ __nv_bfloat16 g_Hh[(size_t)TT * NN * DD], g_Hl[(size_t)TT * NN * DD];
__device__ __nv_bfloat16 g_HAh[(size_t)TT * NN * DD], g_HAl[(size_t)TT * NN * DD];
// weights pre-split to bf16 hi/lo, [N][K] layout
__device__ __nv_bfloat16 g_WIHh[G3 * IN_DIM], g_WIHl[G3 * IN_DIM];
__device__ __nv_bfloat16 g_WHHh[G3 * DD],     g_WHHl[G3 * DD];
__device__ __nv_bfloat16 g_WPKh[2 * QKVS * DD], g_WPKl[2 * QKVS * DD];
__device__ float g_BPK[2 * QKVS];
__device__ float g_OQ[NN], g_OKs[NN], g_OV[NN], g_OSK[NN];
__device__ int   g_RP [TT * (NN + 1)];
__device__ int   g_EID[TT * EE];
__device__ int   g_CNT[TT * NN];
__device__ int   g_CUR[TT * NN];

// ------------------------------- small utility kernels ---------------------------
__global__ void k_zero_i(int* p, int n) {
    int i = blockIdx.x * blockDim.x + threadIdx.x;
    if (i < n) p[i] = 0;
}

__device__ __forceinline__ void split_bf16(float v, __nv_bfloat16& h, __nv_bfloat16& l) {
    h = __float2bfloat16_rn(v);
    l = __float2bfloat16_rn(v - __bfloat162float(h));
}

__global__ void k_split_x(const float* __restrict__ x,
                          __nv_bfloat16* __restrict__ xh, __nv_bfloat16* __restrict__ xl) {
    int i = blockIdx.x * blockDim.x + threadIdx.x;
    if (i < TT * NN * IN_DIM) split_bf16(x[i], xh[i], xl[i]);
}

// GRU weights: W_ih [384,64] and W_hh [384,128] are natively [N,K].
__global__ void k_prep_gru(const float* __restrict__ Wih, const float* __restrict__ Whh,
                           __nv_bfloat16* __restrict__ ah, __nv_bfloat16* __restrict__ al,
                           __nv_bfloat16* __restrict__ bh, __nv_bfloat16* __restrict__ bl) {
    int i = blockIdx.x * blockDim.x + threadIdx.x;
    if (i < G3 * IN_DIM) split_bf16(Wih[i], ah[i], al[i]);
    int j = i - G3 * IN_DIM;
    if (j >= 0 && j < G3 * DD) split_bf16(Whh[j], bh[j], bl[j]);
}

// Pack conv weights transposed into [layer][n(512)][k(128)] hi/lo + bias pack
__global__ void k_prep_conv(const float* __restrict__ Wq, const float* __restrict__ Wk,
                            const float* __restrict__ Wv, const float* __restrict__ Ws,
                            const float* __restrict__ bq, const float* __restrict__ bk,
                            const float* __restrict__ bv, const float* __restrict__ bs,
                            __nv_bfloat16* __restrict__ WPh, __nv_bfloat16* __restrict__ WPl,
                            float* __restrict__ BP) {
    int i = blockIdx.x * blockDim.x + threadIdx.x;
    if (i < 2 * QKVS * DD) {
        int l = i >> 16;
        int rem = i & 65535;
        int n = rem >> 7, k = rem & 127;
        int base = l * DD * DD + k * DD;
        float v;
        if      (n < 128) v = Wq[base + n];
        else if (n < 256) v = Wk[base + n - 128];
        else if (n < 384) v = Wv[base + n - 256];
        else              v = Ws[base + n - 384];
        split_bf16(v, WPh[i], WPl[i]);
    }
    if (i < 2 * QKVS) {
        int l = i >> 9, c = i & 511;
        int b2 = l * DD;
        float v;
        if      (c < 128) v = bq[b2 + c];
        else if (c < 256) v = bk[b2 + c - 128];
        else if (c < 384) v = bv[b2 + c - 256];
        else              v = bs[b2 + c - 384];
        BP[i] = v;
    }
}

// ------------------------------- CSR build ---------------------------------------
__global__ void k_hist(const int* __restrict__ ei, int* __restrict__ cnt) {
    int i = blockIdx.x * blockDim.x + threadIdx.x;
    if (i >= TT * EE) return;
    int t = i / EE, e = i % EE;
    int dst = ei[(size_t)t * 2 * EE + EE + e];
    atomicAdd(&cnt[t * NN + dst], 1);
}

__global__ void k_scan(const int* __restrict__ cnt, int* __restrict__ rowptr, int* __restrict__ cur) {
    int t = blockIdx.x;
    __shared__ int sh[1024];
    const int* c = cnt + t * NN;
    int* rp = rowptr + t * (NN + 1);
    int* cu = cur + t * NN;
    int carry = 0;
    for (int base = 0; base < NN; base += 1024) {
        int idx = base + threadIdx.x;
        int v = (idx < NN) ? c[idx] : 0;
        sh[threadIdx.x] = v;
        __syncthreads();
        for (int off = 1; off < 1024; off <<= 1) {
            int tval = (threadIdx.x >= off) ? sh[threadIdx.x - off] : 0;
            __syncthreads();
            sh[threadIdx.x] += tval;
            __syncthreads();
        }
        int excl = sh[threadIdx.x] - v;
        if (idx < NN) { rp[idx] = carry + excl; cu[idx] = carry + excl; }
        carry += sh[1023];
        __syncthreads();
    }
    if (threadIdx.x == 0) rp[NN] = carry;
}

__global__ void k_scatter(const int* __restrict__ ei, int* __restrict__ cur, int* __restrict__ eids) {
    int i = blockIdx.x * blockDim.x + threadIdx.x;
    if (i >= TT * EE) return;
    int t = i / EE, e = i % EE;
    int dst = ei[(size_t)t * 2 * EE + EE + e];
    int p = atomicAdd(&cur[t * NN + dst], 1);
    eids[(size_t)t * EE + p] = e;
}

// ======== pipelined bf16 HMMA GEMM: cp.async + ldmatrix, 2 CTAs/SM ================
// C[M,Nc] = A @ B^T + bias. A,B pre-split bf16 hi/lo, both stored [rows][K] row-major.
// 3-pass: D = Ahi*Bhi + Ahi*Blo + Alo*Bhi, fp32 accumulate.
#define KC 32
#define STG_WORDS (128 * 16)   // words per array per stage (128 rows x 32 bf16)

__device__ __forceinline__ void mma_bf16(float c[4], const uint32_t a[4],
                                         uint32_t b0, uint32_t b1) {
    asm volatile(
        "mma.sync.aligned.m16n8k16.row.col.f32.bf16.bf16.f32 "
        "{%0,%1,%2,%3}, {%4,%5,%6,%7}, {%8,%9}, {%0,%1,%2,%3};"
        : "+f"(c[0]), "+f"(c[1]), "+f"(c[2]), "+f"(c[3])
        : "r"(a[0]), "r"(a[1]), "r"(a[2]), "r"(a[3]), "r"(b0), "r"(b1));
}

__device__ __forceinline__ void ldsm_x4(uint32_t addr, uint32_t& r0, uint32_t& r1,
                                        uint32_t& r2, uint32_t& r3) {
    asm volatile("ldmatrix.sync.aligned.m8n8.x4.shared.b16 {%0,%1,%2,%3}, [%4];"
                 : "=r"(r0), "=r"(r1), "=r"(r2), "=r"(r3) : "r"(addr));
}

__global__ void __launch_bounds__(256, 2) k_pgemm(
    const __nv_bfloat16* __restrict__ Ah, const __nv_bfloat16* __restrict__ Al,
    const __nv_bfloat16* __restrict__ Bh, const __nv_bfloat16* __restrict__ Bl,
    const float* __restrict__ bias, float* __restrict__ C, int M, int Nc, int K) {
    extern __shared__ uint32_t smw[];   // 2 stages x 4 arrays x STG_WORDS = 64KB

    int tid = threadIdx.x, wid = tid >> 5, lane = tid & 31;
    int gid = lane >> 2, t4 = lane & 3;
    int rowBase = blockIdx.y * 128;
    int colBase = blockIdx.x * 128;
    int warpRow = (wid & 3) * 32;
    int warpCol = (wid >> 2) * 64;

    float acc[2][8][4];
#pragma unroll
    for (int mt = 0; mt < 2; mt++)
#pragma unroll
        for (int nt = 0; nt < 8; nt++)
#pragma unroll
            for (int q = 0; q < 4; q++) acc[mt][nt][q] = 0.f;

    uint32_t sm0;
    asm("{ .reg .u64 t; cvta.to.shared.u64 t, %1; cvt.u32.u64 %0, t; }"
        : "=r"(sm0) : "l"(smw));

    const __nv_bfloat16* srcs[4] = {Ah, Al, Bh, Bl};

    int lm_m = lane >> 3;
    int lm_r = lane & 7;
    int a_row0 = warpRow + ((lm_m & 1) << 3) + lm_r;
    int a_kh   = lm_m >> 1;
    int b_row0 = warpCol + ((lm_m >> 1) << 3) + lm_r;
    int b_kh   = lm_m & 1;

    auto fill = [&](int stage, int k0) {
        uint32_t sb = sm0 + (uint32_t)stage * 4 * STG_WORDS * 4;
#pragma unroll
        for (int it = 0; it < 8; it++) {
            int idx = tid + it * 256;
            int arr = idx >> 9;
            int rem = idx & 511;
            int r = rem >> 2, c = rem & 3;
            int grow = (arr < 2) ? (rowBase + r) : (colBase + r);
            int valid = (arr >= 2) || (grow < M);
            const __nv_bfloat16* src = srcs[arr] + (valid ? ((size_t)grow * K + k0 + c * 8) : 0);
            int sz = valid ? 16 : 0;
            uint32_t dst = sb + (uint32_t)(arr * STG_WORDS + (r << 4) + ((c ^ ((r >> 1) & 3)) << 2)) * 4;
            asm volatile("cp.async.cg.shared.global [%0], [%1], 16, %2;"
                         :: "r"(dst), "l"(src), "r"(sz));
        }
        asm volatile("cp.async.commit_group;");
    };

    fill(0, 0);
    int nch = K / KC;

    for (int ch = 0; ch < nch; ch++) {
        if (ch + 1 < nch) {
            fill((ch + 1) & 1, (ch + 1) * KC);
            asm volatile("cp.async.wait_group 1;");
        } else {
            asm volatile("cp.async.wait_group 0;");
        }
        __syncthreads();

        uint32_t st = sm0 + (uint32_t)(ch & 1) * 4 * STG_WORDS * 4;
        uint32_t pAh = st;
        uint32_t pAl = st + STG_WORDS * 4;
        uint32_t pBh = st + 2 * STG_WORDS * 4;
        uint32_t pBl = st + 3 * STG_WORDS * 4;

#pragma unroll
        for (int ks = 0; ks < KC; ks += 16) {
            uint32_t ah[2][4], al[2][4];
            int ach = (ks >> 3) + a_kh;
#pragma unroll
            for (int mt = 0; mt < 2; mt++) {
                int ar = a_row0 + mt * 16;
                uint32_t aoff = (uint32_t)(ar << 6) + (uint32_t)((ach ^ ((ar >> 1) & 3)) << 4);
                ldsm_x4(pAh + aoff, ah[mt][0], ah[mt][1], ah[mt][2], ah[mt][3]);
                ldsm_x4(pAl + aoff, al[mt][0], al[mt][1], al[mt][2], al[mt][3]);
            }
            int bch = (ks >> 3) + b_kh;
#pragma unroll
            for (int p = 0; p < 4; p++) {
                int br = b_row0 + p * 16;
                uint32_t boff = (uint32_t)(br << 6) + (uint32_t)((bch ^ ((br >> 1) & 3)) << 4);
                uint32_t bh0, bh1, bh2, bh3, bl0, bl1, bl2, bl3;
                ldsm_x4(pBh + boff, bh0, bh1, bh2, bh3);
                ldsm_x4(pBl + boff, bl0, bl1, bl2, bl3);
                int n0 = 2 * p, n1 = 2 * p + 1;
                mma_bf16(acc[0][n0], ah[0], bh0, bh1);
                mma_bf16(acc[0][n1], ah[0], bh2, bh3);
                mma_bf16(acc[1][n0], ah[1], bh0, bh1);
                mma_bf16(acc[1][n1], ah[1], bh2, bh3);
                mma_bf16(acc[0][n0], ah[0], bl0, bl1);
                mma_bf16(acc[0][n1], ah[0], bl2, bl3);
                mma_bf16(acc[1][n0], ah[1], bl0, bl1);
                mma_bf16(acc[1][n1], ah[1], bl2, bl3);
                mma_bf16(acc[0][n0], al[0], bh0, bh1);
                mma_bf16(acc[0][n1], al[0], bh2, bh3);
                mma_bf16(acc[1][n0], al[1], bh0, bh1);
                mma_bf16(acc[1][n1], al[1], bh2, bh3);
            }
        }
        __syncthreads();
    }

#pragma unroll
    for (int mt = 0; mt < 2; mt++) {
        int r0 = rowBase + warpRow + mt * 16 + gid;
        int r1 = r0 + 8;
#pragma unroll
        for (int nt = 0; nt < 8; nt++) {
            int col = colBase + warpCol + nt * 8 + t4 * 2;
            float b0 = bias[col], b1 = bias[col + 1];
            if (r0 < M) {
                float2 o = make_float2(acc[mt][nt][0] + b0, acc[mt][nt][1] + b1);
                *(float2*)&C[(size_t)r0 * Nc + col] = o;
            }
            if (r1 < M) {
                float2 o = make_float2(acc[mt][nt][2] + b0, acc[mt][nt][3] + b1);
                *(float2*)&C[(size_t)r1 * Nc + col] = o;
            }
        }
    }
}

// ------------------------------- GRU gates ---------------------------------------
__global__ void k_gru_gate(const float* __restrict__ GI, const float* __restrict__ GH,
                           const float* __restrict__ bhh, float* __restrict__ H,
                           __nv_bfloat16* __restrict__ Hh, __nv_bfloat16* __restrict__ Hl,
                           int first) {
    int i = blockIdx.x * blockDim.x + threadIdx.x;
    if (i >= NN * DD) return;
    int n = i >> 7, j = i & 127;
    const float* gi = GI + (size_t)n * G3;
    float ir = gi[j], iz = gi[j + 128], in = gi[j + 256];
    float hr, hz, hn, hp;
    if (first) {
        hr = bhh[j]; hz = bhh[j + 128]; hn = bhh[j + 256];
        hp = 0.f;
    } else {
        const float* gh = GH + (size_t)n * G3;
        hr = gh[j]; hz = gh[j + 128]; hn = gh[j + 256];
        hp = H[i];
    }
    float r = 1.f / (1.f + __expf(-(ir + hr)));
    float z = 1.f / (1.f + __expf(-(iz + hz)));
    float nv = tanhf(in + r * hn);
    float h = (1.f - z) * nv + z * hp;
    H[i] = h;
    split_bf16(h, Hh[i], Hl[i]);
}

// ---------------------- TransformerConv edge attention (D=128) -------------------
// mode 0: write bf16 hi/lo split (feeds next GEMM). mode 1: write f32 to out.
__global__ void k_conv_edge(const float* __restrict__ qkvs,
                            const int* __restrict__ rowptr, const int* __restrict__ eids,
                            const int* __restrict__ src_arr, const float* __restrict__ eattr,
                            const float* __restrict__ We, float* __restrict__ out,
                            __nv_bfloat16* __restrict__ oh, __nv_bfloat16* __restrict__ ol,
                            int mode) {
    int w = (blockIdx.x * blockDim.x + threadIdx.x) >> 5;
    if (w >= NN) return;
    int lane = threadIdx.x & 31;
    int c0 = lane * 4;
    float4 q  = *(const float4*)&qkvs[(size_t)w * QKVS + c0];
    float4 sk = *(const float4*)&qkvs[(size_t)w * QKVS + 384 + c0];
    float4 we = *(const float4*)&We[c0];
    float m = -CUDART_INF_F, s = 0.f;
    float4 acc = make_float4(0.f, 0.f, 0.f, 0.f);
    int beg = rowptr[w], end = rowptr[w + 1];
    for (int i = beg; i < end; i++) {
        int e = eids[i];
        int sn = src_arr[e];
        float eaV = eattr[e];
        float4 k4 = *(const float4*)&qkvs[(size_t)sn * QKVS + 128 + c0];
        float4 v4 = *(const float4*)&qkvs[(size_t)sn * QKVS + 256 + c0];
        float ex = eaV * we.x, ey = eaV * we.y, ez = eaV * we.z, ew = eaV * we.w;
        float part = q.x * (k4.x + ex) + q.y * (k4.y + ey) + q.z * (k4.z + ez) + q.w * (k4.w + ew);
#pragma unroll
        for (int o = 16; o; o >>= 1) part += __shfl_xor_sync(0xffffffffu, part, o);
        float alpha = part * 0.08838834764831845f; // 1/sqrt(128)
        float mn = fmaxf(m, alpha);
        float corr = __expf(m - mn);
        float p = __expf(alpha - mn);
        s = s * corr + p;
        acc.x = acc.x * corr + p * (v4.x + ex);
        acc.y = acc.y * corr + p * (v4.y + ey);
        acc.z = acc.z * corr + p * (v4.z + ez);
        acc.w = acc.w * corr + p * (v4.w + ew);
        m = mn;
    }
    float inv = 1.f / (s + 1e-16f);
    float4 o;
    o.x = acc.x * inv + sk.x;
    o.y = acc.y * inv + sk.y;
    o.z = acc.z * inv + sk.z;
    o.w = acc.w * inv + sk.w;
    o.x = o.x > 0.f ? o.x : 0.01f * o.x;
    o.y = o.y > 0.f ? o.y : 0.01f * o.y;
    o.z = o.z > 0.f ? o.z : 0.01f * o.z;
    o.w = o.w > 0.f ? o.w : 0.01f * o.w;
    if (mode) {
        *(float4*)&out[(size_t)w * DD + c0] = o;
    } else {
        __nv_bfloat16 hx, lx, hy, ly, hz, lz, hw, lw;
        split_bf16(o.x, hx, lx);
        split_bf16(o.y, hy, ly);
        split_bf16(o.z, hz, lz);
        split_bf16(o.w, hw, lw);
        __nv_bfloat16 hv[4] = {hx, hy, hz, hw};
        __nv_bfloat16 lv[4] = {lx, ly, lz, lw};
        *(uint2*)&oh[(size_t)w * DD + c0] = *(uint2*)hv;
        *(uint2*)&ol[(size_t)w * DD + c0] = *(uint2*)lv;
    }
}

// ------------------------ output conv (D -> 1) -----------------------------------
// reads 4 per-t slices of HA2, averages, projects to scalars
__global__ void k_out_node(const float* __restrict__ ha2,
                           const float* __restrict__ Wq, const float* __restrict__ bq,
                           const float* __restrict__ Wk, const float* __restrict__ bk,
                           const float* __restrict__ Wv, const float* __restrict__ bv,
                           const float* __restrict__ Ws, const float* __restrict__ bs,
                           float* __restrict__ oq, float* __restrict__ ok,
                           float* __restrict__ ov, float* __restrict__ osk) {
    int w = (blockIdx.x * blockDim.x + threadIdx.x) >> 5;
    if (w >= NN) return;
    int lane = threadIdx.x & 31;
    int c0 = lane * 4;
    float4 h = make_float4(0.f, 0.f, 0.f, 0.f);
#pragma unroll
    for (int t = 0; t < TT; t++) {
        float4 v = *(const float4*)&ha2[(size_t)t * NN * DD + (size_t)w * DD + c0];
        h.x += v.x; h.y += v.y; h.z += v.z; h.w += v.w;
    }
    h.x *= 0.25f; h.y *= 0.25f; h.z *= 0.25f; h.w *= 0.25f;
    float4 wq = *(const float4*)&Wq[c0];
    float4 wk = *(const float4*)&Wk[c0];
    float4 wv = *(const float4*)&Wv[c0];
    float4 ws = *(const float4*)&Ws[c0];
    float dq = h.x * wq.x + h.y * wq.y + h.z * wq.z + h.w * wq.w;
    float dk = h.x * wk.x + h.y * wk.y + h.z * wk.z + h.w * wk.w;
    float dv = h.x * wv.x + h.y * wv.y + h.z * wv.z + h.w * wv.w;
    float ds = h.x * ws.x + h.y * ws.y + h.z * ws.z + h.w * ws.w;
#pragma unroll
    for (int o = 16; o; o >>= 1) {
        dq += __shfl_xor_sync(0xffffffffu, dq, o);
        dk += __shfl_xor_sync(0xffffffffu, dk, o);
        dv += __shfl_xor_sync(0xffffffffu, dv, o);
        ds += __shfl_xor_sync(0xffffffffu, ds, o);
    }
    if (lane == 0) {
        oq[w]  = dq + bq[0];
        ok[w]  = dk + bk[0];
        ov[w]  = dv + bv[0];
        osk[w] = ds + bs[0];
    }
}

__global__ void k_out_edge(const int* __restrict__ rowptr, const int* __restrict__ eids,
                           const int* __restrict__ src_arr, const float* __restrict__ eattr,
                           const float* __restrict__ We,
                           const float* __restrict__ oq, const float* __restrict__ ok,
                           const float* __restrict__ ov, const float* __restrict__ osk,
                           float* __restrict__ out) {
    int n = blockIdx.x * blockDim.x + threadIdx.x;
    if (n >= NN) return;
    float q = oq[n];
    float we = We[0];
    float m = -CUDART_INF_F, s = 0.f, acc = 0.f;
    int beg = rowptr[n], end = rowptr[n + 1];
    for (int i = beg; i < end; i++) {
        int e = eids[i];
        int sn = src_arr[e];
        float et = eattr[e] * we;
        float alpha = q * (ok[sn] + et);
        float mn = fmaxf(m, alpha);
        float corr = __expf(m - mn);
        float p = __expf(alpha - mn);
        s = s * corr + p;
        acc = acc * corr + p * (ov[sn] + et);
        m = mn;
    }
    out[n] = acc / (s + 1e-16f) + osk[n];
}

// =================================== host side ====================================
extern "C" void kernel_launch(void* const* d_in, const int* in_sizes, int n_in,
                              void* d_out, int out_size) {
    const float* x_seq = nullptr;
    const int*   ei    = nullptr;
    const float* ea    = nullptr;
    const float* P[22];
    int r = 0;
    for (int i = 0; i < n_in; i++) {
        if      (in_sizes[i] == TT * NN * IN_DIM) x_seq = (const float*)d_in[i];
        else if (in_sizes[i] == TT * 2 * EE)      ei    = (const int*)d_in[i];
        else if (in_sizes[i] == TT * EE)          ea    = (const float*)d_in[i];
        else if (r < 22)                          P[r++] = (const float*)d_in[i];
    }
    const float* gW_ih = P[0];
    const float* gW_hh = P[1];
    const float* gb_ih = P[2];
    const float* gb_hh = P[3];
    const float* cWq   = P[4];
    const float* cbq   = P[5];
    const float* cWk   = P[6];
    const float* cbk   = P[7];
    const float* cWv   = P[8];
    const float* cbv   = P[9];
    const float* cWe   = P[10];
    const float* cWs   = P[11];
    const float* cbs   = P[12];
    const float* oWq   = P[13];
    const float* obq   = P[14];
    const float* oWk   = P[15];
    const float* obk   = P[16];
    const float* oWv   = P[17];
    const float* obv   = P[18];
    const float* oWe   = P[19];
    const float* oWs   = P[20];
    const float* obs   = P[21];

    float *GI, *GH, *H, *HA2, *QK, *BPK;
    __nv_bfloat16 *Xh, *Xl, *Hh, *Hl, *HAh, *HAl;
    __nv_bfloat16 *WIHh, *WIHl, *WHHh, *WHHl, *WPh, *WPl;
    float *OQ, *OKp, *OV, *OSK;
    int *RP, *EID, *CNT, *CUR;
    cudaGetSymbolAddress((void**)&GI,   g_GI);
    cudaGetSymbolAddress((void**)&GH,   g_GH);
    cudaGetSymbolAddress((void**)&H,    g_H);
    cudaGetSymbolAddress((void**)&HA2,  g_HA2);
    cudaGetSymbolAddress((void**)&QK,   g_QK);
    cudaGetSymbolAddress((void**)&Xh,   g_Xh);
    cudaGetSymbolAddress((void**)&Xl,   g_Xl);
    cudaGetSymbolAddress((void**)&Hh,   g_Hh);
    cudaGetSymbolAddress((void**)&Hl,   g_Hl);
    cudaGetSymbolAddress((void**)&HAh,  g_HAh);
    cudaGetSymbolAddress((void**)&HAl,  g_HAl);
    cudaGetSymbolAddress((void**)&WIHh, g_WIHh);
    cudaGetSymbolAddress((void**)&WIHl, g_WIHl);
    cudaGetSymbolAddress((void**)&WHHh, g_WHHh);
    cudaGetSymbolAddress((void**)&WHHl, g_WHHl);
    cudaGetSymbolAddress((void**)&WPh,  g_WPKh);
    cudaGetSymbolAddress((void**)&WPl,  g_WPKl);
    cudaGetSymbolAddress((void**)&BPK,  g_BPK);
    cudaGetSymbolAddress((void**)&OQ,   g_OQ);
    cudaGetSymbolAddress((void**)&OKp,  g_OKs);
    cudaGetSymbolAddress((void**)&OV,   g_OV);
    cudaGetSymbolAddress((void**)&OSK,  g_OSK);
    cudaGetSymbolAddress((void**)&RP,   g_RP);
    cudaGetSymbolAddress((void**)&EID,  g_EID);
    cudaGetSymbolAddress((void**)&CNT,  g_CNT);
    cudaGetSymbolAddress((void**)&CUR,  g_CUR);

    cudaFuncSetAttribute(k_pgemm, cudaFuncAttributeMaxDynamicSharedMemorySize, 65536);

    const int TPB = 256;
    const int SMEM = 2 * 4 * STG_WORDS * 4;  // 64KB

    // 1..3: prep (GI GEMM stays the 4th launch for ncu's capture window)
    k_split_x<<<(TT * NN * IN_DIM + TPB - 1) / TPB, TPB>>>(x_seq, Xh, Xl);
    k_prep_gru<<<(G3 * IN_DIM + G3 * DD + TPB - 1) / TPB, TPB>>>(gW_ih, gW_hh, WIHh, WIHl, WHHh, WHHl);
    k_prep_conv<<<(2 * QKVS * DD + TPB - 1) / TPB, TPB>>>(cWq, cWk, cWv, cWs, cbq, cbk, cbv, cbs, WPh, WPl, BPK);

    // 4: GI = X @ W_ih^T + b_ih for all T at once: [80000,64] @ [64,384]
    k_pgemm<<<dim3(G3 / 128, (TT * NN + 127) / 128), 256, SMEM>>>(
        Xh, Xl, WIHh, WIHl, gb_ih, GI, TT * NN, G3, IN_DIM);

    // CSR build
    k_zero_i<<<(TT * NN + TPB - 1) / TPB, TPB>>>(CNT, TT * NN);
    k_hist<<<(TT * EE + TPB - 1) / TPB, TPB>>>(ei, CNT);
    k_scan<<<TT, 1024>>>(CNT, RP, CUR);
    k_scatter<<<(TT * EE + TPB - 1) / TPB, TPB>>>(ei, CUR, EID);

    // ---- GRU over time: sequential chain, per-t Hh/Hl stored batched ----
    for (int t = 0; t < TT; t++) {
        if (t > 0) {
            k_pgemm<<<dim3(G3 / 128, (NN + 127) / 128), 256, SMEM>>>(
                Hh + (size_t)(t - 1) * NN * DD, Hl + (size_t)(t - 1) * NN * DD,
                WHHh, WHHl, gb_hh, GH, NN, G3, DD);
        }
        k_gru_gate<<<(NN * DD + TPB - 1) / TPB, TPB>>>(
            GI + (size_t)t * NN * G3, GH, gb_hh, H,
            Hh + (size_t)t * NN * DD, Hl + (size_t)t * NN * DD, t == 0 ? 1 : 0);
    }

    // ---- layer 0: ONE batched qkvs GEMM over all t, then per-t edge conv ----
    k_pgemm<<<dim3(QKVS / 128, (TT * NN + 127) / 128), 256, SMEM>>>(
        Hh, Hl, WPh, WPl, BPK, QK, TT * NN, QKVS, DD);
    for (int t = TT - 1; t >= 0; t--) {  // t=3 first: its QK slice is L2-hot
        k_conv_edge<<<NN / 8, 256>>>(QK + (size_t)t * NN * QKVS,
                                     RP + t * (NN + 1), EID + (size_t)t * EE,
                                     ei + (size_t)t * 2 * EE, ea + (size_t)t * EE,
                                     cWe, nullptr,
                                     HAh + (size_t)t * NN * DD, HAl + (size_t)t * NN * DD, 0);
    }

    // ---- layer 1: ONE batched qkvs GEMM, then per-t edge conv (f32 out) ----
    k_pgemm<<<dim3(QKVS / 128, (TT * NN + 127) / 128), 256, SMEM>>>(
        HAh, HAl, WPh + QKVS * DD, WPl + QKVS * DD, BPK + QKVS, QK, TT * NN, QKVS, DD);
    for (int t = TT - 1; t >= 0; t--) {
        k_conv_edge<<<NN / 8, 256>>>(QK + (size_t)t * NN * QKVS,
                                     RP + t * (NN + 1), EID + (size_t)t * EE,
                                     ei + (size_t)t * 2 * EE, ea + (size_t)t * EE,
                                     cWe + DD, HA2 + (size_t)t * NN * DD,
                                     nullptr, nullptr, 1);
    }

    // ---- output conv (edges of last timestep) ----
    k_out_node<<<NN / 8, 256>>>(HA2, oWq, obq, oWk, obk, oWv, obv, oWs, obs, OQ, OKp, OV, OSK);
    k_out_edge<<<(NN + TPB - 1) / TPB, TPB>>>(RP + (TT - 1) * (NN + 1), EID + (size_t)(TT - 1) * EE,
                                              ei + (size_t)(TT - 1) * 2 * EE, ea + (size_t)(TT - 1) * EE,
                                              oWe, OQ, OKp, OV, OSK, (float*)d_out);
}

// round 7
// speedup vs baseline: 2.1436x; 1.0845x over previous
#include <cuda_runtime.h>
#include <cuda_bf16.h>
#include <math_constants.h>
#include <cstdint>

#define TT 4
#define NN 20000
#define EE 160000
#define IN_DIM 64
#define DD 128
#define G3 384   // 3*D
#define QKVS 512 // q|k|v|skip packed

// ------------------- static device scratch (no runtime allocs) -------------------
__device__ float g_GI[(size_t)TT * NN * G3];
__device__ float g_GH[(size_t)NN * G3];
__device__ float g_H [(size_t)NN * DD];
__device__ float g_HA2[(size_t)TT * NN * DD];          // layer-1 conv outputs (f32, per t)
__device__ float g_QK[(size_t)TT * NN * QKVS];         // batched qkvs for all t
// activations pre-split to bf16 hi/lo (batched over t)
__device__ __nv_bfloat16 g_Xh[(size_t)TT * NN * IN_DIM], g_Xl[(size_t)TT * NN * IN_DIM];
__device__ __nv_bfloat16 g_Hh[(size_t)TT * NN * DD], g_Hl[(size_t)TT * NN * DD];
__device__ __nv_bfloat16 g_HAh[(size_t)TT * NN * DD], g_HAl[(size_t)TT * NN * DD];
// weights pre-split to bf16 hi/lo, [N][K] layout
__device__ __nv_bfloat16 g_WIHh[G3 * IN_DIM], g_WIHl[G3 * IN_DIM];
__device__ __nv_bfloat16 g_WHHh[G3 * DD],     g_WHHl[G3 * DD];
__device__ __nv_bfloat16 g_WPKh[2 * QKVS * DD], g_WPKl[2 * QKVS * DD];
__device__ float g_BPK[2 * QKVS];
__device__ float g_OQ[NN], g_OKs[NN], g_OV[NN], g_OSK[NN];
__device__ int   g_RP [TT * (NN + 1)];
__device__ int   g_EID[TT * EE];
__device__ int   g_CNT[TT * NN];
__device__ int   g_CUR[TT * NN];

// ------------------------------- small utility kernels ---------------------------
__global__ void k_zero_i(int* p, int n) {
    int i = blockIdx.x * blockDim.x + threadIdx.x;
    if (i < n) p[i] = 0;
}

__device__ __forceinline__ void split_bf16(float v, __nv_bfloat16& h, __nv_bfloat16& l) {
    h = __float2bfloat16_rn(v);
    l = __float2bfloat16_rn(v - __bfloat162float(h));
}

__global__ void k_split_x(const float* __restrict__ x,
                          __nv_bfloat16* __restrict__ xh, __nv_bfloat16* __restrict__ xl) {
    int i = blockIdx.x * blockDim.x + threadIdx.x;
    if (i < TT * NN * IN_DIM) split_bf16(x[i], xh[i], xl[i]);
}

// GRU weights: W_ih [384,64] and W_hh [384,128] are natively [N,K].
__global__ void k_prep_gru(const float* __restrict__ Wih, const float* __restrict__ Whh,
                           __nv_bfloat16* __restrict__ ah, __nv_bfloat16* __restrict__ al,
                           __nv_bfloat16* __restrict__ bh, __nv_bfloat16* __restrict__ bl) {
    int i = blockIdx.x * blockDim.x + threadIdx.x;
    if (i < G3 * IN_DIM) split_bf16(Wih[i], ah[i], al[i]);
    int j = i - G3 * IN_DIM;
    if (j >= 0 && j < G3 * DD) split_bf16(Whh[j], bh[j], bl[j]);
}

// Pack conv weights transposed into [layer][n(512)][k(128)] hi/lo + bias pack
__global__ void k_prep_conv(const float* __restrict__ Wq, const float* __restrict__ Wk,
                            const float* __restrict__ Wv, const float* __restrict__ Ws,
                            const float* __restrict__ bq, const float* __restrict__ bk,
                            const float* __restrict__ bv, const float* __restrict__ bs,
                            __nv_bfloat16* __restrict__ WPh, __nv_bfloat16* __restrict__ WPl,
                            float* __restrict__ BP) {
    int i = blockIdx.x * blockDim.x + threadIdx.x;
    if (i < 2 * QKVS * DD) {
        int l = i >> 16;
        int rem = i & 65535;
        int n = rem >> 7, k = rem & 127;
        int base = l * DD * DD + k * DD;
        float v;
        if      (n < 128) v = Wq[base + n];
        else if (n < 256) v = Wk[base + n - 128];
        else if (n < 384) v = Wv[base + n - 256];
        else              v = Ws[base + n - 384];
        split_bf16(v, WPh[i], WPl[i]);
    }
    if (i < 2 * QKVS) {
        int l = i >> 9, c = i & 511;
        int b2 = l * DD;
        float v;
        if      (c < 128) v = bq[b2 + c];
        else if (c < 256) v = bk[b2 + c - 128];
        else if (c < 384) v = bv[b2 + c - 256];
        else              v = bs[b2 + c - 384];
        BP[i] = v;
    }
}

// ------------------------------- CSR build ---------------------------------------
__global__ void k_hist(const int* __restrict__ ei, int* __restrict__ cnt) {
    int i = blockIdx.x * blockDim.x + threadIdx.x;
    if (i >= TT * EE) return;
    int t = i / EE, e = i % EE;
    int dst = ei[(size_t)t * 2 * EE + EE + e];
    atomicAdd(&cnt[t * NN + dst], 1);
}

__global__ void k_scan(const int* __restrict__ cnt, int* __restrict__ rowptr, int* __restrict__ cur) {
    int t = blockIdx.x;
    __shared__ int sh[1024];
    const int* c = cnt + t * NN;
    int* rp = rowptr + t * (NN + 1);
    int* cu = cur + t * NN;
    int carry = 0;
    for (int base = 0; base < NN; base += 1024) {
        int idx = base + threadIdx.x;
        int v = (idx < NN) ? c[idx] : 0;
        sh[threadIdx.x] = v;
        __syncthreads();
        for (int off = 1; off < 1024; off <<= 1) {
            int tval = (threadIdx.x >= off) ? sh[threadIdx.x - off] : 0;
            __syncthreads();
            sh[threadIdx.x] += tval;
            __syncthreads();
        }
        int excl = sh[threadIdx.x] - v;
        if (idx < NN) { rp[idx] = carry + excl; cu[idx] = carry + excl; }
        carry += sh[1023];
        __syncthreads();
    }
    if (threadIdx.x == 0) rp[NN] = carry;
}

__global__ void k_scatter(const int* __restrict__ ei, int* __restrict__ cur, int* __restrict__ eids) {
    int i = blockIdx.x * blockDim.x + threadIdx.x;
    if (i >= TT * EE) return;
    int t = i / EE, e = i % EE;
    int dst = ei[(size_t)t * 2 * EE + EE + e];
    int p = atomicAdd(&cur[t * NN + dst], 1);
    eids[(size_t)t * EE + p] = e;
}

// ==== pipelined bf16 HMMA GEMM: 3-stage cp.async + ldmatrix, 1 barrier/chunk ======
// C[M,Nc] = A @ B^T + bias. A,B pre-split bf16 hi/lo, both stored [rows][K] row-major.
// 3-pass: D = Ahi*Bhi + Ahi*Blo + Alo*Bhi, fp32 accumulate.
#define KC 32
#define NSTG 3
#define STG_WORDS (128 * 16)   // words per array per stage (128 rows x 32 bf16)

__device__ __forceinline__ void mma_bf16(float c[4], const uint32_t a[4],
                                         uint32_t b0, uint32_t b1) {
    asm volatile(
        "mma.sync.aligned.m16n8k16.row.col.f32.bf16.bf16.f32 "
        "{%0,%1,%2,%3}, {%4,%5,%6,%7}, {%8,%9}, {%0,%1,%2,%3};"
        : "+f"(c[0]), "+f"(c[1]), "+f"(c[2]), "+f"(c[3])
        : "r"(a[0]), "r"(a[1]), "r"(a[2]), "r"(a[3]), "r"(b0), "r"(b1));
}

__device__ __forceinline__ void ldsm_x4(uint32_t addr, uint32_t& r0, uint32_t& r1,
                                        uint32_t& r2, uint32_t& r3) {
    asm volatile("ldmatrix.sync.aligned.m8n8.x4.shared.b16 {%0,%1,%2,%3}, [%4];"
                 : "=r"(r0), "=r"(r1), "=r"(r2), "=r"(r3) : "r"(addr));
}

__global__ void __launch_bounds__(256, 2) k_pgemm(
    const __nv_bfloat16* __restrict__ Ah, const __nv_bfloat16* __restrict__ Al,
    const __nv_bfloat16* __restrict__ Bh, const __nv_bfloat16* __restrict__ Bl,
    const float* __restrict__ bias, float* __restrict__ C, int M, int Nc, int K) {
    extern __shared__ uint32_t smw[];   // NSTG stages x 4 arrays x STG_WORDS = 96KB

    int tid = threadIdx.x, wid = tid >> 5, lane = tid & 31;
    int gid = lane >> 2, t4 = lane & 3;
    int rowBase = blockIdx.y * 128;
    int colBase = blockIdx.x * 128;
    int warpRow = (wid & 3) * 32;
    int warpCol = (wid >> 2) * 64;

    float acc[2][8][4];
#pragma unroll
    for (int mt = 0; mt < 2; mt++)
#pragma unroll
        for (int nt = 0; nt < 8; nt++)
#pragma unroll
            for (int q = 0; q < 4; q++) acc[mt][nt][q] = 0.f;

    uint32_t sm0;
    asm("{ .reg .u64 t; cvta.to.shared.u64 t, %1; cvt.u32.u64 %0, t; }"
        : "=r"(sm0) : "l"(smw));

    const __nv_bfloat16* srcs[4] = {Ah, Al, Bh, Bl};

    int lm_m = lane >> 3;
    int lm_r = lane & 7;
    int a_row0 = warpRow + ((lm_m & 1) << 3) + lm_r;
    int a_kh   = lm_m >> 1;
    int b_row0 = warpCol + ((lm_m >> 1) << 3) + lm_r;
    int b_kh   = lm_m & 1;

    auto fill = [&](int stage, int k0) {
        uint32_t sb = sm0 + (uint32_t)stage * 4 * STG_WORDS * 4;
#pragma unroll
        for (int it = 0; it < 8; it++) {
            int idx = tid + it * 256;
            int arr = idx >> 9;
            int rem = idx & 511;
            int r = rem >> 2, c = rem & 3;
            int grow = (arr < 2) ? (rowBase + r) : (colBase + r);
            int valid = (arr >= 2) || (grow < M);
            const __nv_bfloat16* src = srcs[arr] + (valid ? ((size_t)grow * K + k0 + c * 8) : 0);
            int sz = valid ? 16 : 0;
            uint32_t dst = sb + (uint32_t)(arr * STG_WORDS + (r << 4) + ((c ^ ((r >> 1) & 3)) << 2)) * 4;
            asm volatile("cp.async.cg.shared.global [%0], [%1], 16, %2;"
                         :: "r"(dst), "l"(src), "r"(sz));
        }
        asm volatile("cp.async.commit_group;");
    };

    int nch = K / KC;
    fill(0, 0);
    if (nch > 1) fill(1, KC);

    for (int ch = 0; ch < nch; ch++) {
        // ensure chunk ch's group is complete
        if (ch + 2 <= nch) { asm volatile("cp.async.wait_group 1;"); }
        else               { asm volatile("cp.async.wait_group 0;"); }
        __syncthreads();   // also fences: all warps done computing chunk ch-1

        // prefetch chunk ch+2 into stage (ch+2)%3 (== buffer of chunk ch-1)
        if (ch + 2 < nch) fill((ch + 2) % NSTG, (ch + 2) * KC);

        uint32_t st = sm0 + (uint32_t)(ch % NSTG) * 4 * STG_WORDS * 4;
        uint32_t pAh = st;
        uint32_t pAl = st + STG_WORDS * 4;
        uint32_t pBh = st + 2 * STG_WORDS * 4;
        uint32_t pBl = st + 3 * STG_WORDS * 4;

#pragma unroll
        for (int ks = 0; ks < KC; ks += 16) {
            uint32_t ah[2][4], al[2][4];
            int ach = (ks >> 3) + a_kh;
#pragma unroll
            for (int mt = 0; mt < 2; mt++) {
                int ar = a_row0 + mt * 16;
                uint32_t aoff = (uint32_t)(ar << 6) + (uint32_t)((ach ^ ((ar >> 1) & 3)) << 4);
                ldsm_x4(pAh + aoff, ah[mt][0], ah[mt][1], ah[mt][2], ah[mt][3]);
                ldsm_x4(pAl + aoff, al[mt][0], al[mt][1], al[mt][2], al[mt][3]);
            }
            int bch = (ks >> 3) + b_kh;
#pragma unroll
            for (int p = 0; p < 4; p++) {
                int br = b_row0 + p * 16;
                uint32_t boff = (uint32_t)(br << 6) + (uint32_t)((bch ^ ((br >> 1) & 3)) << 4);
                uint32_t bh0, bh1, bh2, bh3, bl0, bl1, bl2, bl3;
                ldsm_x4(pBh + boff, bh0, bh1, bh2, bh3);
                ldsm_x4(pBl + boff, bl0, bl1, bl2, bl3);
                int n0 = 2 * p, n1 = 2 * p + 1;
                mma_bf16(acc[0][n0], ah[0], bh0, bh1);
                mma_bf16(acc[0][n1], ah[0], bh2, bh3);
                mma_bf16(acc[1][n0], ah[1], bh0, bh1);
                mma_bf16(acc[1][n1], ah[1], bh2, bh3);
                mma_bf16(acc[0][n0], ah[0], bl0, bl1);
                mma_bf16(acc[0][n1], ah[0], bl2, bl3);
                mma_bf16(acc[1][n0], ah[1], bl0, bl1);
                mma_bf16(acc[1][n1], ah[1], bl2, bl3);
                mma_bf16(acc[0][n0], al[0], bh0, bh1);
                mma_bf16(acc[0][n1], al[0], bh2, bh3);
                mma_bf16(acc[1][n0], al[1], bh0, bh1);
                mma_bf16(acc[1][n1], al[1], bh2, bh3);
            }
        }
    }

#pragma unroll
    for (int mt = 0; mt < 2; mt++) {
        int r0 = rowBase + warpRow + mt * 16 + gid;
        int r1 = r0 + 8;
#pragma unroll
        for (int nt = 0; nt < 8; nt++) {
            int col = colBase + warpCol + nt * 8 + t4 * 2;
            float b0 = bias[col], b1 = bias[col + 1];
            if (r0 < M) {
                float2 o = make_float2(acc[mt][nt][0] + b0, acc[mt][nt][1] + b1);
                *(float2*)&C[(size_t)r0 * Nc + col] = o;
            }
            if (r1 < M) {
                float2 o = make_float2(acc[mt][nt][2] + b0, acc[mt][nt][3] + b1);
                *(float2*)&C[(size_t)r1 * Nc + col] = o;
            }
        }
    }
}

// ------------------------------- GRU gates ---------------------------------------
__global__ void k_gru_gate(const float* __restrict__ GI, const float* __restrict__ GH,
                           const float* __restrict__ bhh, float* __restrict__ H,
                           __nv_bfloat16* __restrict__ Hh, __nv_bfloat16* __restrict__ Hl,
                           int first) {
    int i = blockIdx.x * blockDim.x + threadIdx.x;
    if (i >= NN * DD) return;
    int n = i >> 7, j = i & 127;
    const float* gi = GI + (size_t)n * G3;
    float ir = gi[j], iz = gi[j + 128], in = gi[j + 256];
    float hr, hz, hn, hp;
    if (first) {
        hr = bhh[j]; hz = bhh[j + 128]; hn = bhh[j + 256];
        hp = 0.f;
    } else {
        const float* gh = GH + (size_t)n * G3;
        hr = gh[j]; hz = gh[j + 128]; hn = gh[j + 256];
        hp = H[i];
    }
    float r = 1.f / (1.f + __expf(-(ir + hr)));
    float z = 1.f / (1.f + __expf(-(iz + hz)));
    float nv = tanhf(in + r * hn);
    float h = (1.f - z) * nv + z * hp;
    H[i] = h;
    split_bf16(h, Hh[i], Hl[i]);
}

// -------------- TransformerConv edge attention, ALL timesteps in one launch ------
// mode 0: write bf16 hi/lo split (feeds next GEMM). mode 1: write f32 to out.
__global__ void k_conv_all(const float* __restrict__ QK,
                           const int* __restrict__ RP, const int* __restrict__ EID,
                           const int* __restrict__ ei, const float* __restrict__ ea,
                           const float* __restrict__ We, float* __restrict__ out,
                           __nv_bfloat16* __restrict__ oh, __nv_bfloat16* __restrict__ ol,
                           int mode) {
    int gw = (blockIdx.x * blockDim.x + threadIdx.x) >> 5;
    if (gw >= TT * NN) return;
    int t = gw / NN;
    int w = gw - t * NN;
    const float* qkvs = QK + (size_t)t * NN * QKVS;
    const int* rowptr = RP + t * (NN + 1);
    const int* eids   = EID + (size_t)t * EE;
    const int* src_arr = ei + (size_t)t * 2 * EE;
    const float* eattr = ea + (size_t)t * EE;

    int lane = threadIdx.x & 31;
    int c0 = lane * 4;
    float4 q  = *(const float4*)&qkvs[(size_t)w * QKVS + c0];
    float4 sk = *(const float4*)&qkvs[(size_t)w * QKVS + 384 + c0];
    float4 we = *(const float4*)&We[c0];
    float m = -CUDART_INF_F, s = 0.f;
    float4 acc = make_float4(0.f, 0.f, 0.f, 0.f);
    int beg = rowptr[w], end = rowptr[w + 1];
    for (int i = beg; i < end; i++) {
        int e = eids[i];
        int sn = src_arr[e];
        float eaV = eattr[e];
        float4 k4 = *(const float4*)&qkvs[(size_t)sn * QKVS + 128 + c0];
        float4 v4 = *(const float4*)&qkvs[(size_t)sn * QKVS + 256 + c0];
        float ex = eaV * we.x, ey = eaV * we.y, ez = eaV * we.z, ew = eaV * we.w;
        float part = q.x * (k4.x + ex) + q.y * (k4.y + ey) + q.z * (k4.z + ez) + q.w * (k4.w + ew);
#pragma unroll
        for (int o = 16; o; o >>= 1) part += __shfl_xor_sync(0xffffffffu, part, o);
        float alpha = part * 0.08838834764831845f; // 1/sqrt(128)
        float mn = fmaxf(m, alpha);
        float corr = __expf(m - mn);
        float p = __expf(alpha - mn);
        s = s * corr + p;
        acc.x = acc.x * corr + p * (v4.x + ex);
        acc.y = acc.y * corr + p * (v4.y + ey);
        acc.z = acc.z * corr + p * (v4.z + ez);
        acc.w = acc.w * corr + p * (v4.w + ew);
        m = mn;
    }
    float inv = 1.f / (s + 1e-16f);
    float4 o;
    o.x = acc.x * inv + sk.x;
    o.y = acc.y * inv + sk.y;
    o.z = acc.z * inv + sk.z;
    o.w = acc.w * inv + sk.w;
    o.x = o.x > 0.f ? o.x : 0.01f * o.x;
    o.y = o.y > 0.f ? o.y : 0.01f * o.y;
    o.z = o.z > 0.f ? o.z : 0.01f * o.z;
    o.w = o.w > 0.f ? o.w : 0.01f * o.w;
    size_t oidx = (size_t)t * NN * DD + (size_t)w * DD + c0;
    if (mode) {
        *(float4*)&out[oidx] = o;
    } else {
        __nv_bfloat16 hx, lx, hy, ly, hz, lz, hw, lw;
        split_bf16(o.x, hx, lx);
        split_bf16(o.y, hy, ly);
        split_bf16(o.z, hz, lz);
        split_bf16(o.w, hw, lw);
        __nv_bfloat16 hv[4] = {hx, hy, hz, hw};
        __nv_bfloat16 lv[4] = {lx, ly, lz, lw};
        *(uint2*)&oh[oidx] = *(uint2*)hv;
        *(uint2*)&ol[oidx] = *(uint2*)lv;
    }
}

// ------------------------ output conv (D -> 1) -----------------------------------
__global__ void k_out_node(const float* __restrict__ ha2,
                           const float* __restrict__ Wq, const float* __restrict__ bq,
                           const float* __restrict__ Wk, const float* __restrict__ bk,
                           const float* __restrict__ Wv, const float* __restrict__ bv,
                           const float* __restrict__ Ws, const float* __restrict__ bs,
                           float* __restrict__ oq, float* __restrict__ ok,
                           float* __restrict__ ov, float* __restrict__ osk) {
    int w = (blockIdx.x * blockDim.x + threadIdx.x) >> 5;
    if (w >= NN) return;
    int lane = threadIdx.x & 31;
    int c0 = lane * 4;
    float4 h = make_float4(0.f, 0.f, 0.f, 0.f);
#pragma unroll
    for (int t = 0; t < TT; t++) {
        float4 v = *(const float4*)&ha2[(size_t)t * NN * DD + (size_t)w * DD + c0];
        h.x += v.x; h.y += v.y; h.z += v.z; h.w += v.w;
    }
    h.x *= 0.25f; h.y *= 0.25f; h.z *= 0.25f; h.w *= 0.25f;
    float4 wq = *(const float4*)&Wq[c0];
    float4 wk = *(const float4*)&Wk[c0];
    float4 wv = *(const float4*)&Wv[c0];
    float4 ws = *(const float4*)&Ws[c0];
    float dq = h.x * wq.x + h.y * wq.y + h.z * wq.z + h.w * wq.w;
    float dk = h.x * wk.x + h.y * wk.y + h.z * wk.z + h.w * wk.w;
    float dv = h.x * wv.x + h.y * wv.y + h.z * wv.z + h.w * wv.w;
    float ds = h.x * ws.x + h.y * ws.y + h.z * ws.z + h.w * ws.w;
#pragma unroll
    for (int o = 16; o; o >>= 1) {
        dq += __shfl_xor_sync(0xffffffffu, dq, o);
        dk += __shfl_xor_sync(0xffffffffu, dk, o);
        dv += __shfl_xor_sync(0xffffffffu, dv, o);
        ds += __shfl_xor_sync(0xffffffffu, ds, o);
    }
    if (lane == 0) {
        oq[w]  = dq + bq[0];
        ok[w]  = dk + bk[0];
        ov[w]  = dv + bv[0];
        osk[w] = ds + bs[0];
    }
}

__global__ void k_out_edge(const int* __restrict__ rowptr, const int* __restrict__ eids,
                           const int* __restrict__ src_arr, const float* __restrict__ eattr,
                           const float* __restrict__ We,
                           const float* __restrict__ oq, const float* __restrict__ ok,
                           const float* __restrict__ ov, const float* __restrict__ osk,
                           float* __restrict__ out) {
    int n = blockIdx.x * blockDim.x + threadIdx.x;
    if (n >= NN) return;
    float q = oq[n];
    float we = We[0];
    float m = -CUDART_INF_F, s = 0.f, acc = 0.f;
    int beg = rowptr[n], end = rowptr[n + 1];
    for (int i = beg; i < end; i++) {
        int e = eids[i];
        int sn = src_arr[e];
        float et = eattr[e] * we;
        float alpha = q * (ok[sn] + et);
        float mn = fmaxf(m, alpha);
        float corr = __expf(m - mn);
        float p = __expf(alpha - mn);
        s = s * corr + p;
        acc = acc * corr + p * (ov[sn] + et);
        m = mn;
    }
    out[n] = acc / (s + 1e-16f) + osk[n];
}

// =================================== host side ====================================
extern "C" void kernel_launch(void* const* d_in, const int* in_sizes, int n_in,
                              void* d_out, int out_size) {
    const float* x_seq = nullptr;
    const int*   ei    = nullptr;
    const float* ea    = nullptr;
    const float* P[22];
    int r = 0;
    for (int i = 0; i < n_in; i++) {
        if      (in_sizes[i] == TT * NN * IN_DIM) x_seq = (const float*)d_in[i];
        else if (in_sizes[i] == TT * 2 * EE)      ei    = (const int*)d_in[i];
        else if (in_sizes[i] == TT * EE)          ea    = (const float*)d_in[i];
        else if (r < 22)                          P[r++] = (const float*)d_in[i];
    }
    const float* gW_ih = P[0];
    const float* gW_hh = P[1];
    const float* gb_ih = P[2];
    const float* gb_hh = P[3];
    const float* cWq   = P[4];
    const float* cbq   = P[5];
    const float* cWk   = P[6];
    const float* cbk   = P[7];
    const float* cWv   = P[8];
    const float* cbv   = P[9];
    const float* cWe   = P[10];
    const float* cWs   = P[11];
    const float* cbs   = P[12];
    const float* oWq   = P[13];
    const float* obq   = P[14];
    const float* oWk   = P[15];
    const float* obk   = P[16];
    const float* oWv   = P[17];
    const float* obv   = P[18];
    const float* oWe   = P[19];
    const float* oWs   = P[20];
    const float* obs   = P[21];

    float *GI, *GH, *H, *HA2, *QK, *BPK;
    __nv_bfloat16 *Xh, *Xl, *Hh, *Hl, *HAh, *HAl;
    __nv_bfloat16 *WIHh, *WIHl, *WHHh, *WHHl, *WPh, *WPl;
    float *OQ, *OKp, *OV, *OSK;
    int *RP, *EID, *CNT, *CUR;
    cudaGetSymbolAddress((void**)&GI,   g_GI);
    cudaGetSymbolAddress((void**)&GH,   g_GH);
    cudaGetSymbolAddress((void**)&H,    g_H);
    cudaGetSymbolAddress((void**)&HA2,  g_HA2);
    cudaGetSymbolAddress((void**)&QK,   g_QK);
    cudaGetSymbolAddress((void**)&Xh,   g_Xh);
    cudaGetSymbolAddress((void**)&Xl,   g_Xl);
    cudaGetSymbolAddress((void**)&Hh,   g_Hh);
    cudaGetSymbolAddress((void**)&Hl,   g_Hl);
    cudaGetSymbolAddress((void**)&HAh,  g_HAh);
    cudaGetSymbolAddress((void**)&HAl,  g_HAl);
    cudaGetSymbolAddress((void**)&WIHh, g_WIHh);
    cudaGetSymbolAddress((void**)&WIHl, g_WIHl);
    cudaGetSymbolAddress((void**)&WHHh, g_WHHh);
    cudaGetSymbolAddress((void**)&WHHl, g_WHHl);
    cudaGetSymbolAddress((void**)&WPh,  g_WPKh);
    cudaGetSymbolAddress((void**)&WPl,  g_WPKl);
    cudaGetSymbolAddress((void**)&BPK,  g_BPK);
    cudaGetSymbolAddress((void**)&OQ,   g_OQ);
    cudaGetSymbolAddress((void**)&OKp,  g_OKs);
    cudaGetSymbolAddress((void**)&OV,   g_OV);
    cudaGetSymbolAddress((void**)&OSK,  g_OSK);
    cudaGetSymbolAddress((void**)&RP,   g_RP);
    cudaGetSymbolAddress((void**)&EID,  g_EID);
    cudaGetSymbolAddress((void**)&CNT,  g_CNT);
    cudaGetSymbolAddress((void**)&CUR,  g_CUR);

    const int SMEM = NSTG * 4 * STG_WORDS * 4;  // 96KB
    cudaFuncSetAttribute(k_pgemm, cudaFuncAttributeMaxDynamicSharedMemorySize, SMEM);

    const int TPB = 256;

    // 1..3: prep (GI GEMM stays the 4th launch for ncu's capture window)
    k_split_x<<<(TT * NN * IN_DIM + TPB - 1) / TPB, TPB>>>(x_seq, Xh, Xl);
    k_prep_gru<<<(G3 * IN_DIM + G3 * DD + TPB - 1) / TPB, TPB>>>(gW_ih, gW_hh, WIHh, WIHl, WHHh, WHHl);
    k_prep_conv<<<(2 * QKVS * DD + TPB - 1) / TPB, TPB>>>(cWq, cWk, cWv, cWs, cbq, cbk, cbv, cbs, WPh, WPl, BPK);

    // 4: GI = X @ W_ih^T + b_ih for all T at once: [80000,64] @ [64,384]
    k_pgemm<<<dim3(G3 / 128, (TT * NN + 127) / 128), 256, SMEM>>>(
        Xh, Xl, WIHh, WIHl, gb_ih, GI, TT * NN, G3, IN_DIM);

    // CSR build
    k_zero_i<<<(TT * NN + TPB - 1) / TPB, TPB>>>(CNT, TT * NN);
    k_hist<<<(TT * EE + TPB - 1) / TPB, TPB>>>(ei, CNT);
    k_scan<<<TT, 1024>>>(CNT, RP, CUR);
    k_scatter<<<(TT * EE + TPB - 1) / TPB, TPB>>>(ei, CUR, EID);

    // ---- GRU over time: sequential chain, per-t Hh/Hl stored batched ----
    for (int t = 0; t < TT; t++) {
        if (t > 0) {
            k_pgemm<<<dim3(G3 / 128, (NN + 127) / 128), 256, SMEM>>>(
                Hh + (size_t)(t - 1) * NN * DD, Hl + (size_t)(t - 1) * NN * DD,
                WHHh, WHHl, gb_hh, GH, NN, G3, DD);
        }
        k_gru_gate<<<(NN * DD + TPB - 1) / TPB, TPB>>>(
            GI + (size_t)t * NN * G3, GH, gb_hh, H,
            Hh + (size_t)t * NN * DD, Hl + (size_t)t * NN * DD, t == 0 ? 1 : 0);
    }

    // ---- layer 0: ONE batched qkvs GEMM over all t, ONE merged conv launch ----
    k_pgemm<<<dim3(QKVS / 128, (TT * NN + 127) / 128), 256, SMEM>>>(
        Hh, Hl, WPh, WPl, BPK, QK, TT * NN, QKVS, DD);
    k_conv_all<<<TT * NN / 8, 256>>>(QK, RP, EID, ei, ea, cWe, nullptr, HAh, HAl, 0);

    // ---- layer 1: ONE batched qkvs GEMM, ONE merged conv launch (f32 out) ----
    k_pgemm<<<dim3(QKVS / 128, (TT * NN + 127) / 128), 256, SMEM>>>(
        HAh, HAl, WPh + QKVS * DD, WPl + QKVS * DD, BPK + QKVS, QK, TT * NN, QKVS, DD);
    k_conv_all<<<TT * NN / 8, 256>>>(QK, RP, EID, ei, ea, cWe + DD, HA2, nullptr, nullptr, 1);

    // ---- output conv (edges of last timestep) ----
    k_out_node<<<NN / 8, 256>>>(HA2, oWq, obq, oWk, obk, oWv, obv, oWs, obs, OQ, OKp, OV, OSK);
    k_out_edge<<<(NN + TPB - 1) / TPB, TPB>>>(RP + (TT - 1) * (NN + 1), EID + (size_t)(TT - 1) * EE,
                                              ei + (size_t)(TT - 1) * 2 * EE, ea + (size_t)(TT - 1) * EE,
                                              oWe, OQ, OKp, OV, OSK, (float*)d_out);
}

// round 8
// speedup vs baseline: 2.2184x; 1.0349x over previous
#include <cuda_runtime.h>
#include <cuda_bf16.h>
#include <math_constants.h>
#include <cstdint>

#define TT 4
#define NN 20000
#define EE 160000
#define IN_DIM 64
#define DD 128
#define G3 384   // 3*D
#define QKVS 512 // q|k|v|skip packed

// ------------------- static device scratch (no runtime allocs) -------------------
__device__ float g_GI[(size_t)TT * NN * G3];
__device__ float g_GH[(size_t)NN * G3];
__device__ float g_H [(size_t)NN * DD];
__device__ float g_HA2[(size_t)TT * NN * DD];          // layer-1 conv outputs (f32, per t)
__device__ float g_QK[(size_t)TT * NN * QKVS];         // batched qkvs for all t
// activations pre-split to bf16 hi/lo (batched over t)
__device__ __nv_bfloat16 g_Xh[(size_t)TT * NN * IN_DIM], g_Xl[(size_t)TT * NN * IN_DIM];
__device__ __nv_bfloat16 g_Hh[(size_t)TT * NN * DD], g_Hl[(size_t)TT * NN * DD];
__device__ __nv_bfloat16 g_HAh[(size_t)TT * NN * DD], g_HAl[(size_t)TT * NN * DD];
// weights pre-split to bf16 hi/lo, [N][K] layout
__device__ __nv_bfloat16 g_WIHh[G3 * IN_DIM], g_WIHl[G3 * IN_DIM];
__device__ __nv_bfloat16 g_WHHh[G3 * DD],     g_WHHl[G3 * DD];
__device__ __nv_bfloat16 g_WPKh[2 * QKVS * DD], g_WPKl[2 * QKVS * DD];
__device__ float g_BPK[2 * QKVS];
__device__ float g_OQ[NN], g_OKs[NN], g_OV[NN], g_OSK[NN];
__device__ int   g_RP [TT * (NN + 1)];
__device__ int   g_ESRC[TT * EE];     // src node id, sorted by dst (CSR order)
__device__ float g_EAS [TT * EE];     // edge attr, sorted by dst (CSR order)
__device__ int   g_CNT[TT * NN];
__device__ int   g_CUR[TT * NN];

// ------------------------------- small utility kernels ---------------------------
__global__ void k_zero_i(int* p, int n) {
    int i = blockIdx.x * blockDim.x + threadIdx.x;
    if (i < n) p[i] = 0;
}

__device__ __forceinline__ void split_bf16(float v, __nv_bfloat16& h, __nv_bfloat16& l) {
    h = __float2bfloat16_rn(v);
    l = __float2bfloat16_rn(v - __bfloat162float(h));
}

__global__ void k_split_x(const float* __restrict__ x,
                          __nv_bfloat16* __restrict__ xh, __nv_bfloat16* __restrict__ xl) {
    int i = blockIdx.x * blockDim.x + threadIdx.x;
    if (i < TT * NN * IN_DIM) split_bf16(x[i], xh[i], xl[i]);
}

// GRU weights: W_ih [384,64] and W_hh [384,128] are natively [N,K].
__global__ void k_prep_gru(const float* __restrict__ Wih, const float* __restrict__ Whh,
                           __nv_bfloat16* __restrict__ ah, __nv_bfloat16* __restrict__ al,
                           __nv_bfloat16* __restrict__ bh, __nv_bfloat16* __restrict__ bl) {
    int i = blockIdx.x * blockDim.x + threadIdx.x;
    if (i < G3 * IN_DIM) split_bf16(Wih[i], ah[i], al[i]);
    int j = i - G3 * IN_DIM;
    if (j >= 0 && j < G3 * DD) split_bf16(Whh[j], bh[j], bl[j]);
}

// Pack conv weights transposed into [layer][n(512)][k(128)] hi/lo + bias pack
__global__ void k_prep_conv(const float* __restrict__ Wq, const float* __restrict__ Wk,
                            const float* __restrict__ Wv, const float* __restrict__ Ws,
                            const float* __restrict__ bq, const float* __restrict__ bk,
                            const float* __restrict__ bv, const float* __restrict__ bs,
                            __nv_bfloat16* __restrict__ WPh, __nv_bfloat16* __restrict__ WPl,
                            float* __restrict__ BP) {
    int i = blockIdx.x * blockDim.x + threadIdx.x;
    if (i < 2 * QKVS * DD) {
        int l = i >> 16;
        int rem = i & 65535;
        int n = rem >> 7, k = rem & 127;
        int base = l * DD * DD + k * DD;
        float v;
        if      (n < 128) v = Wq[base + n];
        else if (n < 256) v = Wk[base + n - 128];
        else if (n < 384) v = Wv[base + n - 256];
        else              v = Ws[base + n - 384];
        split_bf16(v, WPh[i], WPl[i]);
    }
    if (i < 2 * QKVS) {
        int l = i >> 9, c = i & 511;
        int b2 = l * DD;
        float v;
        if      (c < 128) v = bq[b2 + c];
        else if (c < 256) v = bk[b2 + c - 128];
        else if (c < 384) v = bv[b2 + c - 256];
        else              v = bs[b2 + c - 384];
        BP[i] = v;
    }
}

// ------------------------------- CSR build ---------------------------------------
__global__ void k_hist(const int* __restrict__ ei, int* __restrict__ cnt) {
    int i = blockIdx.x * blockDim.x + threadIdx.x;
    if (i >= TT * EE) return;
    int t = i / EE, e = i % EE;
    int dst = ei[(size_t)t * 2 * EE + EE + e];
    atomicAdd(&cnt[t * NN + dst], 1);
}

__global__ void k_scan(const int* __restrict__ cnt, int* __restrict__ rowptr, int* __restrict__ cur) {
    int t = blockIdx.x;
    __shared__ int sh[1024];
    const int* c = cnt + t * NN;
    int* rp = rowptr + t * (NN + 1);
    int* cu = cur + t * NN;
    int carry = 0;
    for (int base = 0; base < NN; base += 1024) {
        int idx = base + threadIdx.x;
        int v = (idx < NN) ? c[idx] : 0;
        sh[threadIdx.x] = v;
        __syncthreads();
        for (int off = 1; off < 1024; off <<= 1) {
            int tval = (threadIdx.x >= off) ? sh[threadIdx.x - off] : 0;
            __syncthreads();
            sh[threadIdx.x] += tval;
            __syncthreads();
        }
        int excl = sh[threadIdx.x] - v;
        if (idx < NN) { rp[idx] = carry + excl; cu[idx] = carry + excl; }
        carry += sh[1023];
        __syncthreads();
    }
    if (threadIdx.x == 0) rp[NN] = carry;
}

// scatter edge records (src, attr) sorted by dst — removes indirections in conv
__global__ void k_scatter(const int* __restrict__ ei, const float* __restrict__ ea,
                          int* __restrict__ cur,
                          int* __restrict__ esrc, float* __restrict__ eas) {
    int i = blockIdx.x * blockDim.x + threadIdx.x;
    if (i >= TT * EE) return;
    int t = i / EE, e = i % EE;
    int src = ei[(size_t)t * 2 * EE + e];
    int dst = ei[(size_t)t * 2 * EE + EE + e];
    int p = atomicAdd(&cur[t * NN + dst], 1);
    esrc[(size_t)t * EE + p] = src;
    eas [(size_t)t * EE + p] = ea[(size_t)t * EE + e];
}

// ==== pipelined bf16 HMMA GEMM: 3-stage cp.async + ldmatrix, 1 barrier/chunk ======
// C[M,Nc] = A @ B^T + bias. A,B pre-split bf16 hi/lo, both stored [rows][K] row-major.
// 3-pass: D = Ahi*Bhi + Ahi*Blo + Alo*Bhi, fp32 accumulate.
// mma ordered so same-accumulator rewrites are >=8 instructions apart (hide HMMA RAW).
#define KC 32
#define NSTG 3
#define STG_WORDS (128 * 16)   // words per array per stage (128 rows x 32 bf16)

__device__ __forceinline__ void mma_bf16(float c[4], const uint32_t a[4],
                                         uint32_t b0, uint32_t b1) {
    asm volatile(
        "mma.sync.aligned.m16n8k16.row.col.f32.bf16.bf16.f32 "
        "{%0,%1,%2,%3}, {%4,%5,%6,%7}, {%8,%9}, {%0,%1,%2,%3};"
        : "+f"(c[0]), "+f"(c[1]), "+f"(c[2]), "+f"(c[3])
        : "r"(a[0]), "r"(a[1]), "r"(a[2]), "r"(a[3]), "r"(b0), "r"(b1));
}

__device__ __forceinline__ void ldsm_x4(uint32_t addr, uint32_t& r0, uint32_t& r1,
                                        uint32_t& r2, uint32_t& r3) {
    asm volatile("ldmatrix.sync.aligned.m8n8.x4.shared.b16 {%0,%1,%2,%3}, [%4];"
                 : "=r"(r0), "=r"(r1), "=r"(r2), "=r"(r3) : "r"(addr));
}

__global__ void __launch_bounds__(256, 2) k_pgemm(
    const __nv_bfloat16* __restrict__ Ah, const __nv_bfloat16* __restrict__ Al,
    const __nv_bfloat16* __restrict__ Bh, const __nv_bfloat16* __restrict__ Bl,
    const float* __restrict__ bias, float* __restrict__ C, int M, int Nc, int K) {
    extern __shared__ uint32_t smw[];   // NSTG stages x 4 arrays x STG_WORDS = 96KB

    int tid = threadIdx.x, wid = tid >> 5, lane = tid & 31;
    int gid = lane >> 2, t4 = lane & 3;
    int rowBase = blockIdx.y * 128;
    int colBase = blockIdx.x * 128;
    int warpRow = (wid & 3) * 32;
    int warpCol = (wid >> 2) * 64;

    float acc[2][8][4];
#pragma unroll
    for (int mt = 0; mt < 2; mt++)
#pragma unroll
        for (int nt = 0; nt < 8; nt++)
#pragma unroll
            for (int q = 0; q < 4; q++) acc[mt][nt][q] = 0.f;

    uint32_t sm0;
    asm("{ .reg .u64 t; cvta.to.shared.u64 t, %1; cvt.u32.u64 %0, t; }"
        : "=r"(sm0) : "l"(smw));

    const __nv_bfloat16* srcs[4] = {Ah, Al, Bh, Bl};

    int lm_m = lane >> 3;
    int lm_r = lane & 7;
    int a_row0 = warpRow + ((lm_m & 1) << 3) + lm_r;
    int a_kh   = lm_m >> 1;
    int b_row0 = warpCol + ((lm_m >> 1) << 3) + lm_r;
    int b_kh   = lm_m & 1;

    auto fill = [&](int stage, int k0) {
        uint32_t sb = sm0 + (uint32_t)stage * 4 * STG_WORDS * 4;
#pragma unroll
        for (int it = 0; it < 8; it++) {
            int idx = tid + it * 256;
            int arr = idx >> 9;
            int rem = idx & 511;
            int r = rem >> 2, c = rem & 3;
            int grow = (arr < 2) ? (rowBase + r) : (colBase + r);
            int valid = (arr >= 2) || (grow < M);
            const __nv_bfloat16* src = srcs[arr] + (valid ? ((size_t)grow * K + k0 + c * 8) : 0);
            int sz = valid ? 16 : 0;
            uint32_t dst = sb + (uint32_t)(arr * STG_WORDS + (r << 4) + ((c ^ ((r >> 1) & 3)) << 2)) * 4;
            asm volatile("cp.async.cg.shared.global [%0], [%1], 16, %2;"
                         :: "r"(dst), "l"(src), "r"(sz));
        }
        asm volatile("cp.async.commit_group;");
    };

    int nch = K / KC;
    fill(0, 0);
    if (nch > 1) fill(1, KC);

    for (int ch = 0; ch < nch; ch++) {
        if (ch + 2 <= nch) { asm volatile("cp.async.wait_group 1;"); }
        else               { asm volatile("cp.async.wait_group 0;"); }
        __syncthreads();

        if (ch + 2 < nch) fill((ch + 2) % NSTG, (ch + 2) * KC);

        uint32_t st = sm0 + (uint32_t)(ch % NSTG) * 4 * STG_WORDS * 4;
        uint32_t pAh = st;
        uint32_t pAl = st + STG_WORDS * 4;
        uint32_t pBh = st + 2 * STG_WORDS * 4;
        uint32_t pBl = st + 3 * STG_WORDS * 4;

#pragma unroll
        for (int ks = 0; ks < KC; ks += 16) {
            uint32_t ah[2][4], al[2][4];
            int ach = (ks >> 3) + a_kh;
#pragma unroll
            for (int mt = 0; mt < 2; mt++) {
                int ar = a_row0 + mt * 16;
                uint32_t aoff = (uint32_t)(ar << 6) + (uint32_t)((ach ^ ((ar >> 1) & 3)) << 4);
                ldsm_x4(pAh + aoff, ah[mt][0], ah[mt][1], ah[mt][2], ah[mt][3]);
                ldsm_x4(pAl + aoff, al[mt][0], al[mt][1], al[mt][2], al[mt][3]);
            }
            int bch = (ks >> 3) + b_kh;
            // process B-pairs two p-groups at a time; same-acc spacing = 8 mma
#pragma unroll
            for (int pp = 0; pp < 2; pp++) {
                uint32_t bh[2][4], bl[2][4];
                uint32_t boffs[2];
#pragma unroll
                for (int pi = 0; pi < 2; pi++) {
                    int br = b_row0 + (2 * pp + pi) * 16;
                    boffs[pi] = (uint32_t)(br << 6) + (uint32_t)((bch ^ ((br >> 1) & 3)) << 4);
                    ldsm_x4(pBh + boffs[pi], bh[pi][0], bh[pi][1], bh[pi][2], bh[pi][3]);
                }
                // pass hh (uses bh)
#pragma unroll
                for (int pi = 0; pi < 2; pi++) {
                    int n0 = (2 * pp + pi) * 2, n1 = n0 + 1;
                    mma_bf16(acc[0][n0], ah[0], bh[pi][0], bh[pi][1]);
                    mma_bf16(acc[0][n1], ah[0], bh[pi][2], bh[pi][3]);
                    mma_bf16(acc[1][n0], ah[1], bh[pi][0], bh[pi][1]);
                    mma_bf16(acc[1][n1], ah[1], bh[pi][2], bh[pi][3]);
                }
                // pass lh (uses bh again; al)
#pragma unroll
                for (int pi = 0; pi < 2; pi++) {
                    int n0 = (2 * pp + pi) * 2, n1 = n0 + 1;
                    mma_bf16(acc[0][n0], al[0], bh[pi][0], bh[pi][1]);
                    mma_bf16(acc[0][n1], al[0], bh[pi][2], bh[pi][3]);
                    mma_bf16(acc[1][n0], al[1], bh[pi][0], bh[pi][1]);
                    mma_bf16(acc[1][n1], al[1], bh[pi][2], bh[pi][3]);
                }
                // load bl late (keeps peak live fragments bounded), pass hl
#pragma unroll
                for (int pi = 0; pi < 2; pi++)
                    ldsm_x4(pBl + boffs[pi], bl[pi][0], bl[pi][1], bl[pi][2], bl[pi][3]);
#pragma unroll
                for (int pi = 0; pi < 2; pi++) {
                    int n0 = (2 * pp + pi) * 2, n1 = n0 + 1;
                    mma_bf16(acc[0][n0], ah[0], bl[pi][0], bl[pi][1]);
                    mma_bf16(acc[0][n1], ah[0], bl[pi][2], bl[pi][3]);
                    mma_bf16(acc[1][n0], ah[1], bl[pi][0], bl[pi][1]);
                    mma_bf16(acc[1][n1], ah[1], bl[pi][2], bl[pi][3]);
                }
            }
        }
    }

#pragma unroll
    for (int mt = 0; mt < 2; mt++) {
        int r0 = rowBase + warpRow + mt * 16 + gid;
        int r1 = r0 + 8;
#pragma unroll
        for (int nt = 0; nt < 8; nt++) {
            int col = colBase + warpCol + nt * 8 + t4 * 2;
            float b0 = bias[col], b1 = bias[col + 1];
            if (r0 < M) {
                float2 o = make_float2(acc[mt][nt][0] + b0, acc[mt][nt][1] + b1);
                *(float2*)&C[(size_t)r0 * Nc + col] = o;
            }
            if (r1 < M) {
                float2 o = make_float2(acc[mt][nt][2] + b0, acc[mt][nt][3] + b1);
                *(float2*)&C[(size_t)r1 * Nc + col] = o;
            }
        }
    }
}

// ------------------------------- GRU gates ---------------------------------------
__global__ void k_gru_gate(const float* __restrict__ GI, const float* __restrict__ GH,
                           const float* __restrict__ bhh, float* __restrict__ H,
                           __nv_bfloat16* __restrict__ Hh, __nv_bfloat16* __restrict__ Hl,
                           int first) {
    int i = blockIdx.x * blockDim.x + threadIdx.x;
    if (i >= NN * DD) return;
    int n = i >> 7, j = i & 127;
    const float* gi = GI + (size_t)n * G3;
    float ir = gi[j], iz = gi[j + 128], in = gi[j + 256];
    float hr, hz, hn, hp;
    if (first) {
        hr = bhh[j]; hz = bhh[j + 128]; hn = bhh[j + 256];
        hp = 0.f;
    } else {
        const float* gh = GH + (size_t)n * G3;
        hr = gh[j]; hz = gh[j + 128]; hn = gh[j + 256];
        hp = H[i];
    }
    float r = 1.f / (1.f + __expf(-(ir + hr)));
    float z = 1.f / (1.f + __expf(-(iz + hz)));
    float nv = tanhf(in + r * hn);
    float h = (1.f - z) * nv + z * hp;
    H[i] = h;
    split_bf16(h, Hh[i], Hl[i]);
}

// -------------- TransformerConv edge attention, ALL timesteps in one launch ------
// mode 0: write bf16 hi/lo split (feeds next GEMM). mode 1: write f32 to out.
// Edge records (src, attr) are CSR-sorted; gathers prefetched one edge ahead.
__global__ void k_conv_all(const float* __restrict__ QK,
                           const int* __restrict__ RP,
                           const int* __restrict__ ESRC, const float* __restrict__ EAS,
                           const float* __restrict__ We, float* __restrict__ out,
                           __nv_bfloat16* __restrict__ oh, __nv_bfloat16* __restrict__ ol,
                           int mode) {
    int gw = (blockIdx.x * blockDim.x + threadIdx.x) >> 5;
    if (gw >= TT * NN) return;
    int t = gw / NN;
    int w = gw - t * NN;
    const float* qkvs = QK + (size_t)t * NN * QKVS;
    const int* rowptr = RP + t * (NN + 1);
    const int* esrc   = ESRC + (size_t)t * EE;
    const float* eas  = EAS + (size_t)t * EE;

    int lane = threadIdx.x & 31;
    int c0 = lane * 4;
    float4 q  = *(const float4*)&qkvs[(size_t)w * QKVS + c0];
    float4 sk = *(const float4*)&qkvs[(size_t)w * QKVS + 384 + c0];
    float4 we = *(const float4*)&We[c0];
    float m = -CUDART_INF_F, s = 0.f;
    float4 acc = make_float4(0.f, 0.f, 0.f, 0.f);
    int beg = rowptr[w], end = rowptr[w + 1];

    float4 k4 = make_float4(0.f, 0.f, 0.f, 0.f), v4 = k4;
    float eaV = 0.f;
    if (beg < end) {
        int sn = esrc[beg];
        eaV = eas[beg];
        k4 = *(const float4*)&qkvs[(size_t)sn * QKVS + 128 + c0];
        v4 = *(const float4*)&qkvs[(size_t)sn * QKVS + 256 + c0];
    }
    for (int i = beg; i < end; i++) {
        float4 ck = k4, cv = v4;
        float cea = eaV;
        if (i + 1 < end) {       // prefetch next edge's gather before reduction chain
            int sn = esrc[i + 1];
            eaV = eas[i + 1];
            k4 = *(const float4*)&qkvs[(size_t)sn * QKVS + 128 + c0];
            v4 = *(const float4*)&qkvs[(size_t)sn * QKVS + 256 + c0];
        }
        float ex = cea * we.x, ey = cea * we.y, ez = cea * we.z, ew = cea * we.w;
        float part = q.x * (ck.x + ex) + q.y * (ck.y + ey) + q.z * (ck.z + ez) + q.w * (ck.w + ew);
#pragma unroll
        for (int o = 16; o; o >>= 1) part += __shfl_xor_sync(0xffffffffu, part, o);
        float alpha = part * 0.08838834764831845f; // 1/sqrt(128)
        float mn = fmaxf(m, alpha);
        float corr = __expf(m - mn);
        float p = __expf(alpha - mn);
        s = s * corr + p;
        acc.x = acc.x * corr + p * (cv.x + ex);
        acc.y = acc.y * corr + p * (cv.y + ey);
        acc.z = acc.z * corr + p * (cv.z + ez);
        acc.w = acc.w * corr + p * (cv.w + ew);
        m = mn;
    }
    float inv = 1.f / (s + 1e-16f);
    float4 o;
    o.x = acc.x * inv + sk.x;
    o.y = acc.y * inv + sk.y;
    o.z = acc.z * inv + sk.z;
    o.w = acc.w * inv + sk.w;
    o.x = o.x > 0.f ? o.x : 0.01f * o.x;
    o.y = o.y > 0.f ? o.y : 0.01f * o.y;
    o.z = o.z > 0.f ? o.z : 0.01f * o.z;
    o.w = o.w > 0.f ? o.w : 0.01f * o.w;
    size_t oidx = (size_t)t * NN * DD + (size_t)w * DD + c0;
    if (mode) {
        *(float4*)&out[oidx] = o;
    } else {
        __nv_bfloat16 hx, lx, hy, ly, hz, lz, hw, lw;
        split_bf16(o.x, hx, lx);
        split_bf16(o.y, hy, ly);
        split_bf16(o.z, hz, lz);
        split_bf16(o.w, hw, lw);
        __nv_bfloat16 hv[4] = {hx, hy, hz, hw};
        __nv_bfloat16 lv[4] = {lx, ly, lz, lw};
        *(uint2*)&oh[oidx] = *(uint2*)hv;
        *(uint2*)&ol[oidx] = *(uint2*)lv;
    }
}

// ------------------------ output conv (D -> 1) -----------------------------------
__global__ void k_out_node(const float* __restrict__ ha2,
                           const float* __restrict__ Wq, const float* __restrict__ bq,
                           const float* __restrict__ Wk, const float* __restrict__ bk,
                           const float* __restrict__ Wv, const float* __restrict__ bv,
                           const float* __restrict__ Ws, const float* __restrict__ bs,
                           float* __restrict__ oq, float* __restrict__ ok,
                           float* __restrict__ ov, float* __restrict__ osk) {
    int w = (blockIdx.x * blockDim.x + threadIdx.x) >> 5;
    if (w >= NN) return;
    int lane = threadIdx.x & 31;
    int c0 = lane * 4;
    float4 h = make_float4(0.f, 0.f, 0.f, 0.f);
#pragma unroll
    for (int t = 0; t < TT; t++) {
        float4 v = *(const float4*)&ha2[(size_t)t * NN * DD + (size_t)w * DD + c0];
        h.x += v.x; h.y += v.y; h.z += v.z; h.w += v.w;
    }
    h.x *= 0.25f; h.y *= 0.25f; h.z *= 0.25f; h.w *= 0.25f;
    float4 wq = *(const float4*)&Wq[c0];
    float4 wk = *(const float4*)&Wk[c0];
    float4 wv = *(const float4*)&Wv[c0];
    float4 ws = *(const float4*)&Ws[c0];
    float dq = h.x * wq.x + h.y * wq.y + h.z * wq.z + h.w * wq.w;
    float dk = h.x * wk.x + h.y * wk.y + h.z * wk.z + h.w * wk.w;
    float dv = h.x * wv.x + h.y * wv.y + h.z * wv.z + h.w * wv.w;
    float ds = h.x * ws.x + h.y * ws.y + h.z * ws.z + h.w * ws.w;
#pragma unroll
    for (int o = 16; o; o >>= 1) {
        dq += __shfl_xor_sync(0xffffffffu, dq, o);
        dk += __shfl_xor_sync(0xffffffffu, dk, o);
        dv += __shfl_xor_sync(0xffffffffu, dv, o);
        ds += __shfl_xor_sync(0xffffffffu, ds, o);
    }
    if (lane == 0) {
        oq[w]  = dq + bq[0];
        ok[w]  = dk + bk[0];
        ov[w]  = dv + bv[0];
        osk[w] = ds + bs[0];
    }
}

__global__ void k_out_edge(const int* __restrict__ rowptr,
                           const int* __restrict__ esrc, const float* __restrict__ eas,
                           const float* __restrict__ We,
                           const float* __restrict__ oq, const float* __restrict__ ok,
                           const float* __restrict__ ov, const float* __restrict__ osk,
                           float* __restrict__ out) {
    int n = blockIdx.x * blockDim.x + threadIdx.x;
    if (n >= NN) return;
    float q = oq[n];
    float we = We[0];
    float m = -CUDART_INF_F, s = 0.f, acc = 0.f;
    int beg = rowptr[n], end = rowptr[n + 1];
    for (int i = beg; i < end; i++) {
        int sn = esrc[i];
        float et = eas[i] * we;
        float alpha = q * (ok[sn] + et);
        float mn = fmaxf(m, alpha);
        float corr = __expf(m - mn);
        float p = __expf(alpha - mn);
        s = s * corr + p;
        acc = acc * corr + p * (ov[sn] + et);
        m = mn;
    }
    out[n] = acc / (s + 1e-16f) + osk[n];
}

// =================================== host side ====================================
extern "C" void kernel_launch(void* const* d_in, const int* in_sizes, int n_in,
                              void* d_out, int out_size) {
    const float* x_seq = nullptr;
    const int*   ei    = nullptr;
    const float* ea    = nullptr;
    const float* P[22];
    int r = 0;
    for (int i = 0; i < n_in; i++) {
        if      (in_sizes[i] == TT * NN * IN_DIM) x_seq = (const float*)d_in[i];
        else if (in_sizes[i] == TT * 2 * EE)      ei    = (const int*)d_in[i];
        else if (in_sizes[i] == TT * EE)          ea    = (const float*)d_in[i];
        else if (r < 22)                          P[r++] = (const float*)d_in[i];
    }
    const float* gW_ih = P[0];
    const float* gW_hh = P[1];
    const float* gb_ih = P[2];
    const float* gb_hh = P[3];
    const float* cWq   = P[4];
    const float* cbq   = P[5];
    const float* cWk   = P[6];
    const float* cbk   = P[7];
    const float* cWv   = P[8];
    const float* cbv   = P[9];
    const float* cWe   = P[10];
    const float* cWs   = P[11];
    const float* cbs   = P[12];
    const float* oWq   = P[13];
    const float* obq   = P[14];
    const float* oWk   = P[15];
    const float* obk   = P[16];
    const float* oWv   = P[17];
    const float* obv   = P[18];
    const float* oWe   = P[19];
    const float* oWs   = P[20];
    const float* obs   = P[21];

    float *GI, *GH, *H, *HA2, *QK, *BPK;
    __nv_bfloat16 *Xh, *Xl, *Hh, *Hl, *HAh, *HAl;
    __nv_bfloat16 *WIHh, *WIHl, *WHHh, *WHHl, *WPh, *WPl;
    float *OQ, *OKp, *OV, *OSK, *EAS;
    int *RP, *ESRC, *CNT, *CUR;
    cudaGetSymbolAddress((void**)&GI,   g_GI);
    cudaGetSymbolAddress((void**)&GH,   g_GH);
    cudaGetSymbolAddress((void**)&H,    g_H);
    cudaGetSymbolAddress((void**)&HA2,  g_HA2);
    cudaGetSymbolAddress((void**)&QK,   g_QK);
    cudaGetSymbolAddress((void**)&Xh,   g_Xh);
    cudaGetSymbolAddress((void**)&Xl,   g_Xl);
    cudaGetSymbolAddress((void**)&Hh,   g_Hh);
    cudaGetSymbolAddress((void**)&Hl,   g_Hl);
    cudaGetSymbolAddress((void**)&HAh,  g_HAh);
    cudaGetSymbolAddress((void**)&HAl,  g_HAl);
    cudaGetSymbolAddress((void**)&WIHh, g_WIHh);
    cudaGetSymbolAddress((void**)&WIHl, g_WIHl);
    cudaGetSymbolAddress((void**)&WHHh, g_WHHh);
    cudaGetSymbolAddress((void**)&WHHl, g_WHHl);
    cudaGetSymbolAddress((void**)&WPh,  g_WPKh);
    cudaGetSymbolAddress((void**)&WPl,  g_WPKl);
    cudaGetSymbolAddress((void**)&BPK,  g_BPK);
    cudaGetSymbolAddress((void**)&OQ,   g_OQ);
    cudaGetSymbolAddress((void**)&OKp,  g_OKs);
    cudaGetSymbolAddress((void**)&OV,   g_OV);
    cudaGetSymbolAddress((void**)&OSK,  g_OSK);
    cudaGetSymbolAddress((void**)&RP,   g_RP);
    cudaGetSymbolAddress((void**)&ESRC, g_ESRC);
    cudaGetSymbolAddress((void**)&EAS,  g_EAS);
    cudaGetSymbolAddress((void**)&CNT,  g_CNT);
    cudaGetSymbolAddress((void**)&CUR,  g_CUR);

    const int SMEM = NSTG * 4 * STG_WORDS * 4;  // 96KB
    cudaFuncSetAttribute(k_pgemm, cudaFuncAttributeMaxDynamicSharedMemorySize, SMEM);

    const int TPB = 256;

    // 1..3: prep (GI GEMM stays the 4th launch for ncu's capture window)
    k_split_x<<<(TT * NN * IN_DIM + TPB - 1) / TPB, TPB>>>(x_seq, Xh, Xl);
    k_prep_gru<<<(G3 * IN_DIM + G3 * DD + TPB - 1) / TPB, TPB>>>(gW_ih, gW_hh, WIHh, WIHl, WHHh, WHHl);
    k_prep_conv<<<(2 * QKVS * DD + TPB - 1) / TPB, TPB>>>(cWq, cWk, cWv, cWs, cbq, cbk, cbv, cbs, WPh, WPl, BPK);

    // 4: GI = X @ W_ih^T + b_ih for all T at once: [80000,64] @ [64,384]
    k_pgemm<<<dim3(G3 / 128, (TT * NN + 127) / 128), 256, SMEM>>>(
        Xh, Xl, WIHh, WIHl, gb_ih, GI, TT * NN, G3, IN_DIM);

    // CSR build (direct (src, attr) records, sorted by dst)
    k_zero_i<<<(TT * NN + TPB - 1) / TPB, TPB>>>(CNT, TT * NN);
    k_hist<<<(TT * EE + TPB - 1) / TPB, TPB>>>(ei, CNT);
    k_scan<<<TT, 1024>>>(CNT, RP, CUR);
    k_scatter<<<(TT * EE + TPB - 1) / TPB, TPB>>>(ei, ea, CUR, ESRC, EAS);

    // ---- GRU over time: sequential chain, per-t Hh/Hl stored batched ----
    for (int t = 0; t < TT; t++) {
        if (t > 0) {
            k_pgemm<<<dim3(G3 / 128, (NN + 127) / 128), 256, SMEM>>>(
                Hh + (size_t)(t - 1) * NN * DD, Hl + (size_t)(t - 1) * NN * DD,
                WHHh, WHHl, gb_hh, GH, NN, G3, DD);
        }
        k_gru_gate<<<(NN * DD + TPB - 1) / TPB, TPB>>>(
            GI + (size_t)t * NN * G3, GH, gb_hh, H,
            Hh + (size_t)t * NN * DD, Hl + (size_t)t * NN * DD, t == 0 ? 1 : 0);
    }

    // ---- layer 0: ONE batched qkvs GEMM over all t, ONE merged conv launch ----
    k_pgemm<<<dim3(QKVS / 128, (TT * NN + 127) / 128), 256, SMEM>>>(
        Hh, Hl, WPh, WPl, BPK, QK, TT * NN, QKVS, DD);
    k_conv_all<<<TT * NN / 8, 256>>>(QK, RP, ESRC, EAS, cWe, nullptr, HAh, HAl, 0);

    // ---- layer 1: ONE batched qkvs GEMM, ONE merged conv launch (f32 out) ----
    k_pgemm<<<dim3(QKVS / 128, (TT * NN + 127) / 128), 256, SMEM>>>(
        HAh, HAl, WPh + QKVS * DD, WPl + QKVS * DD, BPK + QKVS, QK, TT * NN, QKVS, DD);
    k_conv_all<<<TT * NN / 8, 256>>>(QK, RP, ESRC, EAS, cWe + DD, HA2, nullptr, nullptr, 1);

    // ---- output conv (edges of last timestep) ----
    k_out_node<<<NN / 8, 256>>>(HA2, oWq, obq, oWk, obk, oWv, obv, oWs, obs, OQ, OKp, OV, OSK);
    k_out_edge<<<(NN + TPB - 1) / TPB, TPB>>>(RP + (TT - 1) * (NN + 1),
                                              ESRC + (size_t)(TT - 1) * EE, EAS + (size_t)(TT - 1) * EE,
                                              oWe, OQ, OKp, OV, OSK, (float*)d_out);
}

// round 9
// speedup vs baseline: 2.5025x; 1.1281x over previous
#include <cuda_runtime.h>
#include <cuda_fp16.h>
#include <math_constants.h>
#include <cstdint>

#define TT 4
#define NN 20000
#define EE 160000
#define IN_DIM 64
#define DD 128
#define G3 384   // 3*D
#define QKVS 512 // q|k|v|skip packed

// ------------------- static device scratch (no runtime allocs) -------------------
__device__ float g_GI[(size_t)TT * NN * G3];
__device__ float g_GH[(size_t)NN * G3];
__device__ float g_H [(size_t)NN * DD];
__device__ float g_HA2[(size_t)TT * NN * DD];          // layer-1 conv outputs (f32, per t)
__device__ float g_QK[(size_t)TT * NN * QKVS];         // batched qkvs for all t
// activations split to fp16 hi/lo (batched over t)
__device__ __half g_Xh[(size_t)TT * NN * IN_DIM], g_Xl[(size_t)TT * NN * IN_DIM];
__device__ __half g_Hh[(size_t)TT * NN * DD], g_Hl[(size_t)TT * NN * DD];
__device__ __half g_HAh[(size_t)TT * NN * DD], g_HAl[(size_t)TT * NN * DD];
// weights single fp16, [N][K] layout
__device__ __half g_WIH[G3 * IN_DIM];
__device__ __half g_WHH[G3 * DD];
__device__ __half g_WPK[2 * QKVS * DD];
__device__ float g_BPK[2 * QKVS];
__device__ float g_OQ[NN], g_OKs[NN], g_OV[NN], g_OSK[NN];
__device__ int   g_RP [TT * (NN + 1)];
__device__ int   g_ESRC[TT * EE];     // src node id, sorted by dst (CSR order)
__device__ float g_EAS [TT * EE];     // edge attr, sorted by dst (CSR order)
__device__ int   g_CNT[TT * NN];
__device__ int   g_CUR[TT * NN];

// ------------------------------- small utility kernels ---------------------------
__global__ void k_zero_i(int* p, int n) {
    int i = blockIdx.x * blockDim.x + threadIdx.x;
    if (i < n) p[i] = 0;
}

__device__ __forceinline__ void split_f16(float v, __half& h, __half& l) {
    h = __float2half_rn(v);
    l = __float2half_rn(v - __half2float(h));
}

__global__ void k_split_x(const float* __restrict__ x,
                          __half* __restrict__ xh, __half* __restrict__ xl) {
    int i = blockIdx.x * blockDim.x + threadIdx.x;
    if (i < TT * NN * IN_DIM) split_f16(x[i], xh[i], xl[i]);
}

// GRU weights: W_ih [384,64] and W_hh [384,128] are natively [N,K].
__global__ void k_prep_gru(const float* __restrict__ Wih, const float* __restrict__ Whh,
                           __half* __restrict__ a, __half* __restrict__ b) {
    int i = blockIdx.x * blockDim.x + threadIdx.x;
    if (i < G3 * IN_DIM) a[i] = __float2half_rn(Wih[i]);
    int j = i - G3 * IN_DIM;
    if (j >= 0 && j < G3 * DD) b[j] = __float2half_rn(Whh[j]);
}

// Pack conv weights transposed into [layer][n(512)][k(128)] fp16 + bias pack
__global__ void k_prep_conv(const float* __restrict__ Wq, const float* __restrict__ Wk,
                            const float* __restrict__ Wv, const float* __restrict__ Ws,
                            const float* __restrict__ bq, const float* __restrict__ bk,
                            const float* __restrict__ bv, const float* __restrict__ bs,
                            __half* __restrict__ WP, float* __restrict__ BP) {
    int i = blockIdx.x * blockDim.x + threadIdx.x;
    if (i < 2 * QKVS * DD) {
        int l = i >> 16;
        int rem = i & 65535;
        int n = rem >> 7, k = rem & 127;
        int base = l * DD * DD + k * DD;
        float v;
        if      (n < 128) v = Wq[base + n];
        else if (n < 256) v = Wk[base + n - 128];
        else if (n < 384) v = Wv[base + n - 256];
        else              v = Ws[base + n - 384];
        WP[i] = __float2half_rn(v);
    }
    if (i < 2 * QKVS) {
        int l = i >> 9, c = i & 511;
        int b2 = l * DD;
        float v;
        if      (c < 128) v = bq[b2 + c];
        else if (c < 256) v = bk[b2 + c - 128];
        else if (c < 384) v = bv[b2 + c - 256];
        else              v = bs[b2 + c - 384];
        BP[i] = v;
    }
}

// ------------------------------- CSR build ---------------------------------------
__global__ void k_hist(const int* __restrict__ ei, int* __restrict__ cnt) {
    int i = blockIdx.x * blockDim.x + threadIdx.x;
    if (i >= TT * EE) return;
    int t = i / EE, e = i % EE;
    int dst = ei[(size_t)t * 2 * EE + EE + e];
    atomicAdd(&cnt[t * NN + dst], 1);
}

__global__ void k_scan(const int* __restrict__ cnt, int* __restrict__ rowptr, int* __restrict__ cur) {
    int t = blockIdx.x;
    __shared__ int sh[1024];
    const int* c = cnt + t * NN;
    int* rp = rowptr + t * (NN + 1);
    int* cu = cur + t * NN;
    int carry = 0;
    for (int base = 0; base < NN; base += 1024) {
        int idx = base + threadIdx.x;
        int v = (idx < NN) ? c[idx] : 0;
        sh[threadIdx.x] = v;
        __syncthreads();
        for (int off = 1; off < 1024; off <<= 1) {
            int tval = (threadIdx.x >= off) ? sh[threadIdx.x - off] : 0;
            __syncthreads();
            sh[threadIdx.x] += tval;
            __syncthreads();
        }
        int excl = sh[threadIdx.x] - v;
        if (idx < NN) { rp[idx] = carry + excl; cu[idx] = carry + excl; }
        carry += sh[1023];
        __syncthreads();
    }
    if (threadIdx.x == 0) rp[NN] = carry;
}

// scatter edge records (src, attr) sorted by dst — removes indirections in conv
__global__ void k_scatter(const int* __restrict__ ei, const float* __restrict__ ea,
                          int* __restrict__ cur,
                          int* __restrict__ esrc, float* __restrict__ eas) {
    int i = blockIdx.x * blockDim.x + threadIdx.x;
    if (i >= TT * EE) return;
    int t = i / EE, e = i % EE;
    int src = ei[(size_t)t * 2 * EE + e];
    int dst = ei[(size_t)t * 2 * EE + EE + e];
    int p = atomicAdd(&cur[t * NN + dst], 1);
    esrc[(size_t)t * EE + p] = src;
    eas [(size_t)t * EE + p] = ea[(size_t)t * EE + e];
}

// ==== pipelined fp16 HMMA GEMM: 3-stage cp.async + ldmatrix, 2-pass split =========
// C[M,Nc] = (Ahi + Alo) @ B^T + bias. A split fp16 hi/lo, B single fp16 [Nc][K].
#define KC 32
#define NSTG 3
#define STG_WORDS (128 * 16)   // words per array per stage (128 rows x 32 fp16)
#define STG_BYTES (3 * STG_WORDS * 4)

__device__ __forceinline__ void mma_f16(float c[4], const uint32_t a[4],
                                        uint32_t b0, uint32_t b1) {
    asm volatile(
        "mma.sync.aligned.m16n8k16.row.col.f32.f16.f16.f32 "
        "{%0,%1,%2,%3}, {%4,%5,%6,%7}, {%8,%9}, {%0,%1,%2,%3};"
        : "+f"(c[0]), "+f"(c[1]), "+f"(c[2]), "+f"(c[3])
        : "r"(a[0]), "r"(a[1]), "r"(a[2]), "r"(a[3]), "r"(b0), "r"(b1));
}

__device__ __forceinline__ void ldsm_x4(uint32_t addr, uint32_t& r0, uint32_t& r1,
                                        uint32_t& r2, uint32_t& r3) {
    asm volatile("ldmatrix.sync.aligned.m8n8.x4.shared.b16 {%0,%1,%2,%3}, [%4];"
                 : "=r"(r0), "=r"(r1), "=r"(r2), "=r"(r3) : "r"(addr));
}

__global__ void __launch_bounds__(256, 2) k_pgemm(
    const __half* __restrict__ Ah, const __half* __restrict__ Al,
    const __half* __restrict__ B,
    const float* __restrict__ bias, float* __restrict__ C, int M, int Nc, int K) {
    extern __shared__ uint32_t smw[];   // NSTG stages x 3 arrays x STG_WORDS = 72KB

    int tid = threadIdx.x, wid = tid >> 5, lane = tid & 31;
    int gid = lane >> 2, t4 = lane & 3;
    int rowBase = blockIdx.y * 128;
    int colBase = blockIdx.x * 128;
    int warpRow = (wid & 3) * 32;
    int warpCol = (wid >> 2) * 64;

    float acc[2][8][4];
#pragma unroll
    for (int mt = 0; mt < 2; mt++)
#pragma unroll
        for (int nt = 0; nt < 8; nt++)
#pragma unroll
            for (int q = 0; q < 4; q++) acc[mt][nt][q] = 0.f;

    uint32_t sm0;
    asm("{ .reg .u64 t; cvta.to.shared.u64 t, %1; cvt.u32.u64 %0, t; }"
        : "=r"(sm0) : "l"(smw));

    const __half* srcs[3] = {Ah, Al, B};

    int lm_m = lane >> 3;
    int lm_r = lane & 7;
    int a_row0 = warpRow + ((lm_m & 1) << 3) + lm_r;
    int a_kh   = lm_m >> 1;
    int b_row0 = warpCol + ((lm_m >> 1) << 3) + lm_r;
    int b_kh   = lm_m & 1;

    auto fill = [&](int stage, int k0) {
        uint32_t sb = sm0 + (uint32_t)stage * STG_BYTES;
#pragma unroll
        for (int it = 0; it < 6; it++) {
            int idx = tid + it * 256;          // 1536 16B-chunks total
            int arr = idx >> 9;
            int rem = idx & 511;
            int r = rem >> 2, c = rem & 3;
            int grow = (arr < 2) ? (rowBase + r) : (colBase + r);
            int valid = (arr >= 2) || (grow < M);
            const __half* src = srcs[arr] + (valid ? ((size_t)grow * K + k0 + c * 8) : 0);
            int sz = valid ? 16 : 0;
            uint32_t dst = sb + (uint32_t)(arr * STG_WORDS + (r << 4) + ((c ^ ((r >> 1) & 3)) << 2)) * 4;
            asm volatile("cp.async.cg.shared.global [%0], [%1], 16, %2;"
                         :: "r"(dst), "l"(src), "r"(sz));
        }
        asm volatile("cp.async.commit_group;");
    };

    int nch = K / KC;
    fill(0, 0);
    if (nch > 1) fill(1, KC);

    for (int ch = 0; ch < nch; ch++) {
        if (ch + 2 <= nch) { asm volatile("cp.async.wait_group 1;"); }
        else               { asm volatile("cp.async.wait_group 0;"); }
        __syncthreads();

        if (ch + 2 < nch) fill((ch + 2) % NSTG, (ch + 2) * KC);

        uint32_t st = sm0 + (uint32_t)(ch % NSTG) * STG_BYTES;
        uint32_t pAh = st;
        uint32_t pAl = st + STG_WORDS * 4;
        uint32_t pB  = st + 2 * STG_WORDS * 4;

#pragma unroll
        for (int ks = 0; ks < KC; ks += 16) {
            uint32_t ah[2][4], al[2][4];
            int ach = (ks >> 3) + a_kh;
#pragma unroll
            for (int mt = 0; mt < 2; mt++) {
                int ar = a_row0 + mt * 16;
                uint32_t aoff = (uint32_t)(ar << 6) + (uint32_t)((ach ^ ((ar >> 1) & 3)) << 4);
                ldsm_x4(pAh + aoff, ah[mt][0], ah[mt][1], ah[mt][2], ah[mt][3]);
                ldsm_x4(pAl + aoff, al[mt][0], al[mt][1], al[mt][2], al[mt][3]);
            }
            int bch = (ks >> 3) + b_kh;
            // 2 p-groups at a time; same-acc spacing = 8 mma
#pragma unroll
            for (int pp = 0; pp < 2; pp++) {
                uint32_t bh[2][4];
#pragma unroll
                for (int pi = 0; pi < 2; pi++) {
                    int br = b_row0 + (2 * pp + pi) * 16;
                    uint32_t boff = (uint32_t)(br << 6) + (uint32_t)((bch ^ ((br >> 1) & 3)) << 4);
                    ldsm_x4(pB + boff, bh[pi][0], bh[pi][1], bh[pi][2], bh[pi][3]);
                }
                // pass hi
#pragma unroll
                for (int pi = 0; pi < 2; pi++) {
                    int n0 = (2 * pp + pi) * 2, n1 = n0 + 1;
                    mma_f16(acc[0][n0], ah[0], bh[pi][0], bh[pi][1]);
                    mma_f16(acc[0][n1], ah[0], bh[pi][2], bh[pi][3]);
                    mma_f16(acc[1][n0], ah[1], bh[pi][0], bh[pi][1]);
                    mma_f16(acc[1][n1], ah[1], bh[pi][2], bh[pi][3]);
                }
                // pass lo
#pragma unroll
                for (int pi = 0; pi < 2; pi++) {
                    int n0 = (2 * pp + pi) * 2, n1 = n0 + 1;
                    mma_f16(acc[0][n0], al[0], bh[pi][0], bh[pi][1]);
                    mma_f16(acc[0][n1], al[0], bh[pi][2], bh[pi][3]);
                    mma_f16(acc[1][n0], al[1], bh[pi][0], bh[pi][1]);
                    mma_f16(acc[1][n1], al[1], bh[pi][2], bh[pi][3]);
                }
            }
        }
    }

#pragma unroll
    for (int mt = 0; mt < 2; mt++) {
        int r0 = rowBase + warpRow + mt * 16 + gid;
        int r1 = r0 + 8;
#pragma unroll
        for (int nt = 0; nt < 8; nt++) {
            int col = colBase + warpCol + nt * 8 + t4 * 2;
            float b0 = bias[col], b1 = bias[col + 1];
            if (r0 < M) {
                float2 o = make_float2(acc[mt][nt][0] + b0, acc[mt][nt][1] + b1);
                *(float2*)&C[(size_t)r0 * Nc + col] = o;
            }
            if (r1 < M) {
                float2 o = make_float2(acc[mt][nt][2] + b0, acc[mt][nt][3] + b1);
                *(float2*)&C[(size_t)r1 * Nc + col] = o;
            }
        }
    }
}

// ------------------------------- GRU gates ---------------------------------------
__global__ void k_gru_gate(const float* __restrict__ GI, const float* __restrict__ GH,
                           const float* __restrict__ bhh, float* __restrict__ H,
                           __half* __restrict__ Hh, __half* __restrict__ Hl,
                           int first) {
    int i = blockIdx.x * blockDim.x + threadIdx.x;
    if (i >= NN * DD) return;
    int n = i >> 7, j = i & 127;
    const float* gi = GI + (size_t)n * G3;
    float ir = gi[j], iz = gi[j + 128], in = gi[j + 256];
    float hr, hz, hn, hp;
    if (first) {
        hr = bhh[j]; hz = bhh[j + 128]; hn = bhh[j + 256];
        hp = 0.f;
    } else {
        const float* gh = GH + (size_t)n * G3;
        hr = gh[j]; hz = gh[j + 128]; hn = gh[j + 256];
        hp = H[i];
    }
    float r = 1.f / (1.f + __expf(-(ir + hr)));
    float z = 1.f / (1.f + __expf(-(iz + hz)));
    float nv = tanhf(in + r * hn);
    float h = (1.f - z) * nv + z * hp;
    H[i] = h;
    split_f16(h, Hh[i], Hl[i]);
}

// -------------- TransformerConv edge attention, ALL timesteps in one launch ------
// mode 0: write fp16 hi/lo split (feeds next GEMM). mode 1: write f32 to out.
__global__ void k_conv_all(const float* __restrict__ QK,
                           const int* __restrict__ RP,
                           const int* __restrict__ ESRC, const float* __restrict__ EAS,
                           const float* __restrict__ We, float* __restrict__ out,
                           __half* __restrict__ oh, __half* __restrict__ ol,
                           int mode) {
    int gw = (blockIdx.x * blockDim.x + threadIdx.x) >> 5;
    if (gw >= TT * NN) return;
    int t = gw / NN;
    int w = gw - t * NN;
    const float* qkvs = QK + (size_t)t * NN * QKVS;
    const int* rowptr = RP + t * (NN + 1);
    const int* esrc   = ESRC + (size_t)t * EE;
    const float* eas  = EAS + (size_t)t * EE;

    int lane = threadIdx.x & 31;
    int c0 = lane * 4;
    float4 q  = *(const float4*)&qkvs[(size_t)w * QKVS + c0];
    float4 sk = *(const float4*)&qkvs[(size_t)w * QKVS + 384 + c0];
    float4 we = *(const float4*)&We[c0];
    float m = -CUDART_INF_F, s = 0.f;
    float4 acc = make_float4(0.f, 0.f, 0.f, 0.f);
    int beg = rowptr[w], end = rowptr[w + 1];

    float4 k4 = make_float4(0.f, 0.f, 0.f, 0.f), v4 = k4;
    float eaV = 0.f;
    if (beg < end) {
        int sn = esrc[beg];
        eaV = eas[beg];
        k4 = *(const float4*)&qkvs[(size_t)sn * QKVS + 128 + c0];
        v4 = *(const float4*)&qkvs[(size_t)sn * QKVS + 256 + c0];
    }
    for (int i = beg; i < end; i++) {
        float4 ck = k4, cv = v4;
        float cea = eaV;
        if (i + 1 < end) {       // prefetch next edge's gather before reduction chain
            int sn = esrc[i + 1];
            eaV = eas[i + 1];
            k4 = *(const float4*)&qkvs[(size_t)sn * QKVS + 128 + c0];
            v4 = *(const float4*)&qkvs[(size_t)sn * QKVS + 256 + c0];
        }
        float ex = cea * we.x, ey = cea * we.y, ez = cea * we.z, ew = cea * we.w;
        float part = q.x * (ck.x + ex) + q.y * (ck.y + ey) + q.z * (ck.z + ez) + q.w * (ck.w + ew);
#pragma unroll
        for (int o = 16; o; o >>= 1) part += __shfl_xor_sync(0xffffffffu, part, o);
        float alpha = part * 0.08838834764831845f; // 1/sqrt(128)
        float mn = fmaxf(m, alpha);
        float corr = __expf(m - mn);
        float p = __expf(alpha - mn);
        s = s * corr + p;
        acc.x = acc.x * corr + p * (cv.x + ex);
        acc.y = acc.y * corr + p * (cv.y + ey);
        acc.z = acc.z * corr + p * (cv.z + ez);
        acc.w = acc.w * corr + p * (cv.w + ew);
        m = mn;
    }
    float inv = 1.f / (s + 1e-16f);
    float4 o;
    o.x = acc.x * inv + sk.x;
    o.y = acc.y * inv + sk.y;
    o.z = acc.z * inv + sk.z;
    o.w = acc.w * inv + sk.w;
    o.x = o.x > 0.f ? o.x : 0.01f * o.x;
    o.y = o.y > 0.f ? o.y : 0.01f * o.y;
    o.z = o.z > 0.f ? o.z : 0.01f * o.z;
    o.w = o.w > 0.f ? o.w : 0.01f * o.w;
    size_t oidx = (size_t)t * NN * DD + (size_t)w * DD + c0;
    if (mode) {
        *(float4*)&out[oidx] = o;
    } else {
        __half hv[4], lv[4];
        split_f16(o.x, hv[0], lv[0]);
        split_f16(o.y, hv[1], lv[1]);
        split_f16(o.z, hv[2], lv[2]);
        split_f16(o.w, hv[3], lv[3]);
        *(uint2*)&oh[oidx] = *(uint2*)hv;
        *(uint2*)&ol[oidx] = *(uint2*)lv;
    }
}

// ------------------------ output conv (D -> 1) -----------------------------------
__global__ void k_out_node(const float* __restrict__ ha2,
                           const float* __restrict__ Wq, const float* __restrict__ bq,
                           const float* __restrict__ Wk, const float* __restrict__ bk,
                           const float* __restrict__ Wv, const float* __restrict__ bv,
                           const float* __restrict__ Ws, const float* __restrict__ bs,
                           float* __restrict__ oq, float* __restrict__ ok,
                           float* __restrict__ ov, float* __restrict__ osk) {
    int w = (blockIdx.x * blockDim.x + threadIdx.x) >> 5;
    if (w >= NN) return;
    int lane = threadIdx.x & 31;
    int c0 = lane * 4;
    float4 h = make_float4(0.f, 0.f, 0.f, 0.f);
#pragma unroll
    for (int t = 0; t < TT; t++) {
        float4 v = *(const float4*)&ha2[(size_t)t * NN * DD + (size_t)w * DD + c0];
        h.x += v.x; h.y += v.y; h.z += v.z; h.w += v.w;
    }
    h.x *= 0.25f; h.y *= 0.25f; h.z *= 0.25f; h.w *= 0.25f;
    float4 wq = *(const float4*)&Wq[c0];
    float4 wk = *(const float4*)&Wk[c0];
    float4 wv = *(const float4*)&Wv[c0];
    float4 ws = *(const float4*)&Ws[c0];
    float dq = h.x * wq.x + h.y * wq.y + h.z * wq.z + h.w * wq.w;
    float dk = h.x * wk.x + h.y * wk.y + h.z * wk.z + h.w * wk.w;
    float dv = h.x * wv.x + h.y * wv.y + h.z * wv.z + h.w * wv.w;
    float ds = h.x * ws.x + h.y * ws.y + h.z * ws.z + h.w * ws.w;
#pragma unroll
    for (int o = 16; o; o >>= 1) {
        dq += __shfl_xor_sync(0xffffffffu, dq, o);
        dk += __shfl_xor_sync(0xffffffffu, dk, o);
        dv += __shfl_xor_sync(0xffffffffu, dv, o);
        ds += __shfl_xor_sync(0xffffffffu, ds, o);
    }
    if (lane == 0) {
        oq[w]  = dq + bq[0];
        ok[w]  = dk + bk[0];
        ov[w]  = dv + bv[0];
        osk[w] = ds + bs[0];
    }
}

__global__ void k_out_edge(const int* __restrict__ rowptr,
                           const int* __restrict__ esrc, const float* __restrict__ eas,
                           const float* __restrict__ We,
                           const float* __restrict__ oq, const float* __restrict__ ok,
                           const float* __restrict__ ov, const float* __restrict__ osk,
                           float* __restrict__ out) {
    int n = blockIdx.x * blockDim.x + threadIdx.x;
    if (n >= NN) return;
    float q = oq[n];
    float we = We[0];
    float m = -CUDART_INF_F, s = 0.f, acc = 0.f;
    int beg = rowptr[n], end = rowptr[n + 1];
    for (int i = beg; i < end; i++) {
        int sn = esrc[i];
        float et = eas[i] * we;
        float alpha = q * (ok[sn] + et);
        float mn = fmaxf(m, alpha);
        float corr = __expf(m - mn);
        float p = __expf(alpha - mn);
        s = s * corr + p;
        acc = acc * corr + p * (ov[sn] + et);
        m = mn;
    }
    out[n] = acc / (s + 1e-16f) + osk[n];
}

// =================================== host side ====================================
extern "C" void kernel_launch(void* const* d_in, const int* in_sizes, int n_in,
                              void* d_out, int out_size) {
    const float* x_seq = nullptr;
    const int*   ei    = nullptr;
    const float* ea    = nullptr;
    const float* P[22];
    int r = 0;
    for (int i = 0; i < n_in; i++) {
        if      (in_sizes[i] == TT * NN * IN_DIM) x_seq = (const float*)d_in[i];
        else if (in_sizes[i] == TT * 2 * EE)      ei    = (const int*)d_in[i];
        else if (in_sizes[i] == TT * EE)          ea    = (const float*)d_in[i];
        else if (r < 22)                          P[r++] = (const float*)d_in[i];
    }
    const float* gW_ih = P[0];
    const float* gW_hh = P[1];
    const float* gb_ih = P[2];
    const float* gb_hh = P[3];
    const float* cWq   = P[4];
    const float* cbq   = P[5];
    const float* cWk   = P[6];
    const float* cbk   = P[7];
    const float* cWv   = P[8];
    const float* cbv   = P[9];
    const float* cWe   = P[10];
    const float* cWs   = P[11];
    const float* cbs   = P[12];
    const float* oWq   = P[13];
    const float* obq   = P[14];
    const float* oWk   = P[15];
    const float* obk   = P[16];
    const float* oWv   = P[17];
    const float* obv   = P[18];
    const float* oWe   = P[19];
    const float* oWs   = P[20];
    const float* obs   = P[21];

    float *GI, *GH, *H, *HA2, *QK, *BPK;
    __half *Xh, *Xl, *Hh, *Hl, *HAh, *HAl;
    __half *WIH, *WHH, *WP;
    float *OQ, *OKp, *OV, *OSK, *EAS;
    int *RP, *ESRC, *CNT, *CUR;
    cudaGetSymbolAddress((void**)&GI,   g_GI);
    cudaGetSymbolAddress((void**)&GH,   g_GH);
    cudaGetSymbolAddress((void**)&H,    g_H);
    cudaGetSymbolAddress((void**)&HA2,  g_HA2);
    cudaGetSymbolAddress((void**)&QK,   g_QK);
    cudaGetSymbolAddress((void**)&Xh,   g_Xh);
    cudaGetSymbolAddress((void**)&Xl,   g_Xl);
    cudaGetSymbolAddress((void**)&Hh,   g_Hh);
    cudaGetSymbolAddress((void**)&Hl,   g_Hl);
    cudaGetSymbolAddress((void**)&HAh,  g_HAh);
    cudaGetSymbolAddress((void**)&HAl,  g_HAl);
    cudaGetSymbolAddress((void**)&WIH,  g_WIH);
    cudaGetSymbolAddress((void**)&WHH,  g_WHH);
    cudaGetSymbolAddress((void**)&WP,   g_WPK);
    cudaGetSymbolAddress((void**)&BPK,  g_BPK);
    cudaGetSymbolAddress((void**)&OQ,   g_OQ);
    cudaGetSymbolAddress((void**)&OKp,  g_OKs);
    cudaGetSymbolAddress((void**)&OV,   g_OV);
    cudaGetSymbolAddress((void**)&OSK,  g_OSK);
    cudaGetSymbolAddress((void**)&RP,   g_RP);
    cudaGetSymbolAddress((void**)&ESRC, g_ESRC);
    cudaGetSymbolAddress((void**)&EAS,  g_EAS);
    cudaGetSymbolAddress((void**)&CNT,  g_CNT);
    cudaGetSymbolAddress((void**)&CUR,  g_CUR);

    const int SMEM = NSTG * STG_BYTES;  // 72KB
    cudaFuncSetAttribute(k_pgemm, cudaFuncAttributeMaxDynamicSharedMemorySize, SMEM);

    const int TPB = 256;

    // 1..3: prep (GI GEMM stays the 4th launch for ncu's capture window)
    k_split_x<<<(TT * NN * IN_DIM + TPB - 1) / TPB, TPB>>>(x_seq, Xh, Xl);
    k_prep_gru<<<(G3 * IN_DIM + G3 * DD + TPB - 1) / TPB, TPB>>>(gW_ih, gW_hh, WIH, WHH);
    k_prep_conv<<<(2 * QKVS * DD + TPB - 1) / TPB, TPB>>>(cWq, cWk, cWv, cWs, cbq, cbk, cbv, cbs, WP, BPK);

    // 4: GI = X @ W_ih^T + b_ih for all T at once: [80000,64] @ [64,384]
    k_pgemm<<<dim3(G3 / 128, (TT * NN + 127) / 128), 256, SMEM>>>(
        Xh, Xl, WIH, gb_ih, GI, TT * NN, G3, IN_DIM);

    // CSR build (direct (src, attr) records, sorted by dst)
    k_zero_i<<<(TT * NN + TPB - 1) / TPB, TPB>>>(CNT, TT * NN);
    k_hist<<<(TT * EE + TPB - 1) / TPB, TPB>>>(ei, CNT);
    k_scan<<<TT, 1024>>>(CNT, RP, CUR);
    k_scatter<<<(TT * EE + TPB - 1) / TPB, TPB>>>(ei, ea, CUR, ESRC, EAS);

    // ---- GRU over time: sequential chain, per-t Hh/Hl stored batched ----
    for (int t = 0; t < TT; t++) {
        if (t > 0) {
            k_pgemm<<<dim3(G3 / 128, (NN + 127) / 128), 256, SMEM>>>(
                Hh + (size_t)(t - 1) * NN * DD, Hl + (size_t)(t - 1) * NN * DD,
                WHH, gb_hh, GH, NN, G3, DD);
        }
        k_gru_gate<<<(NN * DD + TPB - 1) / TPB, TPB>>>(
            GI + (size_t)t * NN * G3, GH, gb_hh, H,
            Hh + (size_t)t * NN * DD, Hl + (size_t)t * NN * DD, t == 0 ? 1 : 0);
    }

    // ---- layer 0: ONE batched qkvs GEMM over all t, ONE merged conv launch ----
    k_pgemm<<<dim3(QKVS / 128, (TT * NN + 127) / 128), 256, SMEM>>>(
        Hh, Hl, WP, BPK, QK, TT * NN, QKVS, DD);
    k_conv_all<<<TT * NN / 8, 256>>>(QK, RP, ESRC, EAS, cWe, nullptr, HAh, HAl, 0);

    // ---- layer 1: ONE batched qkvs GEMM, ONE merged conv launch (f32 out) ----
    k_pgemm<<<dim3(QKVS / 128, (TT * NN + 127) / 128), 256, SMEM>>>(
        HAh, HAl, WP + QKVS * DD, BPK + QKVS, QK, TT * NN, QKVS, DD);
    k_conv_all<<<TT * NN / 8, 256>>>(QK, RP, ESRC, EAS, cWe + DD, HA2, nullptr, nullptr, 1);

    // ---- output conv (edges of last timestep) ----
    k_out_node<<<NN / 8, 256>>>(HA2, oWq, obq, oWk, obk, oWv, obv, oWs, obs, OQ, OKp, OV, OSK);
    k_out_edge<<<(NN + TPB - 1) / TPB, TPB>>>(RP + (TT - 1) * (NN + 1),
                                              ESRC + (size_t)(TT - 1) * EE, EAS + (size_t)(TT - 1) * EE,
                                              oWe, OQ, OKp, OV, OSK, (float*)d_out);
}

// round 10
// speedup vs baseline: 2.5301x; 1.0110x over previous
#include <cuda_runtime.h>
#include <cuda_fp16.h>
#include <math_constants.h>
#include <cstdint>

#define TT 4
#define NN 20000
#define EE 160000
#define IN_DIM 64
#define DD 128
#define G3 384   // 3*D
#define QKVS 512 // q|k|v|skip packed

// ------------------- static device scratch (no runtime allocs) -------------------
__device__ float g_GI[(size_t)TT * NN * G3];
__device__ float g_GH[(size_t)NN * G3];
__device__ float g_H [(size_t)NN * DD];
__device__ float g_HA2[(size_t)TT * NN * DD];           // layer-1 conv outputs (f32, per t)
__device__ float  g_QKf[(size_t)TT * NN * 256];         // q|skip per node (f32)
__device__ __half g_QKh[(size_t)TT * NN * 256];         // k|v per node (fp16)
// activations split to fp16 hi/lo (batched over t)
__device__ __half g_Xh[(size_t)TT * NN * IN_DIM], g_Xl[(size_t)TT * NN * IN_DIM];
__device__ __half g_Hh[(size_t)TT * NN * DD], g_Hl[(size_t)TT * NN * DD];
__device__ __half g_HAh[(size_t)TT * NN * DD], g_HAl[(size_t)TT * NN * DD];
// weights single fp16, [N][K] layout
__device__ __half g_WIH[G3 * IN_DIM];
__device__ __half g_WHH[G3 * DD];
__device__ __half g_WPK[2 * QKVS * DD];
__device__ float g_BPK[2 * QKVS];
__device__ float g_OQ[NN], g_OKs[NN], g_OV[NN], g_OSK[NN];
__device__ int   g_RP [TT * (NN + 1)];
__device__ int   g_ESRC[TT * EE];     // src node id, sorted by dst (CSR order)
__device__ float g_EAS [TT * EE];     // edge attr, sorted by dst (CSR order)
__device__ int   g_CNT[TT * NN];
__device__ int   g_CUR[TT * NN];

// ------------------------------- small utility kernels ---------------------------
__global__ void k_zero_i(int* p, int n) {
    int i = blockIdx.x * blockDim.x + threadIdx.x;
    if (i < n) p[i] = 0;
}

__device__ __forceinline__ void split_f16(float v, __half& h, __half& l) {
    h = __float2half_rn(v);
    l = __float2half_rn(v - __half2float(h));
}

__global__ void k_split_x(const float* __restrict__ x,
                          __half* __restrict__ xh, __half* __restrict__ xl) {
    int i = blockIdx.x * blockDim.x + threadIdx.x;
    if (i < TT * NN * IN_DIM) split_f16(x[i], xh[i], xl[i]);
}

// GRU weights: W_ih [384,64] and W_hh [384,128] are natively [N,K].
__global__ void k_prep_gru(const float* __restrict__ Wih, const float* __restrict__ Whh,
                           __half* __restrict__ a, __half* __restrict__ b) {
    int i = blockIdx.x * blockDim.x + threadIdx.x;
    if (i < G3 * IN_DIM) a[i] = __float2half_rn(Wih[i]);
    int j = i - G3 * IN_DIM;
    if (j >= 0 && j < G3 * DD) b[j] = __float2half_rn(Whh[j]);
}

// Pack conv weights transposed into [layer][n(512)][k(128)] fp16 + bias pack
__global__ void k_prep_conv(const float* __restrict__ Wq, const float* __restrict__ Wk,
                            const float* __restrict__ Wv, const float* __restrict__ Ws,
                            const float* __restrict__ bq, const float* __restrict__ bk,
                            const float* __restrict__ bv, const float* __restrict__ bs,
                            __half* __restrict__ WP, float* __restrict__ BP) {
    int i = blockIdx.x * blockDim.x + threadIdx.x;
    if (i < 2 * QKVS * DD) {
        int l = i >> 16;
        int rem = i & 65535;
        int n = rem >> 7, k = rem & 127;
        int base = l * DD * DD + k * DD;
        float v;
        if      (n < 128) v = Wq[base + n];
        else if (n < 256) v = Wk[base + n - 128];
        else if (n < 384) v = Wv[base + n - 256];
        else              v = Ws[base + n - 384];
        WP[i] = __float2half_rn(v);
    }
    if (i < 2 * QKVS) {
        int l = i >> 9, c = i & 511;
        int b2 = l * DD;
        float v;
        if      (c < 128) v = bq[b2 + c];
        else if (c < 256) v = bk[b2 + c - 128];
        else if (c < 384) v = bv[b2 + c - 256];
        else              v = bs[b2 + c - 384];
        BP[i] = v;
    }
}

// ------------------------------- CSR build ---------------------------------------
__global__ void k_hist(const int* __restrict__ ei, int* __restrict__ cnt) {
    int i = blockIdx.x * blockDim.x + threadIdx.x;
    if (i >= TT * EE) return;
    int t = i / EE, e = i % EE;
    int dst = ei[(size_t)t * 2 * EE + EE + e];
    atomicAdd(&cnt[t * NN + dst], 1);
}

__global__ void k_scan(const int* __restrict__ cnt, int* __restrict__ rowptr, int* __restrict__ cur) {
    int t = blockIdx.x;
    __shared__ int sh[1024];
    const int* c = cnt + t * NN;
    int* rp = rowptr + t * (NN + 1);
    int* cu = cur + t * NN;
    int carry = 0;
    for (int base = 0; base < NN; base += 1024) {
        int idx = base + threadIdx.x;
        int v = (idx < NN) ? c[idx] : 0;
        sh[threadIdx.x] = v;
        __syncthreads();
        for (int off = 1; off < 1024; off <<= 1) {
            int tval = (threadIdx.x >= off) ? sh[threadIdx.x - off] : 0;
            __syncthreads();
            sh[threadIdx.x] += tval;
            __syncthreads();
        }
        int excl = sh[threadIdx.x] - v;
        if (idx < NN) { rp[idx] = carry + excl; cu[idx] = carry + excl; }
        carry += sh[1023];
        __syncthreads();
    }
    if (threadIdx.x == 0) rp[NN] = carry;
}

// scatter edge records (src, attr) sorted by dst — removes indirections in conv
__global__ void k_scatter(const int* __restrict__ ei, const float* __restrict__ ea,
                          int* __restrict__ cur,
                          int* __restrict__ esrc, float* __restrict__ eas) {
    int i = blockIdx.x * blockDim.x + threadIdx.x;
    if (i >= TT * EE) return;
    int t = i / EE, e = i % EE;
    int src = ei[(size_t)t * 2 * EE + e];
    int dst = ei[(size_t)t * 2 * EE + EE + e];
    int p = atomicAdd(&cur[t * NN + dst], 1);
    esrc[(size_t)t * EE + p] = src;
    eas [(size_t)t * EE + p] = ea[(size_t)t * EE + e];
}

// ==== pipelined fp16 HMMA GEMM: 3-stage cp.async + ldmatrix, 2-pass split =========
// C = (Ahi + Alo) @ B^T + bias.
// Plain mode (Qh==null): f32 C [M, Nc].
// Conv mode (Qh!=null): col-block routed: q(blk0),skip(blk3) -> Qf f32 [M,256];
//                       k(blk1),v(blk2) -> Qh fp16 [M,256].
#define KC 32
#define NSTG 3
#define STG_WORDS (128 * 16)   // words per array per stage (128 rows x 32 fp16)
#define STG_BYTES (3 * STG_WORDS * 4)

__device__ __forceinline__ void mma_f16(float c[4], const uint32_t a[4],
                                        uint32_t b0, uint32_t b1) {
    asm volatile(
        "mma.sync.aligned.m16n8k16.row.col.f32.f16.f16.f32 "
        "{%0,%1,%2,%3}, {%4,%5,%6,%7}, {%8,%9}, {%0,%1,%2,%3};"
        : "+f"(c[0]), "+f"(c[1]), "+f"(c[2]), "+f"(c[3])
        : "r"(a[0]), "r"(a[1]), "r"(a[2]), "r"(a[3]), "r"(b0), "r"(b1));
}

__device__ __forceinline__ void ldsm_x4(uint32_t addr, uint32_t& r0, uint32_t& r1,
                                        uint32_t& r2, uint32_t& r3) {
    asm volatile("ldmatrix.sync.aligned.m8n8.x4.shared.b16 {%0,%1,%2,%3}, [%4];"
                 : "=r"(r0), "=r"(r1), "=r"(r2), "=r"(r3) : "r"(addr));
}

__global__ void __launch_bounds__(256, 2) k_pgemm(
    const __half* __restrict__ Ah, const __half* __restrict__ Al,
    const __half* __restrict__ B,
    const float* __restrict__ bias, float* __restrict__ C,
    float* __restrict__ Qf, __half* __restrict__ Qh,
    int M, int Nc, int K) {
    extern __shared__ uint32_t smw[];   // NSTG stages x 3 arrays x STG_WORDS = 72KB

    int tid = threadIdx.x, wid = tid >> 5, lane = tid & 31;
    int gid = lane >> 2, t4 = lane & 3;
    int rowBase = blockIdx.y * 128;
    int colBase = blockIdx.x * 128;
    int warpRow = (wid & 3) * 32;
    int warpCol = (wid >> 2) * 64;

    float acc[2][8][4];
#pragma unroll
    for (int mt = 0; mt < 2; mt++)
#pragma unroll
        for (int nt = 0; nt < 8; nt++)
#pragma unroll
            for (int q = 0; q < 4; q++) acc[mt][nt][q] = 0.f;

    uint32_t sm0;
    asm("{ .reg .u64 t; cvta.to.shared.u64 t, %1; cvt.u32.u64 %0, t; }"
        : "=r"(sm0) : "l"(smw));

    const __half* srcs[3] = {Ah, Al, B};

    int lm_m = lane >> 3;
    int lm_r = lane & 7;
    int a_row0 = warpRow + ((lm_m & 1) << 3) + lm_r;
    int a_kh   = lm_m >> 1;
    int b_row0 = warpCol + ((lm_m >> 1) << 3) + lm_r;
    int b_kh   = lm_m & 1;

    auto fill = [&](int stage, int k0) {
        uint32_t sb = sm0 + (uint32_t)stage * STG_BYTES;
#pragma unroll
        for (int it = 0; it < 6; it++) {
            int idx = tid + it * 256;          // 1536 16B-chunks total
            int arr = idx >> 9;
            int rem = idx & 511;
            int r = rem >> 2, c = rem & 3;
            int grow = (arr < 2) ? (rowBase + r) : (colBase + r);
            int valid = (arr >= 2) || (grow < M);
            const __half* src = srcs[arr] + (valid ? ((size_t)grow * K + k0 + c * 8) : 0);
            int sz = valid ? 16 : 0;
            uint32_t dst = sb + (uint32_t)(arr * STG_WORDS + (r << 4) + ((c ^ ((r >> 1) & 3)) << 2)) * 4;
            asm volatile("cp.async.cg.shared.global [%0], [%1], 16, %2;"
                         :: "r"(dst), "l"(src), "r"(sz));
        }
        asm volatile("cp.async.commit_group;");
    };

    int nch = K / KC;
    fill(0, 0);
    if (nch > 1) fill(1, KC);

    for (int ch = 0; ch < nch; ch++) {
        if (ch + 2 <= nch) { asm volatile("cp.async.wait_group 1;"); }
        else               { asm volatile("cp.async.wait_group 0;"); }
        __syncthreads();

        if (ch + 2 < nch) fill((ch + 2) % NSTG, (ch + 2) * KC);

        uint32_t st = sm0 + (uint32_t)(ch % NSTG) * STG_BYTES;
        uint32_t pAh = st;
        uint32_t pAl = st + STG_WORDS * 4;
        uint32_t pB  = st + 2 * STG_WORDS * 4;

#pragma unroll
        for (int ks = 0; ks < KC; ks += 16) {
            uint32_t ah[2][4], al[2][4];
            int ach = (ks >> 3) + a_kh;
#pragma unroll
            for (int mt = 0; mt < 2; mt++) {
                int ar = a_row0 + mt * 16;
                uint32_t aoff = (uint32_t)(ar << 6) + (uint32_t)((ach ^ ((ar >> 1) & 3)) << 4);
                ldsm_x4(pAh + aoff, ah[mt][0], ah[mt][1], ah[mt][2], ah[mt][3]);
                ldsm_x4(pAl + aoff, al[mt][0], al[mt][1], al[mt][2], al[mt][3]);
            }
            int bch = (ks >> 3) + b_kh;
#pragma unroll
            for (int pp = 0; pp < 2; pp++) {
                uint32_t bh[2][4];
#pragma unroll
                for (int pi = 0; pi < 2; pi++) {
                    int br = b_row0 + (2 * pp + pi) * 16;
                    uint32_t boff = (uint32_t)(br << 6) + (uint32_t)((bch ^ ((br >> 1) & 3)) << 4);
                    ldsm_x4(pB + boff, bh[pi][0], bh[pi][1], bh[pi][2], bh[pi][3]);
                }
#pragma unroll
                for (int pi = 0; pi < 2; pi++) {
                    int n0 = (2 * pp + pi) * 2, n1 = n0 + 1;
                    mma_f16(acc[0][n0], ah[0], bh[pi][0], bh[pi][1]);
                    mma_f16(acc[0][n1], ah[0], bh[pi][2], bh[pi][3]);
                    mma_f16(acc[1][n0], ah[1], bh[pi][0], bh[pi][1]);
                    mma_f16(acc[1][n1], ah[1], bh[pi][2], bh[pi][3]);
                }
#pragma unroll
                for (int pi = 0; pi < 2; pi++) {
                    int n0 = (2 * pp + pi) * 2, n1 = n0 + 1;
                    mma_f16(acc[0][n0], al[0], bh[pi][0], bh[pi][1]);
                    mma_f16(acc[0][n1], al[0], bh[pi][2], bh[pi][3]);
                    mma_f16(acc[1][n0], al[1], bh[pi][0], bh[pi][1]);
                    mma_f16(acc[1][n1], al[1], bh[pi][2], bh[pi][3]);
                }
            }
        }
    }

    // ---- epilogue ----
    int cb = blockIdx.x;   // 0=q 1=k 2=v 3=skip in conv mode
#pragma unroll
    for (int mt = 0; mt < 2; mt++) {
        int rows[2] = {rowBase + warpRow + mt * 16 + gid, rowBase + warpRow + mt * 16 + gid + 8};
#pragma unroll
        for (int nt = 0; nt < 8; nt++) {
            int lcol = warpCol + nt * 8 + t4 * 2;
            int col = colBase + lcol;
            float b0 = bias[col], b1 = bias[col + 1];
#pragma unroll
            for (int rr = 0; rr < 2; rr++) {
                int rw = rows[rr];
                if (rw >= M) continue;
                float v0 = acc[mt][nt][rr * 2 + 0] + b0;
                float v1 = acc[mt][nt][rr * 2 + 1] + b1;
                if (!Qh) {
                    *(float2*)&C[(size_t)rw * Nc + col] = make_float2(v0, v1);
                } else if (cb == 0) {
                    *(float2*)&Qf[(size_t)rw * 256 + lcol] = make_float2(v0, v1);
                } else if (cb == 3) {
                    *(float2*)&Qf[(size_t)rw * 256 + 128 + lcol] = make_float2(v0, v1);
                } else {
                    // k -> Qh[0..127], v -> Qh[128..255]
                    __half2 hv = __floats2half2_rn(v0, v1);
                    *(__half2*)&Qh[(size_t)rw * 256 + (cb - 1) * 128 + lcol] = hv;
                }
            }
        }
    }
}

// ------------------------------- GRU gates ---------------------------------------
__global__ void k_gru_gate(const float* __restrict__ GI, const float* __restrict__ GH,
                           const float* __restrict__ bhh, float* __restrict__ H,
                           __half* __restrict__ Hh, __half* __restrict__ Hl,
                           int first) {
    int i = blockIdx.x * blockDim.x + threadIdx.x;
    if (i >= NN * DD) return;
    int n = i >> 7, j = i & 127;
    const float* gi = GI + (size_t)n * G3;
    float ir = gi[j], iz = gi[j + 128], in = gi[j + 256];
    float hr, hz, hn, hp;
    if (first) {
        hr = bhh[j]; hz = bhh[j + 128]; hn = bhh[j + 256];
        hp = 0.f;
    } else {
        const float* gh = GH + (size_t)n * G3;
        hr = gh[j]; hz = gh[j + 128]; hn = gh[j + 256];
        hp = H[i];
    }
    float r = 1.f / (1.f + __expf(-(ir + hr)));
    float z = 1.f / (1.f + __expf(-(iz + hz)));
    float nv = tanhf(in + r * hn);
    float h = (1.f - z) * nv + z * hp;
    H[i] = h;
    split_f16(h, Hh[i], Hl[i]);
}

// -------------- TransformerConv edge attention, ALL timesteps in one launch ------
// q/skip read f32 from Qf, k/v gathered fp16 from Qh (halves L2 traffic).
// mode 0: write fp16 hi/lo split (feeds next GEMM). mode 1: write f32 to out.
__global__ void k_conv_all(const float* __restrict__ QKf, const __half* __restrict__ QKh,
                           const int* __restrict__ RP,
                           const int* __restrict__ ESRC, const float* __restrict__ EAS,
                           const float* __restrict__ We, float* __restrict__ out,
                           __half* __restrict__ oh, __half* __restrict__ ol,
                           int mode) {
    int gw = (blockIdx.x * blockDim.x + threadIdx.x) >> 5;
    if (gw >= TT * NN) return;
    int t = gw / NN;
    int w = gw - t * NN;
    const float* qf  = QKf + (size_t)t * NN * 256;
    const __half* qh = QKh + (size_t)t * NN * 256;
    const int* rowptr = RP + t * (NN + 1);
    const int* esrc   = ESRC + (size_t)t * EE;
    const float* eas  = EAS + (size_t)t * EE;

    int lane = threadIdx.x & 31;
    int c0 = lane * 4;
    float4 q  = *(const float4*)&qf[(size_t)w * 256 + c0];
    float4 sk = *(const float4*)&qf[(size_t)w * 256 + 128 + c0];
    float4 we = *(const float4*)&We[c0];
    float m = -CUDART_INF_F, s = 0.f;
    float4 acc = make_float4(0.f, 0.f, 0.f, 0.f);
    int beg = rowptr[w], end = rowptr[w + 1];

    uint2 kraw = make_uint2(0, 0), vraw = make_uint2(0, 0);
    float eaV = 0.f;
    if (beg < end) {
        int sn = esrc[beg];
        eaV = eas[beg];
        kraw = *(const uint2*)&qh[(size_t)sn * 256 + c0];
        vraw = *(const uint2*)&qh[(size_t)sn * 256 + 128 + c0];
    }
    for (int i = beg; i < end; i++) {
        uint2 ck = kraw, cv = vraw;
        float cea = eaV;
        if (i + 1 < end) {       // prefetch next edge's gather before reduction chain
            int sn = esrc[i + 1];
            eaV = eas[i + 1];
            kraw = *(const uint2*)&qh[(size_t)sn * 256 + c0];
            vraw = *(const uint2*)&qh[(size_t)sn * 256 + 128 + c0];
        }
        float2 k01 = __half22float2(*(const __half2*)&ck.x);
        float2 k23 = __half22float2(*(const __half2*)&ck.y);
        float2 v01 = __half22float2(*(const __half2*)&cv.x);
        float2 v23 = __half22float2(*(const __half2*)&cv.y);
        float ex = cea * we.x, ey = cea * we.y, ez = cea * we.z, ew = cea * we.w;
        float part = q.x * (k01.x + ex) + q.y * (k01.y + ey)
                   + q.z * (k23.x + ez) + q.w * (k23.y + ew);
#pragma unroll
        for (int o = 16; o; o >>= 1) part += __shfl_xor_sync(0xffffffffu, part, o);
        float alpha = part * 0.08838834764831845f; // 1/sqrt(128)
        float mn = fmaxf(m, alpha);
        float corr = __expf(m - mn);
        float p = __expf(alpha - mn);
        s = s * corr + p;
        acc.x = acc.x * corr + p * (v01.x + ex);
        acc.y = acc.y * corr + p * (v01.y + ey);
        acc.z = acc.z * corr + p * (v23.x + ez);
        acc.w = acc.w * corr + p * (v23.y + ew);
        m = mn;
    }
    float inv = 1.f / (s + 1e-16f);
    float4 o;
    o.x = acc.x * inv + sk.x;
    o.y = acc.y * inv + sk.y;
    o.z = acc.z * inv + sk.z;
    o.w = acc.w * inv + sk.w;
    o.x = o.x > 0.f ? o.x : 0.01f * o.x;
    o.y = o.y > 0.f ? o.y : 0.01f * o.y;
    o.z = o.z > 0.f ? o.z : 0.01f * o.z;
    o.w = o.w > 0.f ? o.w : 0.01f * o.w;
    size_t oidx = (size_t)t * NN * DD + (size_t)w * DD + c0;
    if (mode) {
        *(float4*)&out[oidx] = o;
    } else {
        __half hv[4], lv[4];
        split_f16(o.x, hv[0], lv[0]);
        split_f16(o.y, hv[1], lv[1]);
        split_f16(o.z, hv[2], lv[2]);
        split_f16(o.w, hv[3], lv[3]);
        *(uint2*)&oh[oidx] = *(uint2*)hv;
        *(uint2*)&ol[oidx] = *(uint2*)lv;
    }
}

// ------------------------ output conv (D -> 1) -----------------------------------
__global__ void k_out_node(const float* __restrict__ ha2,
                           const float* __restrict__ Wq, const float* __restrict__ bq,
                           const float* __restrict__ Wk, const float* __restrict__ bk,
                           const float* __restrict__ Wv, const float* __restrict__ bv,
                           const float* __restrict__ Ws, const float* __restrict__ bs,
                           float* __restrict__ oq, float* __restrict__ ok,
                           float* __restrict__ ov, float* __restrict__ osk) {
    int w = (blockIdx.x * blockDim.x + threadIdx.x) >> 5;
    if (w >= NN) return;
    int lane = threadIdx.x & 31;
    int c0 = lane * 4;
    float4 h = make_float4(0.f, 0.f, 0.f, 0.f);
#pragma unroll
    for (int t = 0; t < TT; t++) {
        float4 v = *(const float4*)&ha2[(size_t)t * NN * DD + (size_t)w * DD + c0];
        h.x += v.x; h.y += v.y; h.z += v.z; h.w += v.w;
    }
    h.x *= 0.25f; h.y *= 0.25f; h.z *= 0.25f; h.w *= 0.25f;
    float4 wq = *(const float4*)&Wq[c0];
    float4 wk = *(const float4*)&Wk[c0];
    float4 wv = *(const float4*)&Wv[c0];
    float4 ws = *(const float4*)&Ws[c0];
    float dq = h.x * wq.x + h.y * wq.y + h.z * wq.z + h.w * wq.w;
    float dk = h.x * wk.x + h.y * wk.y + h.z * wk.z + h.w * wk.w;
    float dv = h.x * wv.x + h.y * wv.y + h.z * wv.z + h.w * wv.w;
    float ds = h.x * ws.x + h.y * ws.y + h.z * ws.z + h.w * ws.w;
#pragma unroll
    for (int o = 16; o; o >>= 1) {
        dq += __shfl_xor_sync(0xffffffffu, dq, o);
        dk += __shfl_xor_sync(0xffffffffu, dk, o);
        dv += __shfl_xor_sync(0xffffffffu, dv, o);
        ds += __shfl_xor_sync(0xffffffffu, ds, o);
    }
    if (lane == 0) {
        oq[w]  = dq + bq[0];
        ok[w]  = dk + bk[0];
        ov[w]  = dv + bv[0];
        osk[w] = ds + bs[0];
    }
}

__global__ void k_out_edge(const int* __restrict__ rowptr,
                           const int* __restrict__ esrc, const float* __restrict__ eas,
                           const float* __restrict__ We,
                           const float* __restrict__ oq, const float* __restrict__ ok,
                           const float* __restrict__ ov, const float* __restrict__ osk,
                           float* __restrict__ out) {
    int n = blockIdx.x * blockDim.x + threadIdx.x;
    if (n >= NN) return;
    float q = oq[n];
    float we = We[0];
    float m = -CUDART_INF_F, s = 0.f, acc = 0.f;
    int beg = rowptr[n], end = rowptr[n + 1];
    for (int i = beg; i < end; i++) {
        int sn = esrc[i];
        float et = eas[i] * we;
        float alpha = q * (ok[sn] + et);
        float mn = fmaxf(m, alpha);
        float corr = __expf(m - mn);
        float p = __expf(alpha - mn);
        s = s * corr + p;
        acc = acc * corr + p * (ov[sn] + et);
        m = mn;
    }
    out[n] = acc / (s + 1e-16f) + osk[n];
}

// =================================== host side ====================================
extern "C" void kernel_launch(void* const* d_in, const int* in_sizes, int n_in,
                              void* d_out, int out_size) {
    const float* x_seq = nullptr;
    const int*   ei    = nullptr;
    const float* ea    = nullptr;
    const float* P[22];
    int r = 0;
    for (int i = 0; i < n_in; i++) {
        if      (in_sizes[i] == TT * NN * IN_DIM) x_seq = (const float*)d_in[i];
        else if (in_sizes[i] == TT * 2 * EE)      ei    = (const int*)d_in[i];
        else if (in_sizes[i] == TT * EE)          ea    = (const float*)d_in[i];
        else if (r < 22)                          P[r++] = (const float*)d_in[i];
    }
    const float* gW_ih = P[0];
    const float* gW_hh = P[1];
    const float* gb_ih = P[2];
    const float* gb_hh = P[3];
    const float* cWq   = P[4];
    const float* cbq   = P[5];
    const float* cWk   = P[6];
    const float* cbk   = P[7];
    const float* cWv   = P[8];
    const float* cbv   = P[9];
    const float* cWe   = P[10];
    const float* cWs   = P[11];
    const float* cbs   = P[12];
    const float* oWq   = P[13];
    const float* obq   = P[14];
    const float* oWk   = P[15];
    const float* obk   = P[16];
    const float* oWv   = P[17];
    const float* obv   = P[18];
    const float* oWe   = P[19];
    const float* oWs   = P[20];
    const float* obs   = P[21];

    float *GI, *GH, *H, *HA2, *QKf, *BPK;
    __half *QKh;
    __half *Xh, *Xl, *Hh, *Hl, *HAh, *HAl;
    __half *WIH, *WHH, *WP;
    float *OQ, *OKp, *OV, *OSK, *EAS;
    int *RP, *ESRC, *CNT, *CUR;
    cudaGetSymbolAddress((void**)&GI,   g_GI);
    cudaGetSymbolAddress((void**)&GH,   g_GH);
    cudaGetSymbolAddress((void**)&H,    g_H);
    cudaGetSymbolAddress((void**)&HA2,  g_HA2);
    cudaGetSymbolAddress((void**)&QKf,  g_QKf);
    cudaGetSymbolAddress((void**)&QKh,  g_QKh);
    cudaGetSymbolAddress((void**)&Xh,   g_Xh);
    cudaGetSymbolAddress((void**)&Xl,   g_Xl);
    cudaGetSymbolAddress((void**)&Hh,   g_Hh);
    cudaGetSymbolAddress((void**)&Hl,   g_Hl);
    cudaGetSymbolAddress((void**)&HAh,  g_HAh);
    cudaGetSymbolAddress((void**)&HAl,  g_HAl);
    cudaGetSymbolAddress((void**)&WIH,  g_WIH);
    cudaGetSymbolAddress((void**)&WHH,  g_WHH);
    cudaGetSymbolAddress((void**)&WP,   g_WPK);
    cudaGetSymbolAddress((void**)&BPK,  g_BPK);
    cudaGetSymbolAddress((void**)&OQ,   g_OQ);
    cudaGetSymbolAddress((void**)&OKp,  g_OKs);
    cudaGetSymbolAddress((void**)&OV,   g_OV);
    cudaGetSymbolAddress((void**)&OSK,  g_OSK);
    cudaGetSymbolAddress((void**)&RP,   g_RP);
    cudaGetSymbolAddress((void**)&ESRC, g_ESRC);
    cudaGetSymbolAddress((void**)&EAS,  g_EAS);
    cudaGetSymbolAddress((void**)&CNT,  g_CNT);
    cudaGetSymbolAddress((void**)&CUR,  g_CUR);

    const int SMEM = NSTG * STG_BYTES;  // 72KB
    cudaFuncSetAttribute(k_pgemm, cudaFuncAttributeMaxDynamicSharedMemorySize, SMEM);

    const int TPB = 256;

    // 1..3: prep (GI GEMM stays the 4th launch for ncu's capture window)
    k_split_x<<<(TT * NN * IN_DIM + TPB - 1) / TPB, TPB>>>(x_seq, Xh, Xl);
    k_prep_gru<<<(G3 * IN_DIM + G3 * DD + TPB - 1) / TPB, TPB>>>(gW_ih, gW_hh, WIH, WHH);
    k_prep_conv<<<(2 * QKVS * DD + TPB - 1) / TPB, TPB>>>(cWq, cWk, cWv, cWs, cbq, cbk, cbv, cbs, WP, BPK);

    // 4: GI = X @ W_ih^T + b_ih for all T at once: [80000,64] @ [64,384]
    k_pgemm<<<dim3(G3 / 128, (TT * NN + 127) / 128), 256, SMEM>>>(
        Xh, Xl, WIH, gb_ih, GI, nullptr, nullptr, TT * NN, G3, IN_DIM);

    // CSR build (direct (src, attr) records, sorted by dst)
    k_zero_i<<<(TT * NN + TPB - 1) / TPB, TPB>>>(CNT, TT * NN);
    k_hist<<<(TT * EE + TPB - 1) / TPB, TPB>>>(ei, CNT);
    k_scan<<<TT, 1024>>>(CNT, RP, CUR);
    k_scatter<<<(TT * EE + TPB - 1) / TPB, TPB>>>(ei, ea, CUR, ESRC, EAS);

    // ---- GRU over time: sequential chain, per-t Hh/Hl stored batched ----
    for (int t = 0; t < TT; t++) {
        if (t > 0) {
            k_pgemm<<<dim3(G3 / 128, (NN + 127) / 128), 256, SMEM>>>(
                Hh + (size_t)(t - 1) * NN * DD, Hl + (size_t)(t - 1) * NN * DD,
                WHH, gb_hh, GH, nullptr, nullptr, NN, G3, DD);
        }
        k_gru_gate<<<(NN * DD + TPB - 1) / TPB, TPB>>>(
            GI + (size_t)t * NN * G3, GH, gb_hh, H,
            Hh + (size_t)t * NN * DD, Hl + (size_t)t * NN * DD, t == 0 ? 1 : 0);
    }

    // ---- layer 0: ONE batched qkvs GEMM (split f32/fp16 out), ONE conv launch ----
    k_pgemm<<<dim3(QKVS / 128, (TT * NN + 127) / 128), 256, SMEM>>>(
        Hh, Hl, WP, BPK, nullptr, QKf, QKh, TT * NN, QKVS, DD);
    k_conv_all<<<TT * NN / 8, 256>>>(QKf, QKh, RP, ESRC, EAS, cWe, nullptr, HAh, HAl, 0);

    // ---- layer 1: ONE batched qkvs GEMM, ONE conv launch (f32 out) ----
    k_pgemm<<<dim3(QKVS / 128, (TT * NN + 127) / 128), 256, SMEM>>>(
        HAh, HAl, WP + QKVS * DD, BPK + QKVS, nullptr, QKf, QKh, TT * NN, QKVS, DD);
    k_conv_all<<<TT * NN / 8, 256>>>(QKf, QKh, RP, ESRC, EAS, cWe + DD, HA2, nullptr, nullptr, 1);

    // ---- output conv (edges of last timestep) ----
    k_out_node<<<NN / 8, 256>>>(HA2, oWq, obq, oWk, obk, oWv, obv, oWs, obs, OQ, OKp, OV, OSK);
    k_out_edge<<<(NN + TPB - 1) / TPB, TPB>>>(RP + (TT - 1) * (NN + 1),
                                              ESRC + (size_t)(TT - 1) * EE, EAS + (size_t)(TT - 1) * EE,
                                              oWe, OQ, OKp, OV, OSK, (float*)d_out);
}

// round 11
// speedup vs baseline: 2.8089x; 1.1102x over previous
#include <cuda_runtime.h>
#include <cuda_fp16.h>
#include <math_constants.h>
#include <cstdint>

#define TT 4
#define NN 20000
#define EE 160000
#define IN_DIM 64
#define DD 128
#define G3 384   // 3*D
#define QKVS 512 // q|k|v|skip packed

// ------------------- static device scratch (no runtime allocs) -------------------
__device__ float g_GI[(size_t)TT * NN * G3];
__device__ float g_GH[(size_t)NN * G3];
__device__ float g_H [(size_t)NN * DD];
__device__ float g_HA2[(size_t)TT * NN * DD];           // layer-1 conv outputs (f32, per t)
__device__ float  g_QKf[(size_t)TT * NN * 256];         // q|skip per node (f32)
__device__ __half g_QKh[(size_t)TT * NN * 256];         // k|v per node (fp16)
// activations fp16 (batched over t)
__device__ __half g_X [(size_t)TT * NN * IN_DIM];
__device__ __half g_Hf[(size_t)TT * NN * DD];
__device__ __half g_HA[(size_t)TT * NN * DD];
// weights fp16, [N][K] layout
__device__ __half g_WIH[G3 * IN_DIM];
__device__ __half g_WHH[G3 * DD];
__device__ __half g_WPK[2 * QKVS * DD];
__device__ float g_BPK[2 * QKVS];
__device__ float g_OQ[NN], g_OKs[NN], g_OV[NN], g_OSK[NN];
__device__ int   g_RP [TT * (NN + 1)];
__device__ int   g_ESRC[TT * EE];     // src node id, sorted by dst (CSR order)
__device__ float g_EAS [TT * EE];     // edge attr, sorted by dst (CSR order)
__device__ int   g_CNT[TT * NN];
__device__ int   g_CUR[TT * NN];

// ------------------------------- small utility kernels ---------------------------
__global__ void k_zero_i(int* p, int n) {
    int i = blockIdx.x * blockDim.x + threadIdx.x;
    if (i < n) p[i] = 0;
}

__global__ void k_split_x(const float* __restrict__ x, __half* __restrict__ xh) {
    int i = blockIdx.x * blockDim.x + threadIdx.x;
    if (i < TT * NN * IN_DIM) xh[i] = __float2half_rn(x[i]);
}

// GRU weights: W_ih [384,64] and W_hh [384,128] are natively [N,K].
__global__ void k_prep_gru(const float* __restrict__ Wih, const float* __restrict__ Whh,
                           __half* __restrict__ a, __half* __restrict__ b) {
    int i = blockIdx.x * blockDim.x + threadIdx.x;
    if (i < G3 * IN_DIM) a[i] = __float2half_rn(Wih[i]);
    int j = i - G3 * IN_DIM;
    if (j >= 0 && j < G3 * DD) b[j] = __float2half_rn(Whh[j]);
}

// Pack conv weights transposed into [layer][n(512)][k(128)] fp16 + bias pack
__global__ void k_prep_conv(const float* __restrict__ Wq, const float* __restrict__ Wk,
                            const float* __restrict__ Wv, const float* __restrict__ Ws,
                            const float* __restrict__ bq, const float* __restrict__ bk,
                            const float* __restrict__ bv, const float* __restrict__ bs,
                            __half* __restrict__ WP, float* __restrict__ BP) {
    int i = blockIdx.x * blockDim.x + threadIdx.x;
    if (i < 2 * QKVS * DD) {
        int l = i >> 16;
        int rem = i & 65535;
        int n = rem >> 7, k = rem & 127;
        int base = l * DD * DD + k * DD;
        float v;
        if      (n < 128) v = Wq[base + n];
        else if (n < 256) v = Wk[base + n - 128];
        else if (n < 384) v = Wv[base + n - 256];
        else              v = Ws[base + n - 384];
        WP[i] = __float2half_rn(v);
    }
    if (i < 2 * QKVS) {
        int l = i >> 9, c = i & 511;
        int b2 = l * DD;
        float v;
        if      (c < 128) v = bq[b2 + c];
        else if (c < 256) v = bk[b2 + c - 128];
        else if (c < 384) v = bv[b2 + c - 256];
        else              v = bs[b2 + c - 384];
        BP[i] = v;
    }
}

// ------------------------------- CSR build ---------------------------------------
__global__ void k_hist(const int* __restrict__ ei, int* __restrict__ cnt) {
    int i = blockIdx.x * blockDim.x + threadIdx.x;
    if (i >= TT * EE) return;
    int t = i / EE, e = i % EE;
    int dst = ei[(size_t)t * 2 * EE + EE + e];
    atomicAdd(&cnt[t * NN + dst], 1);
}

__global__ void k_scan(const int* __restrict__ cnt, int* __restrict__ rowptr, int* __restrict__ cur) {
    int t = blockIdx.x;
    __shared__ int sh[1024];
    const int* c = cnt + t * NN;
    int* rp = rowptr + t * (NN + 1);
    int* cu = cur + t * NN;
    int carry = 0;
    for (int base = 0; base < NN; base += 1024) {
        int idx = base + threadIdx.x;
        int v = (idx < NN) ? c[idx] : 0;
        sh[threadIdx.x] = v;
        __syncthreads();
        for (int off = 1; off < 1024; off <<= 1) {
            int tval = (threadIdx.x >= off) ? sh[threadIdx.x - off] : 0;
            __syncthreads();
            sh[threadIdx.x] += tval;
            __syncthreads();
        }
        int excl = sh[threadIdx.x] - v;
        if (idx < NN) { rp[idx] = carry + excl; cu[idx] = carry + excl; }
        carry += sh[1023];
        __syncthreads();
    }
    if (threadIdx.x == 0) rp[NN] = carry;
}

// scatter edge records (src, attr) sorted by dst — removes indirections in conv
__global__ void k_scatter(const int* __restrict__ ei, const float* __restrict__ ea,
                          int* __restrict__ cur,
                          int* __restrict__ esrc, float* __restrict__ eas) {
    int i = blockIdx.x * blockDim.x + threadIdx.x;
    if (i >= TT * EE) return;
    int t = i / EE, e = i % EE;
    int src = ei[(size_t)t * 2 * EE + e];
    int dst = ei[(size_t)t * 2 * EE + EE + e];
    int p = atomicAdd(&cur[t * NN + dst], 1);
    esrc[(size_t)t * EE + p] = src;
    eas [(size_t)t * EE + p] = ea[(size_t)t * EE + e];
}

// ==== pipelined fp16 HMMA GEMM: 3-stage cp.async + ldmatrix, single pass ==========
// C = A @ B^T + bias, both fp16 [rows][K].
// Plain mode (Qh==null): f32 C [M, Nc].
// Conv mode (Qh!=null): col-block routed: q(blk0),skip(blk3) -> Qf f32 [M,256];
//                       k(blk1),v(blk2) -> Qh fp16 [M,256].
#define KC 32
#define NSTG 3
#define STG_WORDS (128 * 16)   // words per array per stage (128 rows x 32 fp16)
#define STG_BYTES (2 * STG_WORDS * 4)

__device__ __forceinline__ void mma_f16(float c[4], const uint32_t a[4],
                                        uint32_t b0, uint32_t b1) {
    asm volatile(
        "mma.sync.aligned.m16n8k16.row.col.f32.f16.f16.f32 "
        "{%0,%1,%2,%3}, {%4,%5,%6,%7}, {%8,%9}, {%0,%1,%2,%3};"
        : "+f"(c[0]), "+f"(c[1]), "+f"(c[2]), "+f"(c[3])
        : "r"(a[0]), "r"(a[1]), "r"(a[2]), "r"(a[3]), "r"(b0), "r"(b1));
}

__device__ __forceinline__ void ldsm_x4(uint32_t addr, uint32_t& r0, uint32_t& r1,
                                        uint32_t& r2, uint32_t& r3) {
    asm volatile("ldmatrix.sync.aligned.m8n8.x4.shared.b16 {%0,%1,%2,%3}, [%4];"
                 : "=r"(r0), "=r"(r1), "=r"(r2), "=r"(r3) : "r"(addr));
}

__global__ void __launch_bounds__(256, 2) k_pgemm(
    const __half* __restrict__ A, const __half* __restrict__ B,
    const float* __restrict__ bias, float* __restrict__ C,
    float* __restrict__ Qf, __half* __restrict__ Qh,
    int M, int Nc, int K) {
    extern __shared__ uint32_t smw[];   // NSTG stages x 2 arrays x STG_WORDS = 48KB

    int tid = threadIdx.x, wid = tid >> 5, lane = tid & 31;
    int gid = lane >> 2, t4 = lane & 3;
    int rowBase = blockIdx.y * 128;
    int colBase = blockIdx.x * 128;
    int warpRow = (wid & 3) * 32;
    int warpCol = (wid >> 2) * 64;

    float acc[2][8][4];
#pragma unroll
    for (int mt = 0; mt < 2; mt++)
#pragma unroll
        for (int nt = 0; nt < 8; nt++)
#pragma unroll
            for (int q = 0; q < 4; q++) acc[mt][nt][q] = 0.f;

    uint32_t sm0;
    asm("{ .reg .u64 t; cvta.to.shared.u64 t, %1; cvt.u32.u64 %0, t; }"
        : "=r"(sm0) : "l"(smw));

    const __half* srcs[2] = {A, B};

    int lm_m = lane >> 3;
    int lm_r = lane & 7;
    int a_row0 = warpRow + ((lm_m & 1) << 3) + lm_r;
    int a_kh   = lm_m >> 1;
    int b_row0 = warpCol + ((lm_m >> 1) << 3) + lm_r;
    int b_kh   = lm_m & 1;

    auto fill = [&](int stage, int k0) {
        uint32_t sb = sm0 + (uint32_t)stage * STG_BYTES;
#pragma unroll
        for (int it = 0; it < 4; it++) {
            int idx = tid + it * 256;          // 1024 16B-chunks total
            int arr = idx >> 9;
            int rem = idx & 511;
            int r = rem >> 2, c = rem & 3;
            int grow = (arr == 0) ? (rowBase + r) : (colBase + r);
            int valid = (arr == 1) || (grow < M);
            const __half* src = srcs[arr] + (valid ? ((size_t)grow * K + k0 + c * 8) : 0);
            int sz = valid ? 16 : 0;
            uint32_t dst = sb + (uint32_t)(arr * STG_WORDS + (r << 4) + ((c ^ ((r >> 1) & 3)) << 2)) * 4;
            asm volatile("cp.async.cg.shared.global [%0], [%1], 16, %2;"
                         :: "r"(dst), "l"(src), "r"(sz));
        }
        asm volatile("cp.async.commit_group;");
    };

    int nch = K / KC;
    fill(0, 0);
    if (nch > 1) fill(1, KC);

    for (int ch = 0; ch < nch; ch++) {
        if (ch + 2 <= nch) { asm volatile("cp.async.wait_group 1;"); }
        else               { asm volatile("cp.async.wait_group 0;"); }
        __syncthreads();

        if (ch + 2 < nch) fill((ch + 2) % NSTG, (ch + 2) * KC);

        uint32_t st = sm0 + (uint32_t)(ch % NSTG) * STG_BYTES;
        uint32_t pA = st;
        uint32_t pB = st + STG_WORDS * 4;

#pragma unroll
        for (int ks = 0; ks < KC; ks += 16) {
            uint32_t ah[2][4];
            int ach = (ks >> 3) + a_kh;
#pragma unroll
            for (int mt = 0; mt < 2; mt++) {
                int ar = a_row0 + mt * 16;
                uint32_t aoff = (uint32_t)(ar << 6) + (uint32_t)((ach ^ ((ar >> 1) & 3)) << 4);
                ldsm_x4(pA + aoff, ah[mt][0], ah[mt][1], ah[mt][2], ah[mt][3]);
            }
            int bch = (ks >> 3) + b_kh;
#pragma unroll
            for (int pp = 0; pp < 2; pp++) {
                uint32_t bh[2][4];
#pragma unroll
                for (int pi = 0; pi < 2; pi++) {
                    int br = b_row0 + (2 * pp + pi) * 16;
                    uint32_t boff = (uint32_t)(br << 6) + (uint32_t)((bch ^ ((br >> 1) & 3)) << 4);
                    ldsm_x4(pB + boff, bh[pi][0], bh[pi][1], bh[pi][2], bh[pi][3]);
                }
#pragma unroll
                for (int pi = 0; pi < 2; pi++) {
                    int n0 = (2 * pp + pi) * 2, n1 = n0 + 1;
                    mma_f16(acc[0][n0], ah[0], bh[pi][0], bh[pi][1]);
                    mma_f16(acc[0][n1], ah[0], bh[pi][2], bh[pi][3]);
                    mma_f16(acc[1][n0], ah[1], bh[pi][0], bh[pi][1]);
                    mma_f16(acc[1][n1], ah[1], bh[pi][2], bh[pi][3]);
                }
            }
        }
    }

    // ---- epilogue ----
    int cb = blockIdx.x;   // 0=q 1=k 2=v 3=skip in conv mode
#pragma unroll
    for (int mt = 0; mt < 2; mt++) {
        int rows[2] = {rowBase + warpRow + mt * 16 + gid, rowBase + warpRow + mt * 16 + gid + 8};
#pragma unroll
        for (int nt = 0; nt < 8; nt++) {
            int lcol = warpCol + nt * 8 + t4 * 2;
            int col = colBase + lcol;
            float b0 = bias[col], b1 = bias[col + 1];
#pragma unroll
            for (int rr = 0; rr < 2; rr++) {
                int rw = rows[rr];
                if (rw >= M) continue;
                float v0 = acc[mt][nt][rr * 2 + 0] + b0;
                float v1 = acc[mt][nt][rr * 2 + 1] + b1;
                if (!Qh) {
                    *(float2*)&C[(size_t)rw * Nc + col] = make_float2(v0, v1);
                } else if (cb == 0) {
                    *(float2*)&Qf[(size_t)rw * 256 + lcol] = make_float2(v0, v1);
                } else if (cb == 3) {
                    *(float2*)&Qf[(size_t)rw * 256 + 128 + lcol] = make_float2(v0, v1);
                } else {
                    // k -> Qh[0..127], v -> Qh[128..255]
                    __half2 hv = __floats2half2_rn(v0, v1);
                    *(__half2*)&Qh[(size_t)rw * 256 + (cb - 1) * 128 + lcol] = hv;
                }
            }
        }
    }
}

// ------------------------------- GRU gates ---------------------------------------
__global__ void k_gru_gate(const float* __restrict__ GI, const float* __restrict__ GH,
                           const float* __restrict__ bhh, float* __restrict__ H,
                           __half* __restrict__ Hh, int first) {
    int i = blockIdx.x * blockDim.x + threadIdx.x;
    if (i >= NN * DD) return;
    int n = i >> 7, j = i & 127;
    const float* gi = GI + (size_t)n * G3;
    float ir = gi[j], iz = gi[j + 128], in = gi[j + 256];
    float hr, hz, hn, hp;
    if (first) {
        hr = bhh[j]; hz = bhh[j + 128]; hn = bhh[j + 256];
        hp = 0.f;
    } else {
        const float* gh = GH + (size_t)n * G3;
        hr = gh[j]; hz = gh[j + 128]; hn = gh[j + 256];
        hp = H[i];
    }
    float r = 1.f / (1.f + __expf(-(ir + hr)));
    float z = 1.f / (1.f + __expf(-(iz + hz)));
    float nv = tanhf(in + r * hn);
    float h = (1.f - z) * nv + z * hp;
    H[i] = h;
    Hh[i] = __float2half_rn(h);
}

// -------------- TransformerConv edge attention, ALL timesteps in one launch ------
// q/skip read f32 from Qf, k/v gathered fp16 from Qh.
// mode 0: write fp16 (feeds next GEMM). mode 1: write f32 to out.
__global__ void k_conv_all(const float* __restrict__ QKf, const __half* __restrict__ QKh,
                           const int* __restrict__ RP,
                           const int* __restrict__ ESRC, const float* __restrict__ EAS,
                           const float* __restrict__ We, float* __restrict__ out,
                           __half* __restrict__ oh, int mode) {
    int gw = (blockIdx.x * blockDim.x + threadIdx.x) >> 5;
    if (gw >= TT * NN) return;
    int t = gw / NN;
    int w = gw - t * NN;
    const float* qf  = QKf + (size_t)t * NN * 256;
    const __half* qh = QKh + (size_t)t * NN * 256;
    const int* rowptr = RP + t * (NN + 1);
    const int* esrc   = ESRC + (size_t)t * EE;
    const float* eas  = EAS + (size_t)t * EE;

    int lane = threadIdx.x & 31;
    int c0 = lane * 4;
    float4 q  = *(const float4*)&qf[(size_t)w * 256 + c0];
    float4 sk = *(const float4*)&qf[(size_t)w * 256 + 128 + c0];
    float4 we = *(const float4*)&We[c0];
    float m = -CUDART_INF_F, s = 0.f;
    float4 acc = make_float4(0.f, 0.f, 0.f, 0.f);
    int beg = rowptr[w], end = rowptr[w + 1];

    uint2 kraw = make_uint2(0, 0), vraw = make_uint2(0, 0);
    float eaV = 0.f;
    if (beg < end) {
        int sn = esrc[beg];
        eaV = eas[beg];
        kraw = *(const uint2*)&qh[(size_t)sn * 256 + c0];
        vraw = *(const uint2*)&qh[(size_t)sn * 256 + 128 + c0];
    }
    for (int i = beg; i < end; i++) {
        uint2 ck = kraw, cv = vraw;
        float cea = eaV;
        if (i + 1 < end) {       // prefetch next edge's gather before reduction chain
            int sn = esrc[i + 1];
            eaV = eas[i + 1];
            kraw = *(const uint2*)&qh[(size_t)sn * 256 + c0];
            vraw = *(const uint2*)&qh[(size_t)sn * 256 + 128 + c0];
        }
        float2 k01 = __half22float2(*(const __half2*)&ck.x);
        float2 k23 = __half22float2(*(const __half2*)&ck.y);
        float2 v01 = __half22float2(*(const __half2*)&cv.x);
        float2 v23 = __half22float2(*(const __half2*)&cv.y);
        float ex = cea * we.x, ey = cea * we.y, ez = cea * we.z, ew = cea * we.w;
        float part = q.x * (k01.x + ex) + q.y * (k01.y + ey)
                   + q.z * (k23.x + ez) + q.w * (k23.y + ew);
#pragma unroll
        for (int o = 16; o; o >>= 1) part += __shfl_xor_sync(0xffffffffu, part, o);
        float alpha = part * 0.08838834764831845f; // 1/sqrt(128)
        float mn = fmaxf(m, alpha);
        float corr = __expf(m - mn);
        float p = __expf(alpha - mn);
        s = s * corr + p;
        acc.x = acc.x * corr + p * (v01.x + ex);
        acc.y = acc.y * corr + p * (v01.y + ey);
        acc.z = acc.z * corr + p * (v23.x + ez);
        acc.w = acc.w * corr + p * (v23.y + ew);
        m = mn;
    }
    float inv = 1.f / (s + 1e-16f);
    float4 o;
    o.x = acc.x * inv + sk.x;
    o.y = acc.y * inv + sk.y;
    o.z = acc.z * inv + sk.z;
    o.w = acc.w * inv + sk.w;
    o.x = o.x > 0.f ? o.x : 0.01f * o.x;
    o.y = o.y > 0.f ? o.y : 0.01f * o.y;
    o.z = o.z > 0.f ? o.z : 0.01f * o.z;
    o.w = o.w > 0.f ? o.w : 0.01f * o.w;
    size_t oidx = (size_t)t * NN * DD + (size_t)w * DD + c0;
    if (mode) {
        *(float4*)&out[oidx] = o;
    } else {
        __half hv[4];
        hv[0] = __float2half_rn(o.x);
        hv[1] = __float2half_rn(o.y);
        hv[2] = __float2half_rn(o.z);
        hv[3] = __float2half_rn(o.w);
        *(uint2*)&oh[oidx] = *(uint2*)hv;
    }
}

// ------------------------ output conv (D -> 1) -----------------------------------
__global__ void k_out_node(const float* __restrict__ ha2,
                           const float* __restrict__ Wq, const float* __restrict__ bq,
                           const float* __restrict__ Wk, const float* __restrict__ bk,
                           const float* __restrict__ Wv, const float* __restrict__ bv,
                           const float* __restrict__ Ws, const float* __restrict__ bs,
                           float* __restrict__ oq, float* __restrict__ ok,
                           float* __restrict__ ov, float* __restrict__ osk) {
    int w = (blockIdx.x * blockDim.x + threadIdx.x) >> 5;
    if (w >= NN) return;
    int lane = threadIdx.x & 31;
    int c0 = lane * 4;
    float4 h = make_float4(0.f, 0.f, 0.f, 0.f);
#pragma unroll
    for (int t = 0; t < TT; t++) {
        float4 v = *(const float4*)&ha2[(size_t)t * NN * DD + (size_t)w * DD + c0];
        h.x += v.x; h.y += v.y; h.z += v.z; h.w += v.w;
    }
    h.x *= 0.25f; h.y *= 0.25f; h.z *= 0.25f; h.w *= 0.25f;
    float4 wq = *(const float4*)&Wq[c0];
    float4 wk = *(const float4*)&Wk[c0];
    float4 wv = *(const float4*)&Wv[c0];
    float4 ws = *(const float4*)&Ws[c0];
    float dq = h.x * wq.x + h.y * wq.y + h.z * wq.z + h.w * wq.w;
    float dk = h.x * wk.x + h.y * wk.y + h.z * wk.z + h.w * wk.w;
    float dv = h.x * wv.x + h.y * wv.y + h.z * wv.z + h.w * wv.w;
    float ds = h.x * ws.x + h.y * ws.y + h.z * ws.z + h.w * ws.w;
#pragma unroll
    for (int o = 16; o; o >>= 1) {
        dq += __shfl_xor_sync(0xffffffffu, dq, o);
        dk += __shfl_xor_sync(0xffffffffu, dk, o);
        dv += __shfl_xor_sync(0xffffffffu, dv, o);
        ds += __shfl_xor_sync(0xffffffffu, ds, o);
    }
    if (lane == 0) {
        oq[w]  = dq + bq[0];
        ok[w]  = dk + bk[0];
        ov[w]  = dv + bv[0];
        osk[w] = ds + bs[0];
    }
}

__global__ void k_out_edge(const int* __restrict__ rowptr,
                           const int* __restrict__ esrc, const float* __restrict__ eas,
                           const float* __restrict__ We,
                           const float* __restrict__ oq, const float* __restrict__ ok,
                           const float* __restrict__ ov, const float* __restrict__ osk,
                           float* __restrict__ out) {
    int n = blockIdx.x * blockDim.x + threadIdx.x;
    if (n >= NN) return;
    float q = oq[n];
    float we = We[0];
    float m = -CUDART_INF_F, s = 0.f, acc = 0.f;
    int beg = rowptr[n], end = rowptr[n + 1];
    for (int i = beg; i < end; i++) {
        int sn = esrc[i];
        float et = eas[i] * we;
        float alpha = q * (ok[sn] + et);
        float mn = fmaxf(m, alpha);
        float corr = __expf(m - mn);
        float p = __expf(alpha - mn);
        s = s * corr + p;
        acc = acc * corr + p * (ov[sn] + et);
        m = mn;
    }
    out[n] = acc / (s + 1e-16f) + osk[n];
}

// =================================== host side ====================================
extern "C" void kernel_launch(void* const* d_in, const int* in_sizes, int n_in,
                              void* d_out, int out_size) {
    const float* x_seq = nullptr;
    const int*   ei    = nullptr;
    const float* ea    = nullptr;
    const float* P[22];
    int r = 0;
    for (int i = 0; i < n_in; i++) {
        if      (in_sizes[i] == TT * NN * IN_DIM) x_seq = (const float*)d_in[i];
        else if (in_sizes[i] == TT * 2 * EE)      ei    = (const int*)d_in[i];
        else if (in_sizes[i] == TT * EE)          ea    = (const float*)d_in[i];
        else if (r < 22)                          P[r++] = (const float*)d_in[i];
    }
    const float* gW_ih = P[0];
    const float* gW_hh = P[1];
    const float* gb_ih = P[2];
    const float* gb_hh = P[3];
    const float* cWq   = P[4];
    const float* cbq   = P[5];
    const float* cWk   = P[6];
    const float* cbk   = P[7];
    const float* cWv   = P[8];
    const float* cbv   = P[9];
    const float* cWe   = P[10];
    const float* cWs   = P[11];
    const float* cbs   = P[12];
    const float* oWq   = P[13];
    const float* obq   = P[14];
    const float* oWk   = P[15];
    const float* obk   = P[16];
    const float* oWv   = P[17];
    const float* obv   = P[18];
    const float* oWe   = P[19];
    const float* oWs   = P[20];
    const float* obs   = P[21];

    float *GI, *GH, *H, *HA2, *QKf, *BPK;
    __half *QKh, *X, *Hf, *HA, *WIH, *WHH, *WP;
    float *OQ, *OKp, *OV, *OSK, *EAS;
    int *RP, *ESRC, *CNT, *CUR;
    cudaGetSymbolAddress((void**)&GI,   g_GI);
    cudaGetSymbolAddress((void**)&GH,   g_GH);
    cudaGetSymbolAddress((void**)&H,    g_H);
    cudaGetSymbolAddress((void**)&HA2,  g_HA2);
    cudaGetSymbolAddress((void**)&QKf,  g_QKf);
    cudaGetSymbolAddress((void**)&QKh,  g_QKh);
    cudaGetSymbolAddress((void**)&X,    g_X);
    cudaGetSymbolAddress((void**)&Hf,   g_Hf);
    cudaGetSymbolAddress((void**)&HA,   g_HA);
    cudaGetSymbolAddress((void**)&WIH,  g_WIH);
    cudaGetSymbolAddress((void**)&WHH,  g_WHH);
    cudaGetSymbolAddress((void**)&WP,   g_WPK);
    cudaGetSymbolAddress((void**)&BPK,  g_BPK);
    cudaGetSymbolAddress((void**)&OQ,   g_OQ);
    cudaGetSymbolAddress((void**)&OKp,  g_OKs);
    cudaGetSymbolAddress((void**)&OV,   g_OV);
    cudaGetSymbolAddress((void**)&OSK,  g_OSK);
    cudaGetSymbolAddress((void**)&RP,   g_RP);
    cudaGetSymbolAddress((void**)&ESRC, g_ESRC);
    cudaGetSymbolAddress((void**)&EAS,  g_EAS);
    cudaGetSymbolAddress((void**)&CNT,  g_CNT);
    cudaGetSymbolAddress((void**)&CUR,  g_CUR);

    const int SMEM = NSTG * STG_BYTES;  // 48KB
    cudaFuncSetAttribute(k_pgemm, cudaFuncAttributeMaxDynamicSharedMemorySize, SMEM);

    const int TPB = 256;

    // 1..3: prep (GI GEMM stays the 4th launch for ncu's capture window)
    k_split_x<<<(TT * NN * IN_DIM + TPB - 1) / TPB, TPB>>>(x_seq, X);
    k_prep_gru<<<(G3 * IN_DIM + G3 * DD + TPB - 1) / TPB, TPB>>>(gW_ih, gW_hh, WIH, WHH);
    k_prep_conv<<<(2 * QKVS * DD + TPB - 1) / TPB, TPB>>>(cWq, cWk, cWv, cWs, cbq, cbk, cbv, cbs, WP, BPK);

    // 4: GI = X @ W_ih^T + b_ih for all T at once: [80000,64] @ [64,384]
    k_pgemm<<<dim3(G3 / 128, (TT * NN + 127) / 128), 256, SMEM>>>(
        X, WIH, gb_ih, GI, nullptr, nullptr, TT * NN, G3, IN_DIM);

    // CSR build (direct (src, attr) records, sorted by dst)
    k_zero_i<<<(TT * NN + TPB - 1) / TPB, TPB>>>(CNT, TT * NN);
    k_hist<<<(TT * EE + TPB - 1) / TPB, TPB>>>(ei, CNT);
    k_scan<<<TT, 1024>>>(CNT, RP, CUR);
    k_scatter<<<(TT * EE + TPB - 1) / TPB, TPB>>>(ei, ea, CUR, ESRC, EAS);

    // ---- GRU over time: sequential chain, per-t H stored batched ----
    for (int t = 0; t < TT; t++) {
        if (t > 0) {
            k_pgemm<<<dim3(G3 / 128, (NN + 127) / 128), 256, SMEM>>>(
                Hf + (size_t)(t - 1) * NN * DD, WHH, gb_hh, GH,
                nullptr, nullptr, NN, G3, DD);
        }
        k_gru_gate<<<(NN * DD + TPB - 1) / TPB, TPB>>>(
            GI + (size_t)t * NN * G3, GH, gb_hh, H,
            Hf + (size_t)t * NN * DD, t == 0 ? 1 : 0);
    }

    // ---- layer 0: ONE batched qkvs GEMM (split f32/fp16 out), ONE conv launch ----
    k_pgemm<<<dim3(QKVS / 128, (TT * NN + 127) / 128), 256, SMEM>>>(
        Hf, WP, BPK, nullptr, QKf, QKh, TT * NN, QKVS, DD);
    k_conv_all<<<TT * NN / 8, 256>>>(QKf, QKh, RP, ESRC, EAS, cWe, nullptr, HA, 0);

    // ---- layer 1: ONE batched qkvs GEMM, ONE conv launch (f32 out) ----
    k_pgemm<<<dim3(QKVS / 128, (TT * NN + 127) / 128), 256, SMEM>>>(
        HA, WP + QKVS * DD, BPK + QKVS, nullptr, QKf, QKh, TT * NN, QKVS, DD);
    k_conv_all<<<TT * NN / 8, 256>>>(QKf, QKh, RP, ESRC, EAS, cWe + DD, HA2, nullptr, 1);

    // ---- output conv (edges of last timestep) ----
    k_out_node<<<NN / 8, 256>>>(HA2, oWq, obq, oWk, obk, oWv, obv, oWs, obs, OQ, OKp, OV, OSK);
    k_out_edge<<<(NN + TPB - 1) / TPB, TPB>>>(RP + (TT - 1) * (NN + 1),
                                              ESRC + (size_t)(TT - 1) * EE, EAS + (size_t)(TT - 1) * EE,
                                              oWe, OQ, OKp, OV, OSK, (float*)d_out);
}

// round 12
// speedup vs baseline: 2.9898x; 1.0644x over previous
#include <cuda_runtime.h>
#include <cuda_fp16.h>
#include <math_constants.h>
#include <cstdint>

#define TT 4
#define NN 20000
#define EE 160000
#define IN_DIM 64
#define DD 128
#define G3 384   // 3*D
#define QKVS 512 // q|k|v|skip packed

// ------------------- static device scratch (no runtime allocs) -------------------
__device__ __half g_GI[(size_t)TT * NN * G3];          // gi, fp16
__device__ __half g_GH[(size_t)NN * G3];               // gh, fp16
__device__ float  g_H [(size_t)NN * DD];               // GRU hidden state (f32 carry)
__device__ __half g_HA2[(size_t)TT * NN * DD];         // layer-1 conv outputs (fp16, per t)
__device__ __half g_QK[(size_t)TT * NN * QKVS];        // q|k|v|skip per node (fp16)
// activations fp16 (batched over t)
__device__ __half g_X [(size_t)TT * NN * IN_DIM];
__device__ __half g_Hf[(size_t)TT * NN * DD];
__device__ __half g_HA[(size_t)TT * NN * DD];
// weights fp16, [N][K] layout
__device__ __half g_WIH[G3 * IN_DIM];
__device__ __half g_WHH[G3 * DD];
__device__ __half g_WPK[2 * QKVS * DD];
__device__ float g_BPK[2 * QKVS];
__device__ float g_OQ[NN], g_OKs[NN], g_OV[NN], g_OSK[NN];
__device__ int   g_RP [TT * (NN + 1)];
__device__ int   g_ESRC[TT * EE];     // src node id, sorted by dst (CSR order)
__device__ float g_EAS [TT * EE];     // edge attr, sorted by dst (CSR order)
__device__ int   g_CNT[TT * NN];
__device__ int   g_CUR[TT * NN];

// ------------------------------- small utility kernels ---------------------------
__global__ void k_zero_i(int* p, int n) {
    int i = blockIdx.x * blockDim.x + threadIdx.x;
    if (i < n) p[i] = 0;
}

__global__ void k_split_x(const float* __restrict__ x, __half* __restrict__ xh) {
    int i = blockIdx.x * blockDim.x + threadIdx.x;
    if (i < TT * NN * IN_DIM) xh[i] = __float2half_rn(x[i]);
}

// GRU weights: W_ih [384,64] and W_hh [384,128] are natively [N,K].
__global__ void k_prep_gru(const float* __restrict__ Wih, const float* __restrict__ Whh,
                           __half* __restrict__ a, __half* __restrict__ b) {
    int i = blockIdx.x * blockDim.x + threadIdx.x;
    if (i < G3 * IN_DIM) a[i] = __float2half_rn(Wih[i]);
    int j = i - G3 * IN_DIM;
    if (j >= 0 && j < G3 * DD) b[j] = __float2half_rn(Whh[j]);
}

// Pack conv weights transposed into [layer][n(512)][k(128)] fp16 + bias pack
__global__ void k_prep_conv(const float* __restrict__ Wq, const float* __restrict__ Wk,
                            const float* __restrict__ Wv, const float* __restrict__ Ws,
                            const float* __restrict__ bq, const float* __restrict__ bk,
                            const float* __restrict__ bv, const float* __restrict__ bs,
                            __half* __restrict__ WP, float* __restrict__ BP) {
    int i = blockIdx.x * blockDim.x + threadIdx.x;
    if (i < 2 * QKVS * DD) {
        int l = i >> 16;
        int rem = i & 65535;
        int n = rem >> 7, k = rem & 127;
        int base = l * DD * DD + k * DD;
        float v;
        if      (n < 128) v = Wq[base + n];
        else if (n < 256) v = Wk[base + n - 128];
        else if (n < 384) v = Wv[base + n - 256];
        else              v = Ws[base + n - 384];
        WP[i] = __float2half_rn(v);
    }
    if (i < 2 * QKVS) {
        int l = i >> 9, c = i & 511;
        int b2 = l * DD;
        float v;
        if      (c < 128) v = bq[b2 + c];
        else if (c < 256) v = bk[b2 + c - 128];
        else if (c < 384) v = bv[b2 + c - 256];
        else              v = bs[b2 + c - 384];
        BP[i] = v;
    }
}

// ------------------------------- CSR build ---------------------------------------
__global__ void k_hist(const int* __restrict__ ei, int* __restrict__ cnt) {
    int i = blockIdx.x * blockDim.x + threadIdx.x;
    if (i >= TT * EE) return;
    int t = i / EE, e = i % EE;
    int dst = ei[(size_t)t * 2 * EE + EE + e];
    atomicAdd(&cnt[t * NN + dst], 1);
}

__global__ void k_scan(const int* __restrict__ cnt, int* __restrict__ rowptr, int* __restrict__ cur) {
    int t = blockIdx.x;
    __shared__ int sh[1024];
    const int* c = cnt + t * NN;
    int* rp = rowptr + t * (NN + 1);
    int* cu = cur + t * NN;
    int carry = 0;
    for (int base = 0; base < NN; base += 1024) {
        int idx = base + threadIdx.x;
        int v = (idx < NN) ? c[idx] : 0;
        sh[threadIdx.x] = v;
        __syncthreads();
        for (int off = 1; off < 1024; off <<= 1) {
            int tval = (threadIdx.x >= off) ? sh[threadIdx.x - off] : 0;
            __syncthreads();
            sh[threadIdx.x] += tval;
            __syncthreads();
        }
        int excl = sh[threadIdx.x] - v;
        if (idx < NN) { rp[idx] = carry + excl; cu[idx] = carry + excl; }
        carry += sh[1023];
        __syncthreads();
    }
    if (threadIdx.x == 0) rp[NN] = carry;
}

// scatter edge records (src, attr) sorted by dst — removes indirections in conv
__global__ void k_scatter(const int* __restrict__ ei, const float* __restrict__ ea,
                          int* __restrict__ cur,
                          int* __restrict__ esrc, float* __restrict__ eas) {
    int i = blockIdx.x * blockDim.x + threadIdx.x;
    if (i >= TT * EE) return;
    int t = i / EE, e = i % EE;
    int src = ei[(size_t)t * 2 * EE + e];
    int dst = ei[(size_t)t * 2 * EE + EE + e];
    int p = atomicAdd(&cur[t * NN + dst], 1);
    esrc[(size_t)t * EE + p] = src;
    eas [(size_t)t * EE + p] = ea[(size_t)t * EE + e];
}

// ==== pipelined fp16 HMMA GEMM: 3-stage cp.async + ldmatrix, fp16 in, fp16 out ====
// C[M,Nc] (fp16) = A @ B^T + bias, A/B fp16 [rows][K].
#define KC 32
#define NSTG 3
#define STG_WORDS (128 * 16)   // words per array per stage (128 rows x 32 fp16)
#define STG_BYTES (2 * STG_WORDS * 4)

__device__ __forceinline__ void mma_f16(float c[4], const uint32_t a[4],
                                        uint32_t b0, uint32_t b1) {
    asm volatile(
        "mma.sync.aligned.m16n8k16.row.col.f32.f16.f16.f32 "
        "{%0,%1,%2,%3}, {%4,%5,%6,%7}, {%8,%9}, {%0,%1,%2,%3};"
        : "+f"(c[0]), "+f"(c[1]), "+f"(c[2]), "+f"(c[3])
        : "r"(a[0]), "r"(a[1]), "r"(a[2]), "r"(a[3]), "r"(b0), "r"(b1));
}

__device__ __forceinline__ void ldsm_x4(uint32_t addr, uint32_t& r0, uint32_t& r1,
                                        uint32_t& r2, uint32_t& r3) {
    asm volatile("ldmatrix.sync.aligned.m8n8.x4.shared.b16 {%0,%1,%2,%3}, [%4];"
                 : "=r"(r0), "=r"(r1), "=r"(r2), "=r"(r3) : "r"(addr));
}

__global__ void __launch_bounds__(256, 2) k_pgemm(
    const __half* __restrict__ A, const __half* __restrict__ B,
    const float* __restrict__ bias, __half* __restrict__ C,
    int M, int Nc, int K) {
    extern __shared__ uint32_t smw[];   // NSTG stages x 2 arrays x STG_WORDS = 48KB

    int tid = threadIdx.x, wid = tid >> 5, lane = tid & 31;
    int gid = lane >> 2, t4 = lane & 3;
    int rowBase = blockIdx.y * 128;
    int colBase = blockIdx.x * 128;
    int warpRow = (wid & 3) * 32;
    int warpCol = (wid >> 2) * 64;

    float acc[2][8][4];
#pragma unroll
    for (int mt = 0; mt < 2; mt++)
#pragma unroll
        for (int nt = 0; nt < 8; nt++)
#pragma unroll
            for (int q = 0; q < 4; q++) acc[mt][nt][q] = 0.f;

    uint32_t sm0;
    asm("{ .reg .u64 t; cvta.to.shared.u64 t, %1; cvt.u32.u64 %0, t; }"
        : "=r"(sm0) : "l"(smw));

    const __half* srcs[2] = {A, B};

    int lm_m = lane >> 3;
    int lm_r = lane & 7;
    int a_row0 = warpRow + ((lm_m & 1) << 3) + lm_r;
    int a_kh   = lm_m >> 1;
    int b_row0 = warpCol + ((lm_m >> 1) << 3) + lm_r;
    int b_kh   = lm_m & 1;

    auto fill = [&](int stage, int k0) {
        uint32_t sb = sm0 + (uint32_t)stage * STG_BYTES;
#pragma unroll
        for (int it = 0; it < 4; it++) {
            int idx = tid + it * 256;          // 1024 16B-chunks total
            int arr = idx >> 9;
            int rem = idx & 511;
            int r = rem >> 2, c = rem & 3;
            int grow = (arr == 0) ? (rowBase + r) : (colBase + r);
            int valid = (arr == 1) || (grow < M);
            const __half* src = srcs[arr] + (valid ? ((size_t)grow * K + k0 + c * 8) : 0);
            int sz = valid ? 16 : 0;
            uint32_t dst = sb + (uint32_t)(arr * STG_WORDS + (r << 4) + ((c ^ ((r >> 1) & 3)) << 2)) * 4;
            asm volatile("cp.async.cg.shared.global [%0], [%1], 16, %2;"
                         :: "r"(dst), "l"(src), "r"(sz));
        }
        asm volatile("cp.async.commit_group;");
    };

    int nch = K / KC;
    fill(0, 0);
    if (nch > 1) fill(1, KC);

    for (int ch = 0; ch < nch; ch++) {
        if (ch + 2 <= nch) { asm volatile("cp.async.wait_group 1;"); }
        else               { asm volatile("cp.async.wait_group 0;"); }
        __syncthreads();

        if (ch + 2 < nch) fill((ch + 2) % NSTG, (ch + 2) * KC);

        uint32_t st = sm0 + (uint32_t)(ch % NSTG) * STG_BYTES;
        uint32_t pA = st;
        uint32_t pB = st + STG_WORDS * 4;

#pragma unroll
        for (int ks = 0; ks < KC; ks += 16) {
            uint32_t ah[2][4];
            int ach = (ks >> 3) + a_kh;
#pragma unroll
            for (int mt = 0; mt < 2; mt++) {
                int ar = a_row0 + mt * 16;
                uint32_t aoff = (uint32_t)(ar << 6) + (uint32_t)((ach ^ ((ar >> 1) & 3)) << 4);
                ldsm_x4(pA + aoff, ah[mt][0], ah[mt][1], ah[mt][2], ah[mt][3]);
            }
            int bch = (ks >> 3) + b_kh;
#pragma unroll
            for (int pp = 0; pp < 2; pp++) {
                uint32_t bh[2][4];
#pragma unroll
                for (int pi = 0; pi < 2; pi++) {
                    int br = b_row0 + (2 * pp + pi) * 16;
                    uint32_t boff = (uint32_t)(br << 6) + (uint32_t)((bch ^ ((br >> 1) & 3)) << 4);
                    ldsm_x4(pB + boff, bh[pi][0], bh[pi][1], bh[pi][2], bh[pi][3]);
                }
#pragma unroll
                for (int pi = 0; pi < 2; pi++) {
                    int n0 = (2 * pp + pi) * 2, n1 = n0 + 1;
                    mma_f16(acc[0][n0], ah[0], bh[pi][0], bh[pi][1]);
                    mma_f16(acc[0][n1], ah[0], bh[pi][2], bh[pi][3]);
                    mma_f16(acc[1][n0], ah[1], bh[pi][0], bh[pi][1]);
                    mma_f16(acc[1][n1], ah[1], bh[pi][2], bh[pi][3]);
                }
            }
        }
    }

    // ---- epilogue: add bias, store fp16 ----
#pragma unroll
    for (int mt = 0; mt < 2; mt++) {
        int rows[2] = {rowBase + warpRow + mt * 16 + gid, rowBase + warpRow + mt * 16 + gid + 8};
#pragma unroll
        for (int nt = 0; nt < 8; nt++) {
            int col = colBase + warpCol + nt * 8 + t4 * 2;
            float b0 = bias[col], b1 = bias[col + 1];
#pragma unroll
            for (int rr = 0; rr < 2; rr++) {
                int rw = rows[rr];
                if (rw >= M) continue;
                __half2 hv = __floats2half2_rn(acc[mt][nt][rr * 2 + 0] + b0,
                                               acc[mt][nt][rr * 2 + 1] + b1);
                *(__half2*)&C[(size_t)rw * Nc + col] = hv;
            }
        }
    }
}

// ------------------------------- GRU gates (fp16 in) ------------------------------
__global__ void k_gru_gate(const __half* __restrict__ GI, const __half* __restrict__ GH,
                           const float* __restrict__ bhh, float* __restrict__ H,
                           __half* __restrict__ Hh, int first) {
    int i = blockIdx.x * blockDim.x + threadIdx.x;
    if (i >= NN * DD) return;
    int n = i >> 7, j = i & 127;
    const __half* gi = GI + (size_t)n * G3;
    float ir = __half2float(gi[j]);
    float iz = __half2float(gi[j + 128]);
    float in = __half2float(gi[j + 256]);
    float hr, hz, hn, hp;
    if (first) {
        hr = bhh[j]; hz = bhh[j + 128]; hn = bhh[j + 256];
        hp = 0.f;
    } else {
        const __half* gh = GH + (size_t)n * G3;
        hr = __half2float(gh[j]);
        hz = __half2float(gh[j + 128]);
        hn = __half2float(gh[j + 256]);
        hp = H[i];
    }
    float r = 1.f / (1.f + __expf(-(ir + hr)));
    float z = 1.f / (1.f + __expf(-(iz + hz)));
    float nv = tanhf(in + r * hn);
    float h = (1.f - z) * nv + z * hp;
    H[i] = h;
    Hh[i] = __float2half_rn(h);
}

// -------------- TransformerConv edge attention, ALL timesteps in one launch ------
// q/k/v/skip all fp16 in one [N,512] buffer.
// mode 0: write fp16 (feeds next GEMM). mode 1: write fp16 to out (HA2).
__global__ void k_conv_all(const __half* __restrict__ QK,
                           const int* __restrict__ RP,
                           const int* __restrict__ ESRC, const float* __restrict__ EAS,
                           const float* __restrict__ We,
                           __half* __restrict__ oh) {
    int gw = (blockIdx.x * blockDim.x + threadIdx.x) >> 5;
    if (gw >= TT * NN) return;
    int t = gw / NN;
    int w = gw - t * NN;
    const __half* qk = QK + (size_t)t * NN * QKVS;
    const int* rowptr = RP + t * (NN + 1);
    const int* esrc   = ESRC + (size_t)t * EE;
    const float* eas  = EAS + (size_t)t * EE;

    int lane = threadIdx.x & 31;
    int c0 = lane * 4;
    uint2 qraw  = *(const uint2*)&qk[(size_t)w * QKVS + c0];
    uint2 skraw = *(const uint2*)&qk[(size_t)w * QKVS + 384 + c0];
    float2 q01 = __half22float2(*(const __half2*)&qraw.x);
    float2 q23 = __half22float2(*(const __half2*)&qraw.y);
    float2 s01 = __half22float2(*(const __half2*)&skraw.x);
    float2 s23 = __half22float2(*(const __half2*)&skraw.y);
    float4 q  = make_float4(q01.x, q01.y, q23.x, q23.y);
    float4 sk = make_float4(s01.x, s01.y, s23.x, s23.y);
    float4 we = *(const float4*)&We[c0];
    float m = -CUDART_INF_F, s = 0.f;
    float4 acc = make_float4(0.f, 0.f, 0.f, 0.f);
    int beg = rowptr[w], end = rowptr[w + 1];

    uint2 kraw = make_uint2(0, 0), vraw = make_uint2(0, 0);
    float eaV = 0.f;
    if (beg < end) {
        int sn = esrc[beg];
        eaV = eas[beg];
        kraw = *(const uint2*)&qk[(size_t)sn * QKVS + 128 + c0];
        vraw = *(const uint2*)&qk[(size_t)sn * QKVS + 256 + c0];
    }
    for (int i = beg; i < end; i++) {
        uint2 ck = kraw, cv = vraw;
        float cea = eaV;
        if (i + 1 < end) {       // prefetch next edge's gather before reduction chain
            int sn = esrc[i + 1];
            eaV = eas[i + 1];
            kraw = *(const uint2*)&qk[(size_t)sn * QKVS + 128 + c0];
            vraw = *(const uint2*)&qk[(size_t)sn * QKVS + 256 + c0];
        }
        float2 k01 = __half22float2(*(const __half2*)&ck.x);
        float2 k23 = __half22float2(*(const __half2*)&ck.y);
        float2 v01 = __half22float2(*(const __half2*)&cv.x);
        float2 v23 = __half22float2(*(const __half2*)&cv.y);
        float ex = cea * we.x, ey = cea * we.y, ez = cea * we.z, ew = cea * we.w;
        float part = q.x * (k01.x + ex) + q.y * (k01.y + ey)
                   + q.z * (k23.x + ez) + q.w * (k23.y + ew);
#pragma unroll
        for (int o = 16; o; o >>= 1) part += __shfl_xor_sync(0xffffffffu, part, o);
        float alpha = part * 0.08838834764831845f; // 1/sqrt(128)
        float mn = fmaxf(m, alpha);
        float corr = __expf(m - mn);
        float p = __expf(alpha - mn);
        s = s * corr + p;
        acc.x = acc.x * corr + p * (v01.x + ex);
        acc.y = acc.y * corr + p * (v01.y + ey);
        acc.z = acc.z * corr + p * (v23.x + ez);
        acc.w = acc.w * corr + p * (v23.y + ew);
        m = mn;
    }
    float inv = 1.f / (s + 1e-16f);
    float4 o;
    o.x = acc.x * inv + sk.x;
    o.y = acc.y * inv + sk.y;
    o.z = acc.z * inv + sk.z;
    o.w = acc.w * inv + sk.w;
    o.x = o.x > 0.f ? o.x : 0.01f * o.x;
    o.y = o.y > 0.f ? o.y : 0.01f * o.y;
    o.z = o.z > 0.f ? o.z : 0.01f * o.z;
    o.w = o.w > 0.f ? o.w : 0.01f * o.w;
    size_t oidx = (size_t)t * NN * DD + (size_t)w * DD + c0;
    __half2 o01 = __floats2half2_rn(o.x, o.y);
    __half2 o23 = __floats2half2_rn(o.z, o.w);
    uint2 packed;
    packed.x = *(uint32_t*)&o01;
    packed.y = *(uint32_t*)&o23;
    *(uint2*)&oh[oidx] = packed;
}

// ------------------------ output conv (D -> 1) -----------------------------------
__global__ void k_out_node(const __half* __restrict__ ha2,
                           const float* __restrict__ Wq, const float* __restrict__ bq,
                           const float* __restrict__ Wk, const float* __restrict__ bk,
                           const float* __restrict__ Wv, const float* __restrict__ bv,
                           const float* __restrict__ Ws, const float* __restrict__ bs,
                           float* __restrict__ oq, float* __restrict__ ok,
                           float* __restrict__ ov, float* __restrict__ osk) {
    int w = (blockIdx.x * blockDim.x + threadIdx.x) >> 5;
    if (w >= NN) return;
    int lane = threadIdx.x & 31;
    int c0 = lane * 4;
    float4 h = make_float4(0.f, 0.f, 0.f, 0.f);
#pragma unroll
    for (int t = 0; t < TT; t++) {
        uint2 raw = *(const uint2*)&ha2[(size_t)t * NN * DD + (size_t)w * DD + c0];
        float2 a01 = __half22float2(*(const __half2*)&raw.x);
        float2 a23 = __half22float2(*(const __half2*)&raw.y);
        h.x += a01.x; h.y += a01.y; h.z += a23.x; h.w += a23.y;
    }
    h.x *= 0.25f; h.y *= 0.25f; h.z *= 0.25f; h.w *= 0.25f;
    float4 wq = *(const float4*)&Wq[c0];
    float4 wk = *(const float4*)&Wk[c0];
    float4 wv = *(const float4*)&Wv[c0];
    float4 ws = *(const float4*)&Ws[c0];
    float dq = h.x * wq.x + h.y * wq.y + h.z * wq.z + h.w * wq.w;
    float dk = h.x * wk.x + h.y * wk.y + h.z * wk.z + h.w * wk.w;
    float dv = h.x * wv.x + h.y * wv.y + h.z * wv.z + h.w * wv.w;
    float ds = h.x * ws.x + h.y * ws.y + h.z * ws.z + h.w * ws.w;
#pragma unroll
    for (int o = 16; o; o >>= 1) {
        dq += __shfl_xor_sync(0xffffffffu, dq, o);
        dk += __shfl_xor_sync(0xffffffffu, dk, o);
        dv += __shfl_xor_sync(0xffffffffu, dv, o);
        ds += __shfl_xor_sync(0xffffffffu, ds, o);
    }
    if (lane == 0) {
        oq[w]  = dq + bq[0];
        ok[w]  = dk + bk[0];
        ov[w]  = dv + bv[0];
        osk[w] = ds + bs[0];
    }
}

__global__ void k_out_edge(const int* __restrict__ rowptr,
                           const int* __restrict__ esrc, const float* __restrict__ eas,
                           const float* __restrict__ We,
                           const float* __restrict__ oq, const float* __restrict__ ok,
                           const float* __restrict__ ov, const float* __restrict__ osk,
                           float* __restrict__ out) {
    int n = blockIdx.x * blockDim.x + threadIdx.x;
    if (n >= NN) return;
    float q = oq[n];
    float we = We[0];
    float m = -CUDART_INF_F, s = 0.f, acc = 0.f;
    int beg = rowptr[n], end = rowptr[n + 1];
    for (int i = beg; i < end; i++) {
        int sn = esrc[i];
        float et = eas[i] * we;
        float alpha = q * (ok[sn] + et);
        float mn = fmaxf(m, alpha);
        float corr = __expf(m - mn);
        float p = __expf(alpha - mn);
        s = s * corr + p;
        acc = acc * corr + p * (ov[sn] + et);
        m = mn;
    }
    out[n] = acc / (s + 1e-16f) + osk[n];
}

// =================================== host side ====================================
extern "C" void kernel_launch(void* const* d_in, const int* in_sizes, int n_in,
                              void* d_out, int out_size) {
    const float* x_seq = nullptr;
    const int*   ei    = nullptr;
    const float* ea    = nullptr;
    const float* P[22];
    int r = 0;
    for (int i = 0; i < n_in; i++) {
        if      (in_sizes[i] == TT * NN * IN_DIM) x_seq = (const float*)d_in[i];
        else if (in_sizes[i] == TT * 2 * EE)      ei    = (const int*)d_in[i];
        else if (in_sizes[i] == TT * EE)          ea    = (const float*)d_in[i];
        else if (r < 22)                          P[r++] = (const float*)d_in[i];
    }
    const float* gW_ih = P[0];
    const float* gW_hh = P[1];
    const float* gb_ih = P[2];
    const float* gb_hh = P[3];
    const float* cWq   = P[4];
    const float* cbq   = P[5];
    const float* cWk   = P[6];
    const float* cbk   = P[7];
    const float* cWv   = P[8];
    const float* cbv   = P[9];
    const float* cWe   = P[10];
    const float* cWs   = P[11];
    const float* cbs   = P[12];
    const float* oWq   = P[13];
    const float* obq   = P[14];
    const float* oWk   = P[15];
    const float* obk   = P[16];
    const float* oWv   = P[17];
    const float* obv   = P[18];
    const float* oWe   = P[19];
    const float* oWs   = P[20];
    const float* obs   = P[21];

    float *H, *BPK;
    __half *GI, *GH, *HA2, *QK, *X, *Hf, *HA, *WIH, *WHH, *WP;
    float *OQ, *OKp, *OV, *OSK, *EAS;
    int *RP, *ESRC, *CNT, *CUR;
    cudaGetSymbolAddress((void**)&GI,   g_GI);
    cudaGetSymbolAddress((void**)&GH,   g_GH);
    cudaGetSymbolAddress((void**)&H,    g_H);
    cudaGetSymbolAddress((void**)&HA2,  g_HA2);
    cudaGetSymbolAddress((void**)&QK,   g_QK);
    cudaGetSymbolAddress((void**)&X,    g_X);
    cudaGetSymbolAddress((void**)&Hf,   g_Hf);
    cudaGetSymbolAddress((void**)&HA,   g_HA);
    cudaGetSymbolAddress((void**)&WIH,  g_WIH);
    cudaGetSymbolAddress((void**)&WHH,  g_WHH);
    cudaGetSymbolAddress((void**)&WP,   g_WPK);
    cudaGetSymbolAddress((void**)&BPK,  g_BPK);
    cudaGetSymbolAddress((void**)&OQ,   g_OQ);
    cudaGetSymbolAddress((void**)&OKp,  g_OKs);
    cudaGetSymbolAddress((void**)&OV,   g_OV);
    cudaGetSymbolAddress((void**)&OSK,  g_OSK);
    cudaGetSymbolAddress((void**)&RP,   g_RP);
    cudaGetSymbolAddress((void**)&ESRC, g_ESRC);
    cudaGetSymbolAddress((void**)&EAS,  g_EAS);
    cudaGetSymbolAddress((void**)&CNT,  g_CNT);
    cudaGetSymbolAddress((void**)&CUR,  g_CUR);

    const int SMEM = NSTG * STG_BYTES;  // 48KB
    cudaFuncSetAttribute(k_pgemm, cudaFuncAttributeMaxDynamicSharedMemorySize, SMEM);

    const int TPB = 256;

    // 1..3: prep (GI GEMM stays the 4th launch for ncu's capture window)
    k_split_x<<<(TT * NN * IN_DIM + TPB - 1) / TPB, TPB>>>(x_seq, X);
    k_prep_gru<<<(G3 * IN_DIM + G3 * DD + TPB - 1) / TPB, TPB>>>(gW_ih, gW_hh, WIH, WHH);
    k_prep_conv<<<(2 * QKVS * DD + TPB - 1) / TPB, TPB>>>(cWq, cWk, cWv, cWs, cbq, cbk, cbv, cbs, WP, BPK);

    // 4: GI = X @ W_ih^T + b_ih for all T at once: [80000,64] @ [64,384] -> fp16
    k_pgemm<<<dim3(G3 / 128, (TT * NN + 127) / 128), 256, SMEM>>>(
        X, WIH, gb_ih, GI, TT * NN, G3, IN_DIM);

    // CSR build (direct (src, attr) records, sorted by dst)
    k_zero_i<<<(TT * NN + TPB - 1) / TPB, TPB>>>(CNT, TT * NN);
    k_hist<<<(TT * EE + TPB - 1) / TPB, TPB>>>(ei, CNT);
    k_scan<<<TT, 1024>>>(CNT, RP, CUR);
    k_scatter<<<(TT * EE + TPB - 1) / TPB, TPB>>>(ei, ea, CUR, ESRC, EAS);

    // ---- GRU over time: sequential chain, per-t H stored batched ----
    for (int t = 0; t < TT; t++) {
        if (t > 0) {
            k_pgemm<<<dim3(G3 / 128, (NN + 127) / 128), 256, SMEM>>>(
                Hf + (size_t)(t - 1) * NN * DD, WHH, gb_hh, GH, NN, G3, DD);
        }
        k_gru_gate<<<(NN * DD + TPB - 1) / TPB, TPB>>>(
            GI + (size_t)t * NN * G3, GH, gb_hh, H,
            Hf + (size_t)t * NN * DD, t == 0 ? 1 : 0);
    }

    // ---- layer 0: ONE batched qkvs GEMM (fp16 out), ONE conv launch ----
    k_pgemm<<<dim3(QKVS / 128, (TT * NN + 127) / 128), 256, SMEM>>>(
        Hf, WP, BPK, QK, TT * NN, QKVS, DD);
    k_conv_all<<<TT * NN / 8, 256>>>(QK, RP, ESRC, EAS, cWe, HA);

    // ---- layer 1: ONE batched qkvs GEMM, ONE conv launch (fp16 HA2 out) ----
    k_pgemm<<<dim3(QKVS / 128, (TT * NN + 127) / 128), 256, SMEM>>>(
        HA, WP + QKVS * DD, BPK + QKVS, QK, TT * NN, QKVS, DD);
    k_conv_all<<<TT * NN / 8, 256>>>(QK, RP, ESRC, EAS, cWe + DD, HA2);

    // ---- output conv (edges of last timestep) ----
    k_out_node<<<NN / 8, 256>>>(HA2, oWq, obq, oWk, obk, oWv, obv, oWs, obs, OQ, OKp, OV, OSK);
    k_out_edge<<<(NN + TPB - 1) / TPB, TPB>>>(RP + (TT - 1) * (NN + 1),
                                              ESRC + (size_t)(TT - 1) * EE, EAS + (size_t)(TT - 1) * EE,
                                              oWe, OQ, OKp, OV, OSK, (float*)d_out);
}

// round 13
// speedup vs baseline: 2.9918x; 1.0007x over previous
#include <cuda_runtime.h>
#include <cuda_fp16.h>
#include <math_constants.h>
#include <cstdint>

#define TT 4
#define NN 20000
#define EE 160000
#define IN_DIM 64
#define DD 128
#define G3 384   // 3*D
#define QKVS 512 // q|k|v|skip packed

// ------------------- static device scratch (no runtime allocs) -------------------
__device__ __half g_GI[(size_t)TT * NN * G3];
__device__ __half g_GH[(size_t)NN * G3];
__device__ float  g_H [(size_t)NN * DD];
__device__ __half g_HA2[(size_t)TT * NN * DD];
__device__ __half g_QK[(size_t)TT * NN * QKVS];
__device__ __half g_X [(size_t)TT * NN * IN_DIM];
__device__ __half g_Hf[(size_t)TT * NN * DD];
__device__ __half g_HA[(size_t)TT * NN * DD];
__device__ __half g_WIH[G3 * IN_DIM];
__device__ __half g_WHH[G3 * DD];
__device__ __half g_WPK[2 * QKVS * DD];
__device__ float g_BPK[2 * QKVS];
__device__ float g_OQ[NN], g_OKs[NN], g_OV[NN], g_OSK[NN];
__device__ int   g_RP [TT * (NN + 1)];
__device__ int   g_ESRC[TT * EE];
__device__ float g_EAS [TT * EE];
__device__ int   g_CNT[TT * NN];
__device__ int   g_CUR[TT * NN];

// ------------------------------- small utility kernels ---------------------------
__global__ void k_zero_i(int* p, int n) {
    int i = blockIdx.x * blockDim.x + threadIdx.x;
    if (i < n) p[i] = 0;
}

__global__ void k_split_x(const float* __restrict__ x, __half* __restrict__ xh) {
    int i = blockIdx.x * blockDim.x + threadIdx.x;
    if (i < TT * NN * IN_DIM) xh[i] = __float2half_rn(x[i]);
}

__global__ void k_prep_gru(const float* __restrict__ Wih, const float* __restrict__ Whh,
                           __half* __restrict__ a, __half* __restrict__ b) {
    int i = blockIdx.x * blockDim.x + threadIdx.x;
    if (i < G3 * IN_DIM) a[i] = __float2half_rn(Wih[i]);
    int j = i - G3 * IN_DIM;
    if (j >= 0 && j < G3 * DD) b[j] = __float2half_rn(Whh[j]);
}

__global__ void k_prep_conv(const float* __restrict__ Wq, const float* __restrict__ Wk,
                            const float* __restrict__ Wv, const float* __restrict__ Ws,
                            const float* __restrict__ bq, const float* __restrict__ bk,
                            const float* __restrict__ bv, const float* __restrict__ bs,
                            __half* __restrict__ WP, float* __restrict__ BP) {
    int i = blockIdx.x * blockDim.x + threadIdx.x;
    if (i < 2 * QKVS * DD) {
        int l = i >> 16;
        int rem = i & 65535;
        int n = rem >> 7, k = rem & 127;
        int base = l * DD * DD + k * DD;
        float v;
        if      (n < 128) v = Wq[base + n];
        else if (n < 256) v = Wk[base + n - 128];
        else if (n < 384) v = Wv[base + n - 256];
        else              v = Ws[base + n - 384];
        WP[i] = __float2half_rn(v);
    }
    if (i < 2 * QKVS) {
        int l = i >> 9, c = i & 511;
        int b2 = l * DD;
        float v;
        if      (c < 128) v = bq[b2 + c];
        else if (c < 256) v = bk[b2 + c - 128];
        else if (c < 384) v = bv[b2 + c - 256];
        else              v = bs[b2 + c - 384];
        BP[i] = v;
    }
}

// ------------------------------- CSR build ---------------------------------------
__global__ void k_hist(const int* __restrict__ ei, int* __restrict__ cnt) {
    int i = blockIdx.x * blockDim.x + threadIdx.x;
    if (i >= TT * EE) return;
    int t = i / EE, e = i % EE;
    int dst = ei[(size_t)t * 2 * EE + EE + e];
    atomicAdd(&cnt[t * NN + dst], 1);
}

__global__ void k_scan(const int* __restrict__ cnt, int* __restrict__ rowptr, int* __restrict__ cur) {
    int t = blockIdx.x;
    __shared__ int sh[1024];
    const int* c = cnt + t * NN;
    int* rp = rowptr + t * (NN + 1);
    int* cu = cur + t * NN;
    int carry = 0;
    for (int base = 0; base < NN; base += 1024) {
        int idx = base + threadIdx.x;
        int v = (idx < NN) ? c[idx] : 0;
        sh[threadIdx.x] = v;
        __syncthreads();
        for (int off = 1; off < 1024; off <<= 1) {
            int tval = (threadIdx.x >= off) ? sh[threadIdx.x - off] : 0;
            __syncthreads();
            sh[threadIdx.x] += tval;
            __syncthreads();
        }
        int excl = sh[threadIdx.x] - v;
        if (idx < NN) { rp[idx] = carry + excl; cu[idx] = carry + excl; }
        carry += sh[1023];
        __syncthreads();
    }
    if (threadIdx.x == 0) rp[NN] = carry;
}

__global__ void k_scatter(const int* __restrict__ ei, const float* __restrict__ ea,
                          int* __restrict__ cur,
                          int* __restrict__ esrc, float* __restrict__ eas) {
    int i = blockIdx.x * blockDim.x + threadIdx.x;
    if (i >= TT * EE) return;
    int t = i / EE, e = i % EE;
    int src = ei[(size_t)t * 2 * EE + e];
    int dst = ei[(size_t)t * 2 * EE + EE + e];
    int p = atomicAdd(&cur[t * NN + dst], 1);
    esrc[(size_t)t * EE + p] = src;
    eas [(size_t)t * EE + p] = ea[(size_t)t * EE + e];
}

// ==== pipelined fp16 HMMA GEMM: KC=64 chunks (half the barriers), fp16 in/out =====
#define KC 64
#define NSTG 3
#define TWORDS (128 * 16)             // words per 32-col sub-tile
#define STG_BYTES (4 * TWORDS * 4)    // 4 sub-tiles: A-k0, A-k1, B-k0, B-k1 (32KB)

__device__ __forceinline__ void mma_f16(float c[4], const uint32_t a[4],
                                        uint32_t b0, uint32_t b1) {
    asm volatile(
        "mma.sync.aligned.m16n8k16.row.col.f32.f16.f16.f32 "
        "{%0,%1,%2,%3}, {%4,%5,%6,%7}, {%8,%9}, {%0,%1,%2,%3};"
        : "+f"(c[0]), "+f"(c[1]), "+f"(c[2]), "+f"(c[3])
        : "r"(a[0]), "r"(a[1]), "r"(a[2]), "r"(a[3]), "r"(b0), "r"(b1));
}

__device__ __forceinline__ void ldsm_x4(uint32_t addr, uint32_t& r0, uint32_t& r1,
                                        uint32_t& r2, uint32_t& r3) {
    asm volatile("ldmatrix.sync.aligned.m8n8.x4.shared.b16 {%0,%1,%2,%3}, [%4];"
                 : "=r"(r0), "=r"(r1), "=r"(r2), "=r"(r3) : "r"(addr));
}

__global__ void __launch_bounds__(256, 2) k_pgemm(
    const __half* __restrict__ A, const __half* __restrict__ B,
    const float* __restrict__ bias, __half* __restrict__ C,
    int M, int Nc, int K) {
    extern __shared__ uint32_t smw[];   // NSTG x 32KB = 96KB

    int tid = threadIdx.x, wid = tid >> 5, lane = tid & 31;
    int gid = lane >> 2, t4 = lane & 3;
    int rowBase = blockIdx.y * 128;
    int colBase = blockIdx.x * 128;
    int warpRow = (wid & 3) * 32;
    int warpCol = (wid >> 2) * 64;

    float acc[2][8][4];
#pragma unroll
    for (int mt = 0; mt < 2; mt++)
#pragma unroll
        for (int nt = 0; nt < 8; nt++)
#pragma unroll
            for (int q = 0; q < 4; q++) acc[mt][nt][q] = 0.f;

    uint32_t sm0;
    asm("{ .reg .u64 t; cvta.to.shared.u64 t, %1; cvt.u32.u64 %0, t; }"
        : "=r"(sm0) : "l"(smw));

    const __half* srcs[2] = {A, B};

    int lm_m = lane >> 3;
    int lm_r = lane & 7;
    int a_row0 = warpRow + ((lm_m & 1) << 3) + lm_r;
    int a_kh   = lm_m >> 1;
    int b_row0 = warpCol + ((lm_m >> 1) << 3) + lm_r;
    int b_kh   = lm_m & 1;

    // 2048 16B-chunks per stage: arr 0=A|k0-31, 1=A|k32-63, 2=B|k0-31, 3=B|k32-63
    auto fill = [&](int stage, int k0) {
        uint32_t sb = sm0 + (uint32_t)stage * STG_BYTES;
#pragma unroll
        for (int it = 0; it < 8; it++) {
            int idx = tid + it * 256;
            int arr = idx >> 9;
            int rem = idx & 511;
            int r = rem >> 2, c = rem & 3;
            int isB = arr >> 1;
            int kh  = arr & 1;
            int grow = (isB ? colBase : rowBase) + r;
            int valid = isB || (grow < M);
            const __half* src = srcs[isB] + (valid ? ((size_t)grow * K + k0 + kh * 32 + c * 8) : 0);
            int sz = valid ? 16 : 0;
            uint32_t dst = sb + (uint32_t)(arr * TWORDS + (r << 4) + ((c ^ ((r >> 1) & 3)) << 2)) * 4;
            asm volatile("cp.async.cg.shared.global [%0], [%1], 16, %2;"
                         :: "r"(dst), "l"(src), "r"(sz));
        }
        asm volatile("cp.async.commit_group;");
    };

    int nch = K / KC;                // GI: 1, others: 2
    fill(0, 0);
    if (nch > 1) fill(1, KC);

    for (int ch = 0; ch < nch; ch++) {
        if (ch + 2 <= nch) { asm volatile("cp.async.wait_group 1;"); }
        else               { asm volatile("cp.async.wait_group 0;"); }
        __syncthreads();

        if (ch + 2 < nch) fill((ch + 2) % NSTG, (ch + 2) * KC);

        uint32_t st = sm0 + (uint32_t)(ch % NSTG) * STG_BYTES;

#pragma unroll
        for (int ks = 0; ks < KC; ks += 16) {
            int khalf = ks >> 5;                     // 0 or 1
            uint32_t pA = st + (uint32_t)khalf * TWORDS * 4;
            uint32_t pB = st + (uint32_t)(2 + khalf) * TWORDS * 4;
            int kin = ks & 31;

            uint32_t ah[2][4];
            int ach = (kin >> 3) + a_kh;
#pragma unroll
            for (int mt = 0; mt < 2; mt++) {
                int ar = a_row0 + mt * 16;
                uint32_t aoff = (uint32_t)(ar << 6) + (uint32_t)((ach ^ ((ar >> 1) & 3)) << 4);
                ldsm_x4(pA + aoff, ah[mt][0], ah[mt][1], ah[mt][2], ah[mt][3]);
            }
            int bch = (kin >> 3) + b_kh;
#pragma unroll
            for (int pp = 0; pp < 2; pp++) {
                uint32_t bh[2][4];
#pragma unroll
                for (int pi = 0; pi < 2; pi++) {
                    int br = b_row0 + (2 * pp + pi) * 16;
                    uint32_t boff = (uint32_t)(br << 6) + (uint32_t)((bch ^ ((br >> 1) & 3)) << 4);
                    ldsm_x4(pB + boff, bh[pi][0], bh[pi][1], bh[pi][2], bh[pi][3]);
                }
#pragma unroll
                for (int pi = 0; pi < 2; pi++) {
                    int n0 = (2 * pp + pi) * 2, n1 = n0 + 1;
                    mma_f16(acc[0][n0], ah[0], bh[pi][0], bh[pi][1]);
                    mma_f16(acc[0][n1], ah[0], bh[pi][2], bh[pi][3]);
                    mma_f16(acc[1][n0], ah[1], bh[pi][0], bh[pi][1]);
                    mma_f16(acc[1][n1], ah[1], bh[pi][2], bh[pi][3]);
                }
            }
        }
    }

    // ---- epilogue: add bias, store fp16 ----
#pragma unroll
    for (int mt = 0; mt < 2; mt++) {
        int rows[2] = {rowBase + warpRow + mt * 16 + gid, rowBase + warpRow + mt * 16 + gid + 8};
#pragma unroll
        for (int nt = 0; nt < 8; nt++) {
            int col = colBase + warpCol + nt * 8 + t4 * 2;
            float b0 = bias[col], b1 = bias[col + 1];
#pragma unroll
            for (int rr = 0; rr < 2; rr++) {
                int rw = rows[rr];
                if (rw >= M) continue;
                __half2 hv = __floats2half2_rn(acc[mt][nt][rr * 2 + 0] + b0,
                                               acc[mt][nt][rr * 2 + 1] + b1);
                *(__half2*)&C[(size_t)rw * Nc + col] = hv;
            }
        }
    }
}

// ------------------------------- GRU gates (fp16 in) ------------------------------
__global__ void k_gru_gate(const __half* __restrict__ GI, const __half* __restrict__ GH,
                           const float* __restrict__ bhh, float* __restrict__ H,
                           __half* __restrict__ Hh, int first) {
    int i = blockIdx.x * blockDim.x + threadIdx.x;
    if (i >= NN * DD) return;
    int n = i >> 7, j = i & 127;
    const __half* gi = GI + (size_t)n * G3;
    float ir = __half2float(gi[j]);
    float iz = __half2float(gi[j + 128]);
    float in = __half2float(gi[j + 256]);
    float hr, hz, hn, hp;
    if (first) {
        hr = bhh[j]; hz = bhh[j + 128]; hn = bhh[j + 256];
        hp = 0.f;
    } else {
        const __half* gh = GH + (size_t)n * G3;
        hr = __half2float(gh[j]);
        hz = __half2float(gh[j + 128]);
        hn = __half2float(gh[j + 256]);
        hp = H[i];
    }
    float r = 1.f / (1.f + __expf(-(ir + hr)));
    float z = 1.f / (1.f + __expf(-(iz + hz)));
    float nv = tanhf(in + r * hn);
    float h = (1.f - z) * nv + z * hp;
    H[i] = h;
    Hh[i] = __float2half_rn(h);
}

// -------------- TransformerConv edge attention: 2-edge ILP per iteration ----------
__global__ void k_conv_all(const __half* __restrict__ QK,
                           const int* __restrict__ RP,
                           const int* __restrict__ ESRC, const float* __restrict__ EAS,
                           const float* __restrict__ We,
                           __half* __restrict__ oh) {
    int gw = (blockIdx.x * blockDim.x + threadIdx.x) >> 5;
    if (gw >= TT * NN) return;
    int t = gw / NN;
    int w = gw - t * NN;
    const __half* qk = QK + (size_t)t * NN * QKVS;
    const int* rowptr = RP + t * (NN + 1);
    const int* esrc   = ESRC + (size_t)t * EE;
    const float* eas  = EAS + (size_t)t * EE;

    int lane = threadIdx.x & 31;
    int c0 = lane * 4;
    uint2 qraw  = *(const uint2*)&qk[(size_t)w * QKVS + c0];
    uint2 skraw = *(const uint2*)&qk[(size_t)w * QKVS + 384 + c0];
    float2 q01 = __half22float2(*(const __half2*)&qraw.x);
    float2 q23 = __half22float2(*(const __half2*)&qraw.y);
    float2 s01 = __half22float2(*(const __half2*)&skraw.x);
    float2 s23 = __half22float2(*(const __half2*)&skraw.y);
    float4 q  = make_float4(q01.x, q01.y, q23.x, q23.y);
    float4 sk = make_float4(s01.x, s01.y, s23.x, s23.y);
    float4 we = *(const float4*)&We[c0];
    float m = -CUDART_INF_F, s = 0.f;
    float4 acc = make_float4(0.f, 0.f, 0.f, 0.f);
    int beg = rowptr[w], end = rowptr[w + 1];

    uint2 k0r = make_uint2(0, 0), v0r = k0r, k1r = k0r, v1r = k0r;
    float e0 = 0.f, e1 = 0.f;
    if (beg < end) {
        int sn = esrc[beg];
        e0 = eas[beg];
        k0r = *(const uint2*)&qk[(size_t)sn * QKVS + 128 + c0];
        v0r = *(const uint2*)&qk[(size_t)sn * QKVS + 256 + c0];
    }
    if (beg + 1 < end) {
        int sn = esrc[beg + 1];
        e1 = eas[beg + 1];
        k1r = *(const uint2*)&qk[(size_t)sn * QKVS + 128 + c0];
        v1r = *(const uint2*)&qk[(size_t)sn * QKVS + 256 + c0];
    }

    for (int i = beg; i < end; i += 2) {
        uint2 ck0 = k0r, cv0 = v0r, ck1 = k1r, cv1 = v1r;
        float ce0 = e0, ce1 = e1;
        int has1 = (i + 1 < end);
        if (i + 2 < end) {
            int sn = esrc[i + 2];
            e0 = eas[i + 2];
            k0r = *(const uint2*)&qk[(size_t)sn * QKVS + 128 + c0];
            v0r = *(const uint2*)&qk[(size_t)sn * QKVS + 256 + c0];
        }
        if (i + 3 < end) {
            int sn = esrc[i + 3];
            e1 = eas[i + 3];
            k1r = *(const uint2*)&qk[(size_t)sn * QKVS + 128 + c0];
            v1r = *(const uint2*)&qk[(size_t)sn * QKVS + 256 + c0];
        }
        float2 ka01 = __half22float2(*(const __half2*)&ck0.x);
        float2 ka23 = __half22float2(*(const __half2*)&ck0.y);
        float2 kb01 = __half22float2(*(const __half2*)&ck1.x);
        float2 kb23 = __half22float2(*(const __half2*)&ck1.y);
        float ex0 = ce0 * we.x, ey0 = ce0 * we.y, ez0 = ce0 * we.z, ew0 = ce0 * we.w;
        float ex1 = ce1 * we.x, ey1 = ce1 * we.y, ez1 = ce1 * we.z, ew1 = ce1 * we.w;
        float part0 = q.x * (ka01.x + ex0) + q.y * (ka01.y + ey0)
                    + q.z * (ka23.x + ez0) + q.w * (ka23.y + ew0);
        float part1 = q.x * (kb01.x + ex1) + q.y * (kb01.y + ey1)
                    + q.z * (kb23.x + ez1) + q.w * (kb23.y + ew1);
        // interleaved butterflies: two independent chains share the latency
#pragma unroll
        for (int o = 16; o; o >>= 1) {
            part0 += __shfl_xor_sync(0xffffffffu, part0, o);
            part1 += __shfl_xor_sync(0xffffffffu, part1, o);
        }
        float2 va01 = __half22float2(*(const __half2*)&cv0.x);
        float2 va23 = __half22float2(*(const __half2*)&cv0.y);
        float a0 = part0 * 0.08838834764831845f;
        {
            float mn = fmaxf(m, a0);
            float corr = __expf(m - mn);
            float p = __expf(a0 - mn);
            s = s * corr + p;
            acc.x = acc.x * corr + p * (va01.x + ex0);
            acc.y = acc.y * corr + p * (va01.y + ey0);
            acc.z = acc.z * corr + p * (va23.x + ez0);
            acc.w = acc.w * corr + p * (va23.y + ew0);
            m = mn;
        }
        if (has1) {
            float2 vb01 = __half22float2(*(const __half2*)&cv1.x);
            float2 vb23 = __half22float2(*(const __half2*)&cv1.y);
            float a1 = part1 * 0.08838834764831845f;
            float mn = fmaxf(m, a1);
            float corr = __expf(m - mn);
            float p = __expf(a1 - mn);
            s = s * corr + p;
            acc.x = acc.x * corr + p * (vb01.x + ex1);
            acc.y = acc.y * corr + p * (vb01.y + ey1);
            acc.z = acc.z * corr + p * (vb23.x + ez1);
            acc.w = acc.w * corr + p * (vb23.y + ew1);
            m = mn;
        }
    }
    float inv = 1.f / (s + 1e-16f);
    float4 o;
    o.x = acc.x * inv + sk.x;
    o.y = acc.y * inv + sk.y;
    o.z = acc.z * inv + sk.z;
    o.w = acc.w * inv + sk.w;
    o.x = o.x > 0.f ? o.x : 0.01f * o.x;
    o.y = o.y > 0.f ? o.y : 0.01f * o.y;
    o.z = o.z > 0.f ? o.z : 0.01f * o.z;
    o.w = o.w > 0.f ? o.w : 0.01f * o.w;
    size_t oidx = (size_t)t * NN * DD + (size_t)w * DD + c0;
    __half2 o01 = __floats2half2_rn(o.x, o.y);
    __half2 o23 = __floats2half2_rn(o.z, o.w);
    uint2 packed;
    packed.x = *(uint32_t*)&o01;
    packed.y = *(uint32_t*)&o23;
    *(uint2*)&oh[oidx] = packed;
}

// ------------------------ output conv (D -> 1) -----------------------------------
__global__ void k_out_node(const __half* __restrict__ ha2,
                           const float* __restrict__ Wq, const float* __restrict__ bq,
                           const float* __restrict__ Wk, const float* __restrict__ bk,
                           const float* __restrict__ Wv, const float* __restrict__ bv,
                           const float* __restrict__ Ws, const float* __restrict__ bs,
                           float* __restrict__ oq, float* __restrict__ ok,
                           float* __restrict__ ov, float* __restrict__ osk) {
    int w = (blockIdx.x * blockDim.x + threadIdx.x) >> 5;
    if (w >= NN) return;
    int lane = threadIdx.x & 31;
    int c0 = lane * 4;
    float4 h = make_float4(0.f, 0.f, 0.f, 0.f);
#pragma unroll
    for (int t = 0; t < TT; t++) {
        uint2 raw = *(const uint2*)&ha2[(size_t)t * NN * DD + (size_t)w * DD + c0];
        float2 a01 = __half22float2(*(const __half2*)&raw.x);
        float2 a23 = __half22float2(*(const __half2*)&raw.y);
        h.x += a01.x; h.y += a01.y; h.z += a23.x; h.w += a23.y;
    }
    h.x *= 0.25f; h.y *= 0.25f; h.z *= 0.25f; h.w *= 0.25f;
    float4 wq = *(const float4*)&Wq[c0];
    float4 wk = *(const float4*)&Wk[c0];
    float4 wv = *(const float4*)&Wv[c0];
    float4 ws = *(const float4*)&Ws[c0];
    float dq = h.x * wq.x + h.y * wq.y + h.z * wq.z + h.w * wq.w;
    float dk = h.x * wk.x + h.y * wk.y + h.z * wk.z + h.w * wk.w;
    float dv = h.x * wv.x + h.y * wv.y + h.z * wv.z + h.w * wv.w;
    float ds = h.x * ws.x + h.y * ws.y + h.z * ws.z + h.w * ws.w;
#pragma unroll
    for (int o = 16; o; o >>= 1) {
        dq += __shfl_xor_sync(0xffffffffu, dq, o);
        dk += __shfl_xor_sync(0xffffffffu, dk, o);
        dv += __shfl_xor_sync(0xffffffffu, dv, o);
        ds += __shfl_xor_sync(0xffffffffu, ds, o);
    }
    if (lane == 0) {
        oq[w]  = dq + bq[0];
        ok[w]  = dk + bk[0];
        ov[w]  = dv + bv[0];
        osk[w] = ds + bs[0];
    }
}

__global__ void k_out_edge(const int* __restrict__ rowptr,
                           const int* __restrict__ esrc, const float* __restrict__ eas,
                           const float* __restrict__ We,
                           const float* __restrict__ oq, const float* __restrict__ ok,
                           const float* __restrict__ ov, const float* __restrict__ osk,
                           float* __restrict__ out) {
    int n = blockIdx.x * blockDim.x + threadIdx.x;
    if (n >= NN) return;
    float q = oq[n];
    float we = We[0];
    float m = -CUDART_INF_F, s = 0.f, acc = 0.f;
    int beg = rowptr[n], end = rowptr[n + 1];
    for (int i = beg; i < end; i++) {
        int sn = esrc[i];
        float et = eas[i] * we;
        float alpha = q * (ok[sn] + et);
        float mn = fmaxf(m, alpha);
        float corr = __expf(m - mn);
        float p = __expf(alpha - mn);
        s = s * corr + p;
        acc = acc * corr + p * (ov[sn] + et);
        m = mn;
    }
    out[n] = acc / (s + 1e-16f) + osk[n];
}

// =================================== host side ====================================
extern "C" void kernel_launch(void* const* d_in, const int* in_sizes, int n_in,
                              void* d_out, int out_size) {
    const float* x_seq = nullptr;
    const int*   ei    = nullptr;
    const float* ea    = nullptr;
    const float* P[22];
    int r = 0;
    for (int i = 0; i < n_in; i++) {
        if      (in_sizes[i] == TT * NN * IN_DIM) x_seq = (const float*)d_in[i];
        else if (in_sizes[i] == TT * 2 * EE)      ei    = (const int*)d_in[i];
        else if (in_sizes[i] == TT * EE)          ea    = (const float*)d_in[i];
        else if (r < 22)                          P[r++] = (const float*)d_in[i];
    }
    const float* gW_ih = P[0];
    const float* gW_hh = P[1];
    const float* gb_ih = P[2];
    const float* gb_hh = P[3];
    const float* cWq   = P[4];
    const float* cbq   = P[5];
    const float* cWk   = P[6];
    const float* cbk   = P[7];
    const float* cWv   = P[8];
    const float* cbv   = P[9];
    const float* cWe   = P[10];
    const float* cWs   = P[11];
    const float* cbs   = P[12];
    const float* oWq   = P[13];
    const float* obq   = P[14];
    const float* oWk   = P[15];
    const float* obk   = P[16];
    const float* oWv   = P[17];
    const float* obv   = P[18];
    const float* oWe   = P[19];
    const float* oWs   = P[20];
    const float* obs   = P[21];

    float *H, *BPK;
    __half *GI, *GH, *HA2, *QK, *X, *Hf, *HA, *WIH, *WHH, *WP;
    float *OQ, *OKp, *OV, *OSK, *EAS;
    int *RP, *ESRC, *CNT, *CUR;
    cudaGetSymbolAddress((void**)&GI,   g_GI);
    cudaGetSymbolAddress((void**)&GH,   g_GH);
    cudaGetSymbolAddress((void**)&H,    g_H);
    cudaGetSymbolAddress((void**)&HA2,  g_HA2);
    cudaGetSymbolAddress((void**)&QK,   g_QK);
    cudaGetSymbolAddress((void**)&X,    g_X);
    cudaGetSymbolAddress((void**)&Hf,   g_Hf);
    cudaGetSymbolAddress((void**)&HA,   g_HA);
    cudaGetSymbolAddress((void**)&WIH,  g_WIH);
    cudaGetSymbolAddress((void**)&WHH,  g_WHH);
    cudaGetSymbolAddress((void**)&WP,   g_WPK);
    cudaGetSymbolAddress((void**)&BPK,  g_BPK);
    cudaGetSymbolAddress((void**)&OQ,   g_OQ);
    cudaGetSymbolAddress((void**)&OKp,  g_OKs);
    cudaGetSymbolAddress((void**)&OV,   g_OV);
    cudaGetSymbolAddress((void**)&OSK,  g_OSK);
    cudaGetSymbolAddress((void**)&RP,   g_RP);
    cudaGetSymbolAddress((void**)&ESRC, g_ESRC);
    cudaGetSymbolAddress((void**)&EAS,  g_EAS);
    cudaGetSymbolAddress((void**)&CNT,  g_CNT);
    cudaGetSymbolAddress((void**)&CUR,  g_CUR);

    const int SMEM = NSTG * STG_BYTES;  // 96KB
    cudaFuncSetAttribute(k_pgemm, cudaFuncAttributeMaxDynamicSharedMemorySize, SMEM);

    const int TPB = 256;

    // 1..3: prep (GI GEMM stays the 4th launch for ncu's capture window)
    k_split_x<<<(TT * NN * IN_DIM + TPB - 1) / TPB, TPB>>>(x_seq, X);
    k_prep_gru<<<(G3 * IN_DIM + G3 * DD + TPB - 1) / TPB, TPB>>>(gW_ih, gW_hh, WIH, WHH);
    k_prep_conv<<<(2 * QKVS * DD + TPB - 1) / TPB, TPB>>>(cWq, cWk, cWv, cWs, cbq, cbk, cbv, cbs, WP, BPK);

    // 4: GI = X @ W_ih^T + b_ih for all T at once: [80000,64] @ [64,384] -> fp16
    k_pgemm<<<dim3(G3 / 128, (TT * NN + 127) / 128), 256, SMEM>>>(
        X, WIH, gb_ih, GI, TT * NN, G3, IN_DIM);

    // CSR build (direct (src, attr) records, sorted by dst)
    k_zero_i<<<(TT * NN + TPB - 1) / TPB, TPB>>>(CNT, TT * NN);
    k_hist<<<(TT * EE + TPB - 1) / TPB, TPB>>>(ei, CNT);
    k_scan<<<TT, 1024>>>(CNT, RP, CUR);
    k_scatter<<<(TT * EE + TPB - 1) / TPB, TPB>>>(ei, ea, CUR, ESRC, EAS);

    // ---- GRU over time: sequential chain, per-t H stored batched ----
    for (int t = 0; t < TT; t++) {
        if (t > 0) {
            k_pgemm<<<dim3(G3 / 128, (NN + 127) / 128), 256, SMEM>>>(
                Hf + (size_t)(t - 1) * NN * DD, WHH, gb_hh, GH, NN, G3, DD);
        }
        k_gru_gate<<<(NN * DD + TPB - 1) / TPB, TPB>>>(
            GI + (size_t)t * NN * G3, GH, gb_hh, H,
            Hf + (size_t)t * NN * DD, t == 0 ? 1 : 0);
    }

    // ---- layer 0: ONE batched qkvs GEMM (fp16 out), ONE conv launch ----
    k_pgemm<<<dim3(QKVS / 128, (TT * NN + 127) / 128), 256, SMEM>>>(
        Hf, WP, BPK, QK, TT * NN, QKVS, DD);
    k_conv_all<<<TT * NN / 8, 256>>>(QK, RP, ESRC, EAS, cWe, HA);

    // ---- layer 1: ONE batched qkvs GEMM, ONE conv launch (fp16 HA2 out) ----
    k_pgemm<<<dim3(QKVS / 128, (TT * NN + 127) / 128), 256, SMEM>>>(
        HA, WP + QKVS * DD, BPK + QKVS, QK, TT * NN, QKVS, DD);
    k_conv_all<<<TT * NN / 8, 256>>>(QK, RP, ESRC, EAS, cWe + DD, HA2);

    // ---- output conv (edges of last timestep) ----
    k_out_node<<<NN / 8, 256>>>(HA2, oWq, obq, oWk, obk, oWv, obv, oWs, obs, OQ, OKp, OV, OSK);
    k_out_edge<<<(NN + TPB - 1) / TPB, TPB>>>(RP + (TT - 1) * (NN + 1),
                                              ESRC + (size_t)(TT - 1) * EE, EAS + (size_t)(TT - 1) * EE,
                                              oWe, OQ, OKp, OV, OSK, (float*)d_out);
}

// round 14
// speedup vs baseline: 3.3154x; 1.1082x over previous
#include <cuda_runtime.h>
#include <cuda_fp16.h>
#include <math_constants.h>
#include <cstdint>

#define TT 4
#define NN 20000
#define EE 160000
#define IN_DIM 64
#define DD 128
#define G3 384   // 3*D
#define QKVS 512 // q | kv-interleaved | skip packed

// ------------------- static device scratch (no runtime allocs) -------------------
__device__ __half g_GI[(size_t)TT * NN * G3];
__device__ __half g_GH[(size_t)NN * G3];
__device__ float  g_H [(size_t)NN * DD];
__device__ __half g_HA2[(size_t)TT * NN * DD];
__device__ __half g_QK[(size_t)TT * NN * QKVS];   // [q(128) | kv ilv(256) | skip(128)]
__device__ __half g_X [(size_t)TT * NN * IN_DIM];
__device__ __half g_Hf[(size_t)TT * NN * DD];
__device__ __half g_HA[(size_t)TT * NN * DD];
__device__ __half g_WIH[G3 * IN_DIM];
__device__ __half g_WHH[G3 * DD];
__device__ __half g_WPK[2 * QKVS * DD];
__device__ float g_BPK[2 * QKVS];
__device__ float g_OQ[NN], g_OKs[NN], g_OV[NN], g_OSK[NN];
__device__ int   g_RP [TT * (NN + 1)];
__device__ int   g_ESRC[TT * EE];
__device__ float g_EAS [TT * EE];
__device__ int   g_CNT[TT * NN];
__device__ int   g_CUR[TT * NN];

// ------------------------------- small utility kernels ---------------------------
__global__ void k_zero_i(int* p, int n) {
    int i = blockIdx.x * blockDim.x + threadIdx.x;
    if (i < n) p[i] = 0;
}

// merged: split x to fp16 + convert GRU weights
__global__ void k_prep_main(const float* __restrict__ x, __half* __restrict__ xh,
                            const float* __restrict__ Wih, const float* __restrict__ Whh,
                            __half* __restrict__ a, __half* __restrict__ b) {
    int i = blockIdx.x * blockDim.x + threadIdx.x;
    if (i < TT * NN * IN_DIM) xh[i] = __float2half_rn(x[i]);
    if (i < G3 * IN_DIM) a[i] = __float2half_rn(Wih[i]);
    int j = i - G3 * IN_DIM;
    if (j >= 0 && j < G3 * DD) b[j] = __float2half_rn(Whh[j]);
}

__global__ void k_prep_conv(const float* __restrict__ Wq, const float* __restrict__ Wk,
                            const float* __restrict__ Wv, const float* __restrict__ Ws,
                            const float* __restrict__ bq, const float* __restrict__ bk,
                            const float* __restrict__ bv, const float* __restrict__ bs,
                            __half* __restrict__ WP, float* __restrict__ BP) {
    int i = blockIdx.x * blockDim.x + threadIdx.x;
    if (i < 2 * QKVS * DD) {
        int l = i >> 16;
        int rem = i & 65535;
        int n = rem >> 7, k = rem & 127;
        int base = l * DD * DD + k * DD;
        float v;
        if      (n < 128) v = Wq[base + n];
        else if (n < 256) v = Wk[base + n - 128];
        else if (n < 384) v = Wv[base + n - 256];
        else              v = Ws[base + n - 384];
        WP[i] = __float2half_rn(v);
    }
    if (i < 2 * QKVS) {
        int l = i >> 9, c = i & 511;
        int b2 = l * DD;
        float v;
        if      (c < 128) v = bq[b2 + c];
        else if (c < 256) v = bk[b2 + c - 128];
        else if (c < 384) v = bv[b2 + c - 256];
        else              v = bs[b2 + c - 384];
        BP[i] = v;
    }
}

// ------------------------------- CSR build ---------------------------------------
__global__ void k_hist(const int* __restrict__ ei, int* __restrict__ cnt) {
    int i = blockIdx.x * blockDim.x + threadIdx.x;
    if (i >= TT * EE) return;
    int t = i / EE, e = i % EE;
    int dst = ei[(size_t)t * 2 * EE + EE + e];
    atomicAdd(&cnt[t * NN + dst], 1);
}

__global__ void k_scan(const int* __restrict__ cnt, int* __restrict__ rowptr, int* __restrict__ cur) {
    int t = blockIdx.x;
    __shared__ int sh[1024];
    const int* c = cnt + t * NN;
    int* rp = rowptr + t * (NN + 1);
    int* cu = cur + t * NN;
    int carry = 0;
    for (int base = 0; base < NN; base += 1024) {
        int idx = base + threadIdx.x;
        int v = (idx < NN) ? c[idx] : 0;
        sh[threadIdx.x] = v;
        __syncthreads();
        for (int off = 1; off < 1024; off <<= 1) {
            int tval = (threadIdx.x >= off) ? sh[threadIdx.x - off] : 0;
            __syncthreads();
            sh[threadIdx.x] += tval;
            __syncthreads();
        }
        int excl = sh[threadIdx.x] - v;
        if (idx < NN) { rp[idx] = carry + excl; cu[idx] = carry + excl; }
        carry += sh[1023];
        __syncthreads();
    }
    if (threadIdx.x == 0) rp[NN] = carry;
}

__global__ void k_scatter(const int* __restrict__ ei, const float* __restrict__ ea,
                          int* __restrict__ cur,
                          int* __restrict__ esrc, float* __restrict__ eas) {
    int i = blockIdx.x * blockDim.x + threadIdx.x;
    if (i >= TT * EE) return;
    int t = i / EE, e = i % EE;
    int src = ei[(size_t)t * 2 * EE + e];
    int dst = ei[(size_t)t * 2 * EE + EE + e];
    int p = atomicAdd(&cur[t * NN + dst], 1);
    esrc[(size_t)t * EE + p] = src;
    eas [(size_t)t * EE + p] = ea[(size_t)t * EE + e];
}

// ==== pipelined fp16 HMMA GEMM: KC=64, fp16 in/out, optional conv routing ========
#define KC 64
#define NSTG 3
#define TWORDS (128 * 16)
#define STG_BYTES (4 * TWORDS * 4)

__device__ __forceinline__ void mma_f16(float c[4], const uint32_t a[4],
                                        uint32_t b0, uint32_t b1) {
    asm volatile(
        "mma.sync.aligned.m16n8k16.row.col.f32.f16.f16.f32 "
        "{%0,%1,%2,%3}, {%4,%5,%6,%7}, {%8,%9}, {%0,%1,%2,%3};"
        : "+f"(c[0]), "+f"(c[1]), "+f"(c[2]), "+f"(c[3])
        : "r"(a[0]), "r"(a[1]), "r"(a[2]), "r"(a[3]), "r"(b0), "r"(b1));
}

__device__ __forceinline__ void ldsm_x4(uint32_t addr, uint32_t& r0, uint32_t& r1,
                                        uint32_t& r2, uint32_t& r3) {
    asm volatile("ldmatrix.sync.aligned.m8n8.x4.shared.b16 {%0,%1,%2,%3}, [%4];"
                 : "=r"(r0), "=r"(r1), "=r"(r2), "=r"(r3) : "r"(addr));
}

__global__ void __launch_bounds__(256, 2) k_pgemm(
    const __half* __restrict__ A, const __half* __restrict__ B,
    const float* __restrict__ bias, __half* __restrict__ C,
    int M, int Nc, int K, int route) {
    extern __shared__ uint32_t smw[];

    int tid = threadIdx.x, wid = tid >> 5, lane = tid & 31;
    int gid = lane >> 2, t4 = lane & 3;
    int rowBase = blockIdx.y * 128;
    int colBase = blockIdx.x * 128;
    int warpRow = (wid & 3) * 32;
    int warpCol = (wid >> 2) * 64;

    float acc[2][8][4];
#pragma unroll
    for (int mt = 0; mt < 2; mt++)
#pragma unroll
        for (int nt = 0; nt < 8; nt++)
#pragma unroll
            for (int q = 0; q < 4; q++) acc[mt][nt][q] = 0.f;

    uint32_t sm0;
    asm("{ .reg .u64 t; cvta.to.shared.u64 t, %1; cvt.u32.u64 %0, t; }"
        : "=r"(sm0) : "l"(smw));

    const __half* srcs[2] = {A, B};

    int lm_m = lane >> 3;
    int lm_r = lane & 7;
    int a_row0 = warpRow + ((lm_m & 1) << 3) + lm_r;
    int a_kh   = lm_m >> 1;
    int b_row0 = warpCol + ((lm_m >> 1) << 3) + lm_r;
    int b_kh   = lm_m & 1;

    auto fill = [&](int stage, int k0) {
        uint32_t sb = sm0 + (uint32_t)stage * STG_BYTES;
#pragma unroll
        for (int it = 0; it < 8; it++) {
            int idx = tid + it * 256;
            int arr = idx >> 9;
            int rem = idx & 511;
            int r = rem >> 2, c = rem & 3;
            int isB = arr >> 1;
            int kh  = arr & 1;
            int grow = (isB ? colBase : rowBase) + r;
            int valid = isB || (grow < M);
            const __half* src = srcs[isB] + (valid ? ((size_t)grow * K + k0 + kh * 32 + c * 8) : 0);
            int sz = valid ? 16 : 0;
            uint32_t dst = sb + (uint32_t)(arr * TWORDS + (r << 4) + ((c ^ ((r >> 1) & 3)) << 2)) * 4;
            asm volatile("cp.async.cg.shared.global [%0], [%1], 16, %2;"
                         :: "r"(dst), "l"(src), "r"(sz));
        }
        asm volatile("cp.async.commit_group;");
    };

    int nch = K / KC;
    fill(0, 0);
    if (nch > 1) fill(1, KC);

    for (int ch = 0; ch < nch; ch++) {
        if (ch + 2 <= nch) { asm volatile("cp.async.wait_group 1;"); }
        else               { asm volatile("cp.async.wait_group 0;"); }
        __syncthreads();

        if (ch + 2 < nch) fill((ch + 2) % NSTG, (ch + 2) * KC);

        uint32_t st = sm0 + (uint32_t)(ch % NSTG) * STG_BYTES;

#pragma unroll
        for (int ks = 0; ks < KC; ks += 16) {
            int khalf = ks >> 5;
            uint32_t pA = st + (uint32_t)khalf * TWORDS * 4;
            uint32_t pB = st + (uint32_t)(2 + khalf) * TWORDS * 4;
            int kin = ks & 31;

            uint32_t ah[2][4];
            int ach = (kin >> 3) + a_kh;
#pragma unroll
            for (int mt = 0; mt < 2; mt++) {
                int ar = a_row0 + mt * 16;
                uint32_t aoff = (uint32_t)(ar << 6) + (uint32_t)((ach ^ ((ar >> 1) & 3)) << 4);
                ldsm_x4(pA + aoff, ah[mt][0], ah[mt][1], ah[mt][2], ah[mt][3]);
            }
            int bch = (kin >> 3) + b_kh;
#pragma unroll
            for (int pp = 0; pp < 2; pp++) {
                uint32_t bh[2][4];
#pragma unroll
                for (int pi = 0; pi < 2; pi++) {
                    int br = b_row0 + (2 * pp + pi) * 16;
                    uint32_t boff = (uint32_t)(br << 6) + (uint32_t)((bch ^ ((br >> 1) & 3)) << 4);
                    ldsm_x4(pB + boff, bh[pi][0], bh[pi][1], bh[pi][2], bh[pi][3]);
                }
#pragma unroll
                for (int pi = 0; pi < 2; pi++) {
                    int n0 = (2 * pp + pi) * 2, n1 = n0 + 1;
                    mma_f16(acc[0][n0], ah[0], bh[pi][0], bh[pi][1]);
                    mma_f16(acc[0][n1], ah[0], bh[pi][2], bh[pi][3]);
                    mma_f16(acc[1][n0], ah[1], bh[pi][0], bh[pi][1]);
                    mma_f16(acc[1][n1], ah[1], bh[pi][2], bh[pi][3]);
                }
            }
        }
    }

    // ---- epilogue: add bias, store fp16 (conv routing interleaves k|v) ----
    int cb = blockIdx.x;   // conv mode: 0=q 1=k 2=v 3=skip
#pragma unroll
    for (int mt = 0; mt < 2; mt++) {
        int rows[2] = {rowBase + warpRow + mt * 16 + gid, rowBase + warpRow + mt * 16 + gid + 8};
#pragma unroll
        for (int nt = 0; nt < 8; nt++) {
            int lcol = warpCol + nt * 8 + t4 * 2;
            int col = colBase + lcol;
            float b0 = bias[col], b1 = bias[col + 1];
            int outcol;
            if (!route)       outcol = col;
            else if (cb == 0) outcol = lcol;
            else if (cb == 3) outcol = 384 + lcol;
            else              outcol = 128 + ((lcol >> 2) << 3) + ((cb == 2) ? 4 : 0) + (lcol & 3);
#pragma unroll
            for (int rr = 0; rr < 2; rr++) {
                int rw = rows[rr];
                if (rw >= M) continue;
                __half2 hv = __floats2half2_rn(acc[mt][nt][rr * 2 + 0] + b0,
                                               acc[mt][nt][rr * 2 + 1] + b1);
                *(__half2*)&C[(size_t)rw * Nc + outcol] = hv;
            }
        }
    }
}

// ------------------------------- GRU gates (fp16 in) ------------------------------
__global__ void k_gru_gate(const __half* __restrict__ GI, const __half* __restrict__ GH,
                           const float* __restrict__ bhh, float* __restrict__ H,
                           __half* __restrict__ Hh, int first) {
    int i = blockIdx.x * blockDim.x + threadIdx.x;
    if (i >= NN * DD) return;
    int n = i >> 7, j = i & 127;
    const __half* gi = GI + (size_t)n * G3;
    float ir = __half2float(gi[j]);
    float iz = __half2float(gi[j + 128]);
    float in = __half2float(gi[j + 256]);
    float hr, hz, hn, hp;
    if (first) {
        hr = bhh[j]; hz = bhh[j + 128]; hn = bhh[j + 256];
        hp = 0.f;
    } else {
        const __half* gh = GH + (size_t)n * G3;
        hr = __half2float(gh[j]);
        hz = __half2float(gh[j + 128]);
        hn = __half2float(gh[j + 256]);
        hp = H[i];
    }
    float r = 1.f / (1.f + __expf(-(ir + hr)));
    float z = 1.f / (1.f + __expf(-(iz + hz)));
    float nv = tanhf(in + r * hn);
    float h = (1.f - z) * nv + z * hp;
    H[i] = h;
    Hh[i] = __float2half_rn(h);
}

// -------------- TransformerConv edge attention: single uint4 gather/edge ----------
__global__ void k_conv_all(const __half* __restrict__ QK,
                           const int* __restrict__ RP,
                           const int* __restrict__ ESRC, const float* __restrict__ EAS,
                           const float* __restrict__ We,
                           __half* __restrict__ oh) {
    int gw = (blockIdx.x * blockDim.x + threadIdx.x) >> 5;
    if (gw >= TT * NN) return;
    int t = gw / NN;
    int w = gw - t * NN;
    const __half* qk = QK + (size_t)t * NN * QKVS;
    const int* rowptr = RP + t * (NN + 1);
    const int* esrc   = ESRC + (size_t)t * EE;
    const float* eas  = EAS + (size_t)t * EE;

    int lane = threadIdx.x & 31;
    int c0 = lane * 4;
    int kvoff = 128 + lane * 8;      // interleaved [k4|v4] per lane
    uint2 qraw  = *(const uint2*)&qk[(size_t)w * QKVS + c0];
    uint2 skraw = *(const uint2*)&qk[(size_t)w * QKVS + 384 + c0];
    float2 q01 = __half22float2(*(const __half2*)&qraw.x);
    float2 q23 = __half22float2(*(const __half2*)&qraw.y);
    float2 s01 = __half22float2(*(const __half2*)&skraw.x);
    float2 s23 = __half22float2(*(const __half2*)&skraw.y);
    float4 q  = make_float4(q01.x, q01.y, q23.x, q23.y);
    float4 sk = make_float4(s01.x, s01.y, s23.x, s23.y);
    float4 we = *(const float4*)&We[c0];
    float m = -CUDART_INF_F, s = 0.f;
    float4 acc = make_float4(0.f, 0.f, 0.f, 0.f);
    int beg = rowptr[w], end = rowptr[w + 1];

    uint4 kv0 = make_uint4(0, 0, 0, 0), kv1 = kv0;
    float e0 = 0.f, e1 = 0.f;
    if (beg < end) {
        int sn = esrc[beg];
        e0 = eas[beg];
        kv0 = *(const uint4*)&qk[(size_t)sn * QKVS + kvoff];
    }
    if (beg + 1 < end) {
        int sn = esrc[beg + 1];
        e1 = eas[beg + 1];
        kv1 = *(const uint4*)&qk[(size_t)sn * QKVS + kvoff];
    }

    for (int i = beg; i < end; i += 2) {
        uint4 c0v = kv0, c1v = kv1;
        float ce0 = e0, ce1 = e1;
        int has1 = (i + 1 < end);
        if (i + 2 < end) {
            int sn = esrc[i + 2];
            e0 = eas[i + 2];
            kv0 = *(const uint4*)&qk[(size_t)sn * QKVS + kvoff];
        }
        if (i + 3 < end) {
            int sn = esrc[i + 3];
            e1 = eas[i + 3];
            kv1 = *(const uint4*)&qk[(size_t)sn * QKVS + kvoff];
        }
        float2 ka01 = __half22float2(*(const __half2*)&c0v.x);
        float2 ka23 = __half22float2(*(const __half2*)&c0v.y);
        float2 kb01 = __half22float2(*(const __half2*)&c1v.x);
        float2 kb23 = __half22float2(*(const __half2*)&c1v.y);
        float ex0 = ce0 * we.x, ey0 = ce0 * we.y, ez0 = ce0 * we.z, ew0 = ce0 * we.w;
        float ex1 = ce1 * we.x, ey1 = ce1 * we.y, ez1 = ce1 * we.z, ew1 = ce1 * we.w;
        float part0 = q.x * (ka01.x + ex0) + q.y * (ka01.y + ey0)
                    + q.z * (ka23.x + ez0) + q.w * (ka23.y + ew0);
        float part1 = q.x * (kb01.x + ex1) + q.y * (kb01.y + ey1)
                    + q.z * (kb23.x + ez1) + q.w * (kb23.y + ew1);
#pragma unroll
        for (int o = 16; o; o >>= 1) {
            part0 += __shfl_xor_sync(0xffffffffu, part0, o);
            part1 += __shfl_xor_sync(0xffffffffu, part1, o);
        }
        float2 va01 = __half22float2(*(const __half2*)&c0v.z);
        float2 va23 = __half22float2(*(const __half2*)&c0v.w);
        float a0 = part0 * 0.08838834764831845f;
        {
            float mn = fmaxf(m, a0);
            float corr = __expf(m - mn);
            float p = __expf(a0 - mn);
            s = s * corr + p;
            acc.x = acc.x * corr + p * (va01.x + ex0);
            acc.y = acc.y * corr + p * (va01.y + ey0);
            acc.z = acc.z * corr + p * (va23.x + ez0);
            acc.w = acc.w * corr + p * (va23.y + ew0);
            m = mn;
        }
        if (has1) {
            float2 vb01 = __half22float2(*(const __half2*)&c1v.z);
            float2 vb23 = __half22float2(*(const __half2*)&c1v.w);
            float a1 = part1 * 0.08838834764831845f;
            float mn = fmaxf(m, a1);
            float corr = __expf(m - mn);
            float p = __expf(a1 - mn);
            s = s * corr + p;
            acc.x = acc.x * corr + p * (vb01.x + ex1);
            acc.y = acc.y * corr + p * (vb01.y + ey1);
            acc.z = acc.z * corr + p * (vb23.x + ez1);
            acc.w = acc.w * corr + p * (vb23.y + ew1);
            m = mn;
        }
    }
    float inv = 1.f / (s + 1e-16f);
    float4 o;
    o.x = acc.x * inv + sk.x;
    o.y = acc.y * inv + sk.y;
    o.z = acc.z * inv + sk.z;
    o.w = acc.w * inv + sk.w;
    o.x = o.x > 0.f ? o.x : 0.01f * o.x;
    o.y = o.y > 0.f ? o.y : 0.01f * o.y;
    o.z = o.z > 0.f ? o.z : 0.01f * o.z;
    o.w = o.w > 0.f ? o.w : 0.01f * o.w;
    size_t oidx = (size_t)t * NN * DD + (size_t)w * DD + c0;
    __half2 o01 = __floats2half2_rn(o.x, o.y);
    __half2 o23 = __floats2half2_rn(o.z, o.w);
    uint2 packed;
    packed.x = *(uint32_t*)&o01;
    packed.y = *(uint32_t*)&o23;
    *(uint2*)&oh[oidx] = packed;
}

// ------------------------ output conv (D -> 1) -----------------------------------
__global__ void k_out_node(const __half* __restrict__ ha2,
                           const float* __restrict__ Wq, const float* __restrict__ bq,
                           const float* __restrict__ Wk, const float* __restrict__ bk,
                           const float* __restrict__ Wv, const float* __restrict__ bv,
                           const float* __restrict__ Ws, const float* __restrict__ bs,
                           float* __restrict__ oq, float* __restrict__ ok,
                           float* __restrict__ ov, float* __restrict__ osk) {
    int w = (blockIdx.x * blockDim.x + threadIdx.x) >> 5;
    if (w >= NN) return;
    int lane = threadIdx.x & 31;
    int c0 = lane * 4;
    float4 h = make_float4(0.f, 0.f, 0.f, 0.f);
#pragma unroll
    for (int t = 0; t < TT; t++) {
        uint2 raw = *(const uint2*)&ha2[(size_t)t * NN * DD + (size_t)w * DD + c0];
        float2 a01 = __half22float2(*(const __half2*)&raw.x);
        float2 a23 = __half22float2(*(const __half2*)&raw.y);
        h.x += a01.x; h.y += a01.y; h.z += a23.x; h.w += a23.y;
    }
    h.x *= 0.25f; h.y *= 0.25f; h.z *= 0.25f; h.w *= 0.25f;
    float4 wq = *(const float4*)&Wq[c0];
    float4 wk = *(const float4*)&Wk[c0];
    float4 wv = *(const float4*)&Wv[c0];
    float4 ws = *(const float4*)&Ws[c0];
    float dq = h.x * wq.x + h.y * wq.y + h.z * wq.z + h.w * wq.w;
    float dk = h.x * wk.x + h.y * wk.y + h.z * wk.z + h.w * wk.w;
    float dv = h.x * wv.x + h.y * wv.y + h.z * wv.z + h.w * wv.w;
    float ds = h.x * ws.x + h.y * ws.y + h.z * ws.z + h.w * ws.w;
#pragma unroll
    for (int o = 16; o; o >>= 1) {
        dq += __shfl_xor_sync(0xffffffffu, dq, o);
        dk += __shfl_xor_sync(0xffffffffu, dk, o);
        dv += __shfl_xor_sync(0xffffffffu, dv, o);
        ds += __shfl_xor_sync(0xffffffffu, ds, o);
    }
    if (lane == 0) {
        oq[w]  = dq + bq[0];
        ok[w]  = dk + bk[0];
        ov[w]  = dv + bv[0];
        osk[w] = ds + bs[0];
    }
}

__global__ void k_out_edge(const int* __restrict__ rowptr,
                           const int* __restrict__ esrc, const float* __restrict__ eas,
                           const float* __restrict__ We,
                           const float* __restrict__ oq, const float* __restrict__ ok,
                           const float* __restrict__ ov, const float* __restrict__ osk,
                           float* __restrict__ out) {
    int n = blockIdx.x * blockDim.x + threadIdx.x;
    if (n >= NN) return;
    float q = oq[n];
    float we = We[0];
    float m = -CUDART_INF_F, s = 0.f, acc = 0.f;
    int beg = rowptr[n], end = rowptr[n + 1];
    for (int i = beg; i < end; i++) {
        int sn = esrc[i];
        float et = eas[i] * we;
        float alpha = q * (ok[sn] + et);
        float mn = fmaxf(m, alpha);
        float corr = __expf(m - mn);
        float p = __expf(alpha - mn);
        s = s * corr + p;
        acc = acc * corr + p * (ov[sn] + et);
        m = mn;
    }
    out[n] = acc / (s + 1e-16f) + osk[n];
}

// =================================== host side ====================================
extern "C" void kernel_launch(void* const* d_in, const int* in_sizes, int n_in,
                              void* d_out, int out_size) {
    const float* x_seq = nullptr;
    const int*   ei    = nullptr;
    const float* ea    = nullptr;
    const float* P[22];
    int r = 0;
    for (int i = 0; i < n_in; i++) {
        if      (in_sizes[i] == TT * NN * IN_DIM) x_seq = (const float*)d_in[i];
        else if (in_sizes[i] == TT * 2 * EE)      ei    = (const int*)d_in[i];
        else if (in_sizes[i] == TT * EE)          ea    = (const float*)d_in[i];
        else if (r < 22)                          P[r++] = (const float*)d_in[i];
    }
    const float* gW_ih = P[0];
    const float* gW_hh = P[1];
    const float* gb_ih = P[2];
    const float* gb_hh = P[3];
    const float* cWq   = P[4];
    const float* cbq   = P[5];
    const float* cWk   = P[6];
    const float* cbk   = P[7];
    const float* cWv   = P[8];
    const float* cbv   = P[9];
    const float* cWe   = P[10];
    const float* cWs   = P[11];
    const float* cbs   = P[12];
    const float* oWq   = P[13];
    const float* obq   = P[14];
    const float* oWk   = P[15];
    const float* obk   = P[16];
    const float* oWv   = P[17];
    const float* obv   = P[18];
    const float* oWe   = P[19];
    const float* oWs   = P[20];
    const float* obs   = P[21];

    float *H, *BPK;
    __half *GI, *GH, *HA2, *QK, *X, *Hf, *HA, *WIH, *WHH, *WP;
    float *OQ, *OKp, *OV, *OSK, *EAS;
    int *RP, *ESRC, *CNT, *CUR;
    cudaGetSymbolAddress((void**)&GI,   g_GI);
    cudaGetSymbolAddress((void**)&GH,   g_GH);
    cudaGetSymbolAddress((void**)&H,    g_H);
    cudaGetSymbolAddress((void**)&HA2,  g_HA2);
    cudaGetSymbolAddress((void**)&QK,   g_QK);
    cudaGetSymbolAddress((void**)&X,    g_X);
    cudaGetSymbolAddress((void**)&Hf,   g_Hf);
    cudaGetSymbolAddress((void**)&HA,   g_HA);
    cudaGetSymbolAddress((void**)&WIH,  g_WIH);
    cudaGetSymbolAddress((void**)&WHH,  g_WHH);
    cudaGetSymbolAddress((void**)&WP,   g_WPK);
    cudaGetSymbolAddress((void**)&BPK,  g_BPK);
    cudaGetSymbolAddress((void**)&OQ,   g_OQ);
    cudaGetSymbolAddress((void**)&OKp,  g_OKs);
    cudaGetSymbolAddress((void**)&OV,   g_OV);
    cudaGetSymbolAddress((void**)&OSK,  g_OSK);
    cudaGetSymbolAddress((void**)&RP,   g_RP);
    cudaGetSymbolAddress((void**)&ESRC, g_ESRC);
    cudaGetSymbolAddress((void**)&EAS,  g_EAS);
    cudaGetSymbolAddress((void**)&CNT,  g_CNT);
    cudaGetSymbolAddress((void**)&CUR,  g_CUR);

    const int SMEM = NSTG * STG_BYTES;  // 96KB
    cudaFuncSetAttribute(k_pgemm, cudaFuncAttributeMaxDynamicSharedMemorySize, SMEM);

    const int TPB = 256;

    // ---- fork a side stream for the CSR build + conv-weight prep (independent of
    //      the GRU chain). Created fresh each call and leaked (host resources only;
    //      kernel_launch runs twice — correctness + capture). Graph capture records
    //      the fork/join as parallel branches.
    cudaStream_t side;
    cudaStreamCreateWithFlags(&side, cudaStreamNonBlocking);
    cudaEvent_t evF, evJ;
    cudaEventCreateWithFlags(&evF, cudaEventDisableTiming);
    cudaEventCreateWithFlags(&evJ, cudaEventDisableTiming);
    cudaEventRecord(evF, 0);
    cudaStreamWaitEvent(side, evF, 0);

    // side branch: CSR build + conv weight prep
    k_zero_i<<<(TT * NN + TPB - 1) / TPB, TPB, 0, side>>>(CNT, TT * NN);
    k_hist<<<(TT * EE + TPB - 1) / TPB, TPB, 0, side>>>(ei, CNT);
    k_scan<<<TT, 1024, 0, side>>>(CNT, RP, CUR);
    k_scatter<<<(TT * EE + TPB - 1) / TPB, TPB, 0, side>>>(ei, ea, CUR, ESRC, EAS);
    k_prep_conv<<<(2 * QKVS * DD + TPB - 1) / TPB, TPB, 0, side>>>(
        cWq, cWk, cWv, cWs, cbq, cbk, cbv, cbs, WP, BPK);
    cudaEventRecord(evJ, side);

    // main branch: x/GRU prep, GI GEMM, GRU chain
    k_prep_main<<<(TT * NN * IN_DIM + TPB - 1) / TPB, TPB>>>(x_seq, X, gW_ih, gW_hh, WIH, WHH);
    k_pgemm<<<dim3(G3 / 128, (TT * NN + 127) / 128), 256, SMEM>>>(
        X, WIH, gb_ih, GI, TT * NN, G3, IN_DIM, 0);

    for (int t = 0; t < TT; t++) {
        if (t > 0) {
            k_pgemm<<<dim3(G3 / 128, (NN + 127) / 128), 256, SMEM>>>(
                Hf + (size_t)(t - 1) * NN * DD, WHH, gb_hh, GH, NN, G3, DD, 0);
        }
        k_gru_gate<<<(NN * DD + TPB - 1) / TPB, TPB>>>(
            GI + (size_t)t * NN * G3, GH, gb_hh, H,
            Hf + (size_t)t * NN * DD, t == 0 ? 1 : 0);
    }

    // join: conv weights + CSR must be ready
    cudaStreamWaitEvent(0, evJ, 0);

    // ---- layer 0: ONE batched qkvs GEMM (kv-interleaved out), ONE conv launch ----
    k_pgemm<<<dim3(QKVS / 128, (TT * NN + 127) / 128), 256, SMEM>>>(
        Hf, WP, BPK, QK, TT * NN, QKVS, DD, 1);
    k_conv_all<<<TT * NN / 8, 256>>>(QK, RP, ESRC, EAS, cWe, HA);

    // ---- layer 1 ----
    k_pgemm<<<dim3(QKVS / 128, (TT * NN + 127) / 128), 256, SMEM>>>(
        HA, WP + QKVS * DD, BPK + QKVS, QK, TT * NN, QKVS, DD, 1);
    k_conv_all<<<TT * NN / 8, 256>>>(QK, RP, ESRC, EAS, cWe + DD, HA2);

    // ---- output conv (edges of last timestep) ----
    k_out_node<<<NN / 8, 256>>>(HA2, oWq, obq, oWk, obk, oWv, obv, oWs, obs, OQ, OKp, OV, OSK);
    k_out_edge<<<(NN + TPB - 1) / TPB, TPB>>>(RP + (TT - 1) * (NN + 1),
                                              ESRC + (size_t)(TT - 1) * EE, EAS + (size_t)(TT - 1) * EE,
                                              oWe, OQ, OKp, OV, OSK, (float*)d_out);
}

// round 16
// speedup vs baseline: 3.5469x; 1.0698x over previous
#include <cuda_runtime.h>
#include <cuda_fp16.h>
#include <math_constants.h>
#include <cstdint>

#define TT 4
#define NN 20000
#define EE 160000
#define IN_DIM 64
#define DD 128
#define G3 384   // 3*D
#define QKVS 512 // q | kv-interleaved | skip packed

// ------------------- static device scratch (no runtime allocs) -------------------
__device__ __half g_GI[(size_t)TT * NN * G3];
__device__ __half g_GH[(size_t)NN * G3];
__device__ float  g_H [(size_t)NN * DD];
__device__ __half g_HA2[(size_t)TT * NN * DD];
__device__ __half g_QK[(size_t)TT * NN * QKVS];
__device__ __half g_X [(size_t)TT * NN * IN_DIM];
__device__ __half g_Hf[(size_t)TT * NN * DD];
__device__ __half g_HA[(size_t)TT * NN * DD];
__device__ __half g_WIH[G3 * IN_DIM];
__device__ __half g_WHH[G3 * DD];
__device__ __half g_WPK[2 * QKVS * DD];
__device__ float g_BPK[2 * QKVS];
__device__ float g_OQ[NN], g_OKs[NN], g_OV[NN], g_OSK[NN];
__device__ int   g_RP [TT * (NN + 1)];
__device__ int   g_ESRC[TT * EE];
__device__ float g_EAS [TT * EE];
__device__ int   g_CNT[TT * NN];
__device__ int   g_CUR[TT * NN];

// ------------------------------- small utility kernels ---------------------------
__global__ void k_zero_i(int* p, int n) {
    int i = blockIdx.x * blockDim.x + threadIdx.x;
    if (i < n) p[i] = 0;
}

__global__ void k_prep_main(const float* __restrict__ x, __half* __restrict__ xh,
                            const float* __restrict__ Wih, const float* __restrict__ Whh,
                            __half* __restrict__ a, __half* __restrict__ b) {
    int i = blockIdx.x * blockDim.x + threadIdx.x;
    if (i < TT * NN * IN_DIM) xh[i] = __float2half_rn(x[i]);
    if (i < G3 * IN_DIM) a[i] = __float2half_rn(Wih[i]);
    int j = i - G3 * IN_DIM;
    if (j >= 0 && j < G3 * DD) b[j] = __float2half_rn(Whh[j]);
}

__global__ void k_prep_conv(const float* __restrict__ Wq, const float* __restrict__ Wk,
                            const float* __restrict__ Wv, const float* __restrict__ Ws,
                            const float* __restrict__ bq, const float* __restrict__ bk,
                            const float* __restrict__ bv, const float* __restrict__ bs,
                            __half* __restrict__ WP, float* __restrict__ BP) {
    int i = blockIdx.x * blockDim.x + threadIdx.x;
    if (i < 2 * QKVS * DD) {
        int l = i >> 16;
        int rem = i & 65535;
        int n = rem >> 7, k = rem & 127;
        int base = l * DD * DD + k * DD;
        float v;
        if      (n < 128) v = Wq[base + n];
        else if (n < 256) v = Wk[base + n - 128];
        else if (n < 384) v = Wv[base + n - 256];
        else              v = Ws[base + n - 384];
        WP[i] = __float2half_rn(v);
    }
    if (i < 2 * QKVS) {
        int l = i >> 9, c = i & 511;
        int b2 = l * DD;
        float v;
        if      (c < 128) v = bq[b2 + c];
        else if (c < 256) v = bk[b2 + c - 128];
        else if (c < 384) v = bv[b2 + c - 256];
        else              v = bs[b2 + c - 384];
        BP[i] = v;
    }
}

// ------------------------------- CSR build ---------------------------------------
__global__ void k_hist(const int* __restrict__ ei, int* __restrict__ cnt) {
    int i = blockIdx.x * blockDim.x + threadIdx.x;
    if (i >= TT * EE) return;
    int t = i / EE, e = i % EE;
    int dst = ei[(size_t)t * 2 * EE + EE + e];
    atomicAdd(&cnt[t * NN + dst], 1);
}

__global__ void k_scan(const int* __restrict__ cnt, int* __restrict__ rowptr, int* __restrict__ cur) {
    int t = blockIdx.x;
    __shared__ int sh[1024];
    const int* c = cnt + t * NN;
    int* rp = rowptr + t * (NN + 1);
    int* cu = cur + t * NN;
    int carry = 0;
    for (int base = 0; base < NN; base += 1024) {
        int idx = base + threadIdx.x;
        int v = (idx < NN) ? c[idx] : 0;
        sh[threadIdx.x] = v;
        __syncthreads();
        for (int off = 1; off < 1024; off <<= 1) {
            int tval = (threadIdx.x >= off) ? sh[threadIdx.x - off] : 0;
            __syncthreads();
            sh[threadIdx.x] += tval;
            __syncthreads();
        }
        int excl = sh[threadIdx.x] - v;
        if (idx < NN) { rp[idx] = carry + excl; cu[idx] = carry + excl; }
        carry += sh[1023];
        __syncthreads();
    }
    if (threadIdx.x == 0) rp[NN] = carry;
}

__global__ void k_scatter(const int* __restrict__ ei, const float* __restrict__ ea,
                          int* __restrict__ cur,
                          int* __restrict__ esrc, float* __restrict__ eas) {
    int i = blockIdx.x * blockDim.x + threadIdx.x;
    if (i >= TT * EE) return;
    int t = i / EE, e = i % EE;
    int src = ei[(size_t)t * 2 * EE + e];
    int dst = ei[(size_t)t * 2 * EE + EE + e];
    int p = atomicAdd(&cur[t * NN + dst], 1);
    esrc[(size_t)t * EE + p] = src;
    eas [(size_t)t * EE + p] = ea[(size_t)t * EE + e];
}

// ==== pipelined fp16 HMMA GEMM: KC=64, fp16 in/out, optional conv routing ========
#define KC 64
#define NSTG 3
#define TWORDS (128 * 16)
#define STG_BYTES (4 * TWORDS * 4)

__device__ __forceinline__ void mma_f16(float c[4], const uint32_t a[4],
                                        uint32_t b0, uint32_t b1) {
    asm volatile(
        "mma.sync.aligned.m16n8k16.row.col.f32.f16.f16.f32 "
        "{%0,%1,%2,%3}, {%4,%5,%6,%7}, {%8,%9}, {%0,%1,%2,%3};"
        : "+f"(c[0]), "+f"(c[1]), "+f"(c[2]), "+f"(c[3])
        : "r"(a[0]), "r"(a[1]), "r"(a[2]), "r"(a[3]), "r"(b0), "r"(b1));
}

__device__ __forceinline__ void ldsm_x4(uint32_t addr, uint32_t& r0, uint32_t& r1,
                                        uint32_t& r2, uint32_t& r3) {
    asm volatile("ldmatrix.sync.aligned.m8n8.x4.shared.b16 {%0,%1,%2,%3}, [%4];"
                 : "=r"(r0), "=r"(r1), "=r"(r2), "=r"(r3) : "r"(addr));
}

__global__ void __launch_bounds__(256, 2) k_pgemm(
    const __half* __restrict__ A, const __half* __restrict__ B,
    const float* __restrict__ bias, __half* __restrict__ C,
    int M, int Nc, int K, int route) {
    extern __shared__ uint32_t smw[];

    int tid = threadIdx.x, wid = tid >> 5, lane = tid & 31;
    int gid = lane >> 2, t4 = lane & 3;
    int rowBase = blockIdx.y * 128;
    int colBase = blockIdx.x * 128;
    int warpRow = (wid & 3) * 32;
    int warpCol = (wid >> 2) * 64;

    float acc[2][8][4];
#pragma unroll
    for (int mt = 0; mt < 2; mt++)
#pragma unroll
        for (int nt = 0; nt < 8; nt++)
#pragma unroll
            for (int q = 0; q < 4; q++) acc[mt][nt][q] = 0.f;

    uint32_t sm0;
    asm("{ .reg .u64 t; cvta.to.shared.u64 t, %1; cvt.u32.u64 %0, t; }"
        : "=r"(sm0) : "l"(smw));

    const __half* srcs[2] = {A, B};

    int lm_m = lane >> 3;
    int lm_r = lane & 7;
    int a_row0 = warpRow + ((lm_m & 1) << 3) + lm_r;
    int a_kh   = lm_m >> 1;
    int b_row0 = warpCol + ((lm_m >> 1) << 3) + lm_r;
    int b_kh   = lm_m & 1;

    auto fill = [&](int stage, int k0) {
        uint32_t sb = sm0 + (uint32_t)stage * STG_BYTES;
#pragma unroll
        for (int it = 0; it < 8; it++) {
            int idx = tid + it * 256;
            int arr = idx >> 9;
            int rem = idx & 511;
            int r = rem >> 2, c = rem & 3;
            int isB = arr >> 1;
            int kh  = arr & 1;
            int grow = (isB ? colBase : rowBase) + r;
            int valid = isB || (grow < M);
            const __half* src = srcs[isB] + (valid ? ((size_t)grow * K + k0 + kh * 32 + c * 8) : 0);
            int sz = valid ? 16 : 0;
            uint32_t dst = sb + (uint32_t)(arr * TWORDS + (r << 4) + ((c ^ ((r >> 1) & 3)) << 2)) * 4;
            asm volatile("cp.async.cg.shared.global [%0], [%1], 16, %2;"
                         :: "r"(dst), "l"(src), "r"(sz));
        }
        asm volatile("cp.async.commit_group;");
    };

    int nch = K / KC;
    fill(0, 0);
    if (nch > 1) fill(1, KC);

    for (int ch = 0; ch < nch; ch++) {
        if (ch + 2 <= nch) { asm volatile("cp.async.wait_group 1;"); }
        else               { asm volatile("cp.async.wait_group 0;"); }
        __syncthreads();

        if (ch + 2 < nch) fill((ch + 2) % NSTG, (ch + 2) * KC);

        uint32_t st = sm0 + (uint32_t)(ch % NSTG) * STG_BYTES;

#pragma unroll
        for (int ks = 0; ks < KC; ks += 16) {
            int khalf = ks >> 5;
            uint32_t pA = st + (uint32_t)khalf * TWORDS * 4;
            uint32_t pB = st + (uint32_t)(2 + khalf) * TWORDS * 4;
            int kin = ks & 31;

            uint32_t ah[2][4];
            int ach = (kin >> 3) + a_kh;
#pragma unroll
            for (int mt = 0; mt < 2; mt++) {
                int ar = a_row0 + mt * 16;
                uint32_t aoff = (uint32_t)(ar << 6) + (uint32_t)((ach ^ ((ar >> 1) & 3)) << 4);
                ldsm_x4(pA + aoff, ah[mt][0], ah[mt][1], ah[mt][2], ah[mt][3]);
            }
            int bch = (kin >> 3) + b_kh;
#pragma unroll
            for (int pp = 0; pp < 2; pp++) {
                uint32_t bh[2][4];
#pragma unroll
                for (int pi = 0; pi < 2; pi++) {
                    int br = b_row0 + (2 * pp + pi) * 16;
                    uint32_t boff = (uint32_t)(br << 6) + (uint32_t)((bch ^ ((br >> 1) & 3)) << 4);
                    ldsm_x4(pB + boff, bh[pi][0], bh[pi][1], bh[pi][2], bh[pi][3]);
                }
#pragma unroll
                for (int pi = 0; pi < 2; pi++) {
                    int n0 = (2 * pp + pi) * 2, n1 = n0 + 1;
                    mma_f16(acc[0][n0], ah[0], bh[pi][0], bh[pi][1]);
                    mma_f16(acc[0][n1], ah[0], bh[pi][2], bh[pi][3]);
                    mma_f16(acc[1][n0], ah[1], bh[pi][0], bh[pi][1]);
                    mma_f16(acc[1][n1], ah[1], bh[pi][2], bh[pi][3]);
                }
            }
        }
    }

    int cb = blockIdx.x;
#pragma unroll
    for (int mt = 0; mt < 2; mt++) {
        int rows[2] = {rowBase + warpRow + mt * 16 + gid, rowBase + warpRow + mt * 16 + gid + 8};
#pragma unroll
        for (int nt = 0; nt < 8; nt++) {
            int lcol = warpCol + nt * 8 + t4 * 2;
            int col = colBase + lcol;
            float b0 = bias[col], b1 = bias[col + 1];
            int outcol;
            if (!route)       outcol = col;
            else if (cb == 0) outcol = lcol;
            else if (cb == 3) outcol = 384 + lcol;
            else              outcol = 128 + ((lcol >> 2) << 3) + ((cb == 2) ? 4 : 0) + (lcol & 3);
#pragma unroll
            for (int rr = 0; rr < 2; rr++) {
                int rw = rows[rr];
                if (rw >= M) continue;
                __half2 hv = __floats2half2_rn(acc[mt][nt][rr * 2 + 0] + b0,
                                               acc[mt][nt][rr * 2 + 1] + b1);
                *(__half2*)&C[(size_t)rw * Nc + outcol] = hv;
            }
        }
    }
}

// ------------------------------- GRU gates (fp16 in) ------------------------------
__global__ void k_gru_gate(const __half* __restrict__ GI, const __half* __restrict__ GH,
                           const float* __restrict__ bhh, float* __restrict__ H,
                           __half* __restrict__ Hh, int first) {
    int i = blockIdx.x * blockDim.x + threadIdx.x;
    if (i >= NN * DD) return;
    int n = i >> 7, j = i & 127;
    const __half* gi = GI + (size_t)n * G3;
    float ir = __half2float(gi[j]);
    float iz = __half2float(gi[j + 128]);
    float in = __half2float(gi[j + 256]);
    float hr, hz, hn, hp;
    if (first) {
        hr = bhh[j]; hz = bhh[j + 128]; hn = bhh[j + 256];
        hp = 0.f;
    } else {
        const __half* gh = GH + (size_t)n * G3;
        hr = __half2float(gh[j]);
        hz = __half2float(gh[j + 128]);
        hn = __half2float(gh[j + 256]);
        hp = H[i];
    }
    float r = 1.f / (1.f + __expf(-(ir + hr)));
    float z = 1.f / (1.f + __expf(-(iz + hz)));
    float nv = tanhf(in + r * hn);
    float h = (1.f - z) * nv + z * hp;
    H[i] = h;
    Hh[i] = __float2half_rn(h);
}

// -------------- TransformerConv edge attention, single timestep -------------------
__global__ void k_conv_t(const __half* __restrict__ qk,
                         const int* __restrict__ rowptr,
                         const int* __restrict__ esrc, const float* __restrict__ eas,
                         const float* __restrict__ We,
                         __half* __restrict__ oh) {
    int w = (blockIdx.x * blockDim.x + threadIdx.x) >> 5;
    if (w >= NN) return;

    int lane = threadIdx.x & 31;
    int c0 = lane * 4;
    int kvoff = 128 + lane * 8;      // interleaved [k4|v4] per lane
    uint2 qraw  = *(const uint2*)&qk[(size_t)w * QKVS + c0];
    uint2 skraw = *(const uint2*)&qk[(size_t)w * QKVS + 384 + c0];
    float2 q01 = __half22float2(*(const __half2*)&qraw.x);
    float2 q23 = __half22float2(*(const __half2*)&qraw.y);
    float2 s01 = __half22float2(*(const __half2*)&skraw.x);
    float2 s23 = __half22float2(*(const __half2*)&skraw.y);
    float4 q  = make_float4(q01.x, q01.y, q23.x, q23.y);
    float4 sk = make_float4(s01.x, s01.y, s23.x, s23.y);
    float4 we = *(const float4*)&We[c0];
    float m = -CUDART_INF_F, s = 0.f;
    float4 acc = make_float4(0.f, 0.f, 0.f, 0.f);
    int beg = rowptr[w], end = rowptr[w + 1];

    uint4 kv0 = make_uint4(0, 0, 0, 0), kv1 = kv0;
    float e0 = 0.f, e1 = 0.f;
    if (beg < end) {
        int sn = esrc[beg];
        e0 = eas[beg];
        kv0 = *(const uint4*)&qk[(size_t)sn * QKVS + kvoff];
    }
    if (beg + 1 < end) {
        int sn = esrc[beg + 1];
        e1 = eas[beg + 1];
        kv1 = *(const uint4*)&qk[(size_t)sn * QKVS + kvoff];
    }

    for (int i = beg; i < end; i += 2) {
        uint4 c0v = kv0, c1v = kv1;
        float ce0 = e0, ce1 = e1;
        int has1 = (i + 1 < end);
        if (i + 2 < end) {
            int sn = esrc[i + 2];
            e0 = eas[i + 2];
            kv0 = *(const uint4*)&qk[(size_t)sn * QKVS + kvoff];
        }
        if (i + 3 < end) {
            int sn = esrc[i + 3];
            e1 = eas[i + 3];
            kv1 = *(const uint4*)&qk[(size_t)sn * QKVS + kvoff];
        }
        float2 ka01 = __half22float2(*(const __half2*)&c0v.x);
        float2 ka23 = __half22float2(*(const __half2*)&c0v.y);
        float2 kb01 = __half22float2(*(const __half2*)&c1v.x);
        float2 kb23 = __half22float2(*(const __half2*)&c1v.y);
        float ex0 = ce0 * we.x, ey0 = ce0 * we.y, ez0 = ce0 * we.z, ew0 = ce0 * we.w;
        float ex1 = ce1 * we.x, ey1 = ce1 * we.y, ez1 = ce1 * we.z, ew1 = ce1 * we.w;
        float part0 = q.x * (ka01.x + ex0) + q.y * (ka01.y + ey0)
                    + q.z * (ka23.x + ez0) + q.w * (ka23.y + ew0);
        float part1 = q.x * (kb01.x + ex1) + q.y * (kb01.y + ey1)
                    + q.z * (kb23.x + ez1) + q.w * (kb23.y + ew1);
#pragma unroll
        for (int o = 16; o; o >>= 1) {
            part0 += __shfl_xor_sync(0xffffffffu, part0, o);
            part1 += __shfl_xor_sync(0xffffffffu, part1, o);
        }
        float2 va01 = __half22float2(*(const __half2*)&c0v.z);
        float2 va23 = __half22float2(*(const __half2*)&c0v.w);
        float a0 = part0 * 0.08838834764831845f;
        {
            float mn = fmaxf(m, a0);
            float corr = __expf(m - mn);
            float p = __expf(a0 - mn);
            s = s * corr + p;
            acc.x = acc.x * corr + p * (va01.x + ex0);
            acc.y = acc.y * corr + p * (va01.y + ey0);
            acc.z = acc.z * corr + p * (va23.x + ez0);
            acc.w = acc.w * corr + p * (va23.y + ew0);
            m = mn;
        }
        if (has1) {
            float2 vb01 = __half22float2(*(const __half2*)&c1v.z);
            float2 vb23 = __half22float2(*(const __half2*)&c1v.w);
            float a1 = part1 * 0.08838834764831845f;
            float mn = fmaxf(m, a1);
            float corr = __expf(m - mn);
            float p = __expf(a1 - mn);
            s = s * corr + p;
            acc.x = acc.x * corr + p * (vb01.x + ex1);
            acc.y = acc.y * corr + p * (vb01.y + ey1);
            acc.z = acc.z * corr + p * (vb23.x + ez1);
            acc.w = acc.w * corr + p * (vb23.y + ew1);
            m = mn;
        }
    }
    float inv = 1.f / (s + 1e-16f);
    float4 o;
    o.x = acc.x * inv + sk.x;
    o.y = acc.y * inv + sk.y;
    o.z = acc.z * inv + sk.z;
    o.w = acc.w * inv + sk.w;
    o.x = o.x > 0.f ? o.x : 0.01f * o.x;
    o.y = o.y > 0.f ? o.y : 0.01f * o.y;
    o.z = o.z > 0.f ? o.z : 0.01f * o.z;
    o.w = o.w > 0.f ? o.w : 0.01f * o.w;
    size_t oidx = (size_t)w * DD + c0;
    __half2 o01 = __floats2half2_rn(o.x, o.y);
    __half2 o23 = __floats2half2_rn(o.z, o.w);
    uint2 packed;
    packed.x = *(uint32_t*)&o01;
    packed.y = *(uint32_t*)&o23;
    *(uint2*)&oh[oidx] = packed;
}

// ------------------------ output conv (D -> 1) -----------------------------------
__global__ void k_out_node(const __half* __restrict__ ha2,
                           const float* __restrict__ Wq, const float* __restrict__ bq,
                           const float* __restrict__ Wk, const float* __restrict__ bk,
                           const float* __restrict__ Wv, const float* __restrict__ bv,
                           const float* __restrict__ Ws, const float* __restrict__ bs,
                           float* __restrict__ oq, float* __restrict__ ok,
                           float* __restrict__ ov, float* __restrict__ osk) {
    int w = (blockIdx.x * blockDim.x + threadIdx.x) >> 5;
    if (w >= NN) return;
    int lane = threadIdx.x & 31;
    int c0 = lane * 4;
    float4 h = make_float4(0.f, 0.f, 0.f, 0.f);
#pragma unroll
    for (int t = 0; t < TT; t++) {
        uint2 raw = *(const uint2*)&ha2[(size_t)t * NN * DD + (size_t)w * DD + c0];
        float2 a01 = __half22float2(*(const __half2*)&raw.x);
        float2 a23 = __half22float2(*(const __half2*)&raw.y);
        h.x += a01.x; h.y += a01.y; h.z += a23.x; h.w += a23.y;
    }
    h.x *= 0.25f; h.y *= 0.25f; h.z *= 0.25f; h.w *= 0.25f;
    float4 wq = *(const float4*)&Wq[c0];
    float4 wk = *(const float4*)&Wk[c0];
    float4 wv = *(const float4*)&Wv[c0];
    float4 ws = *(const float4*)&Ws[c0];
    float dq = h.x * wq.x + h.y * wq.y + h.z * wq.z + h.w * wq.w;
    float dk = h.x * wk.x + h.y * wk.y + h.z * wk.z + h.w * wk.w;
    float dv = h.x * wv.x + h.y * wv.y + h.z * wv.z + h.w * wv.w;
    float ds = h.x * ws.x + h.y * ws.y + h.z * ws.z + h.w * ws.w;
#pragma unroll
    for (int o = 16; o; o >>= 1) {
        dq += __shfl_xor_sync(0xffffffffu, dq, o);
        dk += __shfl_xor_sync(0xffffffffu, dk, o);
        dv += __shfl_xor_sync(0xffffffffu, dv, o);
        ds += __shfl_xor_sync(0xffffffffu, ds, o);
    }
    if (lane == 0) {
        oq[w]  = dq + bq[0];
        ok[w]  = dk + bk[0];
        ov[w]  = dv + bv[0];
        osk[w] = ds + bs[0];
    }
}

__global__ void k_out_edge(const int* __restrict__ rowptr,
                           const int* __restrict__ esrc, const float* __restrict__ eas,
                           const float* __restrict__ We,
                           const float* __restrict__ oq, const float* __restrict__ ok,
                           const float* __restrict__ ov, const float* __restrict__ osk,
                           float* __restrict__ out) {
    int n = blockIdx.x * blockDim.x + threadIdx.x;
    if (n >= NN) return;
    float q = oq[n];
    float we = We[0];
    float m = -CUDART_INF_F, s = 0.f, acc = 0.f;
    int beg = rowptr[n], end = rowptr[n + 1];
    for (int i = beg; i < end; i++) {
        int sn = esrc[i];
        float et = eas[i] * we;
        float alpha = q * (ok[sn] + et);
        float mn = fmaxf(m, alpha);
        float corr = __expf(m - mn);
        float p = __expf(alpha - mn);
        s = s * corr + p;
        acc = acc * corr + p * (ov[sn] + et);
        m = mn;
    }
    out[n] = acc / (s + 1e-16f) + osk[n];
}

// =================================== host side ====================================
extern "C" void kernel_launch(void* const* d_in, const int* in_sizes, int n_in,
                              void* d_out, int out_size) {
    const float* x_seq = nullptr;
    const int*   ei    = nullptr;
    const float* ea    = nullptr;
    const float* P[22];
    int r = 0;
    for (int i = 0; i < n_in; i++) {
        if      (in_sizes[i] == TT * NN * IN_DIM) x_seq = (const float*)d_in[i];
        else if (in_sizes[i] == TT * 2 * EE)      ei    = (const int*)d_in[i];
        else if (in_sizes[i] == TT * EE)          ea    = (const float*)d_in[i];
        else if (r < 22)                          P[r++] = (const float*)d_in[i];
    }
    const float* gW_ih = P[0];
    const float* gW_hh = P[1];
    const float* gb_ih = P[2];
    const float* gb_hh = P[3];
    const float* cWq   = P[4];
    const float* cbq   = P[5];
    const float* cWk   = P[6];
    const float* cbk   = P[7];
    const float* cWv   = P[8];
    const float* cbv   = P[9];
    const float* cWe   = P[10];
    const float* cWs   = P[11];
    const float* cbs   = P[12];
    const float* oWq   = P[13];
    const float* obq   = P[14];
    const float* oWk   = P[15];
    const float* obk   = P[16];
    const float* oWv   = P[17];
    const float* obv   = P[18];
    const float* oWe   = P[19];
    const float* oWs   = P[20];
    const float* obs   = P[21];

    float *H, *BPK;
    __half *GI, *GH, *HA2, *QK, *X, *Hf, *HA, *WIH, *WHH, *WP;
    float *OQ, *OKp, *OV, *OSK, *EAS;
    int *RP, *ESRC, *CNT, *CUR;
    cudaGetSymbolAddress((void**)&GI,   g_GI);
    cudaGetSymbolAddress((void**)&GH,   g_GH);
    cudaGetSymbolAddress((void**)&H,    g_H);
    cudaGetSymbolAddress((void**)&HA2,  g_HA2);
    cudaGetSymbolAddress((void**)&QK,   g_QK);
    cudaGetSymbolAddress((void**)&X,    g_X);
    cudaGetSymbolAddress((void**)&Hf,   g_Hf);
    cudaGetSymbolAddress((void**)&HA,   g_HA);
    cudaGetSymbolAddress((void**)&WIH,  g_WIH);
    cudaGetSymbolAddress((void**)&WHH,  g_WHH);
    cudaGetSymbolAddress((void**)&WP,   g_WPK);
    cudaGetSymbolAddress((void**)&BPK,  g_BPK);
    cudaGetSymbolAddress((void**)&OQ,   g_OQ);
    cudaGetSymbolAddress((void**)&OKp,  g_OKs);
    cudaGetSymbolAddress((void**)&OV,   g_OV);
    cudaGetSymbolAddress((void**)&OSK,  g_OSK);
    cudaGetSymbolAddress((void**)&RP,   g_RP);
    cudaGetSymbolAddress((void**)&ESRC, g_ESRC);
    cudaGetSymbolAddress((void**)&EAS,  g_EAS);
    cudaGetSymbolAddress((void**)&CNT,  g_CNT);
    cudaGetSymbolAddress((void**)&CUR,  g_CUR);

    const int SMEM = NSTG * STG_BYTES;  // 96KB
    const int TPB = 256;

    // ---- streams/events created ONCE (first call = correctness run), reused on
    //      every subsequent call (incl. graph capture) -> no device-memory delta
    //      during capture. Work launched is identical on every call.
    static cudaStream_t sCSR = nullptr, sW0 = nullptr, sW1 = nullptr;
    static cudaEvent_t evF, evCSR, evGate[TT], evW0, evW1;
    static bool init_done = false;
    if (!init_done) {
        cudaFuncSetAttribute(k_pgemm, cudaFuncAttributeMaxDynamicSharedMemorySize, SMEM);
        cudaStreamCreateWithFlags(&sCSR, cudaStreamNonBlocking);
        cudaStreamCreateWithFlags(&sW0,  cudaStreamNonBlocking);
        cudaStreamCreateWithFlags(&sW1,  cudaStreamNonBlocking);
        cudaEventCreateWithFlags(&evF,   cudaEventDisableTiming);
        cudaEventCreateWithFlags(&evCSR, cudaEventDisableTiming);
        cudaEventCreateWithFlags(&evW0,  cudaEventDisableTiming);
        cudaEventCreateWithFlags(&evW1,  cudaEventDisableTiming);
        for (int t = 0; t < TT; t++) cudaEventCreateWithFlags(&evGate[t], cudaEventDisableTiming);
        init_done = true;
    }

    cudaEventRecord(evF, 0);
    cudaStreamWaitEvent(sCSR, evF, 0);
    cudaStreamWaitEvent(sW0,  evF, 0);
    cudaStreamWaitEvent(sW1,  evF, 0);

    // CSR branch: build CSR + conv weight prep
    k_zero_i<<<(TT * NN + TPB - 1) / TPB, TPB, 0, sCSR>>>(CNT, TT * NN);
    k_hist<<<(TT * EE + TPB - 1) / TPB, TPB, 0, sCSR>>>(ei, CNT);
    k_scan<<<TT, 1024, 0, sCSR>>>(CNT, RP, CUR);
    k_scatter<<<(TT * EE + TPB - 1) / TPB, TPB, 0, sCSR>>>(ei, ea, CUR, ESRC, EAS);
    k_prep_conv<<<(2 * QKVS * DD + TPB - 1) / TPB, TPB, 0, sCSR>>>(
        cWq, cWk, cWv, cWs, cbq, cbk, cbv, cbs, WP, BPK);
    cudaEventRecord(evCSR, sCSR);

    // main branch: GRU chain, recording a gate event per t
    k_prep_main<<<(TT * NN * IN_DIM + TPB - 1) / TPB, TPB>>>(x_seq, X, gW_ih, gW_hh, WIH, WHH);
    k_pgemm<<<dim3(G3 / 128, (TT * NN + 127) / 128), 256, SMEM>>>(
        X, WIH, gb_ih, GI, TT * NN, G3, IN_DIM, 0);

    for (int t = 0; t < TT; t++) {
        if (t > 0) {
            k_pgemm<<<dim3(G3 / 128, (NN + 127) / 128), 256, SMEM>>>(
                Hf + (size_t)(t - 1) * NN * DD, WHH, gb_hh, GH, NN, G3, DD, 0);
        }
        k_gru_gate<<<(NN * DD + TPB - 1) / TPB, TPB>>>(
            GI + (size_t)t * NN * G3, GH, gb_hh, H,
            Hf + (size_t)t * NN * DD, t == 0 ? 1 : 0);
        cudaEventRecord(evGate[t], 0);
    }

    // worker branches: per-t pipelines (QKVS-L0 -> conv-L0 -> QKVS-L1 -> conv-L1)
    cudaStreamWaitEvent(sW0, evCSR, 0);
    cudaStreamWaitEvent(sW1, evCSR, 0);
    cudaStream_t workers[2] = {sW0, sW1};
    for (int t = 0; t < TT; t++) {
        cudaStream_t s = workers[t & 1];
        cudaStreamWaitEvent(s, evGate[t], 0);
        const __half* Hf_t = Hf + (size_t)t * NN * DD;
        __half* QK_t  = QK + (size_t)t * NN * QKVS;
        __half* HA_t  = HA + (size_t)t * NN * DD;
        __half* HA2_t = HA2 + (size_t)t * NN * DD;
        const int* rp_t   = RP + t * (NN + 1);
        const int* es_t   = ESRC + (size_t)t * EE;
        const float* ea_t = EAS + (size_t)t * EE;

        k_pgemm<<<dim3(QKVS / 128, (NN + 127) / 128), 256, SMEM, s>>>(
            Hf_t, WP, BPK, QK_t, NN, QKVS, DD, 1);
        k_conv_t<<<NN / 8, 256, 0, s>>>(QK_t, rp_t, es_t, ea_t, cWe, HA_t);
        k_pgemm<<<dim3(QKVS / 128, (NN + 127) / 128), 256, SMEM, s>>>(
            HA_t, WP + QKVS * DD, BPK + QKVS, QK_t, NN, QKVS, DD, 1);
        k_conv_t<<<NN / 8, 256, 0, s>>>(QK_t, rp_t, es_t, ea_t, cWe + DD, HA2_t);
    }
    cudaEventRecord(evW0, sW0);
    cudaEventRecord(evW1, sW1);

    // join and finish on main stream
    cudaStreamWaitEvent(0, evW0, 0);
    cudaStreamWaitEvent(0, evW1, 0);
    k_out_node<<<NN / 8, 256>>>(HA2, oWq, obq, oWk, obk, oWv, obv, oWs, obs, OQ, OKp, OV, OSK);
    k_out_edge<<<(NN + TPB - 1) / TPB, TPB>>>(RP + (TT - 1) * (NN + 1),
                                              ESRC + (size_t)(TT - 1) * EE, EAS + (size_t)(TT - 1) * EE,
                                              oWe, OQ, OKp, OV, OSK, (float*)d_out);
}